// round 6
// baseline (speedup 1.0000x reference)
#include <cuda_runtime.h>
#include <cstdint>
#include <math.h>

// ---------------- problem constants ----------------
#define BATCH 2
#define CH    128
#define LL    4096
#define NS    8

#define D1M  128
#define D1I  256
#define DT1R 8
#define DBL1 24
#define D2M  4096
#define D2I  8192
#define DT2R 256
#define DBL2 272      // dt_rank(256) + 2*8

#define NCH  32
#define CLEN 128

// ---------------- scratch ----------------
__device__ __align__(16) float g_xn1[BATCH*LL*D1M];
__device__ __align__(16) float g_xz1[BATCH*LL*2*D1I];
__device__ __align__(16) float g_xc1[BATCH*LL*D1I];
__device__ __align__(16) float g_dbl1[BATCH*LL*DBL1];
__device__ __align__(16) float g_delta1[BATCH*LL*D1I];
__device__ __align__(16) float g_y1[BATCH*LL*D1I];
__device__ __align__(16) float g_out1[BATCH*LL*D1M];
__device__ __align__(16) float g_ckP[BATCH*D1I*NCH*NS];
__device__ __align__(16) float g_ckH[BATCH*D1I*NCH*NS];
__device__ __align__(16) float g_hin[BATCH*D1I*NCH*NS];

__device__ __align__(16) float g_xn2[BATCH*CH*D2M];
__device__ __align__(16) float g_xz2[BATCH*CH*2*D2I];
__device__ __align__(16) float g_xc2[BATCH*CH*D2I];
__device__ __align__(16) float g_dbl2[BATCH*CH*DBL2];
__device__ __align__(16) float g_delta2[BATCH*CH*D2I];
__device__ __align__(16) float g_y2[BATCH*CH*D2I];
__device__ __align__(16) float g_out2[BATCH*CH*D2M];

// ---------------- helpers ----------------
__device__ __forceinline__ uint32_t smem_u32(const void* p) {
    uint32_t a;
    asm("{ .reg .u64 t; cvta.to.shared.u64 t, %1; cvt.u32.u64 %0, t; }" : "=r"(a) : "l"(p));
    return a;
}
__device__ __forceinline__ void cp_async16(uint32_t dst, const void* src, int sz) {
    asm volatile("cp.async.cg.shared.global [%0], [%1], 16, %2;"
                 :: "r"(dst), "l"(src), "r"(sz) : "memory");
}
#define CP_COMMIT() asm volatile("cp.async.commit_group;" ::: "memory")
#define CP_WAIT2()  asm volatile("cp.async.wait_group 2;" ::: "memory")
#define CP_WAIT1()  asm volatile("cp.async.wait_group 1;" ::: "memory")
#define CP_WAIT0()  asm volatile("cp.async.wait_group 0;" ::: "memory")

__device__ __forceinline__ uint32_t f2tf32(float f) {
    uint32_t r;
    asm("cvt.rna.tf32.f32 %0, %1;" : "=r"(r) : "f"(f));
    return r;
}
__device__ __forceinline__ float rnd_tf32(float v) { return __uint_as_float(f2tf32(v)); }

__device__ __forceinline__ void mma_tf32(float* d, const uint32_t* a, const uint32_t* b) {
    asm volatile(
        "mma.sync.aligned.m16n8k8.row.col.f32.tf32.tf32.f32 "
        "{%0,%1,%2,%3}, {%4,%5,%6,%7}, {%8,%9}, {%0,%1,%2,%3};"
        : "+f"(d[0]), "+f"(d[1]), "+f"(d[2]), "+f"(d[3])
        : "r"(a[0]), "r"(a[1]), "r"(a[2]), "r"(a[3]), "r"(b[0]), "r"(b[1]));
}

__device__ __forceinline__ float siluf(float v) { return v / (1.f + __expf(-v)); }
__device__ __forceinline__ float softplusf(float v) { return (v > 20.f) ? v : log1pf(__expf(v)); }

// ======================================================================
// tf32 mma.sync GEMM: C[m, n] = sum_k X[m, k] * W[n, k]
// A-side (X, activations) pre-rounded to tf32 at the producer.
// BM=128, BN=128; warp grid 2x4, warp tile 64x32. 4-stage cp.async,
// single __syncthreads per K-iter + double-buffered register fragments.
// grid = (N/128 tiles, M/128 tiles, ksplits); block = 256 threads
// EPI: 0 = store, 1 = atomicAdd (split-K), 2 = softplus(v + bias[n]) store
// ======================================================================
#define SROW 36
#define GROWS 256                       // 128 A rows + 128 B rows per stage
#define GSTG (GROWS * SROW)             // floats per stage
#define GSMEM_BYTES (4 * GSTG * 4)      // 144 KB

template<int EPI>
__global__ void __launch_bounds__(256, 1)
tf32_gemm(const float* __restrict__ X, const float* __restrict__ W,
          const float* __restrict__ bias, float* __restrict__ C,
          int M, int N, int kLen, int ldx, int ldw, int ldc) {
    extern __shared__ float sm[];
    const int tid = threadIdx.x;
    const int wid = tid >> 5, lane = tid & 31;
    const int gid = lane >> 2, tig = lane & 3;
    const int wm = wid >> 2, wn = wid & 3;        // 2 x 4 warp grid
    const int m0 = blockIdx.y * 128, n0 = blockIdx.x * 128;
    const long k0 = (long)blockIdx.z * kLen;
    const int nIter = kLen / 32;
    const uint32_t sS = smem_u32(sm);

    float acc[4][4][4];
    #pragma unroll
    for (int i = 0; i < 4; i++)
        #pragma unroll
        for (int j = 0; j < 4; j++)
            #pragma unroll
            for (int r = 0; r < 4; r++) acc[i][j][r] = 0.f;

    auto load_stage = [&](int buf, long kk) {
        #pragma unroll
        for (int i = 0; i < 8; i++) {
            int idx = tid + i * 256;           // 0..2047
            int row = idx >> 3, ch = idx & 7;
            uint32_t off = (uint32_t)((buf * GROWS + row) * SROW + ch * 4) * 4u;
            if (row < 128) {
                cp_async16(sS + off, X + (long)(m0 + row) * ldx + kk + ch * 4, 16);
            } else {
                int nr = n0 + row - 128;
                const float* gb = W + (long)(nr < N ? nr : 0) * ldw + kk + ch * 4;
                cp_async16(sS + off, gb, nr < N ? 16 : 0);
            }
        }
    };

    // per-warp base pointers (A rows for wm, B rows for wn)
    const int aBase = wm * 64 * SROW;
    const int bBase = (128 + wn * 32) * SROW;

    auto ldfrag = [&](const float* S, int ks, uint32_t (&a)[4][4], uint32_t (&b)[4][2]) {
        const int kc = ks * 8 + tig;
        const float* Aw = S + aBase + gid * SROW + kc;
        #pragma unroll
        for (int mi = 0; mi < 4; mi++) {
            const float* p = Aw + mi * 16 * SROW;
            a[mi][0] = __float_as_uint(p[0]);
            a[mi][1] = __float_as_uint(p[8 * SROW]);
            a[mi][2] = __float_as_uint(p[4]);
            a[mi][3] = __float_as_uint(p[8 * SROW + 4]);
        }
        const float* Bw = S + bBase + gid * SROW + kc;
        #pragma unroll
        for (int ni = 0; ni < 4; ni++) {
            const float* p = Bw + ni * 8 * SROW;
            b[ni][0] = f2tf32(p[0]);
            b[ni][1] = f2tf32(p[4]);
        }
    };

    load_stage(0, k0); CP_COMMIT();
    load_stage(1, k0 + 32); CP_COMMIT();
    load_stage(2, k0 + 64); CP_COMMIT();

    uint32_t aF[2][4][4], bF[2][4][2];

    for (int it = 0; it < nIter; it++) {
        if (it + 2 < nIter) { CP_WAIT2(); }
        else if (it + 1 < nIter) { CP_WAIT1(); }
        else { CP_WAIT0(); }
        __syncthreads();

        const float* S = sm + (it & 3) * GSTG;
        ldfrag(S, 0, aF[0], bF[0]);
        // issue next stage's gmem loads early (writes stage (it+3)&3 — safe post-sync)
        if (it + 3 < nIter) { load_stage((it + 3) & 3, k0 + (long)(it + 3) * 32); CP_COMMIT(); }

        #pragma unroll
        for (int ks = 0; ks < 4; ks++) {
            if (ks < 3) ldfrag(S, ks + 1, aF[(ks + 1) & 1], bF[(ks + 1) & 1]);
            #pragma unroll
            for (int mi = 0; mi < 4; mi++)
                #pragma unroll
                for (int ni = 0; ni < 4; ni++)
                    mma_tf32(acc[mi][ni], aF[ks & 1][mi], bF[ks & 1][ni]);
        }
    }

    // epilogue
    #pragma unroll
    for (int mi = 0; mi < 4; mi++) {
        int m = m0 + wm * 64 + mi * 16 + gid;
        #pragma unroll
        for (int ni = 0; ni < 4; ni++) {
            int n = n0 + wn * 32 + ni * 8 + tig * 2;
            if (n >= N) continue;
            float* p0 = C + (long)m * ldc + n;
            float* p1 = C + (long)(m + 8) * ldc + n;
            float c0 = acc[mi][ni][0], c1 = acc[mi][ni][1];
            float c2 = acc[mi][ni][2], c3 = acc[mi][ni][3];
            if (EPI == 1) {
                atomicAdd(p0, c0); atomicAdd(p0 + 1, c1);
                atomicAdd(p1, c2); atomicAdd(p1 + 1, c3);
            } else if (EPI == 2) {
                float b0v = bias[n], b1v = bias[n + 1];
                *reinterpret_cast<float2*>(p0) =
                    make_float2(softplusf(c0 + b0v), softplusf(c1 + b1v));
                *reinterpret_cast<float2*>(p1) =
                    make_float2(softplusf(c2 + b0v), softplusf(c3 + b1v));
            } else {
                *reinterpret_cast<float2*>(p0) = make_float2(c0, c1);
                *reinterpret_cast<float2*>(p1) = make_float2(c2, c3);
            }
        }
    }
}

// ---------------- LayerNorm 1 (output tf32-rounded) ----------------
__global__ void ln1_kernel(const float* __restrict__ x, const float* __restrict__ g,
                           const float* __restrict__ bta, float* __restrict__ out) {
    int b  = blockIdx.x >> 7;
    int l0 = (blockIdx.x & 127) * 32;
    __shared__ float sm[128 * 33];
    int tid = threadIdx.x;
    #pragma unroll
    for (int i = 0; i < 16; i++) {
        int idx = tid + i * 256;
        int c = idx >> 5, l = idx & 31;
        sm[c * 33 + l] = x[((long)b * CH + c) * LL + l0 + l];
    }
    __syncthreads();
    int warp = tid >> 5, lane = tid & 31;
    for (int t = warp; t < 32; t += 8) {
        float v[4]; float s = 0.f, sq = 0.f;
        #pragma unroll
        for (int j = 0; j < 4; j++) {
            v[j] = sm[(lane + 32 * j) * 33 + t];
            s += v[j]; sq += v[j] * v[j];
        }
        #pragma unroll
        for (int o = 16; o; o >>= 1) {
            s  += __shfl_xor_sync(0xffffffffu, s,  o);
            sq += __shfl_xor_sync(0xffffffffu, sq, o);
        }
        float mu  = s * (1.f / 128.f);
        float var = sq * (1.f / 128.f) - mu * mu;
        float rs  = rsqrtf(var + 1e-5f);
        #pragma unroll
        for (int j = 0; j < 4; j++) {
            int c = lane + 32 * j;
            out[((long)b * LL + l0 + t) * D1M + c] = rnd_tf32((v[j] - mu) * rs * g[c] + bta[c]);
        }
    }
}

// ---------------- LayerNorm 2 (output tf32-rounded) ----------------
__global__ void ln2_kernel(const float* __restrict__ x, const float* __restrict__ g,
                           const float* __restrict__ bta, float* __restrict__ out) {
    long row = blockIdx.x;
    const float* xr = x + row * D2M;
    float* orow = out + row * D2M;
    int tid = threadIdx.x;
    float v[16]; float s = 0.f, sq = 0.f;
    #pragma unroll
    for (int i = 0; i < 16; i++) {
        v[i] = xr[i * 256 + tid];
        s += v[i]; sq += v[i] * v[i];
    }
    #pragma unroll
    for (int o = 16; o; o >>= 1) {
        s  += __shfl_xor_sync(0xffffffffu, s,  o);
        sq += __shfl_xor_sync(0xffffffffu, sq, o);
    }
    __shared__ float ss[8], sqq[8];
    int lane = tid & 31, warp = tid >> 5;
    if (!lane) { ss[warp] = s; sqq[warp] = sq; }
    __syncthreads();
    s = 0.f; sq = 0.f;
    #pragma unroll
    for (int w = 0; w < 8; w++) { s += ss[w]; sq += sqq[w]; }
    float mu  = s * (1.f / 4096.f);
    float var = sq * (1.f / 4096.f) - mu * mu;
    float rs  = rsqrtf(var + 1e-5f);
    #pragma unroll
    for (int i = 0; i < 16; i++) {
        int col = i * 256 + tid;
        orow[col] = rnd_tf32((v[i] - mu) * rs * g[col] + bta[col]);
    }
}

// ---------------- fallback SGEMM (dt1: K=8) ----------------
template<int ACT, bool HASBIAS>
__global__ void sgemm_kernel(const float* __restrict__ X, const float* __restrict__ W,
                             const float* __restrict__ bias, float* __restrict__ out,
                             int M, int N, int K, int lda, int ldc) {
    constexpr int BM = 64, BN = 64, BK = 32, PAD = 4;
    __shared__ float As[BK][BM + PAD];
    __shared__ float Bs[BK][BN + PAD];
    int bm = blockIdx.y * BM, bn = blockIdx.x * BN;
    int tid = threadIdx.x;
    int tx = tid & 15, ty = tid >> 4;
    float acc[4][4] = {};
    for (int k0 = 0; k0 < K; k0 += BK) {
        #pragma unroll
        for (int i = 0; i < 2; i++) {
            int idx = tid + i * 256;
            int row = idx >> 3;
            int kc  = (idx & 7) << 2;
            int k   = k0 + kc;
            float4 va = make_float4(0.f, 0.f, 0.f, 0.f);
            float4 vb = make_float4(0.f, 0.f, 0.f, 0.f);
            if (k < K) {
                int m = bm + row;
                if (m < M) va = *reinterpret_cast<const float4*>(X + (long)m * lda + k);
                int n = bn + row;
                if (n < N) vb = *reinterpret_cast<const float4*>(W + (long)n * K + k);
            }
            As[kc][row] = va.x; As[kc + 1][row] = va.y; As[kc + 2][row] = va.z; As[kc + 3][row] = va.w;
            Bs[kc][row] = vb.x; Bs[kc + 1][row] = vb.y; Bs[kc + 2][row] = vb.z; Bs[kc + 3][row] = vb.w;
        }
        __syncthreads();
        #pragma unroll
        for (int kk = 0; kk < BK; kk++) {
            float4 a = *reinterpret_cast<const float4*>(&As[kk][ty << 2]);
            float4 b = *reinterpret_cast<const float4*>(&Bs[kk][tx << 2]);
            float av[4] = {a.x, a.y, a.z, a.w};
            float bv[4] = {b.x, b.y, b.z, b.w};
            #pragma unroll
            for (int i = 0; i < 4; i++)
                #pragma unroll
                for (int j = 0; j < 4; j++)
                    acc[i][j] += av[i] * bv[j];
        }
        __syncthreads();
    }
    #pragma unroll
    for (int i = 0; i < 4; i++) {
        int m = bm + (ty << 2) + i;
        if (m >= M) continue;
        #pragma unroll
        for (int j = 0; j < 4; j++) {
            int n = bn + (tx << 2) + j;
            if (n >= N) continue;
            float v = acc[i][j];
            if (HASBIAS) v += bias[n];
            if (ACT == 1) v = softplusf(v);
            out[(long)m * ldc + n] = v;
        }
    }
}

// ---------------- causal depthwise conv (K=4) + SiLU, float4-vectorized ----------------
__global__ void conv_silu_kernel(const float* __restrict__ xz, const float* __restrict__ w,
                                 const float* __restrict__ bias, float* __restrict__ out,
                                 int Ltok, int dinner) {
    long tid = (long)blockIdx.x * 256 + threadIdx.x;     // one thread = 4 channels
    long total = (long)BATCH * Ltok * (dinner / 4);
    if (tid >= total) return;
    int d4 = (int)(tid % (dinner / 4)) * 4;
    long t = tid / (dinner / 4);
    int l = (int)(t % Ltok);
    int b = (int)(t / Ltok);
    int rowstride = 2 * dinner;
    const float* base = xz + ((long)b * Ltok + l) * rowstride + d4;
    float4 bv = *reinterpret_cast<const float4*>(bias + d4);
    float acc0 = bv.x, acc1 = bv.y, acc2 = bv.z, acc3 = bv.w;
    #pragma unroll
    for (int k = 0; k < 4; k++) {
        int ll = l - 3 + k;
        if (ll >= 0) {
            float4 xv = *reinterpret_cast<const float4*>(base + (long)(ll - l) * rowstride);
            acc0 += xv.x * w[(d4 + 0) * 4 + k];
            acc1 += xv.y * w[(d4 + 1) * 4 + k];
            acc2 += xv.z * w[(d4 + 2) * 4 + k];
            acc3 += xv.w * w[(d4 + 3) * 4 + k];
        }
    }
    float4 ov;
    ov.x = rnd_tf32(siluf(acc0)); ov.y = rnd_tf32(siluf(acc1));
    ov.z = rnd_tf32(siluf(acc2)); ov.w = rnd_tf32(siluf(acc3));
    *reinterpret_cast<float4*>(out + ((long)b * Ltok + l) * dinner + d4) = ov;
}

// ---------------- path-1 scan ----------------
__global__ void scan1_partial(const float* __restrict__ delta, const float* __restrict__ xc,
                              const float* __restrict__ dbl, const float* __restrict__ Alog) {
    int d = threadIdx.x;
    int chunk = blockIdx.x & (NCH - 1);
    int b = blockIdx.x >> 5;
    float A[NS], h[NS], P[NS];
    #pragma unroll
    for (int s = 0; s < NS; s++) { A[s] = -__expf(Alog[d * NS + s]); h[s] = 0.f; P[s] = 1.f; }
    int l0 = chunk * CLEN;
    for (int i = 0; i < CLEN; i++) {
        long t = (long)b * LL + l0 + i;
        float dl = delta[t * D1I + d];
        float xv = xc[t * D1I + d];
        const float* bl = dbl + t * DBL1 + DT1R;
        float dx = dl * xv;
        #pragma unroll
        for (int s = 0; s < NS; s++) {
            float dA = __expf(dl * A[s]);
            h[s] = dA * h[s] + dx * bl[s];
            P[s] *= dA;
        }
    }
    long o = (((long)b * D1I + d) * NCH + chunk) * NS;
    #pragma unroll
    for (int s = 0; s < NS; s++) { g_ckP[o + s] = P[s]; g_ckH[o + s] = h[s]; }
}

__global__ void scan1_carry() {
    int idx = blockIdx.x * 256 + threadIdx.x;
    if (idx >= BATCH * D1I) return;
    long base = (long)idx * NCH * NS;
    float h[NS];
    #pragma unroll
    for (int s = 0; s < NS; s++) h[s] = 0.f;
    for (int c = 0; c < NCH; c++) {
        long o = base + (long)c * NS;
        #pragma unroll
        for (int s = 0; s < NS; s++) {
            g_hin[o + s] = h[s];
            h[s] = g_ckP[o + s] * h[s] + g_ckH[o + s];
        }
    }
}

__global__ void scan1_final(const float* __restrict__ delta, const float* __restrict__ xc,
                            const float* __restrict__ dbl, const float* __restrict__ Alog,
                            const float* __restrict__ Dp, const float* __restrict__ xz,
                            float* __restrict__ y) {
    int d = threadIdx.x;
    int chunk = blockIdx.x & (NCH - 1);
    int b = blockIdx.x >> 5;
    float A[NS], h[NS];
    long hb = (((long)b * D1I + d) * NCH + chunk) * NS;
    #pragma unroll
    for (int s = 0; s < NS; s++) { A[s] = -__expf(Alog[d * NS + s]); h[s] = g_hin[hb + s]; }
    float Dv = Dp[d];
    int l0 = chunk * CLEN;
    for (int i = 0; i < CLEN; i++) {
        long t = (long)b * LL + l0 + i;
        float dl = delta[t * D1I + d];
        float xv = xc[t * D1I + d];
        const float* bl = dbl + t * DBL1 + DT1R;
        float dx = dl * xv;
        float acc = 0.f;
        #pragma unroll
        for (int s = 0; s < NS; s++) {
            float dA = __expf(dl * A[s]);
            h[s] = dA * h[s] + dx * bl[s];
            acc += h[s] * bl[NS + s];
        }
        float z = xz[t * (2 * D1I) + D1I + d];
        y[t * D1I + d] = rnd_tf32((acc + xv * Dv) * siluf(z));
    }
}

// ---------------- path-2 scan ----------------
__global__ void scan2_kernel(const float* __restrict__ delta, const float* __restrict__ xc,
                             const float* __restrict__ dbl, const float* __restrict__ Alog,
                             const float* __restrict__ Dp, const float* __restrict__ xz,
                             float* __restrict__ y) {
    int d = (blockIdx.x & 31) * 256 + threadIdx.x;
    int b = blockIdx.x >> 5;
    float A[NS], h[NS];
    #pragma unroll
    for (int s = 0; s < NS; s++) { A[s] = -__expf(Alog[d * NS + s]); h[s] = 0.f; }
    float Dv = Dp[d];
    for (int l = 0; l < CH; l++) {
        long t = (long)b * CH + l;
        float dl = delta[t * D2I + d];
        float xv = xc[t * D2I + d];
        const float* bl = dbl + t * DBL2 + DT2R;
        float dx = dl * xv;
        float acc = 0.f;
        #pragma unroll
        for (int s = 0; s < NS; s++) {
            float dA = __expf(dl * A[s]);
            h[s] = dA * h[s] + dx * bl[s];
            acc += h[s] * bl[NS + s];
        }
        float z = xz[t * (2 * D2I) + D2I + d];
        y[t * D2I + d] = rnd_tf32((acc + xv * Dv) * siluf(z));
    }
}

// ---------------- combine ----------------
__global__ void combine_kernel(const float* __restrict__ x, float* __restrict__ out) {
    long i = (long)blockIdx.x * 256 + threadIdx.x;
    if (i >= (long)BATCH * CH * LL) return;
    int l = (int)(i % LL);
    long t = i / LL;
    int c = (int)(t % CH);
    int b = (int)(t / CH);
    out[i] = x[i] + g_out2[i] + g_out1[((long)b * LL + l) * D1M + c];
}

// ---------------- launch ----------------
extern "C" void kernel_launch(void* const* d_in, const int* in_sizes, int n_in,
                              void* d_out, int out_size) {
    const float* x        = (const float*)d_in[0];
    const float* ln1_g    = (const float*)d_in[1];
    const float* ln1_b    = (const float*)d_in[2];
    const float* ln2_g    = (const float*)d_in[3];
    const float* ln2_b    = (const float*)d_in[4];
    const float* m1_in_w  = (const float*)d_in[5];
    const float* m1_cw    = (const float*)d_in[6];
    const float* m1_cb    = (const float*)d_in[7];
    const float* m1_xp_w  = (const float*)d_in[8];
    const float* m1_dt_w  = (const float*)d_in[9];
    const float* m1_dt_b  = (const float*)d_in[10];
    const float* m1_Alog  = (const float*)d_in[11];
    const float* m1_D     = (const float*)d_in[12];
    const float* m1_out_w = (const float*)d_in[13];
    const float* m2_in_w  = (const float*)d_in[14];
    const float* m2_cw    = (const float*)d_in[15];
    const float* m2_cb    = (const float*)d_in[16];
    const float* m2_xp_w  = (const float*)d_in[17];
    const float* m2_dt_w  = (const float*)d_in[18];
    const float* m2_dt_b  = (const float*)d_in[19];
    const float* m2_Alog  = (const float*)d_in[20];
    const float* m2_D     = (const float*)d_in[21];
    const float* m2_out_w = (const float*)d_in[22];
    float* out = (float*)d_out;

    float *pxn1, *pxz1, *pxc1, *pdbl1, *pdelta1, *py1, *pout1;
    float *pxn2, *pxz2, *pxc2, *pdbl2, *pdelta2, *py2, *pout2;
    cudaGetSymbolAddress((void**)&pxn1, g_xn1);
    cudaGetSymbolAddress((void**)&pxz1, g_xz1);
    cudaGetSymbolAddress((void**)&pxc1, g_xc1);
    cudaGetSymbolAddress((void**)&pdbl1, g_dbl1);
    cudaGetSymbolAddress((void**)&pdelta1, g_delta1);
    cudaGetSymbolAddress((void**)&py1, g_y1);
    cudaGetSymbolAddress((void**)&pout1, g_out1);
    cudaGetSymbolAddress((void**)&pxn2, g_xn2);
    cudaGetSymbolAddress((void**)&pxz2, g_xz2);
    cudaGetSymbolAddress((void**)&pxc2, g_xc2);
    cudaGetSymbolAddress((void**)&pdbl2, g_dbl2);
    cudaGetSymbolAddress((void**)&pdelta2, g_delta2);
    cudaGetSymbolAddress((void**)&py2, g_y2);
    cudaGetSymbolAddress((void**)&pout2, g_out2);

    cudaFuncSetAttribute(tf32_gemm<0>, cudaFuncAttributeMaxDynamicSharedMemorySize, GSMEM_BYTES);
    cudaFuncSetAttribute(tf32_gemm<1>, cudaFuncAttributeMaxDynamicSharedMemorySize, GSMEM_BYTES);
    cudaFuncSetAttribute(tf32_gemm<2>, cudaFuncAttributeMaxDynamicSharedMemorySize, GSMEM_BYTES);

    const int T = 256;
    // launch 0,1: split-K accumulators (out1 shares pout1 memset inside same memset? no — separate)
    cudaMemsetAsync(pdbl2, 0, sizeof(float) * BATCH * CH * DBL2);
    cudaMemsetAsync(pout2, 0, sizeof(float) * BATCH * CH * D2M);
    // launch 2,3
    ln1_kernel<<<BATCH * (LL / 32), T>>>(x, ln1_g, ln1_b, pxn1);
    ln2_kernel<<<BATCH * CH, T>>>(x, ln2_g, ln2_b, pxn2);
    // launch 4: in1: xz1[8192, 512] = xn1 @ in_w^T
    tf32_gemm<0><<<dim3(4, 64, 1), 256, GSMEM_BYTES>>>(
        pxn1, m1_in_w, nullptr, pxz1, BATCH * LL, 2 * D1I, D1M, D1M, D1M, 2 * D1I);
    // launch 5 (PROFILED): in2: xz2[256, 16384] = xn2 @ in_w^T  (256 CTAs)
    tf32_gemm<0><<<dim3(128, 2, 1), 256, GSMEM_BYTES>>>(
        pxn2, m2_in_w, nullptr, pxz2, BATCH * CH, 2 * D2I, D2M, D2M, D2M, 2 * D2I);

    // ---- rest of path 1 ----
    conv_silu_kernel<<<(BATCH * LL * D1I / 4 + T - 1) / T, T>>>(pxz1, m1_cw, m1_cb, pxc1, LL, D1I);
    tf32_gemm<0><<<dim3(1, 64, 1), 256, GSMEM_BYTES>>>(
        pxc1, m1_xp_w, nullptr, pdbl1, BATCH * LL, DBL1, D1I, D1I, D1I, DBL1);
    sgemm_kernel<1, true><<<dim3((D1I + 63) / 64, (BATCH * LL) / 64), T>>>(
        pdbl1, m1_dt_w, m1_dt_b, pdelta1, BATCH * LL, D1I, DT1R, DBL1, D1I);
    scan1_partial<<<BATCH * NCH, D1I>>>(pdelta1, pxc1, pdbl1, m1_Alog);
    scan1_carry<<<(BATCH * D1I + T - 1) / T, T>>>();
    scan1_final<<<BATCH * NCH, D1I>>>(pdelta1, pxc1, pdbl1, m1_Alog, m1_D, pxz1, py1);
    // out1: split-K=2 atomic (128 CTAs)
    cudaMemsetAsync(pout1, 0, sizeof(float) * BATCH * LL * D1M);
    tf32_gemm<1><<<dim3(1, 64, 2), 256, GSMEM_BYTES>>>(
        py1, m1_out_w, nullptr, pout1, BATCH * LL, D1M, D1I / 2, D1I, D1I, D1M);

    // ---- rest of path 2 ----
    conv_silu_kernel<<<(BATCH * CH * D2I / 4 + T - 1) / T, T>>>(pxz2, m2_cw, m2_cb, pxc2, CH, D2I);
    // xp2: dbl2[256, 272] split-K=16 atomic (96 CTAs)
    tf32_gemm<1><<<dim3(3, 2, 16), 256, GSMEM_BYTES>>>(
        pxc2, m2_xp_w, nullptr, pdbl2, BATCH * CH, DBL2, D2I / 16, D2I, D2I, DBL2);
    // dt2: delta2[256, 8192] = softplus(dbl2[:, :256] @ dt_w^T + b) (128 CTAs)
    tf32_gemm<2><<<dim3(64, 2, 1), 256, GSMEM_BYTES>>>(
        pdbl2, m2_dt_w, m2_dt_b, pdelta2, BATCH * CH, D2I, DT2R, DBL2, DT2R, D2I);
    scan2_kernel<<<BATCH * (D2I / 256), T>>>(pdelta2, pxc2, pdbl2, m2_Alog, m2_D, pxz2, py2);
    // out2: out2[256, 4096] split-K=4 atomic (256 CTAs)
    tf32_gemm<1><<<dim3(32, 2, 4), 256, GSMEM_BYTES>>>(
        py2, m2_out_w, nullptr, pout2, BATCH * CH, D2M, D2I / 4, D2I, D2I, D2M);

    // ---- combine ----
    combine_kernel<<<(BATCH * CH * LL + T - 1) / T, T>>>(x, out);
}

// round 7
// speedup vs baseline: 1.1044x; 1.1044x over previous
#include <cuda_runtime.h>
#include <cstdint>
#include <math.h>

// ---------------- problem constants ----------------
#define BATCH 2
#define CH    128
#define LL    4096
#define NS    8

#define D1M  128
#define D1I  256
#define DT1R 8
#define DBL1 24
#define D2M  4096
#define D2I  8192
#define DT2R 256
#define DBL2 272      // dt_rank(256) + 2*8

#define NCH  32
#define CLEN 128

// ---------------- scratch ----------------
__device__ __align__(16) float g_xn1[BATCH*LL*D1M];
__device__ __align__(16) float g_xz1[BATCH*LL*2*D1I];
__device__ __align__(16) float g_xc1[BATCH*LL*D1I];
__device__ __align__(16) float g_dbl1[BATCH*LL*DBL1];
__device__ __align__(16) float g_delta1[BATCH*LL*D1I];
__device__ __align__(16) float g_y1[BATCH*LL*D1I];
__device__ __align__(16) float g_out1[BATCH*LL*D1M];
__device__ __align__(16) float g_ckP[BATCH*D1I*NCH*NS];
__device__ __align__(16) float g_ckH[BATCH*D1I*NCH*NS];
__device__ __align__(16) float g_hin[BATCH*D1I*NCH*NS];

__device__ __align__(16) float g_xn2[BATCH*CH*D2M];
__device__ __align__(16) float g_xz2[BATCH*CH*2*D2I];
__device__ __align__(16) float g_xc2[BATCH*CH*D2I];
__device__ __align__(16) float g_dbl2[BATCH*CH*DBL2];
__device__ __align__(16) float g_delta2[BATCH*CH*D2I];
__device__ __align__(16) float g_y2[BATCH*CH*D2I];
__device__ __align__(16) float g_out2[BATCH*CH*D2M];

// ---------------- helpers ----------------
__device__ __forceinline__ uint32_t smem_u32(const void* p) {
    uint32_t a;
    asm("{ .reg .u64 t; cvta.to.shared.u64 t, %1; cvt.u32.u64 %0, t; }" : "=r"(a) : "l"(p));
    return a;
}
__device__ __forceinline__ void cp_async16(uint32_t dst, const void* src, int sz) {
    asm volatile("cp.async.cg.shared.global [%0], [%1], 16, %2;"
                 :: "r"(dst), "l"(src), "r"(sz) : "memory");
}
#define CP_COMMIT() asm volatile("cp.async.commit_group;" ::: "memory")
#define CP_WAIT1()  asm volatile("cp.async.wait_group 1;" ::: "memory")
#define CP_WAIT0()  asm volatile("cp.async.wait_group 0;" ::: "memory")

__device__ __forceinline__ uint32_t f2tf32(float f) {
    uint32_t r;
    asm("cvt.rna.tf32.f32 %0, %1;" : "=r"(r) : "f"(f));
    return r;
}
__device__ __forceinline__ float rnd_tf32(float v) { return __uint_as_float(f2tf32(v)); }

__device__ __forceinline__ void mma_tf32(float* d, const uint32_t* a, const uint32_t* b) {
    asm volatile(
        "mma.sync.aligned.m16n8k8.row.col.f32.tf32.tf32.f32 "
        "{%0,%1,%2,%3}, {%4,%5,%6,%7}, {%8,%9}, {%0,%1,%2,%3};"
        : "+f"(d[0]), "+f"(d[1]), "+f"(d[2]), "+f"(d[3])
        : "r"(a[0]), "r"(a[1]), "r"(a[2]), "r"(a[3]), "r"(b[0]), "r"(b[1]));
}

__device__ __forceinline__ float siluf(float v) { return v / (1.f + __expf(-v)); }
__device__ __forceinline__ float softplusf(float v) { return (v > 20.f) ? v : log1pf(__expf(v)); }

// ======================================================================
// tf32 mma.sync GEMM: C[m, n] = sum_k X[m, k] * W[n, k]
// A-side (X, activations) pre-rounded to tf32 at the producer.
// BM=128, BN=128; warp grid 2x4, warp tile 64x32. 3-stage cp.async,
// single __syncthreads per K-iter; 2 CTAs/SM (regs capped at 128).
// grid = (N/128 tiles, M/128 tiles, ksplits); block = 256 threads
// EPI: 0 = store, 1 = atomicAdd (split-K), 2 = softplus(v + bias[n]) store
// ======================================================================
#define SROW 36
#define GROWS 256                       // 128 A rows + 128 B rows per stage
#define GSTG (GROWS * SROW)             // floats per stage
#define GSMEM_BYTES (3 * GSTG * 4)      // 108 KB -> 2 CTAs/SM

template<int EPI>
__global__ void __launch_bounds__(256, 2)
tf32_gemm(const float* __restrict__ X, const float* __restrict__ W,
          const float* __restrict__ bias, float* __restrict__ C,
          int M, int N, int kLen, int ldx, int ldw, int ldc) {
    extern __shared__ float sm[];
    const int tid = threadIdx.x;
    const int wid = tid >> 5, lane = tid & 31;
    const int gid = lane >> 2, tig = lane & 3;
    const int wm = wid >> 2, wn = wid & 3;        // 2 x 4 warp grid
    const int m0 = blockIdx.y * 128, n0 = blockIdx.x * 128;
    const long k0 = (long)blockIdx.z * kLen;
    const int nIter = kLen / 32;
    const uint32_t sS = smem_u32(sm);

    float acc[4][4][4];
    #pragma unroll
    for (int i = 0; i < 4; i++)
        #pragma unroll
        for (int j = 0; j < 4; j++)
            #pragma unroll
            for (int r = 0; r < 4; r++) acc[i][j][r] = 0.f;

    auto load_stage = [&](int buf, long kk) {
        #pragma unroll
        for (int i = 0; i < 8; i++) {
            int idx = tid + i * 256;           // 0..2047
            int row = idx >> 3, ch = idx & 7;
            uint32_t off = (uint32_t)((buf * GROWS + row) * SROW + ch * 4) * 4u;
            if (row < 128) {
                cp_async16(sS + off, X + (long)(m0 + row) * ldx + kk + ch * 4, 16);
            } else {
                int nr = n0 + row - 128;
                const float* gb = W + (long)(nr < N ? nr : 0) * ldw + kk + ch * 4;
                cp_async16(sS + off, gb, nr < N ? 16 : 0);
            }
        }
    };

    load_stage(0, k0); CP_COMMIT();
    load_stage(1, k0 + 32); CP_COMMIT();

    for (int it = 0; it < nIter; it++) {
        if (it + 1 < nIter) { CP_WAIT1(); } else { CP_WAIT0(); }
        __syncthreads();

        const float* A  = sm + (it % 3) * GSTG;
        const float* Bp = A + 128 * SROW;
        #pragma unroll
        for (int ks = 0; ks < 4; ks++) {
            uint32_t a[4][4], b[4][2];
            const int kc = ks * 8 + tig;
            #pragma unroll
            for (int mi = 0; mi < 4; mi++) {
                int r = wm * 64 + mi * 16 + gid;
                a[mi][0] = __float_as_uint(A[r * SROW + kc]);
                a[mi][1] = __float_as_uint(A[(r + 8) * SROW + kc]);
                a[mi][2] = __float_as_uint(A[r * SROW + kc + 4]);
                a[mi][3] = __float_as_uint(A[(r + 8) * SROW + kc + 4]);
            }
            #pragma unroll
            for (int ni = 0; ni < 4; ni++) {
                int rn = wn * 32 + ni * 8 + gid;
                b[ni][0] = f2tf32(Bp[rn * SROW + kc]);
                b[ni][1] = f2tf32(Bp[rn * SROW + kc + 4]);
            }
            #pragma unroll
            for (int mi = 0; mi < 4; mi++)
                #pragma unroll
                for (int ni = 0; ni < 4; ni++)
                    mma_tf32(acc[mi][ni], a[mi], b[ni]);
        }
        // load AFTER compute: writes stage (it+2)%3, concurrent reads stage it%3 — disjoint
        if (it + 2 < nIter) { load_stage((it + 2) % 3, k0 + (long)(it + 2) * 32); CP_COMMIT(); }
    }

    // epilogue
    #pragma unroll
    for (int mi = 0; mi < 4; mi++) {
        int m = m0 + wm * 64 + mi * 16 + gid;
        #pragma unroll
        for (int ni = 0; ni < 4; ni++) {
            int n = n0 + wn * 32 + ni * 8 + tig * 2;
            if (n >= N) continue;
            float* p0 = C + (long)m * ldc + n;
            float* p1 = C + (long)(m + 8) * ldc + n;
            float c0 = acc[mi][ni][0], c1 = acc[mi][ni][1];
            float c2 = acc[mi][ni][2], c3 = acc[mi][ni][3];
            if (EPI == 1) {
                atomicAdd(p0, c0); atomicAdd(p0 + 1, c1);
                atomicAdd(p1, c2); atomicAdd(p1 + 1, c3);
            } else if (EPI == 2) {
                float b0v = bias[n], b1v = bias[n + 1];
                *reinterpret_cast<float2*>(p0) =
                    make_float2(softplusf(c0 + b0v), softplusf(c1 + b1v));
                *reinterpret_cast<float2*>(p1) =
                    make_float2(softplusf(c2 + b0v), softplusf(c3 + b1v));
            } else {
                *reinterpret_cast<float2*>(p0) = make_float2(c0, c1);
                *reinterpret_cast<float2*>(p1) = make_float2(c2, c3);
            }
        }
    }
}

// ---------------- LayerNorm 1 (output tf32-rounded) ----------------
__global__ void ln1_kernel(const float* __restrict__ x, const float* __restrict__ g,
                           const float* __restrict__ bta, float* __restrict__ out) {
    int b  = blockIdx.x >> 7;
    int l0 = (blockIdx.x & 127) * 32;
    __shared__ float sm[128 * 33];
    int tid = threadIdx.x;
    #pragma unroll
    for (int i = 0; i < 16; i++) {
        int idx = tid + i * 256;
        int c = idx >> 5, l = idx & 31;
        sm[c * 33 + l] = x[((long)b * CH + c) * LL + l0 + l];
    }
    __syncthreads();
    int warp = tid >> 5, lane = tid & 31;
    for (int t = warp; t < 32; t += 8) {
        float v[4]; float s = 0.f, sq = 0.f;
        #pragma unroll
        for (int j = 0; j < 4; j++) {
            v[j] = sm[(lane + 32 * j) * 33 + t];
            s += v[j]; sq += v[j] * v[j];
        }
        #pragma unroll
        for (int o = 16; o; o >>= 1) {
            s  += __shfl_xor_sync(0xffffffffu, s,  o);
            sq += __shfl_xor_sync(0xffffffffu, sq, o);
        }
        float mu  = s * (1.f / 128.f);
        float var = sq * (1.f / 128.f) - mu * mu;
        float rs  = rsqrtf(var + 1e-5f);
        #pragma unroll
        for (int j = 0; j < 4; j++) {
            int c = lane + 32 * j;
            out[((long)b * LL + l0 + t) * D1M + c] = rnd_tf32((v[j] - mu) * rs * g[c] + bta[c]);
        }
    }
}

// ---------------- LayerNorm 2 (output tf32-rounded) ----------------
__global__ void ln2_kernel(const float* __restrict__ x, const float* __restrict__ g,
                           const float* __restrict__ bta, float* __restrict__ out) {
    long row = blockIdx.x;
    const float* xr = x + row * D2M;
    float* orow = out + row * D2M;
    int tid = threadIdx.x;
    float v[16]; float s = 0.f, sq = 0.f;
    #pragma unroll
    for (int i = 0; i < 16; i++) {
        v[i] = xr[i * 256 + tid];
        s += v[i]; sq += v[i] * v[i];
    }
    #pragma unroll
    for (int o = 16; o; o >>= 1) {
        s  += __shfl_xor_sync(0xffffffffu, s,  o);
        sq += __shfl_xor_sync(0xffffffffu, sq, o);
    }
    __shared__ float ss[8], sqq[8];
    int lane = tid & 31, warp = tid >> 5;
    if (!lane) { ss[warp] = s; sqq[warp] = sq; }
    __syncthreads();
    s = 0.f; sq = 0.f;
    #pragma unroll
    for (int w = 0; w < 8; w++) { s += ss[w]; sq += sqq[w]; }
    float mu  = s * (1.f / 4096.f);
    float var = sq * (1.f / 4096.f) - mu * mu;
    float rs  = rsqrtf(var + 1e-5f);
    #pragma unroll
    for (int i = 0; i < 16; i++) {
        int col = i * 256 + tid;
        orow[col] = rnd_tf32((v[i] - mu) * rs * g[col] + bta[col]);
    }
}

// ---------------- fallback SGEMM (dt1: K=8) ----------------
template<int ACT, bool HASBIAS>
__global__ void sgemm_kernel(const float* __restrict__ X, const float* __restrict__ W,
                             const float* __restrict__ bias, float* __restrict__ out,
                             int M, int N, int K, int lda, int ldc) {
    constexpr int BM = 64, BN = 64, BK = 32, PAD = 4;
    __shared__ float As[BK][BM + PAD];
    __shared__ float Bs[BK][BN + PAD];
    int bm = blockIdx.y * BM, bn = blockIdx.x * BN;
    int tid = threadIdx.x;
    int tx = tid & 15, ty = tid >> 4;
    float acc[4][4] = {};
    for (int k0 = 0; k0 < K; k0 += BK) {
        #pragma unroll
        for (int i = 0; i < 2; i++) {
            int idx = tid + i * 256;
            int row = idx >> 3;
            int kc  = (idx & 7) << 2;
            int k   = k0 + kc;
            float4 va = make_float4(0.f, 0.f, 0.f, 0.f);
            float4 vb = make_float4(0.f, 0.f, 0.f, 0.f);
            if (k < K) {
                int m = bm + row;
                if (m < M) va = *reinterpret_cast<const float4*>(X + (long)m * lda + k);
                int n = bn + row;
                if (n < N) vb = *reinterpret_cast<const float4*>(W + (long)n * K + k);
            }
            As[kc][row] = va.x; As[kc + 1][row] = va.y; As[kc + 2][row] = va.z; As[kc + 3][row] = va.w;
            Bs[kc][row] = vb.x; Bs[kc + 1][row] = vb.y; Bs[kc + 2][row] = vb.z; Bs[kc + 3][row] = vb.w;
        }
        __syncthreads();
        #pragma unroll
        for (int kk = 0; kk < BK; kk++) {
            float4 a = *reinterpret_cast<const float4*>(&As[kk][ty << 2]);
            float4 b = *reinterpret_cast<const float4*>(&Bs[kk][tx << 2]);
            float av[4] = {a.x, a.y, a.z, a.w};
            float bv[4] = {b.x, b.y, b.z, b.w};
            #pragma unroll
            for (int i = 0; i < 4; i++)
                #pragma unroll
                for (int j = 0; j < 4; j++)
                    acc[i][j] += av[i] * bv[j];
        }
        __syncthreads();
    }
    #pragma unroll
    for (int i = 0; i < 4; i++) {
        int m = bm + (ty << 2) + i;
        if (m >= M) continue;
        #pragma unroll
        for (int j = 0; j < 4; j++) {
            int n = bn + (tx << 2) + j;
            if (n >= N) continue;
            float v = acc[i][j];
            if (HASBIAS) v += bias[n];
            if (ACT == 1) v = softplusf(v);
            out[(long)m * ldc + n] = v;
        }
    }
}

// ---------------- causal depthwise conv (K=4) + SiLU, float4-vectorized ----------------
__global__ void conv_silu_kernel(const float* __restrict__ xz, const float* __restrict__ w,
                                 const float* __restrict__ bias, float* __restrict__ out,
                                 int Ltok, int dinner) {
    long tid = (long)blockIdx.x * 256 + threadIdx.x;     // one thread = 4 channels
    long total = (long)BATCH * Ltok * (dinner / 4);
    if (tid >= total) return;
    int d4 = (int)(tid % (dinner / 4)) * 4;
    long t = tid / (dinner / 4);
    int l = (int)(t % Ltok);
    int b = (int)(t / Ltok);
    int rowstride = 2 * dinner;
    const float* base = xz + ((long)b * Ltok + l) * rowstride + d4;
    float4 bv = *reinterpret_cast<const float4*>(bias + d4);
    float acc0 = bv.x, acc1 = bv.y, acc2 = bv.z, acc3 = bv.w;
    #pragma unroll
    for (int k = 0; k < 4; k++) {
        int ll = l - 3 + k;
        if (ll >= 0) {
            float4 xv = *reinterpret_cast<const float4*>(base + (long)(ll - l) * rowstride);
            acc0 += xv.x * w[(d4 + 0) * 4 + k];
            acc1 += xv.y * w[(d4 + 1) * 4 + k];
            acc2 += xv.z * w[(d4 + 2) * 4 + k];
            acc3 += xv.w * w[(d4 + 3) * 4 + k];
        }
    }
    float4 ov;
    ov.x = rnd_tf32(siluf(acc0)); ov.y = rnd_tf32(siluf(acc1));
    ov.z = rnd_tf32(siluf(acc2)); ov.w = rnd_tf32(siluf(acc3));
    *reinterpret_cast<float4*>(out + ((long)b * Ltok + l) * dinner + d4) = ov;
}

// ---------------- path-1 scan ----------------
__global__ void scan1_partial(const float* __restrict__ delta, const float* __restrict__ xc,
                              const float* __restrict__ dbl, const float* __restrict__ Alog) {
    int d = threadIdx.x;
    int chunk = blockIdx.x & (NCH - 1);
    int b = blockIdx.x >> 5;
    float A[NS], h[NS], P[NS];
    #pragma unroll
    for (int s = 0; s < NS; s++) { A[s] = -__expf(Alog[d * NS + s]); h[s] = 0.f; P[s] = 1.f; }
    int l0 = chunk * CLEN;
    for (int i = 0; i < CLEN; i++) {
        long t = (long)b * LL + l0 + i;
        float dl = delta[t * D1I + d];
        float xv = xc[t * D1I + d];
        const float* bl = dbl + t * DBL1 + DT1R;
        float dx = dl * xv;
        #pragma unroll
        for (int s = 0; s < NS; s++) {
            float dA = __expf(dl * A[s]);
            h[s] = dA * h[s] + dx * bl[s];
            P[s] *= dA;
        }
    }
    long o = (((long)b * D1I + d) * NCH + chunk) * NS;
    #pragma unroll
    for (int s = 0; s < NS; s++) { g_ckP[o + s] = P[s]; g_ckH[o + s] = h[s]; }
}

__global__ void scan1_carry() {
    int idx = blockIdx.x * 256 + threadIdx.x;
    if (idx >= BATCH * D1I) return;
    long base = (long)idx * NCH * NS;
    float h[NS];
    #pragma unroll
    for (int s = 0; s < NS; s++) h[s] = 0.f;
    for (int c = 0; c < NCH; c++) {
        long o = base + (long)c * NS;
        #pragma unroll
        for (int s = 0; s < NS; s++) {
            g_hin[o + s] = h[s];
            h[s] = g_ckP[o + s] * h[s] + g_ckH[o + s];
        }
    }
}

__global__ void scan1_final(const float* __restrict__ delta, const float* __restrict__ xc,
                            const float* __restrict__ dbl, const float* __restrict__ Alog,
                            const float* __restrict__ Dp, const float* __restrict__ xz,
                            float* __restrict__ y) {
    int d = threadIdx.x;
    int chunk = blockIdx.x & (NCH - 1);
    int b = blockIdx.x >> 5;
    float A[NS], h[NS];
    long hb = (((long)b * D1I + d) * NCH + chunk) * NS;
    #pragma unroll
    for (int s = 0; s < NS; s++) { A[s] = -__expf(Alog[d * NS + s]); h[s] = g_hin[hb + s]; }
    float Dv = Dp[d];
    int l0 = chunk * CLEN;
    for (int i = 0; i < CLEN; i++) {
        long t = (long)b * LL + l0 + i;
        float dl = delta[t * D1I + d];
        float xv = xc[t * D1I + d];
        const float* bl = dbl + t * DBL1 + DT1R;
        float dx = dl * xv;
        float acc = 0.f;
        #pragma unroll
        for (int s = 0; s < NS; s++) {
            float dA = __expf(dl * A[s]);
            h[s] = dA * h[s] + dx * bl[s];
            acc += h[s] * bl[NS + s];
        }
        float z = xz[t * (2 * D1I) + D1I + d];
        y[t * D1I + d] = rnd_tf32((acc + xv * Dv) * siluf(z));
    }
}

// ---------------- path-2 scan ----------------
__global__ void scan2_kernel(const float* __restrict__ delta, const float* __restrict__ xc,
                             const float* __restrict__ dbl, const float* __restrict__ Alog,
                             const float* __restrict__ Dp, const float* __restrict__ xz,
                             float* __restrict__ y) {
    int d = (blockIdx.x & 31) * 256 + threadIdx.x;
    int b = blockIdx.x >> 5;
    float A[NS], h[NS];
    #pragma unroll
    for (int s = 0; s < NS; s++) { A[s] = -__expf(Alog[d * NS + s]); h[s] = 0.f; }
    float Dv = Dp[d];
    for (int l = 0; l < CH; l++) {
        long t = (long)b * CH + l;
        float dl = delta[t * D2I + d];
        float xv = xc[t * D2I + d];
        const float* bl = dbl + t * DBL2 + DT2R;
        float dx = dl * xv;
        float acc = 0.f;
        #pragma unroll
        for (int s = 0; s < NS; s++) {
            float dA = __expf(dl * A[s]);
            h[s] = dA * h[s] + dx * bl[s];
            acc += h[s] * bl[NS + s];
        }
        float z = xz[t * (2 * D2I) + D2I + d];
        y[t * D2I + d] = rnd_tf32((acc + xv * Dv) * siluf(z));
    }
}

// ---------------- combine ----------------
__global__ void combine_kernel(const float* __restrict__ x, float* __restrict__ out) {
    long i = (long)blockIdx.x * 256 + threadIdx.x;
    if (i >= (long)BATCH * CH * LL) return;
    int l = (int)(i % LL);
    long t = i / LL;
    int c = (int)(t % CH);
    int b = (int)(t / CH);
    out[i] = x[i] + g_out2[i] + g_out1[((long)b * LL + l) * D1M + c];
}

// ---------------- launch ----------------
extern "C" void kernel_launch(void* const* d_in, const int* in_sizes, int n_in,
                              void* d_out, int out_size) {
    const float* x        = (const float*)d_in[0];
    const float* ln1_g    = (const float*)d_in[1];
    const float* ln1_b    = (const float*)d_in[2];
    const float* ln2_g    = (const float*)d_in[3];
    const float* ln2_b    = (const float*)d_in[4];
    const float* m1_in_w  = (const float*)d_in[5];
    const float* m1_cw    = (const float*)d_in[6];
    const float* m1_cb    = (const float*)d_in[7];
    const float* m1_xp_w  = (const float*)d_in[8];
    const float* m1_dt_w  = (const float*)d_in[9];
    const float* m1_dt_b  = (const float*)d_in[10];
    const float* m1_Alog  = (const float*)d_in[11];
    const float* m1_D     = (const float*)d_in[12];
    const float* m1_out_w = (const float*)d_in[13];
    const float* m2_in_w  = (const float*)d_in[14];
    const float* m2_cw    = (const float*)d_in[15];
    const float* m2_cb    = (const float*)d_in[16];
    const float* m2_xp_w  = (const float*)d_in[17];
    const float* m2_dt_w  = (const float*)d_in[18];
    const float* m2_dt_b  = (const float*)d_in[19];
    const float* m2_Alog  = (const float*)d_in[20];
    const float* m2_D     = (const float*)d_in[21];
    const float* m2_out_w = (const float*)d_in[22];
    float* out = (float*)d_out;

    float *pxn1, *pxz1, *pxc1, *pdbl1, *pdelta1, *py1, *pout1;
    float *pxn2, *pxz2, *pxc2, *pdbl2, *pdelta2, *py2, *pout2;
    cudaGetSymbolAddress((void**)&pxn1, g_xn1);
    cudaGetSymbolAddress((void**)&pxz1, g_xz1);
    cudaGetSymbolAddress((void**)&pxc1, g_xc1);
    cudaGetSymbolAddress((void**)&pdbl1, g_dbl1);
    cudaGetSymbolAddress((void**)&pdelta1, g_delta1);
    cudaGetSymbolAddress((void**)&py1, g_y1);
    cudaGetSymbolAddress((void**)&pout1, g_out1);
    cudaGetSymbolAddress((void**)&pxn2, g_xn2);
    cudaGetSymbolAddress((void**)&pxz2, g_xz2);
    cudaGetSymbolAddress((void**)&pxc2, g_xc2);
    cudaGetSymbolAddress((void**)&pdbl2, g_dbl2);
    cudaGetSymbolAddress((void**)&pdelta2, g_delta2);
    cudaGetSymbolAddress((void**)&py2, g_y2);
    cudaGetSymbolAddress((void**)&pout2, g_out2);

    cudaFuncSetAttribute(tf32_gemm<0>, cudaFuncAttributeMaxDynamicSharedMemorySize, GSMEM_BYTES);
    cudaFuncSetAttribute(tf32_gemm<1>, cudaFuncAttributeMaxDynamicSharedMemorySize, GSMEM_BYTES);
    cudaFuncSetAttribute(tf32_gemm<2>, cudaFuncAttributeMaxDynamicSharedMemorySize, GSMEM_BYTES);

    const int T = 256;
    // launch 0,1: split-K accumulators
    cudaMemsetAsync(pdbl2, 0, sizeof(float) * BATCH * CH * DBL2);
    cudaMemsetAsync(pout2, 0, sizeof(float) * BATCH * CH * D2M);
    // launch 2,3
    ln1_kernel<<<BATCH * (LL / 32), T>>>(x, ln1_g, ln1_b, pxn1);
    ln2_kernel<<<BATCH * CH, T>>>(x, ln2_g, ln2_b, pxn2);
    // launch 4: in1: xz1[8192, 512] = xn1 @ in_w^T
    tf32_gemm<0><<<dim3(4, 64, 1), 256, GSMEM_BYTES>>>(
        pxn1, m1_in_w, nullptr, pxz1, BATCH * LL, 2 * D1I, D1M, D1M, D1M, 2 * D1I);
    // launch 5 (PROFILED): in2: xz2[256, 16384] = xn2 @ in_w^T  (256 CTAs)
    tf32_gemm<0><<<dim3(128, 2, 1), 256, GSMEM_BYTES>>>(
        pxn2, m2_in_w, nullptr, pxz2, BATCH * CH, 2 * D2I, D2M, D2M, D2M, 2 * D2I);

    // ---- rest of path 1 ----
    conv_silu_kernel<<<(BATCH * LL * D1I / 4 + T - 1) / T, T>>>(pxz1, m1_cw, m1_cb, pxc1, LL, D1I);
    tf32_gemm<0><<<dim3(1, 64, 1), 256, GSMEM_BYTES>>>(
        pxc1, m1_xp_w, nullptr, pdbl1, BATCH * LL, DBL1, D1I, D1I, D1I, DBL1);
    sgemm_kernel<1, true><<<dim3((D1I + 63) / 64, (BATCH * LL) / 64), T>>>(
        pdbl1, m1_dt_w, m1_dt_b, pdelta1, BATCH * LL, D1I, DT1R, DBL1, D1I);
    scan1_partial<<<BATCH * NCH, D1I>>>(pdelta1, pxc1, pdbl1, m1_Alog);
    scan1_carry<<<(BATCH * D1I + T - 1) / T, T>>>();
    scan1_final<<<BATCH * NCH, D1I>>>(pdelta1, pxc1, pdbl1, m1_Alog, m1_D, pxz1, py1);
    // out1: split-K=2 atomic (128 CTAs)
    cudaMemsetAsync(pout1, 0, sizeof(float) * BATCH * LL * D1M);
    tf32_gemm<1><<<dim3(1, 64, 2), 256, GSMEM_BYTES>>>(
        py1, m1_out_w, nullptr, pout1, BATCH * LL, D1M, D1I / 2, D1I, D1I, D1M);

    // ---- rest of path 2 ----
    conv_silu_kernel<<<(BATCH * CH * D2I / 4 + T - 1) / T, T>>>(pxz2, m2_cw, m2_cb, pxc2, CH, D2I);
    // xp2: dbl2[256, 272] split-K=16 atomic (96 CTAs)
    tf32_gemm<1><<<dim3(3, 2, 16), 256, GSMEM_BYTES>>>(
        pxc2, m2_xp_w, nullptr, pdbl2, BATCH * CH, DBL2, D2I / 16, D2I, D2I, DBL2);
    // dt2: delta2[256, 8192] = softplus(dbl2[:, :256] @ dt_w^T + b) (128 CTAs)
    tf32_gemm<2><<<dim3(64, 2, 1), 256, GSMEM_BYTES>>>(
        pdbl2, m2_dt_w, m2_dt_b, pdelta2, BATCH * CH, D2I, DT2R, DBL2, DT2R, D2I);
    scan2_kernel<<<BATCH * (D2I / 256), T>>>(pdelta2, pxc2, pdbl2, m2_Alog, m2_D, pxz2, py2);
    // out2: out2[256, 4096] split-K=4 atomic (256 CTAs)
    tf32_gemm<1><<<dim3(32, 2, 4), 256, GSMEM_BYTES>>>(
        py2, m2_out_w, nullptr, pout2, BATCH * CH, D2M, D2I / 4, D2I, D2I, D2M);

    // ---- combine ----
    combine_kernel<<<(BATCH * CH * LL + T - 1) / T, T>>>(x, out);
}

// round 8
// speedup vs baseline: 1.1405x; 1.0327x over previous
#include <cuda_runtime.h>
#include <cstdint>
#include <math.h>

// ---------------- problem constants ----------------
#define BATCH 2
#define CH    128
#define LL    4096
#define NS    8

#define D1M  128
#define D1I  256
#define DT1R 8
#define DBL1 24
#define D2M  4096
#define D2I  8192
#define DT2R 256
#define DBL2 272      // dt_rank(256) + 2*8

#define NCH  32
#define CLEN 128

// ---------------- scratch ----------------
__device__ __align__(16) float g_xn1[BATCH*LL*D1M];
__device__ __align__(16) float g_xz1[BATCH*LL*2*D1I];
__device__ __align__(16) float g_xc1[BATCH*LL*D1I];
__device__ __align__(16) float g_dbl1[BATCH*LL*DBL1];
__device__ __align__(16) float g_delta1[BATCH*LL*D1I];
__device__ __align__(16) float g_y1[BATCH*LL*D1I];
__device__ __align__(16) float g_out1[BATCH*LL*D1M];
__device__ __align__(16) float g_ckP[BATCH*D1I*NCH*NS];
__device__ __align__(16) float g_ckH[BATCH*D1I*NCH*NS];
__device__ __align__(16) float g_hin[BATCH*D1I*NCH*NS];

__device__ __align__(16) float g_xn2[BATCH*CH*D2M];
__device__ __align__(16) float g_xz2[BATCH*CH*2*D2I];
__device__ __align__(16) float g_xc2[BATCH*CH*D2I];
__device__ __align__(16) float g_dbl2[BATCH*CH*DBL2];
__device__ __align__(16) float g_delta2[BATCH*CH*D2I];
__device__ __align__(16) float g_y2[BATCH*CH*D2I];
__device__ __align__(16) float g_out2[BATCH*CH*D2M];

// ---------------- helpers ----------------
__device__ __forceinline__ uint32_t smem_u32(const void* p) {
    uint32_t a;
    asm("{ .reg .u64 t; cvta.to.shared.u64 t, %1; cvt.u32.u64 %0, t; }" : "=r"(a) : "l"(p));
    return a;
}
__device__ __forceinline__ void cp_async16(uint32_t dst, const void* src, int sz) {
    asm volatile("cp.async.cg.shared.global [%0], [%1], 16, %2;"
                 :: "r"(dst), "l"(src), "r"(sz) : "memory");
}
#define CP_COMMIT() asm volatile("cp.async.commit_group;" ::: "memory")
#define CP_WAIT1()  asm volatile("cp.async.wait_group 1;" ::: "memory")
#define CP_WAIT0()  asm volatile("cp.async.wait_group 0;" ::: "memory")

__device__ __forceinline__ uint32_t f2tf32(float f) {
    uint32_t r;
    asm("cvt.rna.tf32.f32 %0, %1;" : "=r"(r) : "f"(f));
    return r;
}
__device__ __forceinline__ float rnd_tf32(float v) { return __uint_as_float(f2tf32(v)); }

__device__ __forceinline__ void mma_tf32(float* d, const uint32_t* a, const uint32_t* b) {
    asm volatile(
        "mma.sync.aligned.m16n8k8.row.col.f32.tf32.tf32.f32 "
        "{%0,%1,%2,%3}, {%4,%5,%6,%7}, {%8,%9}, {%0,%1,%2,%3};"
        : "+f"(d[0]), "+f"(d[1]), "+f"(d[2]), "+f"(d[3])
        : "r"(a[0]), "r"(a[1]), "r"(a[2]), "r"(a[3]), "r"(b[0]), "r"(b[1]));
}

__device__ __forceinline__ void ldsm_x4(uint32_t& r0, uint32_t& r1, uint32_t& r2, uint32_t& r3,
                                        uint32_t addr) {
    asm volatile("ldmatrix.sync.aligned.m8n8.x4.shared.b16 {%0,%1,%2,%3}, [%4];"
                 : "=r"(r0), "=r"(r1), "=r"(r2), "=r"(r3) : "r"(addr));
}

__device__ __forceinline__ float siluf(float v) { return v / (1.f + __expf(-v)); }
__device__ __forceinline__ float softplusf(float v) { return (v > 20.f) ? v : log1pf(__expf(v)); }

// ======================================================================
// tf32 mma.sync GEMM: C[m, n] = sum_k X[m, k] * W[n, k]
// A-side (X, activations) pre-rounded to tf32 at the producer.
// BM=128, BN=128; warp grid 2x4, warp tile 64x32. 3-stage cp.async,
// single __syncthreads per K-iter; 2 CTAs/SM; ldmatrix fragment loads.
// grid = (N/128 tiles, M/128 tiles, ksplits); block = 256 threads
// EPI: 0 = store, 1 = atomicAdd (split-K), 2 = softplus(v + bias[n]) store
// ======================================================================
#define SROW 36
#define GROWS 256                       // 128 A rows + 128 B rows per stage
#define GSTG (GROWS * SROW)             // floats per stage
#define GSMEM_BYTES (3 * GSTG * 4)      // 108 KB -> 2 CTAs/SM

template<int EPI>
__global__ void __launch_bounds__(256, 2)
tf32_gemm(const float* __restrict__ X, const float* __restrict__ W,
          const float* __restrict__ bias, float* __restrict__ C,
          int M, int N, int kLen, int ldx, int ldw, int ldc) {
    extern __shared__ float sm[];
    const int tid = threadIdx.x;
    const int wid = tid >> 5, lane = tid & 31;
    const int gid = lane >> 2, tig = lane & 3;
    const int wm = wid >> 2, wn = wid & 3;        // 2 x 4 warp grid
    const int m0 = blockIdx.y * 128, n0 = blockIdx.x * 128;
    const long k0 = (long)blockIdx.z * kLen;
    const int nIter = kLen / 32;
    const uint32_t sS = smem_u32(sm);

    float acc[4][4][4];
    #pragma unroll
    for (int i = 0; i < 4; i++)
        #pragma unroll
        for (int j = 0; j < 4; j++)
            #pragma unroll
            for (int r = 0; r < 4; r++) acc[i][j][r] = 0.f;

    auto load_stage = [&](int buf, long kk) {
        #pragma unroll
        for (int i = 0; i < 8; i++) {
            int idx = tid + i * 256;           // 0..2047
            int row = idx >> 3, ch = idx & 7;
            uint32_t off = (uint32_t)((buf * GROWS + row) * SROW + ch * 4) * 4u;
            if (row < 128) {
                cp_async16(sS + off, X + (long)(m0 + row) * ldx + kk + ch * 4, 16);
            } else {
                int nr = n0 + row - 128;
                const float* gb = W + (long)(nr < N ? nr : 0) * ldw + kk + ch * 4;
                cp_async16(sS + off, gb, nr < N ? 16 : 0);
            }
        }
    };

    // ldmatrix per-thread base addresses (bytes):
    // A x4 (per mi): matrices {rows m..m+7, m+8..m+15} x {col kc, kc+4}
    const uint32_t aBase = sS +
        (uint32_t)(((wm * 64 + ((lane >> 3) & 1) * 8 + (lane & 7)) * SROW
                    + ((lane >> 4) & 1) * 4) * 4);
    // B x4 (per ni-pair p): reg0/1 = ni=2p cols {kc,kc+4}; reg2/3 = ni=2p+1
    const uint32_t bBase = sS +
        (uint32_t)(((128 + wn * 32 + ((lane >> 4) & 1) * 8 + (lane & 7)) * SROW
                    + ((lane >> 3) & 1) * 4) * 4);

    load_stage(0, k0); CP_COMMIT();
    load_stage(1, k0 + 32); CP_COMMIT();

    for (int it = 0; it < nIter; it++) {
        if (it + 1 < nIter) { CP_WAIT1(); } else { CP_WAIT0(); }
        __syncthreads();

        const uint32_t stgOff = (uint32_t)((it % 3) * GSTG * 4);
        const uint32_t aS = aBase + stgOff;
        const uint32_t bS = bBase + stgOff;
        #pragma unroll
        for (int ks = 0; ks < 4; ks++) {
            uint32_t a[4][4], b[4][2];
            #pragma unroll
            for (int mi = 0; mi < 4; mi++)
                ldsm_x4(a[mi][0], a[mi][1], a[mi][2], a[mi][3],
                        aS + (uint32_t)(mi * 16 * SROW * 4 + ks * 32));
            #pragma unroll
            for (int p = 0; p < 2; p++) {
                uint32_t r0, r1, r2, r3;
                ldsm_x4(r0, r1, r2, r3,
                        bS + (uint32_t)(p * 16 * SROW * 4 + ks * 32));
                b[2 * p][0]     = f2tf32(__uint_as_float(r0));
                b[2 * p][1]     = f2tf32(__uint_as_float(r1));
                b[2 * p + 1][0] = f2tf32(__uint_as_float(r2));
                b[2 * p + 1][1] = f2tf32(__uint_as_float(r3));
            }
            #pragma unroll
            for (int mi = 0; mi < 4; mi++)
                #pragma unroll
                for (int ni = 0; ni < 4; ni++)
                    mma_tf32(acc[mi][ni], a[mi], b[ni]);
        }
        // load AFTER compute: writes stage (it+2)%3, concurrent reads stage it%3 — disjoint
        if (it + 2 < nIter) { load_stage((it + 2) % 3, k0 + (long)(it + 2) * 32); CP_COMMIT(); }
    }

    // epilogue
    #pragma unroll
    for (int mi = 0; mi < 4; mi++) {
        int m = m0 + wm * 64 + mi * 16 + gid;
        #pragma unroll
        for (int ni = 0; ni < 4; ni++) {
            int n = n0 + wn * 32 + ni * 8 + tig * 2;
            if (n >= N) continue;
            float* p0 = C + (long)m * ldc + n;
            float* p1 = C + (long)(m + 8) * ldc + n;
            float c0 = acc[mi][ni][0], c1 = acc[mi][ni][1];
            float c2 = acc[mi][ni][2], c3 = acc[mi][ni][3];
            if (EPI == 1) {
                atomicAdd(p0, c0); atomicAdd(p0 + 1, c1);
                atomicAdd(p1, c2); atomicAdd(p1 + 1, c3);
            } else if (EPI == 2) {
                float b0v = bias[n], b1v = bias[n + 1];
                *reinterpret_cast<float2*>(p0) =
                    make_float2(softplusf(c0 + b0v), softplusf(c1 + b1v));
                *reinterpret_cast<float2*>(p1) =
                    make_float2(softplusf(c2 + b0v), softplusf(c3 + b1v));
            } else {
                *reinterpret_cast<float2*>(p0) = make_float2(c0, c1);
                *reinterpret_cast<float2*>(p1) = make_float2(c2, c3);
            }
        }
    }
}

// ---------------- LayerNorm 1 (output tf32-rounded) ----------------
__global__ void ln1_kernel(const float* __restrict__ x, const float* __restrict__ g,
                           const float* __restrict__ bta, float* __restrict__ out) {
    int b  = blockIdx.x >> 7;
    int l0 = (blockIdx.x & 127) * 32;
    __shared__ float sm[128 * 33];
    int tid = threadIdx.x;
    #pragma unroll
    for (int i = 0; i < 16; i++) {
        int idx = tid + i * 256;
        int c = idx >> 5, l = idx & 31;
        sm[c * 33 + l] = x[((long)b * CH + c) * LL + l0 + l];
    }
    __syncthreads();
    int warp = tid >> 5, lane = tid & 31;
    for (int t = warp; t < 32; t += 8) {
        float v[4]; float s = 0.f, sq = 0.f;
        #pragma unroll
        for (int j = 0; j < 4; j++) {
            v[j] = sm[(lane + 32 * j) * 33 + t];
            s += v[j]; sq += v[j] * v[j];
        }
        #pragma unroll
        for (int o = 16; o; o >>= 1) {
            s  += __shfl_xor_sync(0xffffffffu, s,  o);
            sq += __shfl_xor_sync(0xffffffffu, sq, o);
        }
        float mu  = s * (1.f / 128.f);
        float var = sq * (1.f / 128.f) - mu * mu;
        float rs  = rsqrtf(var + 1e-5f);
        #pragma unroll
        for (int j = 0; j < 4; j++) {
            int c = lane + 32 * j;
            out[((long)b * LL + l0 + t) * D1M + c] = rnd_tf32((v[j] - mu) * rs * g[c] + bta[c]);
        }
    }
}

// ---------------- LayerNorm 2 (output tf32-rounded) ----------------
__global__ void ln2_kernel(const float* __restrict__ x, const float* __restrict__ g,
                           const float* __restrict__ bta, float* __restrict__ out) {
    long row = blockIdx.x;
    const float* xr = x + row * D2M;
    float* orow = out + row * D2M;
    int tid = threadIdx.x;
    float v[16]; float s = 0.f, sq = 0.f;
    #pragma unroll
    for (int i = 0; i < 16; i++) {
        v[i] = xr[i * 256 + tid];
        s += v[i]; sq += v[i] * v[i];
    }
    #pragma unroll
    for (int o = 16; o; o >>= 1) {
        s  += __shfl_xor_sync(0xffffffffu, s,  o);
        sq += __shfl_xor_sync(0xffffffffu, sq, o);
    }
    __shared__ float ss[8], sqq[8];
    int lane = tid & 31, warp = tid >> 5;
    if (!lane) { ss[warp] = s; sqq[warp] = sq; }
    __syncthreads();
    s = 0.f; sq = 0.f;
    #pragma unroll
    for (int w = 0; w < 8; w++) { s += ss[w]; sq += sqq[w]; }
    float mu  = s * (1.f / 4096.f);
    float var = sq * (1.f / 4096.f) - mu * mu;
    float rs  = rsqrtf(var + 1e-5f);
    #pragma unroll
    for (int i = 0; i < 16; i++) {
        int col = i * 256 + tid;
        orow[col] = rnd_tf32((v[i] - mu) * rs * g[col] + bta[col]);
    }
}

// ---------------- fallback SGEMM (dt1: K=8) ----------------
template<int ACT, bool HASBIAS>
__global__ void sgemm_kernel(const float* __restrict__ X, const float* __restrict__ W,
                             const float* __restrict__ bias, float* __restrict__ out,
                             int M, int N, int K, int lda, int ldc) {
    constexpr int BM = 64, BN = 64, BK = 32, PAD = 4;
    __shared__ float As[BK][BM + PAD];
    __shared__ float Bs[BK][BN + PAD];
    int bm = blockIdx.y * BM, bn = blockIdx.x * BN;
    int tid = threadIdx.x;
    int tx = tid & 15, ty = tid >> 4;
    float acc[4][4] = {};
    for (int k0 = 0; k0 < K; k0 += BK) {
        #pragma unroll
        for (int i = 0; i < 2; i++) {
            int idx = tid + i * 256;
            int row = idx >> 3;
            int kc  = (idx & 7) << 2;
            int k   = k0 + kc;
            float4 va = make_float4(0.f, 0.f, 0.f, 0.f);
            float4 vb = make_float4(0.f, 0.f, 0.f, 0.f);
            if (k < K) {
                int m = bm + row;
                if (m < M) va = *reinterpret_cast<const float4*>(X + (long)m * lda + k);
                int n = bn + row;
                if (n < N) vb = *reinterpret_cast<const float4*>(W + (long)n * K + k);
            }
            As[kc][row] = va.x; As[kc + 1][row] = va.y; As[kc + 2][row] = va.z; As[kc + 3][row] = va.w;
            Bs[kc][row] = vb.x; Bs[kc + 1][row] = vb.y; Bs[kc + 2][row] = vb.z; Bs[kc + 3][row] = vb.w;
        }
        __syncthreads();
        #pragma unroll
        for (int kk = 0; kk < BK; kk++) {
            float4 a = *reinterpret_cast<const float4*>(&As[kk][ty << 2]);
            float4 b = *reinterpret_cast<const float4*>(&Bs[kk][tx << 2]);
            float av[4] = {a.x, a.y, a.z, a.w};
            float bv[4] = {b.x, b.y, b.z, b.w};
            #pragma unroll
            for (int i = 0; i < 4; i++)
                #pragma unroll
                for (int j = 0; j < 4; j++)
                    acc[i][j] += av[i] * bv[j];
        }
        __syncthreads();
    }
    #pragma unroll
    for (int i = 0; i < 4; i++) {
        int m = bm + (ty << 2) + i;
        if (m >= M) continue;
        #pragma unroll
        for (int j = 0; j < 4; j++) {
            int n = bn + (tx << 2) + j;
            if (n >= N) continue;
            float v = acc[i][j];
            if (HASBIAS) v += bias[n];
            if (ACT == 1) v = softplusf(v);
            out[(long)m * ldc + n] = v;
        }
    }
}

// ---------------- causal depthwise conv (K=4) + SiLU, float4-vectorized ----------------
__global__ void conv_silu_kernel(const float* __restrict__ xz, const float* __restrict__ w,
                                 const float* __restrict__ bias, float* __restrict__ out,
                                 int Ltok, int dinner) {
    long tid = (long)blockIdx.x * 256 + threadIdx.x;     // one thread = 4 channels
    long total = (long)BATCH * Ltok * (dinner / 4);
    if (tid >= total) return;
    int d4 = (int)(tid % (dinner / 4)) * 4;
    long t = tid / (dinner / 4);
    int l = (int)(t % Ltok);
    int b = (int)(t / Ltok);
    int rowstride = 2 * dinner;
    const float* base = xz + ((long)b * Ltok + l) * rowstride + d4;
    float4 bv = *reinterpret_cast<const float4*>(bias + d4);
    float acc0 = bv.x, acc1 = bv.y, acc2 = bv.z, acc3 = bv.w;
    #pragma unroll
    for (int k = 0; k < 4; k++) {
        int ll = l - 3 + k;
        if (ll >= 0) {
            float4 xv = *reinterpret_cast<const float4*>(base + (long)(ll - l) * rowstride);
            acc0 += xv.x * w[(d4 + 0) * 4 + k];
            acc1 += xv.y * w[(d4 + 1) * 4 + k];
            acc2 += xv.z * w[(d4 + 2) * 4 + k];
            acc3 += xv.w * w[(d4 + 3) * 4 + k];
        }
    }
    float4 ov;
    ov.x = rnd_tf32(siluf(acc0)); ov.y = rnd_tf32(siluf(acc1));
    ov.z = rnd_tf32(siluf(acc2)); ov.w = rnd_tf32(siluf(acc3));
    *reinterpret_cast<float4*>(out + ((long)b * Ltok + l) * dinner + d4) = ov;
}

// ---------------- path-1 scan ----------------
__global__ void scan1_partial(const float* __restrict__ delta, const float* __restrict__ xc,
                              const float* __restrict__ dbl, const float* __restrict__ Alog) {
    int d = threadIdx.x;
    int chunk = blockIdx.x & (NCH - 1);
    int b = blockIdx.x >> 5;
    float A[NS], h[NS], P[NS];
    #pragma unroll
    for (int s = 0; s < NS; s++) { A[s] = -__expf(Alog[d * NS + s]); h[s] = 0.f; P[s] = 1.f; }
    int l0 = chunk * CLEN;
    for (int i = 0; i < CLEN; i++) {
        long t = (long)b * LL + l0 + i;
        float dl = delta[t * D1I + d];
        float xv = xc[t * D1I + d];
        const float* bl = dbl + t * DBL1 + DT1R;
        float dx = dl * xv;
        #pragma unroll
        for (int s = 0; s < NS; s++) {
            float dA = __expf(dl * A[s]);
            h[s] = dA * h[s] + dx * bl[s];
            P[s] *= dA;
        }
    }
    long o = (((long)b * D1I + d) * NCH + chunk) * NS;
    #pragma unroll
    for (int s = 0; s < NS; s++) { g_ckP[o + s] = P[s]; g_ckH[o + s] = h[s]; }
}

__global__ void scan1_carry() {
    int idx = blockIdx.x * 256 + threadIdx.x;
    if (idx >= BATCH * D1I) return;
    long base = (long)idx * NCH * NS;
    float h[NS];
    #pragma unroll
    for (int s = 0; s < NS; s++) h[s] = 0.f;
    for (int c = 0; c < NCH; c++) {
        long o = base + (long)c * NS;
        #pragma unroll
        for (int s = 0; s < NS; s++) {
            g_hin[o + s] = h[s];
            h[s] = g_ckP[o + s] * h[s] + g_ckH[o + s];
        }
    }
}

__global__ void scan1_final(const float* __restrict__ delta, const float* __restrict__ xc,
                            const float* __restrict__ dbl, const float* __restrict__ Alog,
                            const float* __restrict__ Dp, const float* __restrict__ xz,
                            float* __restrict__ y) {
    int d = threadIdx.x;
    int chunk = blockIdx.x & (NCH - 1);
    int b = blockIdx.x >> 5;
    float A[NS], h[NS];
    long hb = (((long)b * D1I + d) * NCH + chunk) * NS;
    #pragma unroll
    for (int s = 0; s < NS; s++) { A[s] = -__expf(Alog[d * NS + s]); h[s] = g_hin[hb + s]; }
    float Dv = Dp[d];
    int l0 = chunk * CLEN;
    for (int i = 0; i < CLEN; i++) {
        long t = (long)b * LL + l0 + i;
        float dl = delta[t * D1I + d];
        float xv = xc[t * D1I + d];
        const float* bl = dbl + t * DBL1 + DT1R;
        float dx = dl * xv;
        float acc = 0.f;
        #pragma unroll
        for (int s = 0; s < NS; s++) {
            float dA = __expf(dl * A[s]);
            h[s] = dA * h[s] + dx * bl[s];
            acc += h[s] * bl[NS + s];
        }
        float z = xz[t * (2 * D1I) + D1I + d];
        y[t * D1I + d] = rnd_tf32((acc + xv * Dv) * siluf(z));
    }
}

// ---------------- path-2 scan ----------------
__global__ void scan2_kernel(const float* __restrict__ delta, const float* __restrict__ xc,
                             const float* __restrict__ dbl, const float* __restrict__ Alog,
                             const float* __restrict__ Dp, const float* __restrict__ xz,
                             float* __restrict__ y) {
    int d = (blockIdx.x & 31) * 256 + threadIdx.x;
    int b = blockIdx.x >> 5;
    float A[NS], h[NS];
    #pragma unroll
    for (int s = 0; s < NS; s++) { A[s] = -__expf(Alog[d * NS + s]); h[s] = 0.f; }
    float Dv = Dp[d];
    for (int l = 0; l < CH; l++) {
        long t = (long)b * CH + l;
        float dl = delta[t * D2I + d];
        float xv = xc[t * D2I + d];
        const float* bl = dbl + t * DBL2 + DT2R;
        float dx = dl * xv;
        float acc = 0.f;
        #pragma unroll
        for (int s = 0; s < NS; s++) {
            float dA = __expf(dl * A[s]);
            h[s] = dA * h[s] + dx * bl[s];
            acc += h[s] * bl[NS + s];
        }
        float z = xz[t * (2 * D2I) + D2I + d];
        y[t * D2I + d] = rnd_tf32((acc + xv * Dv) * siluf(z));
    }
}

// ---------------- combine ----------------
__global__ void combine_kernel(const float* __restrict__ x, float* __restrict__ out) {
    long i = (long)blockIdx.x * 256 + threadIdx.x;
    if (i >= (long)BATCH * CH * LL) return;
    int l = (int)(i % LL);
    long t = i / LL;
    int c = (int)(t % CH);
    int b = (int)(t / CH);
    out[i] = x[i] + g_out2[i] + g_out1[((long)b * LL + l) * D1M + c];
}

// ---------------- launch ----------------
extern "C" void kernel_launch(void* const* d_in, const int* in_sizes, int n_in,
                              void* d_out, int out_size) {
    const float* x        = (const float*)d_in[0];
    const float* ln1_g    = (const float*)d_in[1];
    const float* ln1_b    = (const float*)d_in[2];
    const float* ln2_g    = (const float*)d_in[3];
    const float* ln2_b    = (const float*)d_in[4];
    const float* m1_in_w  = (const float*)d_in[5];
    const float* m1_cw    = (const float*)d_in[6];
    const float* m1_cb    = (const float*)d_in[7];
    const float* m1_xp_w  = (const float*)d_in[8];
    const float* m1_dt_w  = (const float*)d_in[9];
    const float* m1_dt_b  = (const float*)d_in[10];
    const float* m1_Alog  = (const float*)d_in[11];
    const float* m1_D     = (const float*)d_in[12];
    const float* m1_out_w = (const float*)d_in[13];
    const float* m2_in_w  = (const float*)d_in[14];
    const float* m2_cw    = (const float*)d_in[15];
    const float* m2_cb    = (const float*)d_in[16];
    const float* m2_xp_w  = (const float*)d_in[17];
    const float* m2_dt_w  = (const float*)d_in[18];
    const float* m2_dt_b  = (const float*)d_in[19];
    const float* m2_Alog  = (const float*)d_in[20];
    const float* m2_D     = (const float*)d_in[21];
    const float* m2_out_w = (const float*)d_in[22];
    float* out = (float*)d_out;

    float *pxn1, *pxz1, *pxc1, *pdbl1, *pdelta1, *py1, *pout1;
    float *pxn2, *pxz2, *pxc2, *pdbl2, *pdelta2, *py2, *pout2;
    cudaGetSymbolAddress((void**)&pxn1, g_xn1);
    cudaGetSymbolAddress((void**)&pxz1, g_xz1);
    cudaGetSymbolAddress((void**)&pxc1, g_xc1);
    cudaGetSymbolAddress((void**)&pdbl1, g_dbl1);
    cudaGetSymbolAddress((void**)&pdelta1, g_delta1);
    cudaGetSymbolAddress((void**)&py1, g_y1);
    cudaGetSymbolAddress((void**)&pout1, g_out1);
    cudaGetSymbolAddress((void**)&pxn2, g_xn2);
    cudaGetSymbolAddress((void**)&pxz2, g_xz2);
    cudaGetSymbolAddress((void**)&pxc2, g_xc2);
    cudaGetSymbolAddress((void**)&pdbl2, g_dbl2);
    cudaGetSymbolAddress((void**)&pdelta2, g_delta2);
    cudaGetSymbolAddress((void**)&py2, g_y2);
    cudaGetSymbolAddress((void**)&pout2, g_out2);

    cudaFuncSetAttribute(tf32_gemm<0>, cudaFuncAttributeMaxDynamicSharedMemorySize, GSMEM_BYTES);
    cudaFuncSetAttribute(tf32_gemm<1>, cudaFuncAttributeMaxDynamicSharedMemorySize, GSMEM_BYTES);
    cudaFuncSetAttribute(tf32_gemm<2>, cudaFuncAttributeMaxDynamicSharedMemorySize, GSMEM_BYTES);

    const int T = 256;
    // launch 0,1: split-K accumulators
    cudaMemsetAsync(pdbl2, 0, sizeof(float) * BATCH * CH * DBL2);
    cudaMemsetAsync(pout2, 0, sizeof(float) * BATCH * CH * D2M);
    // launch 2,3
    ln1_kernel<<<BATCH * (LL / 32), T>>>(x, ln1_g, ln1_b, pxn1);
    ln2_kernel<<<BATCH * CH, T>>>(x, ln2_g, ln2_b, pxn2);
    // launch 4: in1: xz1[8192, 512] = xn1 @ in_w^T
    tf32_gemm<0><<<dim3(4, 64, 1), 256, GSMEM_BYTES>>>(
        pxn1, m1_in_w, nullptr, pxz1, BATCH * LL, 2 * D1I, D1M, D1M, D1M, 2 * D1I);
    // launch 5 (PROFILED): in2: xz2[256, 16384] = xn2 @ in_w^T  (256 CTAs)
    tf32_gemm<0><<<dim3(128, 2, 1), 256, GSMEM_BYTES>>>(
        pxn2, m2_in_w, nullptr, pxz2, BATCH * CH, 2 * D2I, D2M, D2M, D2M, 2 * D2I);

    // ---- rest of path 1 ----
    conv_silu_kernel<<<(BATCH * LL * D1I / 4 + T - 1) / T, T>>>(pxz1, m1_cw, m1_cb, pxc1, LL, D1I);
    tf32_gemm<0><<<dim3(1, 64, 1), 256, GSMEM_BYTES>>>(
        pxc1, m1_xp_w, nullptr, pdbl1, BATCH * LL, DBL1, D1I, D1I, D1I, DBL1);
    sgemm_kernel<1, true><<<dim3((D1I + 63) / 64, (BATCH * LL) / 64), T>>>(
        pdbl1, m1_dt_w, m1_dt_b, pdelta1, BATCH * LL, D1I, DT1R, DBL1, D1I);
    scan1_partial<<<BATCH * NCH, D1I>>>(pdelta1, pxc1, pdbl1, m1_Alog);
    scan1_carry<<<(BATCH * D1I + T - 1) / T, T>>>();
    scan1_final<<<BATCH * NCH, D1I>>>(pdelta1, pxc1, pdbl1, m1_Alog, m1_D, pxz1, py1);
    // out1: split-K=2 atomic (128 CTAs)
    cudaMemsetAsync(pout1, 0, sizeof(float) * BATCH * LL * D1M);
    tf32_gemm<1><<<dim3(1, 64, 2), 256, GSMEM_BYTES>>>(
        py1, m1_out_w, nullptr, pout1, BATCH * LL, D1M, D1I / 2, D1I, D1I, D1M);

    // ---- rest of path 2 ----
    conv_silu_kernel<<<(BATCH * CH * D2I / 4 + T - 1) / T, T>>>(pxz2, m2_cw, m2_cb, pxc2, CH, D2I);
    // xp2: dbl2[256, 272] split-K=16 atomic (96 CTAs)
    tf32_gemm<1><<<dim3(3, 2, 16), 256, GSMEM_BYTES>>>(
        pxc2, m2_xp_w, nullptr, pdbl2, BATCH * CH, DBL2, D2I / 16, D2I, D2I, DBL2);
    // dt2: delta2[256, 8192] = softplus(dbl2[:, :256] @ dt_w^T + b) (128 CTAs)
    tf32_gemm<2><<<dim3(64, 2, 1), 256, GSMEM_BYTES>>>(
        pdbl2, m2_dt_w, m2_dt_b, pdelta2, BATCH * CH, D2I, DT2R, DBL2, DT2R, D2I);
    scan2_kernel<<<BATCH * (D2I / 256), T>>>(pdelta2, pxc2, pdbl2, m2_Alog, m2_D, pxz2, py2);
    // out2: out2[256, 4096] split-K=4 atomic (256 CTAs)
    tf32_gemm<1><<<dim3(32, 2, 4), 256, GSMEM_BYTES>>>(
        py2, m2_out_w, nullptr, pout2, BATCH * CH, D2M, D2I / 4, D2I, D2I, D2M);

    // ---- combine ----
    combine_kernel<<<(BATCH * CH * LL + T - 1) / T, T>>>(x, out);
}

// round 9
// speedup vs baseline: 1.4835x; 1.3007x over previous
#include <cuda_runtime.h>
#include <cstdint>
#include <math.h>

// ---------------- problem constants ----------------
#define BATCH 2
#define CH    128
#define LL    4096
#define NS    8

#define D1M  128
#define D1I  256
#define DT1R 8
#define DBL1 24
#define D2M  4096
#define D2I  8192
#define DT2R 256
#define DBL2 272      // dt_rank(256) + 2*8

#define NCH  32
#define CLEN 128

// ---------------- scratch ----------------
__device__ __align__(16) float g_xn1[BATCH*LL*D1M];
__device__ __align__(16) float g_xz1[BATCH*LL*2*D1I];
__device__ __align__(16) float g_xc1[BATCH*LL*D1I];
__device__ __align__(16) float g_dbl1[BATCH*LL*DBL1];
__device__ __align__(16) float g_delta1[BATCH*LL*D1I];
__device__ __align__(16) float g_y1[BATCH*LL*D1I];
__device__ __align__(16) float g_out1[BATCH*LL*D1M];
__device__ __align__(16) float g_ckP[BATCH*D1I*NCH*NS];
__device__ __align__(16) float g_ckH[BATCH*D1I*NCH*NS];
__device__ __align__(16) float g_hin[BATCH*D1I*NCH*NS];

__device__ __align__(16) float g_xn2[BATCH*CH*D2M];
__device__ __align__(16) float g_xz2[BATCH*CH*2*D2I];
__device__ __align__(16) float g_xc2[BATCH*CH*D2I];
__device__ __align__(16) float g_dbl2[BATCH*CH*DBL2];
__device__ __align__(16) float g_delta2[BATCH*CH*D2I];
__device__ __align__(16) float g_y2[BATCH*CH*D2I];
__device__ __align__(16) float g_out2[BATCH*CH*D2M];

// ---------------- helpers ----------------
__device__ __forceinline__ uint32_t smem_u32(const void* p) {
    uint32_t a;
    asm("{ .reg .u64 t; cvta.to.shared.u64 t, %1; cvt.u32.u64 %0, t; }" : "=r"(a) : "l"(p));
    return a;
}
__device__ __forceinline__ void cp_async16(uint32_t dst, const void* src, int sz) {
    asm volatile("cp.async.cg.shared.global [%0], [%1], 16, %2;"
                 :: "r"(dst), "l"(src), "r"(sz) : "memory");
}
#define CP_COMMIT() asm volatile("cp.async.commit_group;" ::: "memory")
#define CP_WAIT1()  asm volatile("cp.async.wait_group 1;" ::: "memory")
#define CP_WAIT0()  asm volatile("cp.async.wait_group 0;" ::: "memory")

__device__ __forceinline__ uint32_t f2tf32(float f) {
    uint32_t r;
    asm("cvt.rna.tf32.f32 %0, %1;" : "=r"(r) : "f"(f));
    return r;
}
__device__ __forceinline__ float rnd_tf32(float v) { return __uint_as_float(f2tf32(v)); }

__device__ __forceinline__ void mma_tf32(float* d, const uint32_t* a, const uint32_t* b) {
    asm volatile(
        "mma.sync.aligned.m16n8k8.row.col.f32.tf32.tf32.f32 "
        "{%0,%1,%2,%3}, {%4,%5,%6,%7}, {%8,%9}, {%0,%1,%2,%3};"
        : "+f"(d[0]), "+f"(d[1]), "+f"(d[2]), "+f"(d[3])
        : "r"(a[0]), "r"(a[1]), "r"(a[2]), "r"(a[3]), "r"(b[0]), "r"(b[1]));
}

__device__ __forceinline__ void ldsm_x4(uint32_t& r0, uint32_t& r1, uint32_t& r2, uint32_t& r3,
                                        uint32_t addr) {
    asm volatile("ldmatrix.sync.aligned.m8n8.x4.shared.b16 {%0,%1,%2,%3}, [%4];"
                 : "=r"(r0), "=r"(r1), "=r"(r2), "=r"(r3) : "r"(addr));
}

__device__ __forceinline__ float siluf(float v) { return v / (1.f + __expf(-v)); }
__device__ __forceinline__ float softplusf(float v) { return (v > 20.f) ? v : log1pf(__expf(v)); }

// ======================================================================
// tf32 mma.sync GEMM: C[m, n] = sum_k X[m, k] * W[n, k]
// A-side (X, activations) pre-rounded to tf32 at the producer.
// BM=128, BN=128; warp grid 2x4, warp tile 64x32. 3-stage cp.async,
// single __syncthreads per K-iter; 2 CTAs/SM; ldmatrix fragment loads.
// grid = (N/128 tiles, M/128 tiles, ksplits); block = 256 threads
// EPI: 0 = store, 1 = atomicAdd (split-K), 2 = softplus(v + bias[n]) store
// ======================================================================
#define SROW 36
#define GROWS 256                       // 128 A rows + 128 B rows per stage
#define GSTG (GROWS * SROW)             // floats per stage
#define GSMEM_BYTES (3 * GSTG * 4)      // 108 KB -> 2 CTAs/SM

template<int EPI>
__global__ void __launch_bounds__(256, 2)
tf32_gemm(const float* __restrict__ X, const float* __restrict__ W,
          const float* __restrict__ bias, float* __restrict__ C,
          int M, int N, int kLen, int ldx, int ldw, int ldc) {
    extern __shared__ float sm[];
    const int tid = threadIdx.x;
    const int wid = tid >> 5, lane = tid & 31;
    const int gid = lane >> 2, tig = lane & 3;
    const int wm = wid >> 2, wn = wid & 3;        // 2 x 4 warp grid
    const int m0 = blockIdx.y * 128, n0 = blockIdx.x * 128;
    const long k0 = (long)blockIdx.z * kLen;
    const int nIter = kLen / 32;
    const uint32_t sS = smem_u32(sm);

    float acc[4][4][4];
    #pragma unroll
    for (int i = 0; i < 4; i++)
        #pragma unroll
        for (int j = 0; j < 4; j++)
            #pragma unroll
            for (int r = 0; r < 4; r++) acc[i][j][r] = 0.f;

    auto load_stage = [&](int buf, long kk) {
        #pragma unroll
        for (int i = 0; i < 8; i++) {
            int idx = tid + i * 256;           // 0..2047
            int row = idx >> 3, ch = idx & 7;
            uint32_t off = (uint32_t)((buf * GROWS + row) * SROW + ch * 4) * 4u;
            if (row < 128) {
                cp_async16(sS + off, X + (long)(m0 + row) * ldx + kk + ch * 4, 16);
            } else {
                int nr = n0 + row - 128;
                const float* gb = W + (long)(nr < N ? nr : 0) * ldw + kk + ch * 4;
                cp_async16(sS + off, gb, nr < N ? 16 : 0);
            }
        }
    };

    // ldmatrix per-thread base addresses (bytes):
    const uint32_t aBase = sS +
        (uint32_t)(((wm * 64 + ((lane >> 3) & 1) * 8 + (lane & 7)) * SROW
                    + ((lane >> 4) & 1) * 4) * 4);
    const uint32_t bBase = sS +
        (uint32_t)(((128 + wn * 32 + ((lane >> 4) & 1) * 8 + (lane & 7)) * SROW
                    + ((lane >> 3) & 1) * 4) * 4);

    load_stage(0, k0); CP_COMMIT();
    load_stage(1, k0 + 32); CP_COMMIT();

    for (int it = 0; it < nIter; it++) {
        if (it + 1 < nIter) { CP_WAIT1(); } else { CP_WAIT0(); }
        __syncthreads();

        const uint32_t stgOff = (uint32_t)((it % 3) * GSTG * 4);
        const uint32_t aS = aBase + stgOff;
        const uint32_t bS = bBase + stgOff;
        #pragma unroll
        for (int ks = 0; ks < 4; ks++) {
            uint32_t a[4][4], b[4][2];
            #pragma unroll
            for (int mi = 0; mi < 4; mi++)
                ldsm_x4(a[mi][0], a[mi][1], a[mi][2], a[mi][3],
                        aS + (uint32_t)(mi * 16 * SROW * 4 + ks * 32));
            #pragma unroll
            for (int p = 0; p < 2; p++) {
                uint32_t r0, r1, r2, r3;
                ldsm_x4(r0, r1, r2, r3,
                        bS + (uint32_t)(p * 16 * SROW * 4 + ks * 32));
                b[2 * p][0]     = f2tf32(__uint_as_float(r0));
                b[2 * p][1]     = f2tf32(__uint_as_float(r1));
                b[2 * p + 1][0] = f2tf32(__uint_as_float(r2));
                b[2 * p + 1][1] = f2tf32(__uint_as_float(r3));
            }
            #pragma unroll
            for (int mi = 0; mi < 4; mi++)
                #pragma unroll
                for (int ni = 0; ni < 4; ni++)
                    mma_tf32(acc[mi][ni], a[mi], b[ni]);
        }
        if (it + 2 < nIter) { load_stage((it + 2) % 3, k0 + (long)(it + 2) * 32); CP_COMMIT(); }
    }

    // epilogue
    #pragma unroll
    for (int mi = 0; mi < 4; mi++) {
        int m = m0 + wm * 64 + mi * 16 + gid;
        #pragma unroll
        for (int ni = 0; ni < 4; ni++) {
            int n = n0 + wn * 32 + ni * 8 + tig * 2;
            if (n >= N) continue;
            float* p0 = C + (long)m * ldc + n;
            float* p1 = C + (long)(m + 8) * ldc + n;
            float c0 = acc[mi][ni][0], c1 = acc[mi][ni][1];
            float c2 = acc[mi][ni][2], c3 = acc[mi][ni][3];
            if (EPI == 1) {
                atomicAdd(p0, c0); atomicAdd(p0 + 1, c1);
                atomicAdd(p1, c2); atomicAdd(p1 + 1, c3);
            } else if (EPI == 2) {
                float b0v = bias[n], b1v = bias[n + 1];
                *reinterpret_cast<float2*>(p0) =
                    make_float2(softplusf(c0 + b0v), softplusf(c1 + b1v));
                *reinterpret_cast<float2*>(p1) =
                    make_float2(softplusf(c2 + b0v), softplusf(c3 + b1v));
            } else {
                *reinterpret_cast<float2*>(p0) = make_float2(c0, c1);
                *reinterpret_cast<float2*>(p1) = make_float2(c2, c3);
            }
        }
    }
}

// ---------------- LayerNorm 1 (output tf32-rounded) ----------------
__global__ void ln1_kernel(const float* __restrict__ x, const float* __restrict__ g,
                           const float* __restrict__ bta, float* __restrict__ out) {
    int b  = blockIdx.x >> 7;
    int l0 = (blockIdx.x & 127) * 32;
    __shared__ float sm[128 * 33];
    int tid = threadIdx.x;
    #pragma unroll
    for (int i = 0; i < 16; i++) {
        int idx = tid + i * 256;
        int c = idx >> 5, l = idx & 31;
        sm[c * 33 + l] = x[((long)b * CH + c) * LL + l0 + l];
    }
    __syncthreads();
    int warp = tid >> 5, lane = tid & 31;
    for (int t = warp; t < 32; t += 8) {
        float v[4]; float s = 0.f, sq = 0.f;
        #pragma unroll
        for (int j = 0; j < 4; j++) {
            v[j] = sm[(lane + 32 * j) * 33 + t];
            s += v[j]; sq += v[j] * v[j];
        }
        #pragma unroll
        for (int o = 16; o; o >>= 1) {
            s  += __shfl_xor_sync(0xffffffffu, s,  o);
            sq += __shfl_xor_sync(0xffffffffu, sq, o);
        }
        float mu  = s * (1.f / 128.f);
        float var = sq * (1.f / 128.f) - mu * mu;
        float rs  = rsqrtf(var + 1e-5f);
        #pragma unroll
        for (int j = 0; j < 4; j++) {
            int c = lane + 32 * j;
            out[((long)b * LL + l0 + t) * D1M + c] = rnd_tf32((v[j] - mu) * rs * g[c] + bta[c]);
        }
    }
}

// ---------------- LayerNorm 2 (output tf32-rounded) ----------------
__global__ void ln2_kernel(const float* __restrict__ x, const float* __restrict__ g,
                           const float* __restrict__ bta, float* __restrict__ out) {
    long row = blockIdx.x;
    const float* xr = x + row * D2M;
    float* orow = out + row * D2M;
    int tid = threadIdx.x;
    float v[16]; float s = 0.f, sq = 0.f;
    #pragma unroll
    for (int i = 0; i < 16; i++) {
        v[i] = xr[i * 256 + tid];
        s += v[i]; sq += v[i] * v[i];
    }
    #pragma unroll
    for (int o = 16; o; o >>= 1) {
        s  += __shfl_xor_sync(0xffffffffu, s,  o);
        sq += __shfl_xor_sync(0xffffffffu, sq, o);
    }
    __shared__ float ss[8], sqq[8];
    int lane = tid & 31, warp = tid >> 5;
    if (!lane) { ss[warp] = s; sqq[warp] = sq; }
    __syncthreads();
    s = 0.f; sq = 0.f;
    #pragma unroll
    for (int w = 0; w < 8; w++) { s += ss[w]; sq += sqq[w]; }
    float mu  = s * (1.f / 4096.f);
    float var = sq * (1.f / 4096.f) - mu * mu;
    float rs  = rsqrtf(var + 1e-5f);
    #pragma unroll
    for (int i = 0; i < 16; i++) {
        int col = i * 256 + tid;
        orow[col] = rnd_tf32((v[i] - mu) * rs * g[col] + bta[col]);
    }
}

// ---------------- fallback SGEMM (dt1: K=8) ----------------
template<int ACT, bool HASBIAS>
__global__ void sgemm_kernel(const float* __restrict__ X, const float* __restrict__ W,
                             const float* __restrict__ bias, float* __restrict__ out,
                             int M, int N, int K, int lda, int ldc) {
    constexpr int BM = 64, BN = 64, BK = 32, PAD = 4;
    __shared__ float As[BK][BM + PAD];
    __shared__ float Bs[BK][BN + PAD];
    int bm = blockIdx.y * BM, bn = blockIdx.x * BN;
    int tid = threadIdx.x;
    int tx = tid & 15, ty = tid >> 4;
    float acc[4][4] = {};
    for (int k0 = 0; k0 < K; k0 += BK) {
        #pragma unroll
        for (int i = 0; i < 2; i++) {
            int idx = tid + i * 256;
            int row = idx >> 3;
            int kc  = (idx & 7) << 2;
            int k   = k0 + kc;
            float4 va = make_float4(0.f, 0.f, 0.f, 0.f);
            float4 vb = make_float4(0.f, 0.f, 0.f, 0.f);
            if (k < K) {
                int m = bm + row;
                if (m < M) va = *reinterpret_cast<const float4*>(X + (long)m * lda + k);
                int n = bn + row;
                if (n < N) vb = *reinterpret_cast<const float4*>(W + (long)n * K + k);
            }
            As[kc][row] = va.x; As[kc + 1][row] = va.y; As[kc + 2][row] = va.z; As[kc + 3][row] = va.w;
            Bs[kc][row] = vb.x; Bs[kc + 1][row] = vb.y; Bs[kc + 2][row] = vb.z; Bs[kc + 3][row] = vb.w;
        }
        __syncthreads();
        #pragma unroll
        for (int kk = 0; kk < BK; kk++) {
            float4 a = *reinterpret_cast<const float4*>(&As[kk][ty << 2]);
            float4 b = *reinterpret_cast<const float4*>(&Bs[kk][tx << 2]);
            float av[4] = {a.x, a.y, a.z, a.w};
            float bv[4] = {b.x, b.y, b.z, b.w};
            #pragma unroll
            for (int i = 0; i < 4; i++)
                #pragma unroll
                for (int j = 0; j < 4; j++)
                    acc[i][j] += av[i] * bv[j];
        }
        __syncthreads();
    }
    #pragma unroll
    for (int i = 0; i < 4; i++) {
        int m = bm + (ty << 2) + i;
        if (m >= M) continue;
        #pragma unroll
        for (int j = 0; j < 4; j++) {
            int n = bn + (tx << 2) + j;
            if (n >= N) continue;
            float v = acc[i][j];
            if (HASBIAS) v += bias[n];
            if (ACT == 1) v = softplusf(v);
            out[(long)m * ldc + n] = v;
        }
    }
}

// ---------------- causal depthwise conv (K=4) + SiLU, float4-vectorized ----------------
__global__ void conv_silu_kernel(const float* __restrict__ xz, const float* __restrict__ w,
                                 const float* __restrict__ bias, float* __restrict__ out,
                                 int Ltok, int dinner) {
    long tid = (long)blockIdx.x * 256 + threadIdx.x;     // one thread = 4 channels
    long total = (long)BATCH * Ltok * (dinner / 4);
    if (tid >= total) return;
    int d4 = (int)(tid % (dinner / 4)) * 4;
    long t = tid / (dinner / 4);
    int l = (int)(t % Ltok);
    int b = (int)(t / Ltok);
    int rowstride = 2 * dinner;
    const float* base = xz + ((long)b * Ltok + l) * rowstride + d4;
    float4 bv = *reinterpret_cast<const float4*>(bias + d4);
    float acc0 = bv.x, acc1 = bv.y, acc2 = bv.z, acc3 = bv.w;
    #pragma unroll
    for (int k = 0; k < 4; k++) {
        int ll = l - 3 + k;
        if (ll >= 0) {
            float4 xv = *reinterpret_cast<const float4*>(base + (long)(ll - l) * rowstride);
            acc0 += xv.x * w[(d4 + 0) * 4 + k];
            acc1 += xv.y * w[(d4 + 1) * 4 + k];
            acc2 += xv.z * w[(d4 + 2) * 4 + k];
            acc3 += xv.w * w[(d4 + 3) * 4 + k];
        }
    }
    float4 ov;
    ov.x = rnd_tf32(siluf(acc0)); ov.y = rnd_tf32(siluf(acc1));
    ov.z = rnd_tf32(siluf(acc2)); ov.w = rnd_tf32(siluf(acc3));
    *reinterpret_cast<float4*>(out + ((long)b * Ltok + l) * dinner + d4) = ov;
}

// ---------------- path-1 scan ----------------
__global__ void scan1_partial(const float* __restrict__ delta, const float* __restrict__ xc,
                              const float* __restrict__ dbl, const float* __restrict__ Alog) {
    int d = threadIdx.x;
    int chunk = blockIdx.x & (NCH - 1);
    int b = blockIdx.x >> 5;
    float A[NS], h[NS], P[NS];
    #pragma unroll
    for (int s = 0; s < NS; s++) { A[s] = -__expf(Alog[d * NS + s]); h[s] = 0.f; P[s] = 1.f; }
    int l0 = chunk * CLEN;
    for (int i = 0; i < CLEN; i++) {
        long t = (long)b * LL + l0 + i;
        float dl = delta[t * D1I + d];
        float xv = xc[t * D1I + d];
        const float* bl = dbl + t * DBL1 + DT1R;
        float dx = dl * xv;
        #pragma unroll
        for (int s = 0; s < NS; s++) {
            float dA = __expf(dl * A[s]);
            h[s] = dA * h[s] + dx * bl[s];
            P[s] *= dA;
        }
    }
    long o = (((long)b * D1I + d) * NCH + chunk) * NS;
    #pragma unroll
    for (int s = 0; s < NS; s++) { g_ckP[o + s] = P[s]; g_ckH[o + s] = h[s]; }
}

__global__ void scan1_carry() {
    int idx = blockIdx.x * 256 + threadIdx.x;
    if (idx >= BATCH * D1I) return;
    long base = (long)idx * NCH * NS;
    float h[NS];
    #pragma unroll
    for (int s = 0; s < NS; s++) h[s] = 0.f;
    for (int c = 0; c < NCH; c++) {
        long o = base + (long)c * NS;
        #pragma unroll
        for (int s = 0; s < NS; s++) {
            g_hin[o + s] = h[s];
            h[s] = g_ckP[o + s] * h[s] + g_ckH[o + s];
        }
    }
}

__global__ void scan1_final(const float* __restrict__ delta, const float* __restrict__ xc,
                            const float* __restrict__ dbl, const float* __restrict__ Alog,
                            const float* __restrict__ Dp, const float* __restrict__ xz,
                            float* __restrict__ y) {
    int d = threadIdx.x;
    int chunk = blockIdx.x & (NCH - 1);
    int b = blockIdx.x >> 5;
    float A[NS], h[NS];
    long hb = (((long)b * D1I + d) * NCH + chunk) * NS;
    #pragma unroll
    for (int s = 0; s < NS; s++) { A[s] = -__expf(Alog[d * NS + s]); h[s] = g_hin[hb + s]; }
    float Dv = Dp[d];
    int l0 = chunk * CLEN;
    for (int i = 0; i < CLEN; i++) {
        long t = (long)b * LL + l0 + i;
        float dl = delta[t * D1I + d];
        float xv = xc[t * D1I + d];
        const float* bl = dbl + t * DBL1 + DT1R;
        float dx = dl * xv;
        float acc = 0.f;
        #pragma unroll
        for (int s = 0; s < NS; s++) {
            float dA = __expf(dl * A[s]);
            h[s] = dA * h[s] + dx * bl[s];
            acc += h[s] * bl[NS + s];
        }
        float z = xz[t * (2 * D1I) + D1I + d];
        y[t * D1I + d] = rnd_tf32((acc + xv * Dv) * siluf(z));
    }
}

// ---------------- path-2 scan ----------------
__global__ void scan2_kernel(const float* __restrict__ delta, const float* __restrict__ xc,
                             const float* __restrict__ dbl, const float* __restrict__ Alog,
                             const float* __restrict__ Dp, const float* __restrict__ xz,
                             float* __restrict__ y) {
    int d = (blockIdx.x & 31) * 256 + threadIdx.x;
    int b = blockIdx.x >> 5;
    float A[NS], h[NS];
    #pragma unroll
    for (int s = 0; s < NS; s++) { A[s] = -__expf(Alog[d * NS + s]); h[s] = 0.f; }
    float Dv = Dp[d];
    for (int l = 0; l < CH; l++) {
        long t = (long)b * CH + l;
        float dl = delta[t * D2I + d];
        float xv = xc[t * D2I + d];
        const float* bl = dbl + t * DBL2 + DT2R;
        float dx = dl * xv;
        float acc = 0.f;
        #pragma unroll
        for (int s = 0; s < NS; s++) {
            float dA = __expf(dl * A[s]);
            h[s] = dA * h[s] + dx * bl[s];
            acc += h[s] * bl[NS + s];
        }
        float z = xz[t * (2 * D2I) + D2I + d];
        y[t * D2I + d] = rnd_tf32((acc + xv * Dv) * siluf(z));
    }
}

// ---------------- combine ----------------
__global__ void combine_kernel(const float* __restrict__ x, float* __restrict__ out) {
    long i = (long)blockIdx.x * 256 + threadIdx.x;
    if (i >= (long)BATCH * CH * LL) return;
    int l = (int)(i % LL);
    long t = i / LL;
    int c = (int)(t % CH);
    int b = (int)(t / CH);
    out[i] = x[i] + g_out2[i] + g_out1[((long)b * LL + l) * D1M + c];
}

// ---------------- launch ----------------
extern "C" void kernel_launch(void* const* d_in, const int* in_sizes, int n_in,
                              void* d_out, int out_size) {
    const float* x        = (const float*)d_in[0];
    const float* ln1_g    = (const float*)d_in[1];
    const float* ln1_b    = (const float*)d_in[2];
    const float* ln2_g    = (const float*)d_in[3];
    const float* ln2_b    = (const float*)d_in[4];
    const float* m1_in_w  = (const float*)d_in[5];
    const float* m1_cw    = (const float*)d_in[6];
    const float* m1_cb    = (const float*)d_in[7];
    const float* m1_xp_w  = (const float*)d_in[8];
    const float* m1_dt_w  = (const float*)d_in[9];
    const float* m1_dt_b  = (const float*)d_in[10];
    const float* m1_Alog  = (const float*)d_in[11];
    const float* m1_D     = (const float*)d_in[12];
    const float* m1_out_w = (const float*)d_in[13];
    const float* m2_in_w  = (const float*)d_in[14];
    const float* m2_cw    = (const float*)d_in[15];
    const float* m2_cb    = (const float*)d_in[16];
    const float* m2_xp_w  = (const float*)d_in[17];
    const float* m2_dt_w  = (const float*)d_in[18];
    const float* m2_dt_b  = (const float*)d_in[19];
    const float* m2_Alog  = (const float*)d_in[20];
    const float* m2_D     = (const float*)d_in[21];
    const float* m2_out_w = (const float*)d_in[22];
    float* out = (float*)d_out;

    float *pxn1, *pxz1, *pxc1, *pdbl1, *pdelta1, *py1, *pout1;
    float *pxn2, *pxz2, *pxc2, *pdbl2, *pdelta2, *py2, *pout2;
    cudaGetSymbolAddress((void**)&pxn1, g_xn1);
    cudaGetSymbolAddress((void**)&pxz1, g_xz1);
    cudaGetSymbolAddress((void**)&pxc1, g_xc1);
    cudaGetSymbolAddress((void**)&pdbl1, g_dbl1);
    cudaGetSymbolAddress((void**)&pdelta1, g_delta1);
    cudaGetSymbolAddress((void**)&py1, g_y1);
    cudaGetSymbolAddress((void**)&pout1, g_out1);
    cudaGetSymbolAddress((void**)&pxn2, g_xn2);
    cudaGetSymbolAddress((void**)&pxz2, g_xz2);
    cudaGetSymbolAddress((void**)&pxc2, g_xc2);
    cudaGetSymbolAddress((void**)&pdbl2, g_dbl2);
    cudaGetSymbolAddress((void**)&pdelta2, g_delta2);
    cudaGetSymbolAddress((void**)&py2, g_y2);
    cudaGetSymbolAddress((void**)&pout2, g_out2);

    cudaFuncSetAttribute(tf32_gemm<0>, cudaFuncAttributeMaxDynamicSharedMemorySize, GSMEM_BYTES);
    cudaFuncSetAttribute(tf32_gemm<1>, cudaFuncAttributeMaxDynamicSharedMemorySize, GSMEM_BYTES);
    cudaFuncSetAttribute(tf32_gemm<2>, cudaFuncAttributeMaxDynamicSharedMemorySize, GSMEM_BYTES);

    // one-time side-stream + events (created on first call, outside graph capture;
    // reused identically every call — deterministic, no device allocation)
    static cudaStream_t s2 = nullptr;
    static cudaEvent_t evFork = nullptr, evJoin = nullptr;
    if (!s2) {
        cudaStreamCreateWithFlags(&s2, cudaStreamNonBlocking);
        cudaEventCreateWithFlags(&evFork, cudaEventDisableTiming);
        cudaEventCreateWithFlags(&evJoin, cudaEventDisableTiming);
    }

    const int T = 256;
    // ---- main stream: path-2 prologue (keeps in2 at launch index 5 for ncu) ----
    cudaMemsetAsync(pdbl2, 0, sizeof(float) * BATCH * CH * DBL2);          // 0
    cudaMemsetAsync(pout2, 0, sizeof(float) * BATCH * CH * D2M);           // 1
    ln2_kernel<<<BATCH * CH, T>>>(x, ln2_g, ln2_b, pxn2);                  // 2

    // fork side stream for path 1
    cudaEventRecord(evFork, 0);
    cudaStreamWaitEvent(s2, evFork, 0);

    cudaMemsetAsync(pout1, 0, sizeof(float) * BATCH * LL * D1M, s2);       // 3
    ln1_kernel<<<BATCH * (LL / 32), T, 0, s2>>>(x, ln1_g, ln1_b, pxn1);    // 4

    // ---- main stream: in2 (launch 5, PROFILED) ----
    tf32_gemm<0><<<dim3(128, 2, 1), 256, GSMEM_BYTES>>>(
        pxn2, m2_in_w, nullptr, pxz2, BATCH * CH, 2 * D2I, D2M, D2M, D2M, 2 * D2I);

    // ---- side stream: rest of path 1 ----
    tf32_gemm<0><<<dim3(4, 64, 1), 256, GSMEM_BYTES, s2>>>(
        pxn1, m1_in_w, nullptr, pxz1, BATCH * LL, 2 * D1I, D1M, D1M, D1M, 2 * D1I);
    conv_silu_kernel<<<(BATCH * LL * D1I / 4 + T - 1) / T, T, 0, s2>>>(
        pxz1, m1_cw, m1_cb, pxc1, LL, D1I);
    tf32_gemm<0><<<dim3(1, 64, 1), 256, GSMEM_BYTES, s2>>>(
        pxc1, m1_xp_w, nullptr, pdbl1, BATCH * LL, DBL1, D1I, D1I, D1I, DBL1);
    sgemm_kernel<1, true><<<dim3((D1I + 63) / 64, (BATCH * LL) / 64), T, 0, s2>>>(
        pdbl1, m1_dt_w, m1_dt_b, pdelta1, BATCH * LL, D1I, DT1R, DBL1, D1I);
    scan1_partial<<<BATCH * NCH, D1I, 0, s2>>>(pdelta1, pxc1, pdbl1, m1_Alog);
    scan1_carry<<<(BATCH * D1I + T - 1) / T, T, 0, s2>>>();
    scan1_final<<<BATCH * NCH, D1I, 0, s2>>>(pdelta1, pxc1, pdbl1, m1_Alog, m1_D, pxz1, py1);
    tf32_gemm<1><<<dim3(1, 64, 2), 256, GSMEM_BYTES, s2>>>(
        py1, m1_out_w, nullptr, pout1, BATCH * LL, D1M, D1I / 2, D1I, D1I, D1M);

    // ---- main stream: rest of path 2 ----
    conv_silu_kernel<<<(BATCH * CH * D2I / 4 + T - 1) / T, T>>>(pxz2, m2_cw, m2_cb, pxc2, CH, D2I);
    // xp2: dbl2[256, 272] split-K=32 atomic (192 CTAs)
    tf32_gemm<1><<<dim3(3, 2, 32), 256, GSMEM_BYTES>>>(
        pxc2, m2_xp_w, nullptr, pdbl2, BATCH * CH, DBL2, D2I / 32, D2I, D2I, DBL2);
    // dt2: delta2[256, 8192] = softplus(dbl2[:, :256] @ dt_w^T + b)
    tf32_gemm<2><<<dim3(64, 2, 1), 256, GSMEM_BYTES>>>(
        pdbl2, m2_dt_w, m2_dt_b, pdelta2, BATCH * CH, D2I, DT2R, DBL2, DT2R, D2I);
    scan2_kernel<<<BATCH * (D2I / 256), T>>>(pdelta2, pxc2, pdbl2, m2_Alog, m2_D, pxz2, py2);
    // out2: out2[256, 4096] split-K=4 atomic (256 CTAs)
    tf32_gemm<1><<<dim3(32, 2, 4), 256, GSMEM_BYTES>>>(
        py2, m2_out_w, nullptr, pout2, BATCH * CH, D2M, D2I / 4, D2I, D2I, D2M);

    // join side stream, then combine
    cudaEventRecord(evJoin, s2);
    cudaStreamWaitEvent(0, evJoin, 0);
    combine_kernel<<<(BATCH * CH * LL + T - 1) / T, T>>>(x, out);
}

// round 10
// speedup vs baseline: 1.5046x; 1.0143x over previous
#include <cuda_runtime.h>
#include <cstdint>
#include <math.h>

// ---------------- problem constants ----------------
#define BATCH 2
#define CH    128
#define LL    4096
#define NS    8

#define D1M  128
#define D1I  256
#define DT1R 8
#define DBL1 24
#define D2M  4096
#define D2I  8192
#define DT2R 256
#define DBL2 272      // dt_rank(256) + 2*8

#define NCH  32
#define CLEN 128

// ---------------- scratch ----------------
__device__ __align__(16) float g_xn1[BATCH*LL*D1M];
__device__ __align__(16) float g_xz1[BATCH*LL*2*D1I];
__device__ __align__(16) float g_xc1[BATCH*LL*D1I];
__device__ __align__(16) float g_dbl1[BATCH*LL*DBL1];
__device__ __align__(16) float g_delta1[BATCH*LL*D1I];
__device__ __align__(16) float g_y1[BATCH*LL*D1I];
__device__ __align__(16) float g_out1[BATCH*LL*D1M];
__device__ __align__(16) float g_ckP[BATCH*D1I*NCH*NS];
__device__ __align__(16) float g_ckH[BATCH*D1I*NCH*NS];
__device__ __align__(16) float g_hin[BATCH*D1I*NCH*NS];

__device__ __align__(16) float g_xn2[BATCH*CH*D2M];
__device__ __align__(16) float g_xz2[BATCH*CH*2*D2I];
__device__ __align__(16) float g_xc2[BATCH*CH*D2I];
__device__ __align__(16) float g_dbl2[BATCH*CH*DBL2];
__device__ __align__(16) float g_delta2[BATCH*CH*D2I];
__device__ __align__(16) float g_y2[BATCH*CH*D2I];
__device__ __align__(16) float g_out2[BATCH*CH*D2M];

// ---------------- helpers ----------------
__device__ __forceinline__ uint32_t smem_u32(const void* p) {
    uint32_t a;
    asm("{ .reg .u64 t; cvta.to.shared.u64 t, %1; cvt.u32.u64 %0, t; }" : "=r"(a) : "l"(p));
    return a;
}
__device__ __forceinline__ void cp_async16(uint32_t dst, const void* src, int sz) {
    asm volatile("cp.async.cg.shared.global [%0], [%1], 16, %2;"
                 :: "r"(dst), "l"(src), "r"(sz) : "memory");
}
#define CP_COMMIT() asm volatile("cp.async.commit_group;" ::: "memory")
#define CP_WAIT1()  asm volatile("cp.async.wait_group 1;" ::: "memory")
#define CP_WAIT0()  asm volatile("cp.async.wait_group 0;" ::: "memory")

__device__ __forceinline__ uint32_t f2tf32(float f) {
    uint32_t r;
    asm("cvt.rna.tf32.f32 %0, %1;" : "=r"(r) : "f"(f));
    return r;
}
__device__ __forceinline__ float rnd_tf32(float v) { return __uint_as_float(f2tf32(v)); }

__device__ __forceinline__ void mma_tf32(float* d, const uint32_t* a, const uint32_t* b) {
    asm volatile(
        "mma.sync.aligned.m16n8k8.row.col.f32.tf32.tf32.f32 "
        "{%0,%1,%2,%3}, {%4,%5,%6,%7}, {%8,%9}, {%0,%1,%2,%3};"
        : "+f"(d[0]), "+f"(d[1]), "+f"(d[2]), "+f"(d[3])
        : "r"(a[0]), "r"(a[1]), "r"(a[2]), "r"(a[3]), "r"(b[0]), "r"(b[1]));
}

__device__ __forceinline__ void ldsm_x4(uint32_t& r0, uint32_t& r1, uint32_t& r2, uint32_t& r3,
                                        uint32_t addr) {
    asm volatile("ldmatrix.sync.aligned.m8n8.x4.shared.b16 {%0,%1,%2,%3}, [%4];"
                 : "=r"(r0), "=r"(r1), "=r"(r2), "=r"(r3) : "r"(addr));
}

__device__ __forceinline__ float siluf(float v) { return v / (1.f + __expf(-v)); }
__device__ __forceinline__ float softplusf(float v) { return (v > 20.f) ? v : log1pf(__expf(v)); }

// ======================================================================
// tf32 mma.sync GEMM: C[m, n] = sum_k X[m, k] * W[n, k]
// A-side (X, activations) pre-rounded to tf32 at the producer.
// BM=128, BN=128; warp grid 2x4, warp tile 64x32. 3-stage cp.async,
// single __syncthreads per K-iter; 2 CTAs/SM; ldmatrix fragment loads.
// grid = (N/128 tiles, M/128 tiles, ksplits); block = 256 threads
// EPI: 0 = store, 1 = atomicAdd (split-K), 2 = softplus(v + bias[n]) store
// ======================================================================
#define SROW 36
#define GROWS 256                       // 128 A rows + 128 B rows per stage
#define GSTG (GROWS * SROW)             // floats per stage
#define GSMEM_BYTES (3 * GSTG * 4)      // 108 KB -> 2 CTAs/SM

template<int EPI>
__global__ void __launch_bounds__(256, 2)
tf32_gemm(const float* __restrict__ X, const float* __restrict__ W,
          const float* __restrict__ bias, float* __restrict__ C,
          int M, int N, int kLen, int ldx, int ldw, int ldc) {
    extern __shared__ float sm[];
    const int tid = threadIdx.x;
    const int wid = tid >> 5, lane = tid & 31;
    const int gid = lane >> 2, tig = lane & 3;
    const int wm = wid >> 2, wn = wid & 3;        // 2 x 4 warp grid
    const int m0 = blockIdx.y * 128, n0 = blockIdx.x * 128;
    const long k0 = (long)blockIdx.z * kLen;
    const int nIter = kLen / 32;
    const uint32_t sS = smem_u32(sm);

    float acc[4][4][4];
    #pragma unroll
    for (int i = 0; i < 4; i++)
        #pragma unroll
        for (int j = 0; j < 4; j++)
            #pragma unroll
            for (int r = 0; r < 4; r++) acc[i][j][r] = 0.f;

    auto load_stage = [&](int buf, long kk) {
        #pragma unroll
        for (int i = 0; i < 8; i++) {
            int idx = tid + i * 256;           // 0..2047
            int row = idx >> 3, ch = idx & 7;
            uint32_t off = (uint32_t)((buf * GROWS + row) * SROW + ch * 4) * 4u;
            if (row < 128) {
                cp_async16(sS + off, X + (long)(m0 + row) * ldx + kk + ch * 4, 16);
            } else {
                int nr = n0 + row - 128;
                const float* gb = W + (long)(nr < N ? nr : 0) * ldw + kk + ch * 4;
                cp_async16(sS + off, gb, nr < N ? 16 : 0);
            }
        }
    };

    // ldmatrix per-thread base addresses (bytes):
    const uint32_t aBase = sS +
        (uint32_t)(((wm * 64 + ((lane >> 3) & 1) * 8 + (lane & 7)) * SROW
                    + ((lane >> 4) & 1) * 4) * 4);
    const uint32_t bBase = sS +
        (uint32_t)(((128 + wn * 32 + ((lane >> 4) & 1) * 8 + (lane & 7)) * SROW
                    + ((lane >> 3) & 1) * 4) * 4);

    load_stage(0, k0); CP_COMMIT();
    load_stage(1, k0 + 32); CP_COMMIT();

    for (int it = 0; it < nIter; it++) {
        if (it + 1 < nIter) { CP_WAIT1(); } else { CP_WAIT0(); }
        __syncthreads();

        const uint32_t stgOff = (uint32_t)((it % 3) * GSTG * 4);
        const uint32_t aS = aBase + stgOff;
        const uint32_t bS = bBase + stgOff;
        #pragma unroll
        for (int ks = 0; ks < 4; ks++) {
            uint32_t a[4][4], b[4][2];
            #pragma unroll
            for (int mi = 0; mi < 4; mi++)
                ldsm_x4(a[mi][0], a[mi][1], a[mi][2], a[mi][3],
                        aS + (uint32_t)(mi * 16 * SROW * 4 + ks * 32));
            #pragma unroll
            for (int p = 0; p < 2; p++) {
                uint32_t r0, r1, r2, r3;
                ldsm_x4(r0, r1, r2, r3,
                        bS + (uint32_t)(p * 16 * SROW * 4 + ks * 32));
                b[2 * p][0]     = f2tf32(__uint_as_float(r0));
                b[2 * p][1]     = f2tf32(__uint_as_float(r1));
                b[2 * p + 1][0] = f2tf32(__uint_as_float(r2));
                b[2 * p + 1][1] = f2tf32(__uint_as_float(r3));
            }
            #pragma unroll
            for (int mi = 0; mi < 4; mi++)
                #pragma unroll
                for (int ni = 0; ni < 4; ni++)
                    mma_tf32(acc[mi][ni], a[mi], b[ni]);
        }
        if (it + 2 < nIter) { load_stage((it + 2) % 3, k0 + (long)(it + 2) * 32); CP_COMMIT(); }
    }

    // epilogue
    #pragma unroll
    for (int mi = 0; mi < 4; mi++) {
        int m = m0 + wm * 64 + mi * 16 + gid;
        #pragma unroll
        for (int ni = 0; ni < 4; ni++) {
            int n = n0 + wn * 32 + ni * 8 + tig * 2;
            if (n >= N) continue;
            float* p0 = C + (long)m * ldc + n;
            float* p1 = C + (long)(m + 8) * ldc + n;
            float c0 = acc[mi][ni][0], c1 = acc[mi][ni][1];
            float c2 = acc[mi][ni][2], c3 = acc[mi][ni][3];
            if (EPI == 1) {
                atomicAdd(p0, c0); atomicAdd(p0 + 1, c1);
                atomicAdd(p1, c2); atomicAdd(p1 + 1, c3);
            } else if (EPI == 2) {
                float b0v = bias[n], b1v = bias[n + 1];
                *reinterpret_cast<float2*>(p0) =
                    make_float2(softplusf(c0 + b0v), softplusf(c1 + b1v));
                *reinterpret_cast<float2*>(p1) =
                    make_float2(softplusf(c2 + b0v), softplusf(c3 + b1v));
            } else {
                *reinterpret_cast<float2*>(p0) = make_float2(c0, c1);
                *reinterpret_cast<float2*>(p1) = make_float2(c2, c3);
            }
        }
    }
}

// ---------------- LayerNorm 1 (output tf32-rounded) ----------------
__global__ void ln1_kernel(const float* __restrict__ x, const float* __restrict__ g,
                           const float* __restrict__ bta, float* __restrict__ out) {
    int b  = blockIdx.x >> 7;
    int l0 = (blockIdx.x & 127) * 32;
    __shared__ float sm[128 * 33];
    int tid = threadIdx.x;
    #pragma unroll
    for (int i = 0; i < 16; i++) {
        int idx = tid + i * 256;
        int c = idx >> 5, l = idx & 31;
        sm[c * 33 + l] = x[((long)b * CH + c) * LL + l0 + l];
    }
    __syncthreads();
    int warp = tid >> 5, lane = tid & 31;
    for (int t = warp; t < 32; t += 8) {
        float v[4]; float s = 0.f, sq = 0.f;
        #pragma unroll
        for (int j = 0; j < 4; j++) {
            v[j] = sm[(lane + 32 * j) * 33 + t];
            s += v[j]; sq += v[j] * v[j];
        }
        #pragma unroll
        for (int o = 16; o; o >>= 1) {
            s  += __shfl_xor_sync(0xffffffffu, s,  o);
            sq += __shfl_xor_sync(0xffffffffu, sq, o);
        }
        float mu  = s * (1.f / 128.f);
        float var = sq * (1.f / 128.f) - mu * mu;
        float rs  = rsqrtf(var + 1e-5f);
        #pragma unroll
        for (int j = 0; j < 4; j++) {
            int c = lane + 32 * j;
            out[((long)b * LL + l0 + t) * D1M + c] = rnd_tf32((v[j] - mu) * rs * g[c] + bta[c]);
        }
    }
}

// ---------------- LayerNorm 2 (output tf32-rounded) ----------------
__global__ void ln2_kernel(const float* __restrict__ x, const float* __restrict__ g,
                           const float* __restrict__ bta, float* __restrict__ out) {
    long row = blockIdx.x;
    const float* xr = x + row * D2M;
    float* orow = out + row * D2M;
    int tid = threadIdx.x;
    float v[16]; float s = 0.f, sq = 0.f;
    #pragma unroll
    for (int i = 0; i < 16; i++) {
        v[i] = xr[i * 256 + tid];
        s += v[i]; sq += v[i] * v[i];
    }
    #pragma unroll
    for (int o = 16; o; o >>= 1) {
        s  += __shfl_xor_sync(0xffffffffu, s,  o);
        sq += __shfl_xor_sync(0xffffffffu, sq, o);
    }
    __shared__ float ss[8], sqq[8];
    int lane = tid & 31, warp = tid >> 5;
    if (!lane) { ss[warp] = s; sqq[warp] = sq; }
    __syncthreads();
    s = 0.f; sq = 0.f;
    #pragma unroll
    for (int w = 0; w < 8; w++) { s += ss[w]; sq += sqq[w]; }
    float mu  = s * (1.f / 4096.f);
    float var = sq * (1.f / 4096.f) - mu * mu;
    float rs  = rsqrtf(var + 1e-5f);
    #pragma unroll
    for (int i = 0; i < 16; i++) {
        int col = i * 256 + tid;
        orow[col] = rnd_tf32((v[i] - mu) * rs * g[col] + bta[col]);
    }
}

// ---------------- fallback SGEMM (dt1: K=8) ----------------
template<int ACT, bool HASBIAS>
__global__ void sgemm_kernel(const float* __restrict__ X, const float* __restrict__ W,
                             const float* __restrict__ bias, float* __restrict__ out,
                             int M, int N, int K, int lda, int ldc) {
    constexpr int BM = 64, BN = 64, BK = 32, PAD = 4;
    __shared__ float As[BK][BM + PAD];
    __shared__ float Bs[BK][BN + PAD];
    int bm = blockIdx.y * BM, bn = blockIdx.x * BN;
    int tid = threadIdx.x;
    int tx = tid & 15, ty = tid >> 4;
    float acc[4][4] = {};
    for (int k0 = 0; k0 < K; k0 += BK) {
        #pragma unroll
        for (int i = 0; i < 2; i++) {
            int idx = tid + i * 256;
            int row = idx >> 3;
            int kc  = (idx & 7) << 2;
            int k   = k0 + kc;
            float4 va = make_float4(0.f, 0.f, 0.f, 0.f);
            float4 vb = make_float4(0.f, 0.f, 0.f, 0.f);
            if (k < K) {
                int m = bm + row;
                if (m < M) va = *reinterpret_cast<const float4*>(X + (long)m * lda + k);
                int n = bn + row;
                if (n < N) vb = *reinterpret_cast<const float4*>(W + (long)n * K + k);
            }
            As[kc][row] = va.x; As[kc + 1][row] = va.y; As[kc + 2][row] = va.z; As[kc + 3][row] = va.w;
            Bs[kc][row] = vb.x; Bs[kc + 1][row] = vb.y; Bs[kc + 2][row] = vb.z; Bs[kc + 3][row] = vb.w;
        }
        __syncthreads();
        #pragma unroll
        for (int kk = 0; kk < BK; kk++) {
            float4 a = *reinterpret_cast<const float4*>(&As[kk][ty << 2]);
            float4 b = *reinterpret_cast<const float4*>(&Bs[kk][tx << 2]);
            float av[4] = {a.x, a.y, a.z, a.w};
            float bv[4] = {b.x, b.y, b.z, b.w};
            #pragma unroll
            for (int i = 0; i < 4; i++)
                #pragma unroll
                for (int j = 0; j < 4; j++)
                    acc[i][j] += av[i] * bv[j];
        }
        __syncthreads();
    }
    #pragma unroll
    for (int i = 0; i < 4; i++) {
        int m = bm + (ty << 2) + i;
        if (m >= M) continue;
        #pragma unroll
        for (int j = 0; j < 4; j++) {
            int n = bn + (tx << 2) + j;
            if (n >= N) continue;
            float v = acc[i][j];
            if (HASBIAS) v += bias[n];
            if (ACT == 1) v = softplusf(v);
            out[(long)m * ldc + n] = v;
        }
    }
}

// ---------------- causal depthwise conv (K=4) + SiLU, float4-vectorized ----------------
__global__ void conv_silu_kernel(const float* __restrict__ xz, const float* __restrict__ w,
                                 const float* __restrict__ bias, float* __restrict__ out,
                                 int Ltok, int dinner) {
    long tid = (long)blockIdx.x * 256 + threadIdx.x;     // one thread = 4 channels
    long total = (long)BATCH * Ltok * (dinner / 4);
    if (tid >= total) return;
    int d4 = (int)(tid % (dinner / 4)) * 4;
    long t = tid / (dinner / 4);
    int l = (int)(t % Ltok);
    int b = (int)(t / Ltok);
    int rowstride = 2 * dinner;
    const float* base = xz + ((long)b * Ltok + l) * rowstride + d4;
    float4 bv = *reinterpret_cast<const float4*>(bias + d4);
    float acc0 = bv.x, acc1 = bv.y, acc2 = bv.z, acc3 = bv.w;
    #pragma unroll
    for (int k = 0; k < 4; k++) {
        int ll = l - 3 + k;
        if (ll >= 0) {
            float4 xv = *reinterpret_cast<const float4*>(base + (long)(ll - l) * rowstride);
            acc0 += xv.x * w[(d4 + 0) * 4 + k];
            acc1 += xv.y * w[(d4 + 1) * 4 + k];
            acc2 += xv.z * w[(d4 + 2) * 4 + k];
            acc3 += xv.w * w[(d4 + 3) * 4 + k];
        }
    }
    float4 ov;
    ov.x = rnd_tf32(siluf(acc0)); ov.y = rnd_tf32(siluf(acc1));
    ov.z = rnd_tf32(siluf(acc2)); ov.w = rnd_tf32(siluf(acc3));
    *reinterpret_cast<float4*>(out + ((long)b * Ltok + l) * dinner + d4) = ov;
}

// ---------------- path-1 scan ----------------
__global__ void scan1_partial(const float* __restrict__ delta, const float* __restrict__ xc,
                              const float* __restrict__ dbl, const float* __restrict__ Alog) {
    int d = threadIdx.x;
    int chunk = blockIdx.x & (NCH - 1);
    int b = blockIdx.x >> 5;
    float A[NS], h[NS], P[NS];
    #pragma unroll
    for (int s = 0; s < NS; s++) { A[s] = -__expf(Alog[d * NS + s]); h[s] = 0.f; P[s] = 1.f; }
    int l0 = chunk * CLEN;
    for (int i = 0; i < CLEN; i++) {
        long t = (long)b * LL + l0 + i;
        float dl = delta[t * D1I + d];
        float xv = xc[t * D1I + d];
        const float* bl = dbl + t * DBL1 + DT1R;
        float dx = dl * xv;
        #pragma unroll
        for (int s = 0; s < NS; s++) {
            float dA = __expf(dl * A[s]);
            h[s] = dA * h[s] + dx * bl[s];
            P[s] *= dA;
        }
    }
    long o = (((long)b * D1I + d) * NCH + chunk) * NS;
    #pragma unroll
    for (int s = 0; s < NS; s++) { g_ckP[o + s] = P[s]; g_ckH[o + s] = h[s]; }
}

__global__ void scan1_carry() {
    int idx = blockIdx.x * 256 + threadIdx.x;
    if (idx >= BATCH * D1I) return;
    long base = (long)idx * NCH * NS;
    float h[NS];
    #pragma unroll
    for (int s = 0; s < NS; s++) h[s] = 0.f;
    for (int c = 0; c < NCH; c++) {
        long o = base + (long)c * NS;
        #pragma unroll
        for (int s = 0; s < NS; s++) {
            g_hin[o + s] = h[s];
            h[s] = g_ckP[o + s] * h[s] + g_ckH[o + s];
        }
    }
}

__global__ void scan1_final(const float* __restrict__ delta, const float* __restrict__ xc,
                            const float* __restrict__ dbl, const float* __restrict__ Alog,
                            const float* __restrict__ Dp, const float* __restrict__ xz,
                            float* __restrict__ y) {
    int d = threadIdx.x;
    int chunk = blockIdx.x & (NCH - 1);
    int b = blockIdx.x >> 5;
    float A[NS], h[NS];
    long hb = (((long)b * D1I + d) * NCH + chunk) * NS;
    #pragma unroll
    for (int s = 0; s < NS; s++) { A[s] = -__expf(Alog[d * NS + s]); h[s] = g_hin[hb + s]; }
    float Dv = Dp[d];
    int l0 = chunk * CLEN;
    for (int i = 0; i < CLEN; i++) {
        long t = (long)b * LL + l0 + i;
        float dl = delta[t * D1I + d];
        float xv = xc[t * D1I + d];
        const float* bl = dbl + t * DBL1 + DT1R;
        float dx = dl * xv;
        float acc = 0.f;
        #pragma unroll
        for (int s = 0; s < NS; s++) {
            float dA = __expf(dl * A[s]);
            h[s] = dA * h[s] + dx * bl[s];
            acc += h[s] * bl[NS + s];
        }
        float z = xz[t * (2 * D1I) + D1I + d];
        y[t * D1I + d] = rnd_tf32((acc + xv * Dv) * siluf(z));
    }
}

// ---------------- path-2 scan ----------------
__global__ void scan2_kernel(const float* __restrict__ delta, const float* __restrict__ xc,
                             const float* __restrict__ dbl, const float* __restrict__ Alog,
                             const float* __restrict__ Dp, const float* __restrict__ xz,
                             float* __restrict__ y) {
    int d = (blockIdx.x & 31) * 256 + threadIdx.x;
    int b = blockIdx.x >> 5;
    float A[NS], h[NS];
    #pragma unroll
    for (int s = 0; s < NS; s++) { A[s] = -__expf(Alog[d * NS + s]); h[s] = 0.f; }
    float Dv = Dp[d];
    for (int l = 0; l < CH; l++) {
        long t = (long)b * CH + l;
        float dl = delta[t * D2I + d];
        float xv = xc[t * D2I + d];
        const float* bl = dbl + t * DBL2 + DT2R;
        float dx = dl * xv;
        float acc = 0.f;
        #pragma unroll
        for (int s = 0; s < NS; s++) {
            float dA = __expf(dl * A[s]);
            h[s] = dA * h[s] + dx * bl[s];
            acc += h[s] * bl[NS + s];
        }
        float z = xz[t * (2 * D2I) + D2I + d];
        y[t * D2I + d] = rnd_tf32((acc + xv * Dv) * siluf(z));
    }
}

// ---------------- combine ----------------
__global__ void combine_kernel(const float* __restrict__ x, float* __restrict__ out) {
    long i = (long)blockIdx.x * 256 + threadIdx.x;
    if (i >= (long)BATCH * CH * LL) return;
    int l = (int)(i % LL);
    long t = i / LL;
    int c = (int)(t % CH);
    int b = (int)(t / CH);
    out[i] = x[i] + g_out2[i] + g_out1[((long)b * LL + l) * D1M + c];
}

// ---------------- launch ----------------
extern "C" void kernel_launch(void* const* d_in, const int* in_sizes, int n_in,
                              void* d_out, int out_size) {
    const float* x        = (const float*)d_in[0];
    const float* ln1_g    = (const float*)d_in[1];
    const float* ln1_b    = (const float*)d_in[2];
    const float* ln2_g    = (const float*)d_in[3];
    const float* ln2_b    = (const float*)d_in[4];
    const float* m1_in_w  = (const float*)d_in[5];
    const float* m1_cw    = (const float*)d_in[6];
    const float* m1_cb    = (const float*)d_in[7];
    const float* m1_xp_w  = (const float*)d_in[8];
    const float* m1_dt_w  = (const float*)d_in[9];
    const float* m1_dt_b  = (const float*)d_in[10];
    const float* m1_Alog  = (const float*)d_in[11];
    const float* m1_D     = (const float*)d_in[12];
    const float* m1_out_w = (const float*)d_in[13];
    const float* m2_in_w  = (const float*)d_in[14];
    const float* m2_cw    = (const float*)d_in[15];
    const float* m2_cb    = (const float*)d_in[16];
    const float* m2_xp_w  = (const float*)d_in[17];
    const float* m2_dt_w  = (const float*)d_in[18];
    const float* m2_dt_b  = (const float*)d_in[19];
    const float* m2_Alog  = (const float*)d_in[20];
    const float* m2_D     = (const float*)d_in[21];
    const float* m2_out_w = (const float*)d_in[22];
    float* out = (float*)d_out;

    float *pxn1, *pxz1, *pxc1, *pdbl1, *pdelta1, *py1, *pout1;
    float *pxn2, *pxz2, *pxc2, *pdbl2, *pdelta2, *py2, *pout2;
    cudaGetSymbolAddress((void**)&pxn1, g_xn1);
    cudaGetSymbolAddress((void**)&pxz1, g_xz1);
    cudaGetSymbolAddress((void**)&pxc1, g_xc1);
    cudaGetSymbolAddress((void**)&pdbl1, g_dbl1);
    cudaGetSymbolAddress((void**)&pdelta1, g_delta1);
    cudaGetSymbolAddress((void**)&py1, g_y1);
    cudaGetSymbolAddress((void**)&pout1, g_out1);
    cudaGetSymbolAddress((void**)&pxn2, g_xn2);
    cudaGetSymbolAddress((void**)&pxz2, g_xz2);
    cudaGetSymbolAddress((void**)&pxc2, g_xc2);
    cudaGetSymbolAddress((void**)&pdbl2, g_dbl2);
    cudaGetSymbolAddress((void**)&pdelta2, g_delta2);
    cudaGetSymbolAddress((void**)&py2, g_y2);
    cudaGetSymbolAddress((void**)&pout2, g_out2);

    cudaFuncSetAttribute(tf32_gemm<0>, cudaFuncAttributeMaxDynamicSharedMemorySize, GSMEM_BYTES);
    cudaFuncSetAttribute(tf32_gemm<1>, cudaFuncAttributeMaxDynamicSharedMemorySize, GSMEM_BYTES);
    cudaFuncSetAttribute(tf32_gemm<2>, cudaFuncAttributeMaxDynamicSharedMemorySize, GSMEM_BYTES);

    // one-time side streams + events (created on first call, outside graph capture;
    // reused identically every call — deterministic, no device allocation)
    static cudaStream_t s2 = nullptr, s3 = nullptr;
    static cudaEvent_t evFork = nullptr, evFork3 = nullptr, evJoin = nullptr, evJoinB = nullptr;
    if (!s2) {
        cudaStreamCreateWithFlags(&s2, cudaStreamNonBlocking);
        cudaStreamCreateWithFlags(&s3, cudaStreamNonBlocking);
        cudaEventCreateWithFlags(&evFork, cudaEventDisableTiming);
        cudaEventCreateWithFlags(&evFork3, cudaEventDisableTiming);
        cudaEventCreateWithFlags(&evJoin, cudaEventDisableTiming);
        cudaEventCreateWithFlags(&evJoinB, cudaEventDisableTiming);
    }

    const int T = 256;
    // ---- main stream: path-2 prologue ----
    cudaMemsetAsync(pdbl2, 0, sizeof(float) * BATCH * CH * DBL2);
    cudaMemsetAsync(pout2, 0, sizeof(float) * BATCH * CH * D2M);
    ln2_kernel<<<BATCH * CH, T>>>(x, ln2_g, ln2_b, pxn2);

    // fork s2 (path 1) and s3 (in2b) — both depend on work queued so far
    cudaEventRecord(evFork, 0);
    cudaStreamWaitEvent(s2, evFork, 0);
    cudaEventRecord(evFork3, 0);
    cudaStreamWaitEvent(s3, evFork3, 0);

    // ---- s2: full path 1 ----
    cudaMemsetAsync(pout1, 0, sizeof(float) * BATCH * LL * D1M, s2);
    ln1_kernel<<<BATCH * (LL / 32), T, 0, s2>>>(x, ln1_g, ln1_b, pxn1);
    tf32_gemm<0><<<dim3(4, 64, 1), 256, GSMEM_BYTES, s2>>>(
        pxn1, m1_in_w, nullptr, pxz1, BATCH * LL, 2 * D1I, D1M, D1M, D1M, 2 * D1I);
    conv_silu_kernel<<<(BATCH * LL * D1I / 4 + T - 1) / T, T, 0, s2>>>(
        pxz1, m1_cw, m1_cb, pxc1, LL, D1I);
    tf32_gemm<0><<<dim3(1, 64, 1), 256, GSMEM_BYTES, s2>>>(
        pxc1, m1_xp_w, nullptr, pdbl1, BATCH * LL, DBL1, D1I, D1I, D1I, DBL1);
    sgemm_kernel<1, true><<<dim3((D1I + 63) / 64, (BATCH * LL) / 64), T, 0, s2>>>(
        pdbl1, m1_dt_w, m1_dt_b, pdelta1, BATCH * LL, D1I, DT1R, DBL1, D1I);
    scan1_partial<<<BATCH * NCH, D1I, 0, s2>>>(pdelta1, pxc1, pdbl1, m1_Alog);
    scan1_carry<<<(BATCH * D1I + T - 1) / T, T, 0, s2>>>();
    scan1_final<<<BATCH * NCH, D1I, 0, s2>>>(pdelta1, pxc1, pdbl1, m1_Alog, m1_D, pxz1, py1);
    tf32_gemm<1><<<dim3(1, 64, 2), 256, GSMEM_BYTES, s2>>>(
        py1, m1_out_w, nullptr, pout1, BATCH * LL, D1M, D1I / 2, D1I, D1I, D1M);

    // ---- s3: in2b — z half: xz2[:, 8192:16384] = xn2 @ in_w[8192:16384]^T ----
    tf32_gemm<0><<<dim3(64, 2, 1), 256, GSMEM_BYTES, s3>>>(
        pxn2, m2_in_w + (long)D2I * D2M, nullptr, pxz2 + D2I,
        BATCH * CH, D2I, D2M, D2M, D2M, 2 * D2I);
    cudaEventRecord(evJoinB, s3);

    // ---- main stream: in2a — xi half: xz2[:, 0:8192] = xn2 @ in_w[0:8192]^T ----
    tf32_gemm<0><<<dim3(64, 2, 1), 256, GSMEM_BYTES>>>(
        pxn2, m2_in_w, nullptr, pxz2, BATCH * CH, D2I, D2M, D2M, D2M, 2 * D2I);

    // dependent chain on xi half only
    conv_silu_kernel<<<(BATCH * CH * D2I / 4 + T - 1) / T, T>>>(pxz2, m2_cw, m2_cb, pxc2, CH, D2I);
    // xp2: dbl2[256, 272] split-K=32 atomic (192 CTAs)
    tf32_gemm<1><<<dim3(3, 2, 32), 256, GSMEM_BYTES>>>(
        pxc2, m2_xp_w, nullptr, pdbl2, BATCH * CH, DBL2, D2I / 32, D2I, D2I, DBL2);
    // dt2: delta2[256, 8192] = softplus(dbl2[:, :256] @ dt_w^T + b)
    tf32_gemm<2><<<dim3(64, 2, 1), 256, GSMEM_BYTES>>>(
        pdbl2, m2_dt_w, m2_dt_b, pdelta2, BATCH * CH, D2I, DT2R, DBL2, DT2R, D2I);

    // scan2 needs the z half — join s3 first
    cudaStreamWaitEvent(0, evJoinB, 0);
    scan2_kernel<<<BATCH * (D2I / 256), T>>>(pdelta2, pxc2, pdbl2, m2_Alog, m2_D, pxz2, py2);
    // out2: out2[256, 4096] split-K=4 atomic (256 CTAs)
    tf32_gemm<1><<<dim3(32, 2, 4), 256, GSMEM_BYTES>>>(
        py2, m2_out_w, nullptr, pout2, BATCH * CH, D2M, D2I / 4, D2I, D2I, D2M);

    // join s2 (path 1), then combine
    cudaEventRecord(evJoin, s2);
    cudaStreamWaitEvent(0, evJoin, 0);
    combine_kernel<<<(BATCH * CH * LL + T - 1) / T, T>>>(x, out);
}

// round 11
// speedup vs baseline: 1.6675x; 1.1083x over previous
#include <cuda_runtime.h>
#include <cuda_fp16.h>
#include <cstdint>
#include <math.h>

// ---------------- problem constants ----------------
#define BATCH 2
#define CH    128
#define LL    4096
#define NS    8

#define D1M  128
#define D1I  256
#define DT1R 8
#define DBL1 24
#define D2M  4096
#define D2I  8192
#define DT2R 256
#define DBL2 272      // dt_rank(256) + 2*8

#define NCH  32
#define CLEN 128

// ---------------- scratch ----------------
__device__ __align__(16) float g_xn1[BATCH*LL*D1M];
__device__ __align__(16) float g_xz1[BATCH*LL*2*D1I];
__device__ __align__(16) float g_xc1[BATCH*LL*D1I];
__device__ __align__(16) float g_dbl1[BATCH*LL*DBL1];
__device__ __align__(16) float g_delta1[BATCH*LL*D1I];
__device__ __align__(16) float g_y1[BATCH*LL*D1I];
__device__ __align__(16) float g_out1[BATCH*LL*D1M];
__device__ __align__(16) float g_ckP[BATCH*D1I*NCH*NS];
__device__ __align__(16) float g_ckH[BATCH*D1I*NCH*NS];
__device__ __align__(16) float g_hin[BATCH*D1I*NCH*NS];

__device__ __align__(16) float g_xn2[BATCH*CH*D2M];
__device__ __align__(16) float g_xz2[BATCH*CH*2*D2I];
__device__ __align__(16) float g_dbl2[BATCH*CH*DBL2];
__device__ __align__(16) float g_delta2[BATCH*CH*D2I];
__device__ __align__(16) float g_out2[BATCH*CH*D2M];

// fp16 scratch
__device__ __align__(16) __half g_xc2h[BATCH*CH*D2I];
__device__ __align__(16) __half g_y2h[BATCH*CH*D2I];
__device__ __align__(16) __half g_dbl2h[BATCH*CH*DBL2];
__device__ __align__(16) __half g_xpw_h[DBL2*D2I];
__device__ __align__(16) __half g_dtw_h[D2I*DT2R];
__device__ __align__(16) __half g_outw_h[(long)D2M*D2I];

// ---------------- helpers ----------------
__device__ __forceinline__ uint32_t smem_u32(const void* p) {
    uint32_t a;
    asm("{ .reg .u64 t; cvta.to.shared.u64 t, %1; cvt.u32.u64 %0, t; }" : "=r"(a) : "l"(p));
    return a;
}
__device__ __forceinline__ void cp_async16(uint32_t dst, const void* src, int sz) {
    asm volatile("cp.async.cg.shared.global [%0], [%1], 16, %2;"
                 :: "r"(dst), "l"(src), "r"(sz) : "memory");
}
#define CP_COMMIT() asm volatile("cp.async.commit_group;" ::: "memory")
#define CP_WAIT1()  asm volatile("cp.async.wait_group 1;" ::: "memory")
#define CP_WAIT0()  asm volatile("cp.async.wait_group 0;" ::: "memory")

__device__ __forceinline__ uint32_t f2tf32(float f) {
    uint32_t r;
    asm("cvt.rna.tf32.f32 %0, %1;" : "=r"(r) : "f"(f));
    return r;
}
__device__ __forceinline__ float rnd_tf32(float v) { return __uint_as_float(f2tf32(v)); }

__device__ __forceinline__ void mma_tf32(float* d, const uint32_t* a, const uint32_t* b) {
    asm volatile(
        "mma.sync.aligned.m16n8k8.row.col.f32.tf32.tf32.f32 "
        "{%0,%1,%2,%3}, {%4,%5,%6,%7}, {%8,%9}, {%0,%1,%2,%3};"
        : "+f"(d[0]), "+f"(d[1]), "+f"(d[2]), "+f"(d[3])
        : "r"(a[0]), "r"(a[1]), "r"(a[2]), "r"(a[3]), "r"(b[0]), "r"(b[1]));
}
__device__ __forceinline__ void mma_f16(float* d, const uint32_t* a, const uint32_t* b) {
    asm volatile(
        "mma.sync.aligned.m16n8k16.row.col.f32.f16.f16.f32 "
        "{%0,%1,%2,%3}, {%4,%5,%6,%7}, {%8,%9}, {%0,%1,%2,%3};"
        : "+f"(d[0]), "+f"(d[1]), "+f"(d[2]), "+f"(d[3])
        : "r"(a[0]), "r"(a[1]), "r"(a[2]), "r"(a[3]), "r"(b[0]), "r"(b[1]));
}
__device__ __forceinline__ void ldsm_x4(uint32_t& r0, uint32_t& r1, uint32_t& r2, uint32_t& r3,
                                        uint32_t addr) {
    asm volatile("ldmatrix.sync.aligned.m8n8.x4.shared.b16 {%0,%1,%2,%3}, [%4];"
                 : "=r"(r0), "=r"(r1), "=r"(r2), "=r"(r3) : "r"(addr));
}

__device__ __forceinline__ float siluf(float v) { return v / (1.f + __expf(-v)); }
__device__ __forceinline__ float softplusf(float v) { return (v > 20.f) ? v : log1pf(__expf(v)); }

// ======================================================================
// tf32 mma.sync GEMM (unchanged from round 10) — used for in1/in2/xp1/out1
// ======================================================================
#define SROW 36
#define GROWS 256
#define GSTG (GROWS * SROW)
#define GSMEM_BYTES (3 * GSTG * 4)      // 108 KB -> 2 CTAs/SM

template<int EPI>
__global__ void __launch_bounds__(256, 2)
tf32_gemm(const float* __restrict__ X, const float* __restrict__ W,
          const float* __restrict__ bias, float* __restrict__ C,
          int M, int N, int kLen, int ldx, int ldw, int ldc) {
    extern __shared__ float sm[];
    const int tid = threadIdx.x;
    const int wid = tid >> 5, lane = tid & 31;
    const int gid = lane >> 2, tig = lane & 3;
    const int wm = wid >> 2, wn = wid & 3;
    const int m0 = blockIdx.y * 128, n0 = blockIdx.x * 128;
    const long k0 = (long)blockIdx.z * kLen;
    const int nIter = kLen / 32;
    const uint32_t sS = smem_u32(sm);

    float acc[4][4][4];
    #pragma unroll
    for (int i = 0; i < 4; i++)
        #pragma unroll
        for (int j = 0; j < 4; j++)
            #pragma unroll
            for (int r = 0; r < 4; r++) acc[i][j][r] = 0.f;

    auto load_stage = [&](int buf, long kk) {
        #pragma unroll
        for (int i = 0; i < 8; i++) {
            int idx = tid + i * 256;
            int row = idx >> 3, ch = idx & 7;
            uint32_t off = (uint32_t)((buf * GROWS + row) * SROW + ch * 4) * 4u;
            if (row < 128) {
                cp_async16(sS + off, X + (long)(m0 + row) * ldx + kk + ch * 4, 16);
            } else {
                int nr = n0 + row - 128;
                const float* gb = W + (long)(nr < N ? nr : 0) * ldw + kk + ch * 4;
                cp_async16(sS + off, gb, nr < N ? 16 : 0);
            }
        }
    };

    const uint32_t aBase = sS +
        (uint32_t)(((wm * 64 + ((lane >> 3) & 1) * 8 + (lane & 7)) * SROW
                    + ((lane >> 4) & 1) * 4) * 4);
    const uint32_t bBase = sS +
        (uint32_t)(((128 + wn * 32 + ((lane >> 4) & 1) * 8 + (lane & 7)) * SROW
                    + ((lane >> 3) & 1) * 4) * 4);

    load_stage(0, k0); CP_COMMIT();
    load_stage(1, k0 + 32); CP_COMMIT();

    for (int it = 0; it < nIter; it++) {
        if (it + 1 < nIter) { CP_WAIT1(); } else { CP_WAIT0(); }
        __syncthreads();
        const uint32_t stgOff = (uint32_t)((it % 3) * GSTG * 4);
        const uint32_t aS = aBase + stgOff;
        const uint32_t bS = bBase + stgOff;
        #pragma unroll
        for (int ks = 0; ks < 4; ks++) {
            uint32_t a[4][4], b[4][2];
            #pragma unroll
            for (int mi = 0; mi < 4; mi++)
                ldsm_x4(a[mi][0], a[mi][1], a[mi][2], a[mi][3],
                        aS + (uint32_t)(mi * 16 * SROW * 4 + ks * 32));
            #pragma unroll
            for (int p = 0; p < 2; p++) {
                uint32_t r0, r1, r2, r3;
                ldsm_x4(r0, r1, r2, r3, bS + (uint32_t)(p * 16 * SROW * 4 + ks * 32));
                b[2 * p][0]     = f2tf32(__uint_as_float(r0));
                b[2 * p][1]     = f2tf32(__uint_as_float(r1));
                b[2 * p + 1][0] = f2tf32(__uint_as_float(r2));
                b[2 * p + 1][1] = f2tf32(__uint_as_float(r3));
            }
            #pragma unroll
            for (int mi = 0; mi < 4; mi++)
                #pragma unroll
                for (int ni = 0; ni < 4; ni++)
                    mma_tf32(acc[mi][ni], a[mi], b[ni]);
        }
        if (it + 2 < nIter) { load_stage((it + 2) % 3, k0 + (long)(it + 2) * 32); CP_COMMIT(); }
    }

    #pragma unroll
    for (int mi = 0; mi < 4; mi++) {
        int m = m0 + wm * 64 + mi * 16 + gid;
        #pragma unroll
        for (int ni = 0; ni < 4; ni++) {
            int n = n0 + wn * 32 + ni * 8 + tig * 2;
            if (n >= N) continue;
            float* p0 = C + (long)m * ldc + n;
            float* p1 = C + (long)(m + 8) * ldc + n;
            float c0 = acc[mi][ni][0], c1 = acc[mi][ni][1];
            float c2 = acc[mi][ni][2], c3 = acc[mi][ni][3];
            if (EPI == 1) {
                atomicAdd(p0, c0); atomicAdd(p0 + 1, c1);
                atomicAdd(p1, c2); atomicAdd(p1 + 1, c3);
            } else if (EPI == 2) {
                float b0v = bias[n], b1v = bias[n + 1];
                *reinterpret_cast<float2*>(p0) =
                    make_float2(softplusf(c0 + b0v), softplusf(c1 + b1v));
                *reinterpret_cast<float2*>(p1) =
                    make_float2(softplusf(c2 + b0v), softplusf(c3 + b1v));
            } else {
                *reinterpret_cast<float2*>(p0) = make_float2(c0, c1);
                *reinterpret_cast<float2*>(p1) = make_float2(c2, c3);
            }
        }
    }
}

// ======================================================================
// fp16 mma.sync GEMM (m16n8k16): same structure, fp16 A/B, fp32 accum.
// BM=128, BN=128; warp tile 64x32; BK=32 halves; 3-stage cp.async.
// EPI: 1 = atomicAdd (split-K), 2 = softplus(v + bias[n]) store
// ======================================================================
#define SROWH 40
#define HSTG (256 * SROWH)              // halves per stage
#define HSMEM_BYTES (3 * HSTG * 2)      // 60 KB -> 2 CTAs/SM

template<int EPI>
__global__ void __launch_bounds__(256, 2)
fp16_gemm(const __half* __restrict__ X, const __half* __restrict__ W,
          const float* __restrict__ bias, float* __restrict__ C,
          int M, int N, int kLen, int ldx, int ldw, int ldc) {
    extern __shared__ __half smh[];
    const int tid = threadIdx.x;
    const int wid = tid >> 5, lane = tid & 31;
    const int gid = lane >> 2, tig = lane & 3;
    const int wm = wid >> 2, wn = wid & 3;
    const int m0 = blockIdx.y * 128, n0 = blockIdx.x * 128;
    const long k0 = (long)blockIdx.z * kLen;
    const int nIter = kLen / 32;
    const uint32_t sS = smem_u32(smh);

    float acc[4][4][4];
    #pragma unroll
    for (int i = 0; i < 4; i++)
        #pragma unroll
        for (int j = 0; j < 4; j++)
            #pragma unroll
            for (int r = 0; r < 4; r++) acc[i][j][r] = 0.f;

    auto load_stage = [&](int buf, long kk) {
        #pragma unroll
        for (int i = 0; i < 4; i++) {
            int idx = tid + i * 256;           // 0..1023
            int row = idx >> 2, ch = idx & 3;  // 4 x 16B chunks per 32-half row
            uint32_t off = (uint32_t)((buf * 256 + row) * SROWH + ch * 8) * 2u;
            if (row < 128) {
                cp_async16(sS + off, X + (long)(m0 + row) * ldx + kk + ch * 8, 16);
            } else {
                int nr = n0 + row - 128;
                const __half* gb = W + (long)(nr < N ? nr : 0) * ldw + kk + ch * 8;
                cp_async16(sS + off, gb, nr < N ? 16 : 0);
            }
        }
    };

    // ldmatrix bases (bytes). A: rows {+0,+8} x k {0,8}; B: n {+0,+8} x k {0,8}
    const uint32_t aBase = sS +
        (uint32_t)(((wm * 64 + ((lane >> 3) & 1) * 8 + (lane & 7)) * SROWH
                    + ((lane >> 4) & 1) * 8) * 2);
    const uint32_t bBase = sS +
        (uint32_t)(((128 + wn * 32 + ((lane >> 4) & 1) * 8 + (lane & 7)) * SROWH
                    + ((lane >> 3) & 1) * 8) * 2);

    load_stage(0, k0); CP_COMMIT();
    load_stage(1, k0 + 32); CP_COMMIT();

    for (int it = 0; it < nIter; it++) {
        if (it + 1 < nIter) { CP_WAIT1(); } else { CP_WAIT0(); }
        __syncthreads();
        const uint32_t stgOff = (uint32_t)((it % 3) * HSTG * 2);
        const uint32_t aS = aBase + stgOff;
        const uint32_t bS = bBase + stgOff;
        #pragma unroll
        for (int ks = 0; ks < 2; ks++) {           // two K=16 steps per 32-half tile
            uint32_t a[4][4], b[4][2];
            #pragma unroll
            for (int mi = 0; mi < 4; mi++)
                ldsm_x4(a[mi][0], a[mi][1], a[mi][2], a[mi][3],
                        aS + (uint32_t)(mi * 16 * SROWH * 2 + ks * 32));
            #pragma unroll
            for (int p = 0; p < 2; p++) {
                uint32_t r0, r1, r2, r3;
                ldsm_x4(r0, r1, r2, r3, bS + (uint32_t)(p * 16 * SROWH * 2 + ks * 32));
                b[2 * p][0] = r0;     b[2 * p][1] = r1;
                b[2 * p + 1][0] = r2; b[2 * p + 1][1] = r3;
            }
            #pragma unroll
            for (int mi = 0; mi < 4; mi++)
                #pragma unroll
                for (int ni = 0; ni < 4; ni++)
                    mma_f16(acc[mi][ni], a[mi], b[ni]);
        }
        if (it + 2 < nIter) { load_stage((it + 2) % 3, k0 + (long)(it + 2) * 32); CP_COMMIT(); }
    }

    #pragma unroll
    for (int mi = 0; mi < 4; mi++) {
        int m = m0 + wm * 64 + mi * 16 + gid;
        #pragma unroll
        for (int ni = 0; ni < 4; ni++) {
            int n = n0 + wn * 32 + ni * 8 + tig * 2;
            if (n >= N) continue;
            float* p0 = C + (long)m * ldc + n;
            float* p1 = C + (long)(m + 8) * ldc + n;
            float c0 = acc[mi][ni][0], c1 = acc[mi][ni][1];
            float c2 = acc[mi][ni][2], c3 = acc[mi][ni][3];
            if (EPI == 1) {
                atomicAdd(p0, c0); atomicAdd(p0 + 1, c1);
                atomicAdd(p1, c2); atomicAdd(p1 + 1, c3);
            } else if (EPI == 2) {
                float b0v = bias[n], b1v = bias[n + 1];
                *reinterpret_cast<float2*>(p0) =
                    make_float2(softplusf(c0 + b0v), softplusf(c1 + b1v));
                *reinterpret_cast<float2*>(p1) =
                    make_float2(softplusf(c2 + b0v), softplusf(c3 + b1v));
            } else {
                *reinterpret_cast<float2*>(p0) = make_float2(c0, c1);
                *reinterpret_cast<float2*>(p1) = make_float2(c2, c3);
            }
        }
    }
}

// ---------------- fp32 -> fp16 conversion (8 elts/thread) ----------------
__global__ void cvt_f2h(const float* __restrict__ src, __half* __restrict__ dst, long n) {
    long i = ((long)blockIdx.x * 256 + threadIdx.x) * 8;
    if (i >= n) return;
    float4 v0 = *reinterpret_cast<const float4*>(src + i);
    float4 v1 = *reinterpret_cast<const float4*>(src + i + 4);
    __half2 h[4];
    h[0] = __floats2half2_rn(v0.x, v0.y);
    h[1] = __floats2half2_rn(v0.z, v0.w);
    h[2] = __floats2half2_rn(v1.x, v1.y);
    h[3] = __floats2half2_rn(v1.z, v1.w);
    *reinterpret_cast<uint4*>(dst + i) = *reinterpret_cast<uint4*>(h);
}

// ---------------- LayerNorm 1 (tf32-rounded) ----------------
__global__ void ln1_kernel(const float* __restrict__ x, const float* __restrict__ g,
                           const float* __restrict__ bta, float* __restrict__ out) {
    int b  = blockIdx.x >> 7;
    int l0 = (blockIdx.x & 127) * 32;
    __shared__ float sm[128 * 33];
    int tid = threadIdx.x;
    #pragma unroll
    for (int i = 0; i < 16; i++) {
        int idx = tid + i * 256;
        int c = idx >> 5, l = idx & 31;
        sm[c * 33 + l] = x[((long)b * CH + c) * LL + l0 + l];
    }
    __syncthreads();
    int warp = tid >> 5, lane = tid & 31;
    for (int t = warp; t < 32; t += 8) {
        float v[4]; float s = 0.f, sq = 0.f;
        #pragma unroll
        for (int j = 0; j < 4; j++) {
            v[j] = sm[(lane + 32 * j) * 33 + t];
            s += v[j]; sq += v[j] * v[j];
        }
        #pragma unroll
        for (int o = 16; o; o >>= 1) {
            s  += __shfl_xor_sync(0xffffffffu, s,  o);
            sq += __shfl_xor_sync(0xffffffffu, sq, o);
        }
        float mu  = s * (1.f / 128.f);
        float var = sq * (1.f / 128.f) - mu * mu;
        float rs  = rsqrtf(var + 1e-5f);
        #pragma unroll
        for (int j = 0; j < 4; j++) {
            int c = lane + 32 * j;
            out[((long)b * LL + l0 + t) * D1M + c] = rnd_tf32((v[j] - mu) * rs * g[c] + bta[c]);
        }
    }
}

// ---------------- LayerNorm 2 (tf32-rounded) ----------------
__global__ void ln2_kernel(const float* __restrict__ x, const float* __restrict__ g,
                           const float* __restrict__ bta, float* __restrict__ out) {
    long row = blockIdx.x;
    const float* xr = x + row * D2M;
    float* orow = out + row * D2M;
    int tid = threadIdx.x;
    float v[16]; float s = 0.f, sq = 0.f;
    #pragma unroll
    for (int i = 0; i < 16; i++) {
        v[i] = xr[i * 256 + tid];
        s += v[i]; sq += v[i] * v[i];
    }
    #pragma unroll
    for (int o = 16; o; o >>= 1) {
        s  += __shfl_xor_sync(0xffffffffu, s,  o);
        sq += __shfl_xor_sync(0xffffffffu, sq, o);
    }
    __shared__ float ss[8], sqq[8];
    int lane = tid & 31, warp = tid >> 5;
    if (!lane) { ss[warp] = s; sqq[warp] = sq; }
    __syncthreads();
    s = 0.f; sq = 0.f;
    #pragma unroll
    for (int w = 0; w < 8; w++) { s += ss[w]; sq += sqq[w]; }
    float mu  = s * (1.f / 4096.f);
    float var = sq * (1.f / 4096.f) - mu * mu;
    float rs  = rsqrtf(var + 1e-5f);
    #pragma unroll
    for (int i = 0; i < 16; i++) {
        int col = i * 256 + tid;
        orow[col] = rnd_tf32((v[i] - mu) * rs * g[col] + bta[col]);
    }
}

// ---------------- fallback SGEMM (dt1: K=8) ----------------
template<int ACT, bool HASBIAS>
__global__ void sgemm_kernel(const float* __restrict__ X, const float* __restrict__ W,
                             const float* __restrict__ bias, float* __restrict__ out,
                             int M, int N, int K, int lda, int ldc) {
    constexpr int BM = 64, BN = 64, BK = 32, PAD = 4;
    __shared__ float As[BK][BM + PAD];
    __shared__ float Bs[BK][BN + PAD];
    int bm = blockIdx.y * BM, bn = blockIdx.x * BN;
    int tid = threadIdx.x;
    int tx = tid & 15, ty = tid >> 4;
    float acc[4][4] = {};
    for (int k0 = 0; k0 < K; k0 += BK) {
        #pragma unroll
        for (int i = 0; i < 2; i++) {
            int idx = tid + i * 256;
            int row = idx >> 3;
            int kc  = (idx & 7) << 2;
            int k   = k0 + kc;
            float4 va = make_float4(0.f, 0.f, 0.f, 0.f);
            float4 vb = make_float4(0.f, 0.f, 0.f, 0.f);
            if (k < K) {
                int m = bm + row;
                if (m < M) va = *reinterpret_cast<const float4*>(X + (long)m * lda + k);
                int n = bn + row;
                if (n < N) vb = *reinterpret_cast<const float4*>(W + (long)n * K + k);
            }
            As[kc][row] = va.x; As[kc + 1][row] = va.y; As[kc + 2][row] = va.z; As[kc + 3][row] = va.w;
            Bs[kc][row] = vb.x; Bs[kc + 1][row] = vb.y; Bs[kc + 2][row] = vb.z; Bs[kc + 3][row] = vb.w;
        }
        __syncthreads();
        #pragma unroll
        for (int kk = 0; kk < BK; kk++) {
            float4 a = *reinterpret_cast<const float4*>(&As[kk][ty << 2]);
            float4 b = *reinterpret_cast<const float4*>(&Bs[kk][tx << 2]);
            float av[4] = {a.x, a.y, a.z, a.w};
            float bv[4] = {b.x, b.y, b.z, b.w};
            #pragma unroll
            for (int i = 0; i < 4; i++)
                #pragma unroll
                for (int j = 0; j < 4; j++)
                    acc[i][j] += av[i] * bv[j];
        }
        __syncthreads();
    }
    #pragma unroll
    for (int i = 0; i < 4; i++) {
        int m = bm + (ty << 2) + i;
        if (m >= M) continue;
        #pragma unroll
        for (int j = 0; j < 4; j++) {
            int n = bn + (tx << 2) + j;
            if (n >= N) continue;
            float v = acc[i][j];
            if (HASBIAS) v += bias[n];
            if (ACT == 1) v = softplusf(v);
            out[(long)m * ldc + n] = v;
        }
    }
}

// ---------------- causal depthwise conv (K=4) + SiLU; HOUT: 0=float(tf32), 1=half ----------------
template<int HOUT>
__global__ void conv_silu_kernel(const float* __restrict__ xz, const float* __restrict__ w,
                                 const float* __restrict__ bias, void* __restrict__ outv,
                                 int Ltok, int dinner) {
    long tid = (long)blockIdx.x * 256 + threadIdx.x;
    long total = (long)BATCH * Ltok * (dinner / 4);
    if (tid >= total) return;
    int d4 = (int)(tid % (dinner / 4)) * 4;
    long t = tid / (dinner / 4);
    int l = (int)(t % Ltok);
    int b = (int)(t / Ltok);
    int rowstride = 2 * dinner;
    const float* base = xz + ((long)b * Ltok + l) * rowstride + d4;
    float4 bv = *reinterpret_cast<const float4*>(bias + d4);
    float acc0 = bv.x, acc1 = bv.y, acc2 = bv.z, acc3 = bv.w;
    #pragma unroll
    for (int k = 0; k < 4; k++) {
        int ll = l - 3 + k;
        if (ll >= 0) {
            float4 xv = *reinterpret_cast<const float4*>(base + (long)(ll - l) * rowstride);
            acc0 += xv.x * w[(d4 + 0) * 4 + k];
            acc1 += xv.y * w[(d4 + 1) * 4 + k];
            acc2 += xv.z * w[(d4 + 2) * 4 + k];
            acc3 += xv.w * w[(d4 + 3) * 4 + k];
        }
    }
    acc0 = siluf(acc0); acc1 = siluf(acc1); acc2 = siluf(acc2); acc3 = siluf(acc3);
    long o = ((long)b * Ltok + l) * dinner + d4;
    if (HOUT) {
        __half2 h0 = __floats2half2_rn(acc0, acc1);
        __half2 h1 = __floats2half2_rn(acc2, acc3);
        __half* out = (__half*)outv;
        *reinterpret_cast<uint2*>(out + o) = make_uint2(
            *reinterpret_cast<uint32_t*>(&h0), *reinterpret_cast<uint32_t*>(&h1));
    } else {
        float4 ov;
        ov.x = rnd_tf32(acc0); ov.y = rnd_tf32(acc1);
        ov.z = rnd_tf32(acc2); ov.w = rnd_tf32(acc3);
        *reinterpret_cast<float4*>((float*)outv + o) = ov;
    }
}

// ---------------- path-1 scan ----------------
__global__ void scan1_partial(const float* __restrict__ delta, const float* __restrict__ xc,
                              const float* __restrict__ dbl, const float* __restrict__ Alog) {
    int d = threadIdx.x;
    int chunk = blockIdx.x & (NCH - 1);
    int b = blockIdx.x >> 5;
    float A[NS], h[NS], P[NS];
    #pragma unroll
    for (int s = 0; s < NS; s++) { A[s] = -__expf(Alog[d * NS + s]); h[s] = 0.f; P[s] = 1.f; }
    int l0 = chunk * CLEN;
    for (int i = 0; i < CLEN; i++) {
        long t = (long)b * LL + l0 + i;
        float dl = delta[t * D1I + d];
        float xv = xc[t * D1I + d];
        const float* bl = dbl + t * DBL1 + DT1R;
        float dx = dl * xv;
        #pragma unroll
        for (int s = 0; s < NS; s++) {
            float dA = __expf(dl * A[s]);
            h[s] = dA * h[s] + dx * bl[s];
            P[s] *= dA;
        }
    }
    long o = (((long)b * D1I + d) * NCH + chunk) * NS;
    #pragma unroll
    for (int s = 0; s < NS; s++) { g_ckP[o + s] = P[s]; g_ckH[o + s] = h[s]; }
}

__global__ void scan1_carry() {
    int idx = blockIdx.x * 256 + threadIdx.x;
    if (idx >= BATCH * D1I) return;
    long base = (long)idx * NCH * NS;
    float h[NS];
    #pragma unroll
    for (int s = 0; s < NS; s++) h[s] = 0.f;
    for (int c = 0; c < NCH; c++) {
        long o = base + (long)c * NS;
        #pragma unroll
        for (int s = 0; s < NS; s++) {
            g_hin[o + s] = h[s];
            h[s] = g_ckP[o + s] * h[s] + g_ckH[o + s];
        }
    }
}

__global__ void scan1_final(const float* __restrict__ delta, const float* __restrict__ xc,
                            const float* __restrict__ dbl, const float* __restrict__ Alog,
                            const float* __restrict__ Dp, const float* __restrict__ xz,
                            float* __restrict__ y) {
    int d = threadIdx.x;
    int chunk = blockIdx.x & (NCH - 1);
    int b = blockIdx.x >> 5;
    float A[NS], h[NS];
    long hb = (((long)b * D1I + d) * NCH + chunk) * NS;
    #pragma unroll
    for (int s = 0; s < NS; s++) { A[s] = -__expf(Alog[d * NS + s]); h[s] = g_hin[hb + s]; }
    float Dv = Dp[d];
    int l0 = chunk * CLEN;
    for (int i = 0; i < CLEN; i++) {
        long t = (long)b * LL + l0 + i;
        float dl = delta[t * D1I + d];
        float xv = xc[t * D1I + d];
        const float* bl = dbl + t * DBL1 + DT1R;
        float dx = dl * xv;
        float acc = 0.f;
        #pragma unroll
        for (int s = 0; s < NS; s++) {
            float dA = __expf(dl * A[s]);
            h[s] = dA * h[s] + dx * bl[s];
            acc += h[s] * bl[NS + s];
        }
        float z = xz[t * (2 * D1I) + D1I + d];
        y[t * D1I + d] = rnd_tf32((acc + xv * Dv) * siluf(z));
    }
}

// ---------------- path-2 scan (xc fp16 in, y fp16 out) ----------------
__global__ void scan2_kernel(const float* __restrict__ delta, const __half* __restrict__ xc,
                             const float* __restrict__ dbl, const float* __restrict__ Alog,
                             const float* __restrict__ Dp, const float* __restrict__ xz,
                             __half* __restrict__ y) {
    int d = (blockIdx.x & 31) * 256 + threadIdx.x;
    int b = blockIdx.x >> 5;
    float A[NS], h[NS];
    #pragma unroll
    for (int s = 0; s < NS; s++) { A[s] = -__expf(Alog[d * NS + s]); h[s] = 0.f; }
    float Dv = Dp[d];
    for (int l = 0; l < CH; l++) {
        long t = (long)b * CH + l;
        float dl = delta[t * D2I + d];
        float xv = __half2float(xc[t * D2I + d]);
        const float* bl = dbl + t * DBL2 + DT2R;
        float dx = dl * xv;
        float acc = 0.f;
        #pragma unroll
        for (int s = 0; s < NS; s++) {
            float dA = __expf(dl * A[s]);
            h[s] = dA * h[s] + dx * bl[s];
            acc += h[s] * bl[NS + s];
        }
        float z = xz[t * (2 * D2I) + D2I + d];
        y[t * D2I + d] = __float2half_rn((acc + xv * Dv) * siluf(z));
    }
}

// ---------------- combine ----------------
__global__ void combine_kernel(const float* __restrict__ x, float* __restrict__ out) {
    long i = (long)blockIdx.x * 256 + threadIdx.x;
    if (i >= (long)BATCH * CH * LL) return;
    int l = (int)(i % LL);
    long t = i / LL;
    int c = (int)(t % CH);
    int b = (int)(t / CH);
    out[i] = x[i] + g_out2[i] + g_out1[((long)b * LL + l) * D1M + c];
}

// ---------------- launch ----------------
extern "C" void kernel_launch(void* const* d_in, const int* in_sizes, int n_in,
                              void* d_out, int out_size) {
    const float* x        = (const float*)d_in[0];
    const float* ln1_g    = (const float*)d_in[1];
    const float* ln1_b    = (const float*)d_in[2];
    const float* ln2_g    = (const float*)d_in[3];
    const float* ln2_b    = (const float*)d_in[4];
    const float* m1_in_w  = (const float*)d_in[5];
    const float* m1_cw    = (const float*)d_in[6];
    const float* m1_cb    = (const float*)d_in[7];
    const float* m1_xp_w  = (const float*)d_in[8];
    const float* m1_dt_w  = (const float*)d_in[9];
    const float* m1_dt_b  = (const float*)d_in[10];
    const float* m1_Alog  = (const float*)d_in[11];
    const float* m1_D     = (const float*)d_in[12];
    const float* m1_out_w = (const float*)d_in[13];
    const float* m2_in_w  = (const float*)d_in[14];
    const float* m2_cw    = (const float*)d_in[15];
    const float* m2_cb    = (const float*)d_in[16];
    const float* m2_xp_w  = (const float*)d_in[17];
    const float* m2_dt_w  = (const float*)d_in[18];
    const float* m2_dt_b  = (const float*)d_in[19];
    const float* m2_Alog  = (const float*)d_in[20];
    const float* m2_D     = (const float*)d_in[21];
    const float* m2_out_w = (const float*)d_in[22];
    float* out = (float*)d_out;

    float *pxn1, *pxz1, *pxc1, *pdbl1, *pdelta1, *py1, *pout1;
    float *pxn2, *pxz2, *pdbl2, *pdelta2, *pout2;
    __half *pxc2h, *py2h, *pdbl2h, *pxpwh, *pdtwh, *poutwh;
    cudaGetSymbolAddress((void**)&pxn1, g_xn1);
    cudaGetSymbolAddress((void**)&pxz1, g_xz1);
    cudaGetSymbolAddress((void**)&pxc1, g_xc1);
    cudaGetSymbolAddress((void**)&pdbl1, g_dbl1);
    cudaGetSymbolAddress((void**)&pdelta1, g_delta1);
    cudaGetSymbolAddress((void**)&py1, g_y1);
    cudaGetSymbolAddress((void**)&pout1, g_out1);
    cudaGetSymbolAddress((void**)&pxn2, g_xn2);
    cudaGetSymbolAddress((void**)&pxz2, g_xz2);
    cudaGetSymbolAddress((void**)&pdbl2, g_dbl2);
    cudaGetSymbolAddress((void**)&pdelta2, g_delta2);
    cudaGetSymbolAddress((void**)&pout2, g_out2);
    cudaGetSymbolAddress((void**)&pxc2h, g_xc2h);
    cudaGetSymbolAddress((void**)&py2h, g_y2h);
    cudaGetSymbolAddress((void**)&pdbl2h, g_dbl2h);
    cudaGetSymbolAddress((void**)&pxpwh, g_xpw_h);
    cudaGetSymbolAddress((void**)&pdtwh, g_dtw_h);
    cudaGetSymbolAddress((void**)&poutwh, g_outw_h);

    cudaFuncSetAttribute(tf32_gemm<0>, cudaFuncAttributeMaxDynamicSharedMemorySize, GSMEM_BYTES);
    cudaFuncSetAttribute(tf32_gemm<1>, cudaFuncAttributeMaxDynamicSharedMemorySize, GSMEM_BYTES);
    cudaFuncSetAttribute(fp16_gemm<1>, cudaFuncAttributeMaxDynamicSharedMemorySize, HSMEM_BYTES);
    cudaFuncSetAttribute(fp16_gemm<2>, cudaFuncAttributeMaxDynamicSharedMemorySize, HSMEM_BYTES);

    static cudaStream_t s2 = nullptr, s3 = nullptr;
    static cudaEvent_t evFork = nullptr, evFork3 = nullptr, evJoin = nullptr,
                       evJoinB = nullptr, evCvtS = nullptr, evCvtO = nullptr;
    if (!s2) {
        cudaStreamCreateWithFlags(&s2, cudaStreamNonBlocking);
        cudaStreamCreateWithFlags(&s3, cudaStreamNonBlocking);
        cudaEventCreateWithFlags(&evFork, cudaEventDisableTiming);
        cudaEventCreateWithFlags(&evFork3, cudaEventDisableTiming);
        cudaEventCreateWithFlags(&evJoin, cudaEventDisableTiming);
        cudaEventCreateWithFlags(&evJoinB, cudaEventDisableTiming);
        cudaEventCreateWithFlags(&evCvtS, cudaEventDisableTiming);
        cudaEventCreateWithFlags(&evCvtO, cudaEventDisableTiming);
    }

    const int T = 256;
    // ---- main: path-2 prologue ----
    cudaMemsetAsync(pdbl2, 0, sizeof(float) * BATCH * CH * DBL2);
    cudaMemsetAsync(pout2, 0, sizeof(float) * BATCH * CH * D2M);
    ln2_kernel<<<BATCH * CH, T>>>(x, ln2_g, ln2_b, pxn2);

    cudaEventRecord(evFork, 0);
    cudaStreamWaitEvent(s2, evFork, 0);
    cudaEventRecord(evFork3, 0);
    cudaStreamWaitEvent(s3, evFork3, 0);

    // ---- s2: out_w conversion (hidden; needed ~350us in), then full path 1 ----
    cvt_f2h<<<(int)(((long)D2M * D2I) / 2048), T, 0, s2>>>(m2_out_w, poutwh, (long)D2M * D2I);
    cudaEventRecord(evCvtO, s2);
    cudaMemsetAsync(pout1, 0, sizeof(float) * BATCH * LL * D1M, s2);
    ln1_kernel<<<BATCH * (LL / 32), T, 0, s2>>>(x, ln1_g, ln1_b, pxn1);
    tf32_gemm<0><<<dim3(4, 64, 1), 256, GSMEM_BYTES, s2>>>(
        pxn1, m1_in_w, nullptr, pxz1, BATCH * LL, 2 * D1I, D1M, D1M, D1M, 2 * D1I);
    conv_silu_kernel<0><<<(BATCH * LL * D1I / 4 + T - 1) / T, T, 0, s2>>>(
        pxz1, m1_cw, m1_cb, pxc1, LL, D1I);
    tf32_gemm<0><<<dim3(1, 64, 1), 256, GSMEM_BYTES, s2>>>(
        pxc1, m1_xp_w, nullptr, pdbl1, BATCH * LL, DBL1, D1I, D1I, D1I, DBL1);
    sgemm_kernel<1, true><<<dim3((D1I + 63) / 64, (BATCH * LL) / 64), T, 0, s2>>>(
        pdbl1, m1_dt_w, m1_dt_b, pdelta1, BATCH * LL, D1I, DT1R, DBL1, D1I);
    scan1_partial<<<BATCH * NCH, D1I, 0, s2>>>(pdelta1, pxc1, pdbl1, m1_Alog);
    scan1_carry<<<(BATCH * D1I + T - 1) / T, T, 0, s2>>>();
    scan1_final<<<BATCH * NCH, D1I, 0, s2>>>(pdelta1, pxc1, pdbl1, m1_Alog, m1_D, pxz1, py1);
    tf32_gemm<1><<<dim3(1, 64, 2), 256, GSMEM_BYTES, s2>>>(
        py1, m1_out_w, nullptr, pout1, BATCH * LL, D1M, D1I / 2, D1I, D1I, D1M);
    cudaEventRecord(evJoin, s2);

    // ---- s3: small weight conversions, then in2b (z half) ----
    cvt_f2h<<<(int)(((long)DBL2 * D2I) / 2048), T, 0, s3>>>(m2_xp_w, pxpwh, (long)DBL2 * D2I);
    cvt_f2h<<<(int)(((long)D2I * DT2R) / 2048), T, 0, s3>>>(m2_dt_w, pdtwh, (long)D2I * DT2R);
    cudaEventRecord(evCvtS, s3);
    tf32_gemm<0><<<dim3(64, 2, 1), 256, GSMEM_BYTES, s3>>>(
        pxn2, m2_in_w + (long)D2I * D2M, nullptr, pxz2 + D2I,
        BATCH * CH, D2I, D2M, D2M, D2M, 2 * D2I);
    cudaEventRecord(evJoinB, s3);

    // ---- main: in2a (xi half), then dependent chain ----
    tf32_gemm<0><<<dim3(64, 2, 1), 256, GSMEM_BYTES>>>(
        pxn2, m2_in_w, nullptr, pxz2, BATCH * CH, D2I, D2M, D2M, D2M, 2 * D2I);
    conv_silu_kernel<1><<<(BATCH * CH * D2I / 4 + T - 1) / T, T>>>(
        pxz2, m2_cw, m2_cb, pxc2h, CH, D2I);
    cudaStreamWaitEvent(0, evCvtS, 0);
    // xp2 (fp16): dbl2[256, 272] split-K=32 atomic (192 CTAs)
    fp16_gemm<1><<<dim3(3, 2, 32), 256, HSMEM_BYTES>>>(
        pxc2h, pxpwh, nullptr, pdbl2, BATCH * CH, DBL2, D2I / 32, D2I, D2I, DBL2);
    cvt_f2h<<<(int)(((long)BATCH * CH * DBL2) / 2048), T>>>(pdbl2, pdbl2h, (long)BATCH * CH * DBL2);
    // dt2 (fp16): delta2 = softplus(dbl2h[:, :256] @ dt_w_h^T + b)
    fp16_gemm<2><<<dim3(64, 2, 1), 256, HSMEM_BYTES>>>(
        pdbl2h, pdtwh, m2_dt_b, pdelta2, BATCH * CH, D2I, DT2R, DBL2, DT2R, D2I);
    cudaStreamWaitEvent(0, evJoinB, 0);
    scan2_kernel<<<BATCH * (D2I / 256), T>>>(pdelta2, pxc2h, pdbl2, m2_Alog, m2_D, pxz2, py2h);
    cudaStreamWaitEvent(0, evCvtO, 0);
    // out2 (fp16): split-K=4 atomic (256 CTAs)
    fp16_gemm<1><<<dim3(32, 2, 4), 256, HSMEM_BYTES>>>(
        py2h, poutwh, nullptr, pout2, BATCH * CH, D2M, D2I / 4, D2I, D2I, D2M);

    cudaStreamWaitEvent(0, evJoin, 0);
    combine_kernel<<<(BATCH * CH * LL + T - 1) / T, T>>>(x, out);
}

// round 12
// speedup vs baseline: 1.7140x; 1.0279x over previous
#include <cuda_runtime.h>
#include <cuda_fp16.h>
#include <cstdint>
#include <math.h>

// ---------------- problem constants ----------------
#define BATCH 2
#define CH    128
#define LL    4096
#define NS    8

#define D1M  128
#define D1I  256
#define DT1R 8
#define DBL1 24
#define D2M  4096
#define D2I  8192
#define DT2R 256
#define DBL2 272      // dt_rank(256) + 2*8

#define NCH  32
#define CLEN 128

// ---------------- scratch ----------------
__device__ __align__(16) float g_xn1[BATCH*LL*D1M];
__device__ __align__(16) float g_xz1[BATCH*LL*2*D1I];
__device__ __align__(16) float g_xc1[BATCH*LL*D1I];
__device__ __align__(16) float g_dbl1[BATCH*LL*DBL1];
__device__ __align__(16) float g_delta1[BATCH*LL*D1I];
__device__ __align__(16) float g_y1[BATCH*LL*D1I];
__device__ __align__(16) float g_out1[BATCH*LL*D1M];
__device__ __align__(16) float g_ckP[BATCH*D1I*NCH*NS];
__device__ __align__(16) float g_ckH[BATCH*D1I*NCH*NS];
__device__ __align__(16) float g_hin[BATCH*D1I*NCH*NS];

__device__ __align__(16) float g_xz2[BATCH*CH*2*D2I];
__device__ __align__(16) float g_dbl2[BATCH*CH*DBL2];
__device__ __align__(16) float g_delta2[BATCH*CH*D2I];
__device__ __align__(16) float g_out2[BATCH*CH*D2M];

// fp16 scratch
__device__ __align__(16) __half g_xn2h[BATCH*CH*D2M];
__device__ __align__(16) __half g_xc2h[BATCH*CH*D2I];
__device__ __align__(16) __half g_y2h[BATCH*CH*D2I];
__device__ __align__(16) __half g_dbl2h[BATCH*CH*DBL2];
__device__ __align__(16) __half g_xpw_h[DBL2*D2I];
__device__ __align__(16) __half g_dtw_h[D2I*DT2R];
__device__ __align__(16) __half g_outw_h[(long)D2M*D2I];
__device__ __align__(16) __half g_inw_h[(long)(2*D2I)*D2M];

// ---------------- helpers ----------------
__device__ __forceinline__ uint32_t smem_u32(const void* p) {
    uint32_t a;
    asm("{ .reg .u64 t; cvta.to.shared.u64 t, %1; cvt.u32.u64 %0, t; }" : "=r"(a) : "l"(p));
    return a;
}
__device__ __forceinline__ void cp_async16(uint32_t dst, const void* src, int sz) {
    asm volatile("cp.async.cg.shared.global [%0], [%1], 16, %2;"
                 :: "r"(dst), "l"(src), "r"(sz) : "memory");
}
#define CP_COMMIT() asm volatile("cp.async.commit_group;" ::: "memory")
#define CP_WAIT1()  asm volatile("cp.async.wait_group 1;" ::: "memory")
#define CP_WAIT0()  asm volatile("cp.async.wait_group 0;" ::: "memory")

__device__ __forceinline__ uint32_t f2tf32(float f) {
    uint32_t r;
    asm("cvt.rna.tf32.f32 %0, %1;" : "=r"(r) : "f"(f));
    return r;
}
__device__ __forceinline__ float rnd_tf32(float v) { return __uint_as_float(f2tf32(v)); }

__device__ __forceinline__ void mma_tf32(float* d, const uint32_t* a, const uint32_t* b) {
    asm volatile(
        "mma.sync.aligned.m16n8k8.row.col.f32.tf32.tf32.f32 "
        "{%0,%1,%2,%3}, {%4,%5,%6,%7}, {%8,%9}, {%0,%1,%2,%3};"
        : "+f"(d[0]), "+f"(d[1]), "+f"(d[2]), "+f"(d[3])
        : "r"(a[0]), "r"(a[1]), "r"(a[2]), "r"(a[3]), "r"(b[0]), "r"(b[1]));
}
__device__ __forceinline__ void mma_f16(float* d, const uint32_t* a, const uint32_t* b) {
    asm volatile(
        "mma.sync.aligned.m16n8k16.row.col.f32.f16.f16.f32 "
        "{%0,%1,%2,%3}, {%4,%5,%6,%7}, {%8,%9}, {%0,%1,%2,%3};"
        : "+f"(d[0]), "+f"(d[1]), "+f"(d[2]), "+f"(d[3])
        : "r"(a[0]), "r"(a[1]), "r"(a[2]), "r"(a[3]), "r"(b[0]), "r"(b[1]));
}
__device__ __forceinline__ void ldsm_x4(uint32_t& r0, uint32_t& r1, uint32_t& r2, uint32_t& r3,
                                        uint32_t addr) {
    asm volatile("ldmatrix.sync.aligned.m8n8.x4.shared.b16 {%0,%1,%2,%3}, [%4];"
                 : "=r"(r0), "=r"(r1), "=r"(r2), "=r"(r3) : "r"(addr));
}

__device__ __forceinline__ float siluf(float v) { return v / (1.f + __expf(-v)); }
__device__ __forceinline__ float softplusf(float v) { return (v > 20.f) ? v : log1pf(__expf(v)); }

// ======================================================================
// tf32 mma.sync GEMM — path-1 GEMMs
// ======================================================================
#define SROW 36
#define GROWS 256
#define GSTG (GROWS * SROW)
#define GSMEM_BYTES (3 * GSTG * 4)      // 108 KB -> 2 CTAs/SM

template<int EPI>
__global__ void __launch_bounds__(256, 2)
tf32_gemm(const float* __restrict__ X, const float* __restrict__ W,
          const float* __restrict__ bias, float* __restrict__ C,
          int M, int N, int kLen, int ldx, int ldw, int ldc) {
    extern __shared__ float sm[];
    const int tid = threadIdx.x;
    const int wid = tid >> 5, lane = tid & 31;
    const int gid = lane >> 2, tig = lane & 3;
    const int wm = wid >> 2, wn = wid & 3;
    const int m0 = blockIdx.y * 128, n0 = blockIdx.x * 128;
    const long k0 = (long)blockIdx.z * kLen;
    const int nIter = kLen / 32;
    const uint32_t sS = smem_u32(sm);

    float acc[4][4][4];
    #pragma unroll
    for (int i = 0; i < 4; i++)
        #pragma unroll
        for (int j = 0; j < 4; j++)
            #pragma unroll
            for (int r = 0; r < 4; r++) acc[i][j][r] = 0.f;

    auto load_stage = [&](int buf, long kk) {
        #pragma unroll
        for (int i = 0; i < 8; i++) {
            int idx = tid + i * 256;
            int row = idx >> 3, ch = idx & 7;
            uint32_t off = (uint32_t)((buf * GROWS + row) * SROW + ch * 4) * 4u;
            if (row < 128) {
                cp_async16(sS + off, X + (long)(m0 + row) * ldx + kk + ch * 4, 16);
            } else {
                int nr = n0 + row - 128;
                const float* gb = W + (long)(nr < N ? nr : 0) * ldw + kk + ch * 4;
                cp_async16(sS + off, gb, nr < N ? 16 : 0);
            }
        }
    };

    const uint32_t aBase = sS +
        (uint32_t)(((wm * 64 + ((lane >> 3) & 1) * 8 + (lane & 7)) * SROW
                    + ((lane >> 4) & 1) * 4) * 4);
    const uint32_t bBase = sS +
        (uint32_t)(((128 + wn * 32 + ((lane >> 4) & 1) * 8 + (lane & 7)) * SROW
                    + ((lane >> 3) & 1) * 4) * 4);

    load_stage(0, k0); CP_COMMIT();
    load_stage(1, k0 + 32); CP_COMMIT();

    for (int it = 0; it < nIter; it++) {
        if (it + 1 < nIter) { CP_WAIT1(); } else { CP_WAIT0(); }
        __syncthreads();
        const uint32_t stgOff = (uint32_t)((it % 3) * GSTG * 4);
        const uint32_t aS = aBase + stgOff;
        const uint32_t bS = bBase + stgOff;
        #pragma unroll
        for (int ks = 0; ks < 4; ks++) {
            uint32_t a[4][4], b[4][2];
            #pragma unroll
            for (int mi = 0; mi < 4; mi++)
                ldsm_x4(a[mi][0], a[mi][1], a[mi][2], a[mi][3],
                        aS + (uint32_t)(mi * 16 * SROW * 4 + ks * 32));
            #pragma unroll
            for (int p = 0; p < 2; p++) {
                uint32_t r0, r1, r2, r3;
                ldsm_x4(r0, r1, r2, r3, bS + (uint32_t)(p * 16 * SROW * 4 + ks * 32));
                b[2 * p][0]     = f2tf32(__uint_as_float(r0));
                b[2 * p][1]     = f2tf32(__uint_as_float(r1));
                b[2 * p + 1][0] = f2tf32(__uint_as_float(r2));
                b[2 * p + 1][1] = f2tf32(__uint_as_float(r3));
            }
            #pragma unroll
            for (int mi = 0; mi < 4; mi++)
                #pragma unroll
                for (int ni = 0; ni < 4; ni++)
                    mma_tf32(acc[mi][ni], a[mi], b[ni]);
        }
        if (it + 2 < nIter) { load_stage((it + 2) % 3, k0 + (long)(it + 2) * 32); CP_COMMIT(); }
    }

    #pragma unroll
    for (int mi = 0; mi < 4; mi++) {
        int m = m0 + wm * 64 + mi * 16 + gid;
        #pragma unroll
        for (int ni = 0; ni < 4; ni++) {
            int n = n0 + wn * 32 + ni * 8 + tig * 2;
            if (n >= N) continue;
            float* p0 = C + (long)m * ldc + n;
            float* p1 = C + (long)(m + 8) * ldc + n;
            float c0 = acc[mi][ni][0], c1 = acc[mi][ni][1];
            float c2 = acc[mi][ni][2], c3 = acc[mi][ni][3];
            if (EPI == 1) {
                atomicAdd(p0, c0); atomicAdd(p0 + 1, c1);
                atomicAdd(p1, c2); atomicAdd(p1 + 1, c3);
            } else if (EPI == 2) {
                float b0v = bias[n], b1v = bias[n + 1];
                *reinterpret_cast<float2*>(p0) =
                    make_float2(softplusf(c0 + b0v), softplusf(c1 + b1v));
                *reinterpret_cast<float2*>(p1) =
                    make_float2(softplusf(c2 + b0v), softplusf(c3 + b1v));
            } else {
                *reinterpret_cast<float2*>(p0) = make_float2(c0, c1);
                *reinterpret_cast<float2*>(p1) = make_float2(c2, c3);
            }
        }
    }
}

// ======================================================================
// fp16 mma.sync GEMM (m16n8k16) — all path-2 GEMMs
// EPI: 0 = store, 1 = atomicAdd, 2 = softplus(v + bias[n]) store
// ======================================================================
#define SROWH 40
#define HSTG (256 * SROWH)
#define HSMEM_BYTES (3 * HSTG * 2)      // 60 KB -> 2 CTAs/SM

template<int EPI>
__global__ void __launch_bounds__(256, 2)
fp16_gemm(const __half* __restrict__ X, const __half* __restrict__ W,
          const float* __restrict__ bias, float* __restrict__ C,
          int M, int N, int kLen, int ldx, int ldw, int ldc) {
    extern __shared__ __half smh[];
    const int tid = threadIdx.x;
    const int wid = tid >> 5, lane = tid & 31;
    const int gid = lane >> 2, tig = lane & 3;
    const int wm = wid >> 2, wn = wid & 3;
    const int m0 = blockIdx.y * 128, n0 = blockIdx.x * 128;
    const long k0 = (long)blockIdx.z * kLen;
    const int nIter = kLen / 32;
    const uint32_t sS = smem_u32(smh);

    float acc[4][4][4];
    #pragma unroll
    for (int i = 0; i < 4; i++)
        #pragma unroll
        for (int j = 0; j < 4; j++)
            #pragma unroll
            for (int r = 0; r < 4; r++) acc[i][j][r] = 0.f;

    auto load_stage = [&](int buf, long kk) {
        #pragma unroll
        for (int i = 0; i < 4; i++) {
            int idx = tid + i * 256;
            int row = idx >> 2, ch = idx & 3;
            uint32_t off = (uint32_t)((buf * 256 + row) * SROWH + ch * 8) * 2u;
            if (row < 128) {
                cp_async16(sS + off, X + (long)(m0 + row) * ldx + kk + ch * 8, 16);
            } else {
                int nr = n0 + row - 128;
                const __half* gb = W + (long)(nr < N ? nr : 0) * ldw + kk + ch * 8;
                cp_async16(sS + off, gb, nr < N ? 16 : 0);
            }
        }
    };

    const uint32_t aBase = sS +
        (uint32_t)(((wm * 64 + ((lane >> 3) & 1) * 8 + (lane & 7)) * SROWH
                    + ((lane >> 4) & 1) * 8) * 2);
    const uint32_t bBase = sS +
        (uint32_t)(((128 + wn * 32 + ((lane >> 4) & 1) * 8 + (lane & 7)) * SROWH
                    + ((lane >> 3) & 1) * 8) * 2);

    load_stage(0, k0); CP_COMMIT();
    load_stage(1, k0 + 32); CP_COMMIT();

    for (int it = 0; it < nIter; it++) {
        if (it + 1 < nIter) { CP_WAIT1(); } else { CP_WAIT0(); }
        __syncthreads();
        const uint32_t stgOff = (uint32_t)((it % 3) * HSTG * 2);
        const uint32_t aS = aBase + stgOff;
        const uint32_t bS = bBase + stgOff;
        #pragma unroll
        for (int ks = 0; ks < 2; ks++) {
            uint32_t a[4][4], b[4][2];
            #pragma unroll
            for (int mi = 0; mi < 4; mi++)
                ldsm_x4(a[mi][0], a[mi][1], a[mi][2], a[mi][3],
                        aS + (uint32_t)(mi * 16 * SROWH * 2 + ks * 32));
            #pragma unroll
            for (int p = 0; p < 2; p++) {
                uint32_t r0, r1, r2, r3;
                ldsm_x4(r0, r1, r2, r3, bS + (uint32_t)(p * 16 * SROWH * 2 + ks * 32));
                b[2 * p][0] = r0;     b[2 * p][1] = r1;
                b[2 * p + 1][0] = r2; b[2 * p + 1][1] = r3;
            }
            #pragma unroll
            for (int mi = 0; mi < 4; mi++)
                #pragma unroll
                for (int ni = 0; ni < 4; ni++)
                    mma_f16(acc[mi][ni], a[mi], b[ni]);
        }
        if (it + 2 < nIter) { load_stage((it + 2) % 3, k0 + (long)(it + 2) * 32); CP_COMMIT(); }
    }

    #pragma unroll
    for (int mi = 0; mi < 4; mi++) {
        int m = m0 + wm * 64 + mi * 16 + gid;
        #pragma unroll
        for (int ni = 0; ni < 4; ni++) {
            int n = n0 + wn * 32 + ni * 8 + tig * 2;
            if (n >= N) continue;
            float* p0 = C + (long)m * ldc + n;
            float* p1 = C + (long)(m + 8) * ldc + n;
            float c0 = acc[mi][ni][0], c1 = acc[mi][ni][1];
            float c2 = acc[mi][ni][2], c3 = acc[mi][ni][3];
            if (EPI == 1) {
                atomicAdd(p0, c0); atomicAdd(p0 + 1, c1);
                atomicAdd(p1, c2); atomicAdd(p1 + 1, c3);
            } else if (EPI == 2) {
                float b0v = bias[n], b1v = bias[n + 1];
                *reinterpret_cast<float2*>(p0) =
                    make_float2(softplusf(c0 + b0v), softplusf(c1 + b1v));
                *reinterpret_cast<float2*>(p1) =
                    make_float2(softplusf(c2 + b0v), softplusf(c3 + b1v));
            } else {
                *reinterpret_cast<float2*>(p0) = make_float2(c0, c1);
                *reinterpret_cast<float2*>(p1) = make_float2(c2, c3);
            }
        }
    }
}

// ---------------- fp32 -> fp16 conversion (8 elts/thread) ----------------
__global__ void cvt_f2h(const float* __restrict__ src, __half* __restrict__ dst, long n) {
    long i = ((long)blockIdx.x * 256 + threadIdx.x) * 8;
    if (i >= n) return;
    float4 v0 = *reinterpret_cast<const float4*>(src + i);
    float4 v1 = *reinterpret_cast<const float4*>(src + i + 4);
    __half2 h[4];
    h[0] = __floats2half2_rn(v0.x, v0.y);
    h[1] = __floats2half2_rn(v0.z, v0.w);
    h[2] = __floats2half2_rn(v1.x, v1.y);
    h[3] = __floats2half2_rn(v1.z, v1.w);
    *reinterpret_cast<uint4*>(dst + i) = *reinterpret_cast<uint4*>(h);
}

// ---------------- LayerNorm 1 (tf32-rounded) ----------------
__global__ void ln1_kernel(const float* __restrict__ x, const float* __restrict__ g,
                           const float* __restrict__ bta, float* __restrict__ out) {
    int b  = blockIdx.x >> 7;
    int l0 = (blockIdx.x & 127) * 32;
    __shared__ float sm[128 * 33];
    int tid = threadIdx.x;
    #pragma unroll
    for (int i = 0; i < 16; i++) {
        int idx = tid + i * 256;
        int c = idx >> 5, l = idx & 31;
        sm[c * 33 + l] = x[((long)b * CH + c) * LL + l0 + l];
    }
    __syncthreads();
    int warp = tid >> 5, lane = tid & 31;
    for (int t = warp; t < 32; t += 8) {
        float v[4]; float s = 0.f, sq = 0.f;
        #pragma unroll
        for (int j = 0; j < 4; j++) {
            v[j] = sm[(lane + 32 * j) * 33 + t];
            s += v[j]; sq += v[j] * v[j];
        }
        #pragma unroll
        for (int o = 16; o; o >>= 1) {
            s  += __shfl_xor_sync(0xffffffffu, s,  o);
            sq += __shfl_xor_sync(0xffffffffu, sq, o);
        }
        float mu  = s * (1.f / 128.f);
        float var = sq * (1.f / 128.f) - mu * mu;
        float rs  = rsqrtf(var + 1e-5f);
        #pragma unroll
        for (int j = 0; j < 4; j++) {
            int c = lane + 32 * j;
            out[((long)b * LL + l0 + t) * D1M + c] = rnd_tf32((v[j] - mu) * rs * g[c] + bta[c]);
        }
    }
}

// ---------------- LayerNorm 2 (fp16 output) ----------------
__global__ void ln2_kernel(const float* __restrict__ x, const float* __restrict__ g,
                           const float* __restrict__ bta, __half* __restrict__ out) {
    long row = blockIdx.x;
    const float* xr = x + row * D2M;
    __half* orow = out + row * D2M;
    int tid = threadIdx.x;
    float v[16]; float s = 0.f, sq = 0.f;
    #pragma unroll
    for (int i = 0; i < 16; i++) {
        v[i] = xr[i * 256 + tid];
        s += v[i]; sq += v[i] * v[i];
    }
    #pragma unroll
    for (int o = 16; o; o >>= 1) {
        s  += __shfl_xor_sync(0xffffffffu, s,  o);
        sq += __shfl_xor_sync(0xffffffffu, sq, o);
    }
    __shared__ float ss[8], sqq[8];
    int lane = tid & 31, warp = tid >> 5;
    if (!lane) { ss[warp] = s; sqq[warp] = sq; }
    __syncthreads();
    s = 0.f; sq = 0.f;
    #pragma unroll
    for (int w = 0; w < 8; w++) { s += ss[w]; sq += sqq[w]; }
    float mu  = s * (1.f / 4096.f);
    float var = sq * (1.f / 4096.f) - mu * mu;
    float rs  = rsqrtf(var + 1e-5f);
    #pragma unroll
    for (int i = 0; i < 16; i++) {
        int col = i * 256 + tid;
        orow[col] = __float2half_rn((v[i] - mu) * rs * g[col] + bta[col]);
    }
}

// ---------------- fallback SGEMM (dt1: K=8) ----------------
template<int ACT, bool HASBIAS>
__global__ void sgemm_kernel(const float* __restrict__ X, const float* __restrict__ W,
                             const float* __restrict__ bias, float* __restrict__ out,
                             int M, int N, int K, int lda, int ldc) {
    constexpr int BM = 64, BN = 64, BK = 32, PAD = 4;
    __shared__ float As[BK][BM + PAD];
    __shared__ float Bs[BK][BN + PAD];
    int bm = blockIdx.y * BM, bn = blockIdx.x * BN;
    int tid = threadIdx.x;
    int tx = tid & 15, ty = tid >> 4;
    float acc[4][4] = {};
    for (int k0 = 0; k0 < K; k0 += BK) {
        #pragma unroll
        for (int i = 0; i < 2; i++) {
            int idx = tid + i * 256;
            int row = idx >> 3;
            int kc  = (idx & 7) << 2;
            int k   = k0 + kc;
            float4 va = make_float4(0.f, 0.f, 0.f, 0.f);
            float4 vb = make_float4(0.f, 0.f, 0.f, 0.f);
            if (k < K) {
                int m = bm + row;
                if (m < M) va = *reinterpret_cast<const float4*>(X + (long)m * lda + k);
                int n = bn + row;
                if (n < N) vb = *reinterpret_cast<const float4*>(W + (long)n * K + k);
            }
            As[kc][row] = va.x; As[kc + 1][row] = va.y; As[kc + 2][row] = va.z; As[kc + 3][row] = va.w;
            Bs[kc][row] = vb.x; Bs[kc + 1][row] = vb.y; Bs[kc + 2][row] = vb.z; Bs[kc + 3][row] = vb.w;
        }
        __syncthreads();
        #pragma unroll
        for (int kk = 0; kk < BK; kk++) {
            float4 a = *reinterpret_cast<const float4*>(&As[kk][ty << 2]);
            float4 b = *reinterpret_cast<const float4*>(&Bs[kk][tx << 2]);
            float av[4] = {a.x, a.y, a.z, a.w};
            float bv[4] = {b.x, b.y, b.z, b.w};
            #pragma unroll
            for (int i = 0; i < 4; i++)
                #pragma unroll
                for (int j = 0; j < 4; j++)
                    acc[i][j] += av[i] * bv[j];
        }
        __syncthreads();
    }
    #pragma unroll
    for (int i = 0; i < 4; i++) {
        int m = bm + (ty << 2) + i;
        if (m >= M) continue;
        #pragma unroll
        for (int j = 0; j < 4; j++) {
            int n = bn + (tx << 2) + j;
            if (n >= N) continue;
            float v = acc[i][j];
            if (HASBIAS) v += bias[n];
            if (ACT == 1) v = softplusf(v);
            out[(long)m * ldc + n] = v;
        }
    }
}

// ---------------- causal depthwise conv (K=4) + SiLU; HOUT: 0=float(tf32), 1=half ----------------
template<int HOUT>
__global__ void conv_silu_kernel(const float* __restrict__ xz, const float* __restrict__ w,
                                 const float* __restrict__ bias, void* __restrict__ outv,
                                 int Ltok, int dinner) {
    long tid = (long)blockIdx.x * 256 + threadIdx.x;
    long total = (long)BATCH * Ltok * (dinner / 4);
    if (tid >= total) return;
    int d4 = (int)(tid % (dinner / 4)) * 4;
    long t = tid / (dinner / 4);
    int l = (int)(t % Ltok);
    int b = (int)(t / Ltok);
    int rowstride = 2 * dinner;
    const float* base = xz + ((long)b * Ltok + l) * rowstride + d4;
    float4 bv = *reinterpret_cast<const float4*>(bias + d4);
    float acc0 = bv.x, acc1 = bv.y, acc2 = bv.z, acc3 = bv.w;
    #pragma unroll
    for (int k = 0; k < 4; k++) {
        int ll = l - 3 + k;
        if (ll >= 0) {
            float4 xv = *reinterpret_cast<const float4*>(base + (long)(ll - l) * rowstride);
            acc0 += xv.x * w[(d4 + 0) * 4 + k];
            acc1 += xv.y * w[(d4 + 1) * 4 + k];
            acc2 += xv.z * w[(d4 + 2) * 4 + k];
            acc3 += xv.w * w[(d4 + 3) * 4 + k];
        }
    }
    acc0 = siluf(acc0); acc1 = siluf(acc1); acc2 = siluf(acc2); acc3 = siluf(acc3);
    long o = ((long)b * Ltok + l) * dinner + d4;
    if (HOUT) {
        __half2 h0 = __floats2half2_rn(acc0, acc1);
        __half2 h1 = __floats2half2_rn(acc2, acc3);
        __half* out = (__half*)outv;
        *reinterpret_cast<uint2*>(out + o) = make_uint2(
            *reinterpret_cast<uint32_t*>(&h0), *reinterpret_cast<uint32_t*>(&h1));
    } else {
        float4 ov;
        ov.x = rnd_tf32(acc0); ov.y = rnd_tf32(acc1);
        ov.z = rnd_tf32(acc2); ov.w = rnd_tf32(acc3);
        *reinterpret_cast<float4*>((float*)outv + o) = ov;
    }
}

// ---------------- path-1 scan ----------------
__global__ void scan1_partial(const float* __restrict__ delta, const float* __restrict__ xc,
                              const float* __restrict__ dbl, const float* __restrict__ Alog) {
    int d = threadIdx.x;
    int chunk = blockIdx.x & (NCH - 1);
    int b = blockIdx.x >> 5;
    float A[NS], h[NS], P[NS];
    #pragma unroll
    for (int s = 0; s < NS; s++) { A[s] = -__expf(Alog[d * NS + s]); h[s] = 0.f; P[s] = 1.f; }
    int l0 = chunk * CLEN;
    for (int i = 0; i < CLEN; i++) {
        long t = (long)b * LL + l0 + i;
        float dl = delta[t * D1I + d];
        float xv = xc[t * D1I + d];
        const float* bl = dbl + t * DBL1 + DT1R;
        float dx = dl * xv;
        #pragma unroll
        for (int s = 0; s < NS; s++) {
            float dA = __expf(dl * A[s]);
            h[s] = dA * h[s] + dx * bl[s];
            P[s] *= dA;
        }
    }
    long o = (((long)b * D1I + d) * NCH + chunk) * NS;
    #pragma unroll
    for (int s = 0; s < NS; s++) { g_ckP[o + s] = P[s]; g_ckH[o + s] = h[s]; }
}

__global__ void scan1_carry() {
    int idx = blockIdx.x * 256 + threadIdx.x;
    if (idx >= BATCH * D1I) return;
    long base = (long)idx * NCH * NS;
    float h[NS];
    #pragma unroll
    for (int s = 0; s < NS; s++) h[s] = 0.f;
    for (int c = 0; c < NCH; c++) {
        long o = base + (long)c * NS;
        #pragma unroll
        for (int s = 0; s < NS; s++) {
            g_hin[o + s] = h[s];
            h[s] = g_ckP[o + s] * h[s] + g_ckH[o + s];
        }
    }
}

__global__ void scan1_final(const float* __restrict__ delta, const float* __restrict__ xc,
                            const float* __restrict__ dbl, const float* __restrict__ Alog,
                            const float* __restrict__ Dp, const float* __restrict__ xz,
                            float* __restrict__ y) {
    int d = threadIdx.x;
    int chunk = blockIdx.x & (NCH - 1);
    int b = blockIdx.x >> 5;
    float A[NS], h[NS];
    long hb = (((long)b * D1I + d) * NCH + chunk) * NS;
    #pragma unroll
    for (int s = 0; s < NS; s++) { A[s] = -__expf(Alog[d * NS + s]); h[s] = g_hin[hb + s]; }
    float Dv = Dp[d];
    int l0 = chunk * CLEN;
    for (int i = 0; i < CLEN; i++) {
        long t = (long)b * LL + l0 + i;
        float dl = delta[t * D1I + d];
        float xv = xc[t * D1I + d];
        const float* bl = dbl + t * DBL1 + DT1R;
        float dx = dl * xv;
        float acc = 0.f;
        #pragma unroll
        for (int s = 0; s < NS; s++) {
            float dA = __expf(dl * A[s]);
            h[s] = dA * h[s] + dx * bl[s];
            acc += h[s] * bl[NS + s];
        }
        float z = xz[t * (2 * D1I) + D1I + d];
        y[t * D1I + d] = rnd_tf32((acc + xv * Dv) * siluf(z));
    }
}

// ---------------- path-2 scan (xc fp16 in, y fp16 out) ----------------
__global__ void scan2_kernel(const float* __restrict__ delta, const __half* __restrict__ xc,
                             const float* __restrict__ dbl, const float* __restrict__ Alog,
                             const float* __restrict__ Dp, const float* __restrict__ xz,
                             __half* __restrict__ y) {
    int d = (blockIdx.x & 31) * 256 + threadIdx.x;
    int b = blockIdx.x >> 5;
    float A[NS], h[NS];
    #pragma unroll
    for (int s = 0; s < NS; s++) { A[s] = -__expf(Alog[d * NS + s]); h[s] = 0.f; }
    float Dv = Dp[d];
    for (int l = 0; l < CH; l++) {
        long t = (long)b * CH + l;
        float dl = delta[t * D2I + d];
        float xv = __half2float(xc[t * D2I + d]);
        const float* bl = dbl + t * DBL2 + DT2R;
        float dx = dl * xv;
        float acc = 0.f;
        #pragma unroll
        for (int s = 0; s < NS; s++) {
            float dA = __expf(dl * A[s]);
            h[s] = dA * h[s] + dx * bl[s];
            acc += h[s] * bl[NS + s];
        }
        float z = xz[t * (2 * D2I) + D2I + d];
        y[t * D2I + d] = __float2half_rn((acc + xv * Dv) * siluf(z));
    }
}

// ---------------- combine ----------------
__global__ void combine_kernel(const float* __restrict__ x, float* __restrict__ out) {
    long i = (long)blockIdx.x * 256 + threadIdx.x;
    if (i >= (long)BATCH * CH * LL) return;
    int l = (int)(i % LL);
    long t = i / LL;
    int c = (int)(t % CH);
    int b = (int)(t / CH);
    out[i] = x[i] + g_out2[i] + g_out1[((long)b * LL + l) * D1M + c];
}

// ---------------- launch ----------------
extern "C" void kernel_launch(void* const* d_in, const int* in_sizes, int n_in,
                              void* d_out, int out_size) {
    const float* x        = (const float*)d_in[0];
    const float* ln1_g    = (const float*)d_in[1];
    const float* ln1_b    = (const float*)d_in[2];
    const float* ln2_g    = (const float*)d_in[3];
    const float* ln2_b    = (const float*)d_in[4];
    const float* m1_in_w  = (const float*)d_in[5];
    const float* m1_cw    = (const float*)d_in[6];
    const float* m1_cb    = (const float*)d_in[7];
    const float* m1_xp_w  = (const float*)d_in[8];
    const float* m1_dt_w  = (const float*)d_in[9];
    const float* m1_dt_b  = (const float*)d_in[10];
    const float* m1_Alog  = (const float*)d_in[11];
    const float* m1_D     = (const float*)d_in[12];
    const float* m1_out_w = (const float*)d_in[13];
    const float* m2_in_w  = (const float*)d_in[14];
    const float* m2_cw    = (const float*)d_in[15];
    const float* m2_cb    = (const float*)d_in[16];
    const float* m2_xp_w  = (const float*)d_in[17];
    const float* m2_dt_w  = (const float*)d_in[18];
    const float* m2_dt_b  = (const float*)d_in[19];
    const float* m2_Alog  = (const float*)d_in[20];
    const float* m2_D     = (const float*)d_in[21];
    const float* m2_out_w = (const float*)d_in[22];
    float* out = (float*)d_out;

    float *pxn1, *pxz1, *pxc1, *pdbl1, *pdelta1, *py1, *pout1;
    float *pxz2, *pdbl2, *pdelta2, *pout2;
    __half *pxn2h, *pxc2h, *py2h, *pdbl2h, *pxpwh, *pdtwh, *poutwh, *pinwh;
    cudaGetSymbolAddress((void**)&pxn1, g_xn1);
    cudaGetSymbolAddress((void**)&pxz1, g_xz1);
    cudaGetSymbolAddress((void**)&pxc1, g_xc1);
    cudaGetSymbolAddress((void**)&pdbl1, g_dbl1);
    cudaGetSymbolAddress((void**)&pdelta1, g_delta1);
    cudaGetSymbolAddress((void**)&py1, g_y1);
    cudaGetSymbolAddress((void**)&pout1, g_out1);
    cudaGetSymbolAddress((void**)&pxz2, g_xz2);
    cudaGetSymbolAddress((void**)&pdbl2, g_dbl2);
    cudaGetSymbolAddress((void**)&pdelta2, g_delta2);
    cudaGetSymbolAddress((void**)&pout2, g_out2);
    cudaGetSymbolAddress((void**)&pxn2h, g_xn2h);
    cudaGetSymbolAddress((void**)&pxc2h, g_xc2h);
    cudaGetSymbolAddress((void**)&py2h, g_y2h);
    cudaGetSymbolAddress((void**)&pdbl2h, g_dbl2h);
    cudaGetSymbolAddress((void**)&pxpwh, g_xpw_h);
    cudaGetSymbolAddress((void**)&pdtwh, g_dtw_h);
    cudaGetSymbolAddress((void**)&poutwh, g_outw_h);
    cudaGetSymbolAddress((void**)&pinwh, g_inw_h);

    cudaFuncSetAttribute(tf32_gemm<0>, cudaFuncAttributeMaxDynamicSharedMemorySize, GSMEM_BYTES);
    cudaFuncSetAttribute(tf32_gemm<1>, cudaFuncAttributeMaxDynamicSharedMemorySize, GSMEM_BYTES);
    cudaFuncSetAttribute(fp16_gemm<0>, cudaFuncAttributeMaxDynamicSharedMemorySize, HSMEM_BYTES);
    cudaFuncSetAttribute(fp16_gemm<1>, cudaFuncAttributeMaxDynamicSharedMemorySize, HSMEM_BYTES);
    cudaFuncSetAttribute(fp16_gemm<2>, cudaFuncAttributeMaxDynamicSharedMemorySize, HSMEM_BYTES);

    static cudaStream_t s2 = nullptr, s3 = nullptr;
    static cudaEvent_t evFork = nullptr, evFork3 = nullptr, evJoin = nullptr,
                       evJoinB = nullptr, evCvtS = nullptr, evCvtO = nullptr,
                       evIn2rdy = nullptr;
    if (!s2) {
        cudaStreamCreateWithFlags(&s2, cudaStreamNonBlocking);
        cudaStreamCreateWithFlags(&s3, cudaStreamNonBlocking);
        cudaEventCreateWithFlags(&evFork, cudaEventDisableTiming);
        cudaEventCreateWithFlags(&evFork3, cudaEventDisableTiming);
        cudaEventCreateWithFlags(&evJoin, cudaEventDisableTiming);
        cudaEventCreateWithFlags(&evJoinB, cudaEventDisableTiming);
        cudaEventCreateWithFlags(&evCvtS, cudaEventDisableTiming);
        cudaEventCreateWithFlags(&evCvtO, cudaEventDisableTiming);
        cudaEventCreateWithFlags(&evIn2rdy, cudaEventDisableTiming);
    }

    const int T = 256;
    // fork everything at t=0 (inputs ready; streams diverge immediately)
    cudaEventRecord(evFork, 0);
    cudaStreamWaitEvent(s2, evFork, 0);
    cudaEventRecord(evFork3, 0);
    cudaStreamWaitEvent(s3, evFork3, 0);

    // ---- main: in_w conversion (critical head) + ln2, then in2a fp16 ----
    cudaMemsetAsync(pdbl2, 0, sizeof(float) * BATCH * CH * DBL2);
    cudaMemsetAsync(pout2, 0, sizeof(float) * BATCH * CH * D2M);
    cvt_f2h<<<(int)(((long)(2 * D2I) * D2M) / 2048), T>>>(m2_in_w, pinwh, (long)(2 * D2I) * D2M);
    ln2_kernel<<<BATCH * CH, T>>>(x, ln2_g, ln2_b, pxn2h);
    cudaEventRecord(evIn2rdy, 0);

    // ---- s2: out_w conversion + full path 1 ----
    cvt_f2h<<<(int)(((long)D2M * D2I) / 2048), T, 0, s2>>>(m2_out_w, poutwh, (long)D2M * D2I);
    cudaEventRecord(evCvtO, s2);
    cudaMemsetAsync(pout1, 0, sizeof(float) * BATCH * LL * D1M, s2);
    ln1_kernel<<<BATCH * (LL / 32), T, 0, s2>>>(x, ln1_g, ln1_b, pxn1);
    tf32_gemm<0><<<dim3(4, 64, 1), 256, GSMEM_BYTES, s2>>>(
        pxn1, m1_in_w, nullptr, pxz1, BATCH * LL, 2 * D1I, D1M, D1M, D1M, 2 * D1I);
    conv_silu_kernel<0><<<(BATCH * LL * D1I / 4 + T - 1) / T, T, 0, s2>>>(
        pxz1, m1_cw, m1_cb, pxc1, LL, D1I);
    tf32_gemm<0><<<dim3(1, 64, 1), 256, GSMEM_BYTES, s2>>>(
        pxc1, m1_xp_w, nullptr, pdbl1, BATCH * LL, DBL1, D1I, D1I, D1I, DBL1);
    sgemm_kernel<1, true><<<dim3((D1I + 63) / 64, (BATCH * LL) / 64), T, 0, s2>>>(
        pdbl1, m1_dt_w, m1_dt_b, pdelta1, BATCH * LL, D1I, DT1R, DBL1, D1I);
    scan1_partial<<<BATCH * NCH, D1I, 0, s2>>>(pdelta1, pxc1, pdbl1, m1_Alog);
    scan1_carry<<<(BATCH * D1I + T - 1) / T, T, 0, s2>>>();
    scan1_final<<<BATCH * NCH, D1I, 0, s2>>>(pdelta1, pxc1, pdbl1, m1_Alog, m1_D, pxz1, py1);
    tf32_gemm<1><<<dim3(1, 64, 2), 256, GSMEM_BYTES, s2>>>(
        py1, m1_out_w, nullptr, pout1, BATCH * LL, D1M, D1I / 2, D1I, D1I, D1M);
    cudaEventRecord(evJoin, s2);

    // ---- s3: small weight conversions, then in2b (z half, fp16) ----
    cvt_f2h<<<(int)(((long)DBL2 * D2I) / 2048), T, 0, s3>>>(m2_xp_w, pxpwh, (long)DBL2 * D2I);
    cvt_f2h<<<(int)(((long)D2I * DT2R) / 2048), T, 0, s3>>>(m2_dt_w, pdtwh, (long)D2I * DT2R);
    cudaEventRecord(evCvtS, s3);
    cudaStreamWaitEvent(s3, evIn2rdy, 0);
    fp16_gemm<0><<<dim3(64, 2, 1), 256, HSMEM_BYTES, s3>>>(
        pxn2h, pinwh + (long)D2I * D2M, nullptr, pxz2 + D2I,
        BATCH * CH, D2I, D2M, D2M, D2M, 2 * D2I);
    cudaEventRecord(evJoinB, s3);

    // ---- main: in2a (xi half, fp16), then dependent chain ----
    fp16_gemm<0><<<dim3(64, 2, 1), 256, HSMEM_BYTES>>>(
        pxn2h, pinwh, nullptr, pxz2, BATCH * CH, D2I, D2M, D2M, D2M, 2 * D2I);
    conv_silu_kernel<1><<<(BATCH * CH * D2I / 4 + T - 1) / T, T>>>(
        pxz2, m2_cw, m2_cb, pxc2h, CH, D2I);
    cudaStreamWaitEvent(0, evCvtS, 0);
    // xp2 (fp16): dbl2[256, 272] split-K=32 atomic (192 CTAs)
    fp16_gemm<1><<<dim3(3, 2, 32), 256, HSMEM_BYTES>>>(
        pxc2h, pxpwh, nullptr, pdbl2, BATCH * CH, DBL2, D2I / 32, D2I, D2I, DBL2);
    cvt_f2h<<<(int)(((long)BATCH * CH * DBL2) / 2048), T>>>(pdbl2, pdbl2h, (long)BATCH * CH * DBL2);
    // dt2 (fp16): delta2 = softplus(dbl2h[:, :256] @ dt_w_h^T + b)
    fp16_gemm<2><<<dim3(64, 2, 1), 256, HSMEM_BYTES>>>(
        pdbl2h, pdtwh, m2_dt_b, pdelta2, BATCH * CH, D2I, DT2R, DBL2, DT2R, D2I);
    cudaStreamWaitEvent(0, evJoinB, 0);
    scan2_kernel<<<BATCH * (D2I / 256), T>>>(pdelta2, pxc2h, pdbl2, m2_Alog, m2_D, pxz2, py2h);
    cudaStreamWaitEvent(0, evCvtO, 0);
    // out2 (fp16): split-K=4 atomic (256 CTAs)
    fp16_gemm<1><<<dim3(32, 2, 4), 256, HSMEM_BYTES>>>(
        py2h, poutwh, nullptr, pout2, BATCH * CH, D2M, D2I / 4, D2I, D2I, D2M);

    cudaStreamWaitEvent(0, evJoin, 0);
    combine_kernel<<<(BATCH * CH * LL + T - 1) / T, T>>>(x, out);
}

// round 13
// speedup vs baseline: 1.7141x; 1.0001x over previous
#include <cuda_runtime.h>
#include <cuda_fp16.h>
#include <cstdint>
#include <math.h>

// ---------------- problem constants ----------------
#define BATCH 2
#define CH    128
#define LL    4096
#define NS    8

#define D1M  128
#define D1I  256
#define DT1R 8
#define DBL1 24
#define D2M  4096
#define D2I  8192
#define DT2R 256
#define DBL2 272      // dt_rank(256) + 2*8

#define NCH  32
#define CLEN 128

// ---------------- scratch ----------------
__device__ __align__(16) float g_xn1[BATCH*LL*D1M];
__device__ __align__(16) float g_xz1[BATCH*LL*2*D1I];
__device__ __align__(16) float g_xc1[BATCH*LL*D1I];
__device__ __align__(16) float g_dbl1[BATCH*LL*DBL1];
__device__ __align__(16) float g_delta1[BATCH*LL*D1I];
__device__ __align__(16) float g_y1[BATCH*LL*D1I];
__device__ __align__(16) float g_out1[BATCH*LL*D1M];
__device__ __align__(16) float g_ckP[BATCH*D1I*NCH*NS];
__device__ __align__(16) float g_ckH[BATCH*D1I*NCH*NS];
__device__ __align__(16) float g_hin[BATCH*D1I*NCH*NS];

__device__ __align__(16) float g_xz2[BATCH*CH*2*D2I];
__device__ __align__(16) float g_dbl2[BATCH*CH*DBL2];
__device__ __align__(16) float g_delta2[BATCH*CH*D2I];
__device__ __align__(16) float g_out2[BATCH*CH*D2M];

// fp16 scratch
__device__ __align__(16) __half g_xn2h[BATCH*CH*D2M];
__device__ __align__(16) __half g_xc2h[BATCH*CH*D2I];
__device__ __align__(16) __half g_y2h[BATCH*CH*D2I];
__device__ __align__(16) __half g_dbl2h[BATCH*CH*DBL2];
__device__ __align__(16) __half g_xpw_h[DBL2*D2I];
__device__ __align__(16) __half g_dtw_h[D2I*DT2R];
__device__ __align__(16) __half g_outw_h[(long)D2M*D2I];
__device__ __align__(16) __half g_inw_h[(long)(2*D2I)*D2M];

// ---------------- helpers ----------------
__device__ __forceinline__ uint32_t smem_u32(const void* p) {
    uint32_t a;
    asm("{ .reg .u64 t; cvta.to.shared.u64 t, %1; cvt.u32.u64 %0, t; }" : "=r"(a) : "l"(p));
    return a;
}
__device__ __forceinline__ void cp_async16(uint32_t dst, const void* src, int sz) {
    asm volatile("cp.async.cg.shared.global [%0], [%1], 16, %2;"
                 :: "r"(dst), "l"(src), "r"(sz) : "memory");
}
#define CP_COMMIT() asm volatile("cp.async.commit_group;" ::: "memory")
#define CP_WAIT1()  asm volatile("cp.async.wait_group 1;" ::: "memory")
#define CP_WAIT0()  asm volatile("cp.async.wait_group 0;" ::: "memory")

__device__ __forceinline__ uint32_t f2tf32(float f) {
    uint32_t r;
    asm("cvt.rna.tf32.f32 %0, %1;" : "=r"(r) : "f"(f));
    return r;
}
__device__ __forceinline__ float rnd_tf32(float v) { return __uint_as_float(f2tf32(v)); }

__device__ __forceinline__ void mma_tf32(float* d, const uint32_t* a, const uint32_t* b) {
    asm volatile(
        "mma.sync.aligned.m16n8k8.row.col.f32.tf32.tf32.f32 "
        "{%0,%1,%2,%3}, {%4,%5,%6,%7}, {%8,%9}, {%0,%1,%2,%3};"
        : "+f"(d[0]), "+f"(d[1]), "+f"(d[2]), "+f"(d[3])
        : "r"(a[0]), "r"(a[1]), "r"(a[2]), "r"(a[3]), "r"(b[0]), "r"(b[1]));
}
__device__ __forceinline__ void mma_f16(float* d, const uint32_t* a, const uint32_t* b) {
    asm volatile(
        "mma.sync.aligned.m16n8k16.row.col.f32.f16.f16.f32 "
        "{%0,%1,%2,%3}, {%4,%5,%6,%7}, {%8,%9}, {%0,%1,%2,%3};"
        : "+f"(d[0]), "+f"(d[1]), "+f"(d[2]), "+f"(d[3])
        : "r"(a[0]), "r"(a[1]), "r"(a[2]), "r"(a[3]), "r"(b[0]), "r"(b[1]));
}
__device__ __forceinline__ void ldsm_x4(uint32_t& r0, uint32_t& r1, uint32_t& r2, uint32_t& r3,
                                        uint32_t addr) {
    asm volatile("ldmatrix.sync.aligned.m8n8.x4.shared.b16 {%0,%1,%2,%3}, [%4];"
                 : "=r"(r0), "=r"(r1), "=r"(r2), "=r"(r3) : "r"(addr));
}

__device__ __forceinline__ float siluf(float v) { return v / (1.f + __expf(-v)); }
__device__ __forceinline__ float softplusf(float v) { return (v > 20.f) ? v : log1pf(__expf(v)); }

// ======================================================================
// tf32 mma.sync GEMM — path-1 GEMMs (unchanged)
// ======================================================================
#define SROW 36
#define GROWS 256
#define GSTG (GROWS * SROW)
#define GSMEM_BYTES (3 * GSTG * 4)      // 108 KB -> 2 CTAs/SM

template<int EPI>
__global__ void __launch_bounds__(256, 2)
tf32_gemm(const float* __restrict__ X, const float* __restrict__ W,
          const float* __restrict__ bias, float* __restrict__ C,
          int M, int N, int kLen, int ldx, int ldw, int ldc) {
    extern __shared__ float sm[];
    const int tid = threadIdx.x;
    const int wid = tid >> 5, lane = tid & 31;
    const int gid = lane >> 2, tig = lane & 3;
    const int wm = wid >> 2, wn = wid & 3;
    const int m0 = blockIdx.y * 128, n0 = blockIdx.x * 128;
    const long k0 = (long)blockIdx.z * kLen;
    const int nIter = kLen / 32;
    const uint32_t sS = smem_u32(sm);

    float acc[4][4][4];
    #pragma unroll
    for (int i = 0; i < 4; i++)
        #pragma unroll
        for (int j = 0; j < 4; j++)
            #pragma unroll
            for (int r = 0; r < 4; r++) acc[i][j][r] = 0.f;

    auto load_stage = [&](int buf, long kk) {
        #pragma unroll
        for (int i = 0; i < 8; i++) {
            int idx = tid + i * 256;
            int row = idx >> 3, ch = idx & 7;
            uint32_t off = (uint32_t)((buf * GROWS + row) * SROW + ch * 4) * 4u;
            if (row < 128) {
                cp_async16(sS + off, X + (long)(m0 + row) * ldx + kk + ch * 4, 16);
            } else {
                int nr = n0 + row - 128;
                const float* gb = W + (long)(nr < N ? nr : 0) * ldw + kk + ch * 4;
                cp_async16(sS + off, gb, nr < N ? 16 : 0);
            }
        }
    };

    const uint32_t aBase = sS +
        (uint32_t)(((wm * 64 + ((lane >> 3) & 1) * 8 + (lane & 7)) * SROW
                    + ((lane >> 4) & 1) * 4) * 4);
    const uint32_t bBase = sS +
        (uint32_t)(((128 + wn * 32 + ((lane >> 4) & 1) * 8 + (lane & 7)) * SROW
                    + ((lane >> 3) & 1) * 4) * 4);

    load_stage(0, k0); CP_COMMIT();
    load_stage(1, k0 + 32); CP_COMMIT();

    for (int it = 0; it < nIter; it++) {
        if (it + 1 < nIter) { CP_WAIT1(); } else { CP_WAIT0(); }
        __syncthreads();
        const uint32_t stgOff = (uint32_t)((it % 3) * GSTG * 4);
        const uint32_t aS = aBase + stgOff;
        const uint32_t bS = bBase + stgOff;
        #pragma unroll
        for (int ks = 0; ks < 4; ks++) {
            uint32_t a[4][4], b[4][2];
            #pragma unroll
            for (int mi = 0; mi < 4; mi++)
                ldsm_x4(a[mi][0], a[mi][1], a[mi][2], a[mi][3],
                        aS + (uint32_t)(mi * 16 * SROW * 4 + ks * 32));
            #pragma unroll
            for (int p = 0; p < 2; p++) {
                uint32_t r0, r1, r2, r3;
                ldsm_x4(r0, r1, r2, r3, bS + (uint32_t)(p * 16 * SROW * 4 + ks * 32));
                b[2 * p][0]     = f2tf32(__uint_as_float(r0));
                b[2 * p][1]     = f2tf32(__uint_as_float(r1));
                b[2 * p + 1][0] = f2tf32(__uint_as_float(r2));
                b[2 * p + 1][1] = f2tf32(__uint_as_float(r3));
            }
            #pragma unroll
            for (int mi = 0; mi < 4; mi++)
                #pragma unroll
                for (int ni = 0; ni < 4; ni++)
                    mma_tf32(acc[mi][ni], a[mi], b[ni]);
        }
        if (it + 2 < nIter) { load_stage((it + 2) % 3, k0 + (long)(it + 2) * 32); CP_COMMIT(); }
    }

    #pragma unroll
    for (int mi = 0; mi < 4; mi++) {
        int m = m0 + wm * 64 + mi * 16 + gid;
        #pragma unroll
        for (int ni = 0; ni < 4; ni++) {
            int n = n0 + wn * 32 + ni * 8 + tig * 2;
            if (n >= N) continue;
            float* p0 = C + (long)m * ldc + n;
            float* p1 = C + (long)(m + 8) * ldc + n;
            float c0 = acc[mi][ni][0], c1 = acc[mi][ni][1];
            float c2 = acc[mi][ni][2], c3 = acc[mi][ni][3];
            if (EPI == 1) {
                atomicAdd(p0, c0); atomicAdd(p0 + 1, c1);
                atomicAdd(p1, c2); atomicAdd(p1 + 1, c3);
            } else if (EPI == 2) {
                float b0v = bias[n], b1v = bias[n + 1];
                *reinterpret_cast<float2*>(p0) =
                    make_float2(softplusf(c0 + b0v), softplusf(c1 + b1v));
                *reinterpret_cast<float2*>(p1) =
                    make_float2(softplusf(c2 + b0v), softplusf(c3 + b1v));
            } else {
                *reinterpret_cast<float2*>(p0) = make_float2(c0, c1);
                *reinterpret_cast<float2*>(p1) = make_float2(c2, c3);
            }
        }
    }
}

// ======================================================================
// fp16 mma.sync GEMM (m16n8k16), BM=256 x BN=64 (weights read ONCE).
// 8 warps in 4(m) x 2(n) grid, warp tile 64x32; 3-stage cp.async.
// grid = (N/64 tiles, 1, ksplits); M must be 256.
// EPI: 0 = store, 1 = atomicAdd, 2 = softplus(v + bias[n]) store
// ======================================================================
#define SROWH 40
#define HROWS 320                        // 256 A rows + 64 B rows
#define HSTG (HROWS * SROWH)
#define HSMEM_BYTES (3 * HSTG * 2)       // 76.8 KB -> 2 CTAs/SM

template<int EPI>
__global__ void __launch_bounds__(256, 2)
fp16_gemm(const __half* __restrict__ X, const __half* __restrict__ W,
          const float* __restrict__ bias, float* __restrict__ C,
          int M, int N, int kLen, int ldx, int ldw, int ldc) {
    extern __shared__ __half smh[];
    const int tid = threadIdx.x;
    const int wid = tid >> 5, lane = tid & 31;
    const int gid = lane >> 2, tig = lane & 3;
    const int wm = wid >> 1, wn = wid & 1;       // 4 x 2 warp grid
    const int n0 = blockIdx.x * 64;
    const long k0 = (long)blockIdx.z * kLen;
    const int nIter = kLen / 32;
    const uint32_t sS = smem_u32(smh);

    float acc[4][4][4];
    #pragma unroll
    for (int i = 0; i < 4; i++)
        #pragma unroll
        for (int j = 0; j < 4; j++)
            #pragma unroll
            for (int r = 0; r < 4; r++) acc[i][j][r] = 0.f;

    auto load_stage = [&](int buf, long kk) {
        #pragma unroll
        for (int i = 0; i < 5; i++) {
            int idx = tid + i * 256;            // 0..1279
            int row = idx >> 2, ch = idx & 3;
            uint32_t off = (uint32_t)((buf * HROWS + row) * SROWH + ch * 8) * 2u;
            if (row < 256) {
                cp_async16(sS + off, X + (long)row * ldx + kk + ch * 8, 16);
            } else {
                int nr = n0 + row - 256;
                const __half* gb = W + (long)(nr < N ? nr : 0) * ldw + kk + ch * 8;
                cp_async16(sS + off, gb, nr < N ? 16 : 0);
            }
        }
    };

    const uint32_t aBase = sS +
        (uint32_t)(((wm * 64 + ((lane >> 3) & 1) * 8 + (lane & 7)) * SROWH
                    + ((lane >> 4) & 1) * 8) * 2);
    const uint32_t bBase = sS +
        (uint32_t)(((256 + wn * 32 + ((lane >> 4) & 1) * 8 + (lane & 7)) * SROWH
                    + ((lane >> 3) & 1) * 8) * 2);

    load_stage(0, k0); CP_COMMIT();
    load_stage(1, k0 + 32); CP_COMMIT();

    for (int it = 0; it < nIter; it++) {
        if (it + 1 < nIter) { CP_WAIT1(); } else { CP_WAIT0(); }
        __syncthreads();
        const uint32_t stgOff = (uint32_t)((it % 3) * HSTG * 2);
        const uint32_t aS = aBase + stgOff;
        const uint32_t bS = bBase + stgOff;
        #pragma unroll
        for (int ks = 0; ks < 2; ks++) {
            uint32_t a[4][4], b[4][2];
            #pragma unroll
            for (int mi = 0; mi < 4; mi++)
                ldsm_x4(a[mi][0], a[mi][1], a[mi][2], a[mi][3],
                        aS + (uint32_t)(mi * 16 * SROWH * 2 + ks * 32));
            #pragma unroll
            for (int p = 0; p < 2; p++) {
                uint32_t r0, r1, r2, r3;
                ldsm_x4(r0, r1, r2, r3, bS + (uint32_t)(p * 16 * SROWH * 2 + ks * 32));
                b[2 * p][0] = r0;     b[2 * p][1] = r1;
                b[2 * p + 1][0] = r2; b[2 * p + 1][1] = r3;
            }
            #pragma unroll
            for (int mi = 0; mi < 4; mi++)
                #pragma unroll
                for (int ni = 0; ni < 4; ni++)
                    mma_f16(acc[mi][ni], a[mi], b[ni]);
        }
        if (it + 2 < nIter) { load_stage((it + 2) % 3, k0 + (long)(it + 2) * 32); CP_COMMIT(); }
    }

    #pragma unroll
    for (int mi = 0; mi < 4; mi++) {
        int m = wm * 64 + mi * 16 + gid;
        #pragma unroll
        for (int ni = 0; ni < 4; ni++) {
            int n = n0 + wn * 32 + ni * 8 + tig * 2;
            if (n >= N) continue;
            float* p0 = C + (long)m * ldc + n;
            float* p1 = C + (long)(m + 8) * ldc + n;
            float c0 = acc[mi][ni][0], c1 = acc[mi][ni][1];
            float c2 = acc[mi][ni][2], c3 = acc[mi][ni][3];
            if (EPI == 1) {
                atomicAdd(p0, c0); atomicAdd(p0 + 1, c1);
                atomicAdd(p1, c2); atomicAdd(p1 + 1, c3);
            } else if (EPI == 2) {
                float b0v = bias[n], b1v = bias[n + 1];
                *reinterpret_cast<float2*>(p0) =
                    make_float2(softplusf(c0 + b0v), softplusf(c1 + b1v));
                *reinterpret_cast<float2*>(p1) =
                    make_float2(softplusf(c2 + b0v), softplusf(c3 + b1v));
            } else {
                *reinterpret_cast<float2*>(p0) = make_float2(c0, c1);
                *reinterpret_cast<float2*>(p1) = make_float2(c2, c3);
            }
        }
    }
}

// ---------------- fp32 -> fp16 conversion (8 elts/thread) ----------------
__global__ void cvt_f2h(const float* __restrict__ src, __half* __restrict__ dst, long n) {
    long i = ((long)blockIdx.x * 256 + threadIdx.x) * 8;
    if (i >= n) return;
    float4 v0 = *reinterpret_cast<const float4*>(src + i);
    float4 v1 = *reinterpret_cast<const float4*>(src + i + 4);
    __half2 h[4];
    h[0] = __floats2half2_rn(v0.x, v0.y);
    h[1] = __floats2half2_rn(v0.z, v0.w);
    h[2] = __floats2half2_rn(v1.x, v1.y);
    h[3] = __floats2half2_rn(v1.z, v1.w);
    *reinterpret_cast<uint4*>(dst + i) = *reinterpret_cast<uint4*>(h);
}

// ---------------- LayerNorm 1 (tf32-rounded) ----------------
__global__ void ln1_kernel(const float* __restrict__ x, const float* __restrict__ g,
                           const float* __restrict__ bta, float* __restrict__ out) {
    int b  = blockIdx.x >> 7;
    int l0 = (blockIdx.x & 127) * 32;
    __shared__ float sm[128 * 33];
    int tid = threadIdx.x;
    #pragma unroll
    for (int i = 0; i < 16; i++) {
        int idx = tid + i * 256;
        int c = idx >> 5, l = idx & 31;
        sm[c * 33 + l] = x[((long)b * CH + c) * LL + l0 + l];
    }
    __syncthreads();
    int warp = tid >> 5, lane = tid & 31;
    for (int t = warp; t < 32; t += 8) {
        float v[4]; float s = 0.f, sq = 0.f;
        #pragma unroll
        for (int j = 0; j < 4; j++) {
            v[j] = sm[(lane + 32 * j) * 33 + t];
            s += v[j]; sq += v[j] * v[j];
        }
        #pragma unroll
        for (int o = 16; o; o >>= 1) {
            s  += __shfl_xor_sync(0xffffffffu, s,  o);
            sq += __shfl_xor_sync(0xffffffffu, sq, o);
        }
        float mu  = s * (1.f / 128.f);
        float var = sq * (1.f / 128.f) - mu * mu;
        float rs  = rsqrtf(var + 1e-5f);
        #pragma unroll
        for (int j = 0; j < 4; j++) {
            int c = lane + 32 * j;
            out[((long)b * LL + l0 + t) * D1M + c] = rnd_tf32((v[j] - mu) * rs * g[c] + bta[c]);
        }
    }
}

// ---------------- LayerNorm 2 (fp16 output) ----------------
__global__ void ln2_kernel(const float* __restrict__ x, const float* __restrict__ g,
                           const float* __restrict__ bta, __half* __restrict__ out) {
    long row = blockIdx.x;
    const float* xr = x + row * D2M;
    __half* orow = out + row * D2M;
    int tid = threadIdx.x;
    float v[16]; float s = 0.f, sq = 0.f;
    #pragma unroll
    for (int i = 0; i < 16; i++) {
        v[i] = xr[i * 256 + tid];
        s += v[i]; sq += v[i] * v[i];
    }
    #pragma unroll
    for (int o = 16; o; o >>= 1) {
        s  += __shfl_xor_sync(0xffffffffu, s,  o);
        sq += __shfl_xor_sync(0xffffffffu, sq, o);
    }
    __shared__ float ss[8], sqq[8];
    int lane = tid & 31, warp = tid >> 5;
    if (!lane) { ss[warp] = s; sqq[warp] = sq; }
    __syncthreads();
    s = 0.f; sq = 0.f;
    #pragma unroll
    for (int w = 0; w < 8; w++) { s += ss[w]; sq += sqq[w]; }
    float mu  = s * (1.f / 4096.f);
    float var = sq * (1.f / 4096.f) - mu * mu;
    float rs  = rsqrtf(var + 1e-5f);
    #pragma unroll
    for (int i = 0; i < 16; i++) {
        int col = i * 256 + tid;
        orow[col] = __float2half_rn((v[i] - mu) * rs * g[col] + bta[col]);
    }
}

// ---------------- fallback SGEMM (dt1: K=8) ----------------
template<int ACT, bool HASBIAS>
__global__ void sgemm_kernel(const float* __restrict__ X, const float* __restrict__ W,
                             const float* __restrict__ bias, float* __restrict__ out,
                             int M, int N, int K, int lda, int ldc) {
    constexpr int BM = 64, BN = 64, BK = 32, PAD = 4;
    __shared__ float As[BK][BM + PAD];
    __shared__ float Bs[BK][BN + PAD];
    int bm = blockIdx.y * BM, bn = blockIdx.x * BN;
    int tid = threadIdx.x;
    int tx = tid & 15, ty = tid >> 4;
    float acc[4][4] = {};
    for (int k0 = 0; k0 < K; k0 += BK) {
        #pragma unroll
        for (int i = 0; i < 2; i++) {
            int idx = tid + i * 256;
            int row = idx >> 3;
            int kc  = (idx & 7) << 2;
            int k   = k0 + kc;
            float4 va = make_float4(0.f, 0.f, 0.f, 0.f);
            float4 vb = make_float4(0.f, 0.f, 0.f, 0.f);
            if (k < K) {
                int m = bm + row;
                if (m < M) va = *reinterpret_cast<const float4*>(X + (long)m * lda + k);
                int n = bn + row;
                if (n < N) vb = *reinterpret_cast<const float4*>(W + (long)n * K + k);
            }
            As[kc][row] = va.x; As[kc + 1][row] = va.y; As[kc + 2][row] = va.z; As[kc + 3][row] = va.w;
            Bs[kc][row] = vb.x; Bs[kc + 1][row] = vb.y; Bs[kc + 2][row] = vb.z; Bs[kc + 3][row] = vb.w;
        }
        __syncthreads();
        #pragma unroll
        for (int kk = 0; kk < BK; kk++) {
            float4 a = *reinterpret_cast<const float4*>(&As[kk][ty << 2]);
            float4 b = *reinterpret_cast<const float4*>(&Bs[kk][tx << 2]);
            float av[4] = {a.x, a.y, a.z, a.w};
            float bv[4] = {b.x, b.y, b.z, b.w};
            #pragma unroll
            for (int i = 0; i < 4; i++)
                #pragma unroll
                for (int j = 0; j < 4; j++)
                    acc[i][j] += av[i] * bv[j];
        }
        __syncthreads();
    }
    #pragma unroll
    for (int i = 0; i < 4; i++) {
        int m = bm + (ty << 2) + i;
        if (m >= M) continue;
        #pragma unroll
        for (int j = 0; j < 4; j++) {
            int n = bn + (tx << 2) + j;
            if (n >= N) continue;
            float v = acc[i][j];
            if (HASBIAS) v += bias[n];
            if (ACT == 1) v = softplusf(v);
            out[(long)m * ldc + n] = v;
        }
    }
}

// ---------------- causal depthwise conv (K=4) + SiLU; HOUT: 0=float(tf32), 1=half ----------------
template<int HOUT>
__global__ void conv_silu_kernel(const float* __restrict__ xz, const float* __restrict__ w,
                                 const float* __restrict__ bias, void* __restrict__ outv,
                                 int Ltok, int dinner) {
    long tid = (long)blockIdx.x * 256 + threadIdx.x;
    long total = (long)BATCH * Ltok * (dinner / 4);
    if (tid >= total) return;
    int d4 = (int)(tid % (dinner / 4)) * 4;
    long t = tid / (dinner / 4);
    int l = (int)(t % Ltok);
    int b = (int)(t / Ltok);
    int rowstride = 2 * dinner;
    const float* base = xz + ((long)b * Ltok + l) * rowstride + d4;
    float4 bv = *reinterpret_cast<const float4*>(bias + d4);
    float acc0 = bv.x, acc1 = bv.y, acc2 = bv.z, acc3 = bv.w;
    #pragma unroll
    for (int k = 0; k < 4; k++) {
        int ll = l - 3 + k;
        if (ll >= 0) {
            float4 xv = *reinterpret_cast<const float4*>(base + (long)(ll - l) * rowstride);
            acc0 += xv.x * w[(d4 + 0) * 4 + k];
            acc1 += xv.y * w[(d4 + 1) * 4 + k];
            acc2 += xv.z * w[(d4 + 2) * 4 + k];
            acc3 += xv.w * w[(d4 + 3) * 4 + k];
        }
    }
    acc0 = siluf(acc0); acc1 = siluf(acc1); acc2 = siluf(acc2); acc3 = siluf(acc3);
    long o = ((long)b * Ltok + l) * dinner + d4;
    if (HOUT) {
        __half2 h0 = __floats2half2_rn(acc0, acc1);
        __half2 h1 = __floats2half2_rn(acc2, acc3);
        __half* out = (__half*)outv;
        *reinterpret_cast<uint2*>(out + o) = make_uint2(
            *reinterpret_cast<uint32_t*>(&h0), *reinterpret_cast<uint32_t*>(&h1));
    } else {
        float4 ov;
        ov.x = rnd_tf32(acc0); ov.y = rnd_tf32(acc1);
        ov.z = rnd_tf32(acc2); ov.w = rnd_tf32(acc3);
        *reinterpret_cast<float4*>((float*)outv + o) = ov;
    }
}

// ---------------- path-1 scan ----------------
__global__ void scan1_partial(const float* __restrict__ delta, const float* __restrict__ xc,
                              const float* __restrict__ dbl, const float* __restrict__ Alog) {
    int d = threadIdx.x;
    int chunk = blockIdx.x & (NCH - 1);
    int b = blockIdx.x >> 5;
    float A[NS], h[NS], P[NS];
    #pragma unroll
    for (int s = 0; s < NS; s++) { A[s] = -__expf(Alog[d * NS + s]); h[s] = 0.f; P[s] = 1.f; }
    int l0 = chunk * CLEN;
    for (int i = 0; i < CLEN; i++) {
        long t = (long)b * LL + l0 + i;
        float dl = delta[t * D1I + d];
        float xv = xc[t * D1I + d];
        const float* bl = dbl + t * DBL1 + DT1R;
        float dx = dl * xv;
        #pragma unroll
        for (int s = 0; s < NS; s++) {
            float dA = __expf(dl * A[s]);
            h[s] = dA * h[s] + dx * bl[s];
            P[s] *= dA;
        }
    }
    long o = (((long)b * D1I + d) * NCH + chunk) * NS;
    #pragma unroll
    for (int s = 0; s < NS; s++) { g_ckP[o + s] = P[s]; g_ckH[o + s] = h[s]; }
}

__global__ void scan1_carry() {
    int idx = blockIdx.x * 256 + threadIdx.x;
    if (idx >= BATCH * D1I) return;
    long base = (long)idx * NCH * NS;
    float h[NS];
    #pragma unroll
    for (int s = 0; s < NS; s++) h[s] = 0.f;
    for (int c = 0; c < NCH; c++) {
        long o = base + (long)c * NS;
        #pragma unroll
        for (int s = 0; s < NS; s++) {
            g_hin[o + s] = h[s];
            h[s] = g_ckP[o + s] * h[s] + g_ckH[o + s];
        }
    }
}

__global__ void scan1_final(const float* __restrict__ delta, const float* __restrict__ xc,
                            const float* __restrict__ dbl, const float* __restrict__ Alog,
                            const float* __restrict__ Dp, const float* __restrict__ xz,
                            float* __restrict__ y) {
    int d = threadIdx.x;
    int chunk = blockIdx.x & (NCH - 1);
    int b = blockIdx.x >> 5;
    float A[NS], h[NS];
    long hb = (((long)b * D1I + d) * NCH + chunk) * NS;
    #pragma unroll
    for (int s = 0; s < NS; s++) { A[s] = -__expf(Alog[d * NS + s]); h[s] = g_hin[hb + s]; }
    float Dv = Dp[d];
    int l0 = chunk * CLEN;
    for (int i = 0; i < CLEN; i++) {
        long t = (long)b * LL + l0 + i;
        float dl = delta[t * D1I + d];
        float xv = xc[t * D1I + d];
        const float* bl = dbl + t * DBL1 + DT1R;
        float dx = dl * xv;
        float acc = 0.f;
        #pragma unroll
        for (int s = 0; s < NS; s++) {
            float dA = __expf(dl * A[s]);
            h[s] = dA * h[s] + dx * bl[s];
            acc += h[s] * bl[NS + s];
        }
        float z = xz[t * (2 * D1I) + D1I + d];
        y[t * D1I + d] = rnd_tf32((acc + xv * Dv) * siluf(z));
    }
}

// ---------------- path-2 scan (xc fp16 in, y fp16 out) ----------------
__global__ void scan2_kernel(const float* __restrict__ delta, const __half* __restrict__ xc,
                             const float* __restrict__ dbl, const float* __restrict__ Alog,
                             const float* __restrict__ Dp, const float* __restrict__ xz,
                             __half* __restrict__ y) {
    int d = (blockIdx.x & 31) * 256 + threadIdx.x;
    int b = blockIdx.x >> 5;
    float A[NS], h[NS];
    #pragma unroll
    for (int s = 0; s < NS; s++) { A[s] = -__expf(Alog[d * NS + s]); h[s] = 0.f; }
    float Dv = Dp[d];
    for (int l = 0; l < CH; l++) {
        long t = (long)b * CH + l;
        float dl = delta[t * D2I + d];
        float xv = __half2float(xc[t * D2I + d]);
        const float* bl = dbl + t * DBL2 + DT2R;
        float dx = dl * xv;
        float acc = 0.f;
        #pragma unroll
        for (int s = 0; s < NS; s++) {
            float dA = __expf(dl * A[s]);
            h[s] = dA * h[s] + dx * bl[s];
            acc += h[s] * bl[NS + s];
        }
        float z = xz[t * (2 * D2I) + D2I + d];
        y[t * D2I + d] = __float2half_rn((acc + xv * Dv) * siluf(z));
    }
}

// ---------------- combine ----------------
__global__ void combine_kernel(const float* __restrict__ x, float* __restrict__ out) {
    long i = (long)blockIdx.x * 256 + threadIdx.x;
    if (i >= (long)BATCH * CH * LL) return;
    int l = (int)(i % LL);
    long t = i / LL;
    int c = (int)(t % CH);
    int b = (int)(t / CH);
    out[i] = x[i] + g_out2[i] + g_out1[((long)b * LL + l) * D1M + c];
}

// ---------------- launch ----------------
extern "C" void kernel_launch(void* const* d_in, const int* in_sizes, int n_in,
                              void* d_out, int out_size) {
    const float* x        = (const float*)d_in[0];
    const float* ln1_g    = (const float*)d_in[1];
    const float* ln1_b    = (const float*)d_in[2];
    const float* ln2_g    = (const float*)d_in[3];
    const float* ln2_b    = (const float*)d_in[4];
    const float* m1_in_w  = (const float*)d_in[5];
    const float* m1_cw    = (const float*)d_in[6];
    const float* m1_cb    = (const float*)d_in[7];
    const float* m1_xp_w  = (const float*)d_in[8];
    const float* m1_dt_w  = (const float*)d_in[9];
    const float* m1_dt_b  = (const float*)d_in[10];
    const float* m1_Alog  = (const float*)d_in[11];
    const float* m1_D     = (const float*)d_in[12];
    const float* m1_out_w = (const float*)d_in[13];
    const float* m2_in_w  = (const float*)d_in[14];
    const float* m2_cw    = (const float*)d_in[15];
    const float* m2_cb    = (const float*)d_in[16];
    const float* m2_xp_w  = (const float*)d_in[17];
    const float* m2_dt_w  = (const float*)d_in[18];
    const float* m2_dt_b  = (const float*)d_in[19];
    const float* m2_Alog  = (const float*)d_in[20];
    const float* m2_D     = (const float*)d_in[21];
    const float* m2_out_w = (const float*)d_in[22];
    float* out = (float*)d_out;

    float *pxn1, *pxz1, *pxc1, *pdbl1, *pdelta1, *py1, *pout1;
    float *pxz2, *pdbl2, *pdelta2, *pout2;
    __half *pxn2h, *pxc2h, *py2h, *pdbl2h, *pxpwh, *pdtwh, *poutwh, *pinwh;
    cudaGetSymbolAddress((void**)&pxn1, g_xn1);
    cudaGetSymbolAddress((void**)&pxz1, g_xz1);
    cudaGetSymbolAddress((void**)&pxc1, g_xc1);
    cudaGetSymbolAddress((void**)&pdbl1, g_dbl1);
    cudaGetSymbolAddress((void**)&pdelta1, g_delta1);
    cudaGetSymbolAddress((void**)&py1, g_y1);
    cudaGetSymbolAddress((void**)&pout1, g_out1);
    cudaGetSymbolAddress((void**)&pxz2, g_xz2);
    cudaGetSymbolAddress((void**)&pdbl2, g_dbl2);
    cudaGetSymbolAddress((void**)&pdelta2, g_delta2);
    cudaGetSymbolAddress((void**)&pout2, g_out2);
    cudaGetSymbolAddress((void**)&pxn2h, g_xn2h);
    cudaGetSymbolAddress((void**)&pxc2h, g_xc2h);
    cudaGetSymbolAddress((void**)&py2h, g_y2h);
    cudaGetSymbolAddress((void**)&pdbl2h, g_dbl2h);
    cudaGetSymbolAddress((void**)&pxpwh, g_xpw_h);
    cudaGetSymbolAddress((void**)&pdtwh, g_dtw_h);
    cudaGetSymbolAddress((void**)&poutwh, g_outw_h);
    cudaGetSymbolAddress((void**)&pinwh, g_inw_h);

    cudaFuncSetAttribute(tf32_gemm<0>, cudaFuncAttributeMaxDynamicSharedMemorySize, GSMEM_BYTES);
    cudaFuncSetAttribute(tf32_gemm<1>, cudaFuncAttributeMaxDynamicSharedMemorySize, GSMEM_BYTES);
    cudaFuncSetAttribute(fp16_gemm<0>, cudaFuncAttributeMaxDynamicSharedMemorySize, HSMEM_BYTES);
    cudaFuncSetAttribute(fp16_gemm<1>, cudaFuncAttributeMaxDynamicSharedMemorySize, HSMEM_BYTES);
    cudaFuncSetAttribute(fp16_gemm<2>, cudaFuncAttributeMaxDynamicSharedMemorySize, HSMEM_BYTES);

    static cudaStream_t s2 = nullptr, s3 = nullptr;
    static cudaEvent_t evFork = nullptr, evFork3 = nullptr, evJoin = nullptr,
                       evJoinB = nullptr, evCvtS = nullptr, evCvtO = nullptr,
                       evLn2 = nullptr;
    if (!s2) {
        cudaStreamCreateWithFlags(&s2, cudaStreamNonBlocking);
        cudaStreamCreateWithFlags(&s3, cudaStreamNonBlocking);
        cudaEventCreateWithFlags(&evFork, cudaEventDisableTiming);
        cudaEventCreateWithFlags(&evFork3, cudaEventDisableTiming);
        cudaEventCreateWithFlags(&evJoin, cudaEventDisableTiming);
        cudaEventCreateWithFlags(&evJoinB, cudaEventDisableTiming);
        cudaEventCreateWithFlags(&evCvtS, cudaEventDisableTiming);
        cudaEventCreateWithFlags(&evCvtO, cudaEventDisableTiming);
        cudaEventCreateWithFlags(&evLn2, cudaEventDisableTiming);
    }

    const int T = 256;
    const long IN_HALF = (long)D2I * D2M;   // elements per in_w half
    // fork at t=0
    cudaEventRecord(evFork, 0);
    cudaStreamWaitEvent(s2, evFork, 0);
    cudaEventRecord(evFork3, 0);
    cudaStreamWaitEvent(s3, evFork3, 0);

    // ---- main: convert xi half of in_w + ln2, then in2a (fp16, weights once) ----
    cudaMemsetAsync(pdbl2, 0, sizeof(float) * BATCH * CH * DBL2);
    cudaMemsetAsync(pout2, 0, sizeof(float) * BATCH * CH * D2M);
    cvt_f2h<<<(int)(IN_HALF / 2048), T>>>(m2_in_w, pinwh, IN_HALF);
    ln2_kernel<<<BATCH * CH, T>>>(x, ln2_g, ln2_b, pxn2h);
    cudaEventRecord(evLn2, 0);
    fp16_gemm<0><<<dim3(128, 1, 1), 256, HSMEM_BYTES>>>(
        pxn2h, pinwh, nullptr, pxz2, BATCH * CH, D2I, D2M, D2M, D2M, 2 * D2I);

    // ---- s3: convert z half of in_w (hides under in2a), then in2b ----
    cvt_f2h<<<(int)(((long)DBL2 * D2I) / 2048), T, 0, s3>>>(m2_xp_w, pxpwh, (long)DBL2 * D2I);
    cvt_f2h<<<(int)(((long)D2I * DT2R) / 2048), T, 0, s3>>>(m2_dt_w, pdtwh, (long)D2I * DT2R);
    cudaEventRecord(evCvtS, s3);
    cvt_f2h<<<(int)(IN_HALF / 2048), T, 0, s3>>>(m2_in_w + IN_HALF, pinwh + IN_HALF, IN_HALF);
    cudaStreamWaitEvent(s3, evLn2, 0);
    fp16_gemm<0><<<dim3(128, 1, 1), 256, HSMEM_BYTES, s3>>>(
        pxn2h, pinwh + IN_HALF, nullptr, pxz2 + D2I,
        BATCH * CH, D2I, D2M, D2M, D2M, 2 * D2I);
    cudaEventRecord(evJoinB, s3);

    // ---- s2: out_w conversion + full path 1 ----
    cvt_f2h<<<(int)(((long)D2M * D2I) / 2048), T, 0, s2>>>(m2_out_w, poutwh, (long)D2M * D2I);
    cudaEventRecord(evCvtO, s2);
    cudaMemsetAsync(pout1, 0, sizeof(float) * BATCH * LL * D1M, s2);
    ln1_kernel<<<BATCH * (LL / 32), T, 0, s2>>>(x, ln1_g, ln1_b, pxn1);
    tf32_gemm<0><<<dim3(4, 64, 1), 256, GSMEM_BYTES, s2>>>(
        pxn1, m1_in_w, nullptr, pxz1, BATCH * LL, 2 * D1I, D1M, D1M, D1M, 2 * D1I);
    conv_silu_kernel<0><<<(BATCH * LL * D1I / 4 + T - 1) / T, T, 0, s2>>>(
        pxz1, m1_cw, m1_cb, pxc1, LL, D1I);
    tf32_gemm<0><<<dim3(1, 64, 1), 256, GSMEM_BYTES, s2>>>(
        pxc1, m1_xp_w, nullptr, pdbl1, BATCH * LL, DBL1, D1I, D1I, D1I, DBL1);
    sgemm_kernel<1, true><<<dim3((D1I + 63) / 64, (BATCH * LL) / 64), T, 0, s2>>>(
        pdbl1, m1_dt_w, m1_dt_b, pdelta1, BATCH * LL, D1I, DT1R, DBL1, D1I);
    scan1_partial<<<BATCH * NCH, D1I, 0, s2>>>(pdelta1, pxc1, pdbl1, m1_Alog);
    scan1_carry<<<(BATCH * D1I + T - 1) / T, T, 0, s2>>>();
    scan1_final<<<BATCH * NCH, D1I, 0, s2>>>(pdelta1, pxc1, pdbl1, m1_Alog, m1_D, pxz1, py1);
    tf32_gemm<1><<<dim3(1, 64, 2), 256, GSMEM_BYTES, s2>>>(
        py1, m1_out_w, nullptr, pout1, BATCH * LL, D1M, D1I / 2, D1I, D1I, D1M);
    cudaEventRecord(evJoin, s2);

    // ---- main: dependent chain on xi half ----
    conv_silu_kernel<1><<<(BATCH * CH * D2I / 4 + T - 1) / T, T>>>(
        pxz2, m2_cw, m2_cb, pxc2h, CH, D2I);
    cudaStreamWaitEvent(0, evCvtS, 0);
    // xp2 (fp16, BM=256): dbl2[256, 272] split-K=32 atomic (160 CTAs)
    fp16_gemm<1><<<dim3(5, 1, 32), 256, HSMEM_BYTES>>>(
        pxc2h, pxpwh, nullptr, pdbl2, BATCH * CH, DBL2, D2I / 32, D2I, D2I, DBL2);
    cvt_f2h<<<(int)(((long)BATCH * CH * DBL2) / 2048), T>>>(pdbl2, pdbl2h, (long)BATCH * CH * DBL2);
    // dt2 (fp16, BM=256): delta2 = softplus(dbl2h[:, :256] @ dt_w_h^T + b) (128 CTAs)
    fp16_gemm<2><<<dim3(128, 1, 1), 256, HSMEM_BYTES>>>(
        pdbl2h, pdtwh, m2_dt_b, pdelta2, BATCH * CH, D2I, DT2R, DBL2, DT2R, D2I);
    cudaStreamWaitEvent(0, evJoinB, 0);
    scan2_kernel<<<BATCH * (D2I / 256), T>>>(pdelta2, pxc2h, pdbl2, m2_Alog, m2_D, pxz2, py2h);
    cudaStreamWaitEvent(0, evCvtO, 0);
    // out2 (fp16, BM=256): split-K=4 atomic (256 CTAs)
    fp16_gemm<1><<<dim3(64, 1, 4), 256, HSMEM_BYTES>>>(
        py2h, poutwh, nullptr, pout2, BATCH * CH, D2M, D2I / 4, D2I, D2I, D2M);

    cudaStreamWaitEvent(0, evJoin, 0);
    combine_kernel<<<(BATCH * CH * LL + T - 1) / T, T>>>(x, out);
}

// round 14
// speedup vs baseline: 1.8098x; 1.0559x over previous
#include <cuda_runtime.h>
#include <cuda_fp16.h>
#include <cstdint>
#include <math.h>

// ---------------- problem constants ----------------
#define BATCH 2
#define CH    128
#define LL    4096
#define NS    8

#define D1M  128
#define D1I  256
#define DT1R 8
#define DBL1 24
#define D2M  4096
#define D2I  8192
#define DT2R 256
#define DBL2 272      // dt_rank(256) + 2*8

#define NCH  32
#define CLEN 128

// ---------------- scratch ----------------
__device__ __align__(16) float g_xn1[BATCH*LL*D1M];
__device__ __align__(16) float g_xz1[BATCH*LL*2*D1I];
__device__ __align__(16) float g_xc1[BATCH*LL*D1I];
__device__ __align__(16) float g_dbl1[BATCH*LL*DBL1];
__device__ __align__(16) float g_delta1[BATCH*LL*D1I];
__device__ __align__(16) float g_y1[BATCH*LL*D1I];
__device__ __align__(16) float g_out1[BATCH*LL*D1M];
__device__ __align__(16) float g_ckP[BATCH*D1I*NCH*NS];
__device__ __align__(16) float g_ckH[BATCH*D1I*NCH*NS];
__device__ __align__(16) float g_hin[BATCH*D1I*NCH*NS];

__device__ __align__(16) float g_xz2[BATCH*CH*2*D2I];
__device__ __align__(16) float g_dbl2[BATCH*CH*DBL2];
__device__ __align__(16) float g_delta2[BATCH*CH*D2I];
__device__ __align__(16) float g_out2[BATCH*CH*D2M];

// fp16 scratch (activations only — weights stay fp32 in gmem)
__device__ __align__(16) __half g_xn2h[BATCH*CH*D2M];
__device__ __align__(16) __half g_xc2h[BATCH*CH*D2I];
__device__ __align__(16) __half g_y2h[BATCH*CH*D2I];
__device__ __align__(16) __half g_dbl2h[BATCH*CH*DBL2];

// ---------------- helpers ----------------
__device__ __forceinline__ uint32_t smem_u32(const void* p) {
    uint32_t a;
    asm("{ .reg .u64 t; cvta.to.shared.u64 t, %1; cvt.u32.u64 %0, t; }" : "=r"(a) : "l"(p));
    return a;
}
__device__ __forceinline__ void cp_async16(uint32_t dst, const void* src, int sz) {
    asm volatile("cp.async.cg.shared.global [%0], [%1], 16, %2;"
                 :: "r"(dst), "l"(src), "r"(sz) : "memory");
}
#define CP_COMMIT() asm volatile("cp.async.commit_group;" ::: "memory")
#define CP_WAIT1()  asm volatile("cp.async.wait_group 1;" ::: "memory")
#define CP_WAIT0()  asm volatile("cp.async.wait_group 0;" ::: "memory")

__device__ __forceinline__ uint32_t f2tf32(float f) {
    uint32_t r;
    asm("cvt.rna.tf32.f32 %0, %1;" : "=r"(r) : "f"(f));
    return r;
}
__device__ __forceinline__ float rnd_tf32(float v) { return __uint_as_float(f2tf32(v)); }

__device__ __forceinline__ void mma_tf32(float* d, const uint32_t* a, const uint32_t* b) {
    asm volatile(
        "mma.sync.aligned.m16n8k8.row.col.f32.tf32.tf32.f32 "
        "{%0,%1,%2,%3}, {%4,%5,%6,%7}, {%8,%9}, {%0,%1,%2,%3};"
        : "+f"(d[0]), "+f"(d[1]), "+f"(d[2]), "+f"(d[3])
        : "r"(a[0]), "r"(a[1]), "r"(a[2]), "r"(a[3]), "r"(b[0]), "r"(b[1]));
}
__device__ __forceinline__ void mma_f16(float* d, const uint32_t* a, const uint32_t* b) {
    asm volatile(
        "mma.sync.aligned.m16n8k16.row.col.f32.f16.f16.f32 "
        "{%0,%1,%2,%3}, {%4,%5,%6,%7}, {%8,%9}, {%0,%1,%2,%3};"
        : "+f"(d[0]), "+f"(d[1]), "+f"(d[2]), "+f"(d[3])
        : "r"(a[0]), "r"(a[1]), "r"(a[2]), "r"(a[3]), "r"(b[0]), "r"(b[1]));
}
__device__ __forceinline__ void ldsm_x4(uint32_t& r0, uint32_t& r1, uint32_t& r2, uint32_t& r3,
                                        uint32_t addr) {
    asm volatile("ldmatrix.sync.aligned.m8n8.x4.shared.b16 {%0,%1,%2,%3}, [%4];"
                 : "=r"(r0), "=r"(r1), "=r"(r2), "=r"(r3) : "r"(addr));
}

__device__ __forceinline__ float siluf(float v) { return v / (1.f + __expf(-v)); }
__device__ __forceinline__ float softplusf(float v) { return (v > 20.f) ? v : log1pf(__expf(v)); }

// ======================================================================
// tf32 mma.sync GEMM — path-1 GEMMs (unchanged)
// ======================================================================
#define SROW 36
#define GROWS 256
#define GSTG (GROWS * SROW)
#define GSMEM_BYTES (3 * GSTG * 4)      // 108 KB -> 2 CTAs/SM

template<int EPI>
__global__ void __launch_bounds__(256, 2)
tf32_gemm(const float* __restrict__ X, const float* __restrict__ W,
          const float* __restrict__ bias, float* __restrict__ C,
          int M, int N, int kLen, int ldx, int ldw, int ldc) {
    extern __shared__ float sm[];
    const int tid = threadIdx.x;
    const int wid = tid >> 5, lane = tid & 31;
    const int gid = lane >> 2, tig = lane & 3;
    const int wm = wid >> 2, wn = wid & 3;
    const int m0 = blockIdx.y * 128, n0 = blockIdx.x * 128;
    const long k0 = (long)blockIdx.z * kLen;
    const int nIter = kLen / 32;
    const uint32_t sS = smem_u32(sm);

    float acc[4][4][4];
    #pragma unroll
    for (int i = 0; i < 4; i++)
        #pragma unroll
        for (int j = 0; j < 4; j++)
            #pragma unroll
            for (int r = 0; r < 4; r++) acc[i][j][r] = 0.f;

    auto load_stage = [&](int buf, long kk) {
        #pragma unroll
        for (int i = 0; i < 8; i++) {
            int idx = tid + i * 256;
            int row = idx >> 3, ch = idx & 7;
            uint32_t off = (uint32_t)((buf * GROWS + row) * SROW + ch * 4) * 4u;
            if (row < 128) {
                cp_async16(sS + off, X + (long)(m0 + row) * ldx + kk + ch * 4, 16);
            } else {
                int nr = n0 + row - 128;
                const float* gb = W + (long)(nr < N ? nr : 0) * ldw + kk + ch * 4;
                cp_async16(sS + off, gb, nr < N ? 16 : 0);
            }
        }
    };

    const uint32_t aBase = sS +
        (uint32_t)(((wm * 64 + ((lane >> 3) & 1) * 8 + (lane & 7)) * SROW
                    + ((lane >> 4) & 1) * 4) * 4);
    const uint32_t bBase = sS +
        (uint32_t)(((128 + wn * 32 + ((lane >> 4) & 1) * 8 + (lane & 7)) * SROW
                    + ((lane >> 3) & 1) * 4) * 4);

    load_stage(0, k0); CP_COMMIT();
    load_stage(1, k0 + 32); CP_COMMIT();

    for (int it = 0; it < nIter; it++) {
        if (it + 1 < nIter) { CP_WAIT1(); } else { CP_WAIT0(); }
        __syncthreads();
        const uint32_t stgOff = (uint32_t)((it % 3) * GSTG * 4);
        const uint32_t aS = aBase + stgOff;
        const uint32_t bS = bBase + stgOff;
        #pragma unroll
        for (int ks = 0; ks < 4; ks++) {
            uint32_t a[4][4], b[4][2];
            #pragma unroll
            for (int mi = 0; mi < 4; mi++)
                ldsm_x4(a[mi][0], a[mi][1], a[mi][2], a[mi][3],
                        aS + (uint32_t)(mi * 16 * SROW * 4 + ks * 32));
            #pragma unroll
            for (int p = 0; p < 2; p++) {
                uint32_t r0, r1, r2, r3;
                ldsm_x4(r0, r1, r2, r3, bS + (uint32_t)(p * 16 * SROW * 4 + ks * 32));
                b[2 * p][0]     = f2tf32(__uint_as_float(r0));
                b[2 * p][1]     = f2tf32(__uint_as_float(r1));
                b[2 * p + 1][0] = f2tf32(__uint_as_float(r2));
                b[2 * p + 1][1] = f2tf32(__uint_as_float(r3));
            }
            #pragma unroll
            for (int mi = 0; mi < 4; mi++)
                #pragma unroll
                for (int ni = 0; ni < 4; ni++)
                    mma_tf32(acc[mi][ni], a[mi], b[ni]);
        }
        if (it + 2 < nIter) { load_stage((it + 2) % 3, k0 + (long)(it + 2) * 32); CP_COMMIT(); }
    }

    #pragma unroll
    for (int mi = 0; mi < 4; mi++) {
        int m = m0 + wm * 64 + mi * 16 + gid;
        #pragma unroll
        for (int ni = 0; ni < 4; ni++) {
            int n = n0 + wn * 32 + ni * 8 + tig * 2;
            if (n >= N) continue;
            float* p0 = C + (long)m * ldc + n;
            float* p1 = C + (long)(m + 8) * ldc + n;
            float c0 = acc[mi][ni][0], c1 = acc[mi][ni][1];
            float c2 = acc[mi][ni][2], c3 = acc[mi][ni][3];
            if (EPI == 1) {
                atomicAdd(p0, c0); atomicAdd(p0 + 1, c1);
                atomicAdd(p1, c2); atomicAdd(p1 + 1, c3);
            } else if (EPI == 2) {
                float b0v = bias[n], b1v = bias[n + 1];
                *reinterpret_cast<float2*>(p0) =
                    make_float2(softplusf(c0 + b0v), softplusf(c1 + b1v));
                *reinterpret_cast<float2*>(p1) =
                    make_float2(softplusf(c2 + b0v), softplusf(c3 + b1v));
            } else {
                *reinterpret_cast<float2*>(p0) = make_float2(c0, c1);
                *reinterpret_cast<float2*>(p1) = make_float2(c2, c3);
            }
        }
    }
}

// ======================================================================
// fp16 mma.sync GEMM, fp32 WEIGHTS CONVERTED IN-KERNEL.
// BM=256 (weights read once), BN=64; warps 4(m) x 2(n), warp tile 64x32.
// A fp16 from gmem; W fp32 cp.async'd into a per-stage staging region,
// converted cooperatively to fp16 ldmatrix layout each K-iter.
// grid = (N/64 tiles, 1, ksplits); M must be 256.
// EPI: 0 = store, 1 = atomicAdd, 2 = softplus(v + bias[n]) store
// ======================================================================
#define SROWH 40
#define SROWB 36
#define HA_BYTES (256 * SROWH * 2)              // 20480
#define HB_BYTES (64 * SROWH * 2)               // 5120
#define HBF_OFF  (HA_BYTES + HB_BYTES)          // 25600
#define HSTAGE_BYTES (HBF_OFF + 64 * SROWB * 4) // 34816
#define HSMEM_BYTES (3 * HSTAGE_BYTES)          // 104448 -> 2 CTAs/SM

template<int EPI>
__global__ void __launch_bounds__(256, 2)
fp16w_gemm(const __half* __restrict__ X, const float* __restrict__ W,
           const float* __restrict__ bias, float* __restrict__ C,
           int M, int N, int kLen, int ldx, int ldw, int ldc) {
    extern __shared__ char smc[];
    const int tid = threadIdx.x;
    const int wid = tid >> 5, lane = tid & 31;
    const int gid = lane >> 2, tig = lane & 3;
    const int wm = wid >> 1, wn = wid & 1;       // 4 x 2 warp grid
    const int n0 = blockIdx.x * 64;
    const long k0 = (long)blockIdx.z * kLen;
    const int nIter = kLen / 32;
    const uint32_t sS = smem_u32(smc);

    float acc[4][4][4];
    #pragma unroll
    for (int i = 0; i < 4; i++)
        #pragma unroll
        for (int j = 0; j < 4; j++)
            #pragma unroll
            for (int r = 0; r < 4; r++) acc[i][j][r] = 0.f;

    auto load_stage = [&](int buf, long kk) {
        // A fp16: 256 rows x 32 halves (64B) = 4 chunks/row
        #pragma unroll
        for (int i = 0; i < 4; i++) {
            int idx = tid + i * 256;
            int row = idx >> 2, ch = idx & 3;
            uint32_t off = (uint32_t)(buf * HSTAGE_BYTES + row * (SROWH * 2) + ch * 16);
            cp_async16(sS + off, X + (long)row * ldx + kk + ch * 8, 16);
        }
        // B fp32 staging: 64 rows x 32 floats (128B) = 8 chunks/row
        #pragma unroll
        for (int i = 0; i < 2; i++) {
            int idx = tid + i * 256;
            int row = idx >> 3, ch = idx & 7;
            int nr = n0 + row;
            const float* gb = W + (long)(nr < N ? nr : 0) * ldw + kk + ch * 4;
            uint32_t off = (uint32_t)(buf * HSTAGE_BYTES + HBF_OFF + row * (SROWB * 4) + ch * 16);
            cp_async16(sS + off, gb, nr < N ? 16 : 0);
        }
    };

    const uint32_t aBase = sS +
        (uint32_t)(((wm * 64 + ((lane >> 3) & 1) * 8 + (lane & 7)) * SROWH
                    + ((lane >> 4) & 1) * 8) * 2);
    const uint32_t bBase = sS + HA_BYTES +
        (uint32_t)(((wn * 32 + ((lane >> 4) & 1) * 8 + (lane & 7)) * SROWH
                    + ((lane >> 3) & 1) * 8) * 2);

    load_stage(0, k0); CP_COMMIT();
    load_stage(1, k0 + 32); CP_COMMIT();

    for (int it = 0; it < nIter; it++) {
        if (it + 1 < nIter) { CP_WAIT1(); } else { CP_WAIT0(); }
        __syncthreads();
        const uint32_t stgOff = (uint32_t)((it % 3) * HSTAGE_BYTES);
        // prefetch next stage (writes (it+2)%3 — disjoint from reads of it%3)
        if (it + 2 < nIter) { load_stage((it + 2) % 3, k0 + (long)(it + 2) * 32); CP_COMMIT(); }

        // convert this stage's B: 64 rows x 32 fp32 -> fp16 layout (8 elts/thread)
        {
            int row = tid >> 2, seg = tid & 3;
            const float* src = reinterpret_cast<const float*>(
                smc + stgOff + HBF_OFF) + row * SROWB + seg * 8;
            float4 v0 = *reinterpret_cast<const float4*>(src);
            float4 v1 = *reinterpret_cast<const float4*>(src + 4);
            __half2 h[4];
            h[0] = __floats2half2_rn(v0.x, v0.y);
            h[1] = __floats2half2_rn(v0.z, v0.w);
            h[2] = __floats2half2_rn(v1.x, v1.y);
            h[3] = __floats2half2_rn(v1.z, v1.w);
            __half* dst = reinterpret_cast<__half*>(smc + stgOff + HA_BYTES)
                          + row * SROWH + seg * 8;
            *reinterpret_cast<uint4*>(dst) = *reinterpret_cast<uint4*>(h);
        }
        __syncthreads();

        const uint32_t aS = aBase + stgOff;
        const uint32_t bS = bBase + stgOff;
        #pragma unroll
        for (int ks = 0; ks < 2; ks++) {
            uint32_t a[4][4], b[4][2];
            #pragma unroll
            for (int mi = 0; mi < 4; mi++)
                ldsm_x4(a[mi][0], a[mi][1], a[mi][2], a[mi][3],
                        aS + (uint32_t)(mi * 16 * SROWH * 2 + ks * 32));
            #pragma unroll
            for (int p = 0; p < 2; p++) {
                uint32_t r0, r1, r2, r3;
                ldsm_x4(r0, r1, r2, r3, bS + (uint32_t)(p * 16 * SROWH * 2 + ks * 32));
                b[2 * p][0] = r0;     b[2 * p][1] = r1;
                b[2 * p + 1][0] = r2; b[2 * p + 1][1] = r3;
            }
            #pragma unroll
            for (int mi = 0; mi < 4; mi++)
                #pragma unroll
                for (int ni = 0; ni < 4; ni++)
                    mma_f16(acc[mi][ni], a[mi], b[ni]);
        }
    }

    #pragma unroll
    for (int mi = 0; mi < 4; mi++) {
        int m = wm * 64 + mi * 16 + gid;
        #pragma unroll
        for (int ni = 0; ni < 4; ni++) {
            int n = n0 + wn * 32 + ni * 8 + tig * 2;
            if (n >= N) continue;
            float* p0 = C + (long)m * ldc + n;
            float* p1 = C + (long)(m + 8) * ldc + n;
            float c0 = acc[mi][ni][0], c1 = acc[mi][ni][1];
            float c2 = acc[mi][ni][2], c3 = acc[mi][ni][3];
            if (EPI == 1) {
                atomicAdd(p0, c0); atomicAdd(p0 + 1, c1);
                atomicAdd(p1, c2); atomicAdd(p1 + 1, c3);
            } else if (EPI == 2) {
                float b0v = bias[n], b1v = bias[n + 1];
                *reinterpret_cast<float2*>(p0) =
                    make_float2(softplusf(c0 + b0v), softplusf(c1 + b1v));
                *reinterpret_cast<float2*>(p1) =
                    make_float2(softplusf(c2 + b0v), softplusf(c3 + b1v));
            } else {
                *reinterpret_cast<float2*>(p0) = make_float2(c0, c1);
                *reinterpret_cast<float2*>(p1) = make_float2(c2, c3);
            }
        }
    }
}

// ---------------- fp32 -> fp16 conversion (8 elts/thread) ----------------
__global__ void cvt_f2h(const float* __restrict__ src, __half* __restrict__ dst, long n) {
    long i = ((long)blockIdx.x * 256 + threadIdx.x) * 8;
    if (i >= n) return;
    float4 v0 = *reinterpret_cast<const float4*>(src + i);
    float4 v1 = *reinterpret_cast<const float4*>(src + i + 4);
    __half2 h[4];
    h[0] = __floats2half2_rn(v0.x, v0.y);
    h[1] = __floats2half2_rn(v0.z, v0.w);
    h[2] = __floats2half2_rn(v1.x, v1.y);
    h[3] = __floats2half2_rn(v1.z, v1.w);
    *reinterpret_cast<uint4*>(dst + i) = *reinterpret_cast<uint4*>(h);
}

// ---------------- LayerNorm 1 (tf32-rounded) ----------------
__global__ void ln1_kernel(const float* __restrict__ x, const float* __restrict__ g,
                           const float* __restrict__ bta, float* __restrict__ out) {
    int b  = blockIdx.x >> 7;
    int l0 = (blockIdx.x & 127) * 32;
    __shared__ float sm[128 * 33];
    int tid = threadIdx.x;
    #pragma unroll
    for (int i = 0; i < 16; i++) {
        int idx = tid + i * 256;
        int c = idx >> 5, l = idx & 31;
        sm[c * 33 + l] = x[((long)b * CH + c) * LL + l0 + l];
    }
    __syncthreads();
    int warp = tid >> 5, lane = tid & 31;
    for (int t = warp; t < 32; t += 8) {
        float v[4]; float s = 0.f, sq = 0.f;
        #pragma unroll
        for (int j = 0; j < 4; j++) {
            v[j] = sm[(lane + 32 * j) * 33 + t];
            s += v[j]; sq += v[j] * v[j];
        }
        #pragma unroll
        for (int o = 16; o; o >>= 1) {
            s  += __shfl_xor_sync(0xffffffffu, s,  o);
            sq += __shfl_xor_sync(0xffffffffu, sq, o);
        }
        float mu  = s * (1.f / 128.f);
        float var = sq * (1.f / 128.f) - mu * mu;
        float rs  = rsqrtf(var + 1e-5f);
        #pragma unroll
        for (int j = 0; j < 4; j++) {
            int c = lane + 32 * j;
            out[((long)b * LL + l0 + t) * D1M + c] = rnd_tf32((v[j] - mu) * rs * g[c] + bta[c]);
        }
    }
}

// ---------------- LayerNorm 2 (fp16 output) ----------------
__global__ void ln2_kernel(const float* __restrict__ x, const float* __restrict__ g,
                           const float* __restrict__ bta, __half* __restrict__ out) {
    long row = blockIdx.x;
    const float* xr = x + row * D2M;
    __half* orow = out + row * D2M;
    int tid = threadIdx.x;
    float v[16]; float s = 0.f, sq = 0.f;
    #pragma unroll
    for (int i = 0; i < 16; i++) {
        v[i] = xr[i * 256 + tid];
        s += v[i]; sq += v[i] * v[i];
    }
    #pragma unroll
    for (int o = 16; o; o >>= 1) {
        s  += __shfl_xor_sync(0xffffffffu, s,  o);
        sq += __shfl_xor_sync(0xffffffffu, sq, o);
    }
    __shared__ float ss[8], sqq[8];
    int lane = tid & 31, warp = tid >> 5;
    if (!lane) { ss[warp] = s; sqq[warp] = sq; }
    __syncthreads();
    s = 0.f; sq = 0.f;
    #pragma unroll
    for (int w = 0; w < 8; w++) { s += ss[w]; sq += sqq[w]; }
    float mu  = s * (1.f / 4096.f);
    float var = sq * (1.f / 4096.f) - mu * mu;
    float rs  = rsqrtf(var + 1e-5f);
    #pragma unroll
    for (int i = 0; i < 16; i++) {
        int col = i * 256 + tid;
        orow[col] = __float2half_rn((v[i] - mu) * rs * g[col] + bta[col]);
    }
}

// ---------------- fallback SGEMM (dt1: K=8) ----------------
template<int ACT, bool HASBIAS>
__global__ void sgemm_kernel(const float* __restrict__ X, const float* __restrict__ W,
                             const float* __restrict__ bias, float* __restrict__ out,
                             int M, int N, int K, int lda, int ldc) {
    constexpr int BM = 64, BN = 64, BK = 32, PAD = 4;
    __shared__ float As[BK][BM + PAD];
    __shared__ float Bs[BK][BN + PAD];
    int bm = blockIdx.y * BM, bn = blockIdx.x * BN;
    int tid = threadIdx.x;
    int tx = tid & 15, ty = tid >> 4;
    float acc[4][4] = {};
    for (int k0 = 0; k0 < K; k0 += BK) {
        #pragma unroll
        for (int i = 0; i < 2; i++) {
            int idx = tid + i * 256;
            int row = idx >> 3;
            int kc  = (idx & 7) << 2;
            int k   = k0 + kc;
            float4 va = make_float4(0.f, 0.f, 0.f, 0.f);
            float4 vb = make_float4(0.f, 0.f, 0.f, 0.f);
            if (k < K) {
                int m = bm + row;
                if (m < M) va = *reinterpret_cast<const float4*>(X + (long)m * lda + k);
                int n = bn + row;
                if (n < N) vb = *reinterpret_cast<const float4*>(W + (long)n * K + k);
            }
            As[kc][row] = va.x; As[kc + 1][row] = va.y; As[kc + 2][row] = va.z; As[kc + 3][row] = va.w;
            Bs[kc][row] = vb.x; Bs[kc + 1][row] = vb.y; Bs[kc + 2][row] = vb.z; Bs[kc + 3][row] = vb.w;
        }
        __syncthreads();
        #pragma unroll
        for (int kk = 0; kk < BK; kk++) {
            float4 a = *reinterpret_cast<const float4*>(&As[kk][ty << 2]);
            float4 b = *reinterpret_cast<const float4*>(&Bs[kk][tx << 2]);
            float av[4] = {a.x, a.y, a.z, a.w};
            float bv[4] = {b.x, b.y, b.z, b.w};
            #pragma unroll
            for (int i = 0; i < 4; i++)
                #pragma unroll
                for (int j = 0; j < 4; j++)
                    acc[i][j] += av[i] * bv[j];
        }
        __syncthreads();
    }
    #pragma unroll
    for (int i = 0; i < 4; i++) {
        int m = bm + (ty << 2) + i;
        if (m >= M) continue;
        #pragma unroll
        for (int j = 0; j < 4; j++) {
            int n = bn + (tx << 2) + j;
            if (n >= N) continue;
            float v = acc[i][j];
            if (HASBIAS) v += bias[n];
            if (ACT == 1) v = softplusf(v);
            out[(long)m * ldc + n] = v;
        }
    }
}

// ---------------- causal depthwise conv (K=4) + SiLU; HOUT: 0=float(tf32), 1=half ----------------
template<int HOUT>
__global__ void conv_silu_kernel(const float* __restrict__ xz, const float* __restrict__ w,
                                 const float* __restrict__ bias, void* __restrict__ outv,
                                 int Ltok, int dinner) {
    long tid = (long)blockIdx.x * 256 + threadIdx.x;
    long total = (long)BATCH * Ltok * (dinner / 4);
    if (tid >= total) return;
    int d4 = (int)(tid % (dinner / 4)) * 4;
    long t = tid / (dinner / 4);
    int l = (int)(t % Ltok);
    int b = (int)(t / Ltok);
    int rowstride = 2 * dinner;
    const float* base = xz + ((long)b * Ltok + l) * rowstride + d4;
    float4 bv = *reinterpret_cast<const float4*>(bias + d4);
    float acc0 = bv.x, acc1 = bv.y, acc2 = bv.z, acc3 = bv.w;
    #pragma unroll
    for (int k = 0; k < 4; k++) {
        int ll = l - 3 + k;
        if (ll >= 0) {
            float4 xv = *reinterpret_cast<const float4*>(base + (long)(ll - l) * rowstride);
            acc0 += xv.x * w[(d4 + 0) * 4 + k];
            acc1 += xv.y * w[(d4 + 1) * 4 + k];
            acc2 += xv.z * w[(d4 + 2) * 4 + k];
            acc3 += xv.w * w[(d4 + 3) * 4 + k];
        }
    }
    acc0 = siluf(acc0); acc1 = siluf(acc1); acc2 = siluf(acc2); acc3 = siluf(acc3);
    long o = ((long)b * Ltok + l) * dinner + d4;
    if (HOUT) {
        __half2 h0 = __floats2half2_rn(acc0, acc1);
        __half2 h1 = __floats2half2_rn(acc2, acc3);
        __half* out = (__half*)outv;
        *reinterpret_cast<uint2*>(out + o) = make_uint2(
            *reinterpret_cast<uint32_t*>(&h0), *reinterpret_cast<uint32_t*>(&h1));
    } else {
        float4 ov;
        ov.x = rnd_tf32(acc0); ov.y = rnd_tf32(acc1);
        ov.z = rnd_tf32(acc2); ov.w = rnd_tf32(acc3);
        *reinterpret_cast<float4*>((float*)outv + o) = ov;
    }
}

// ---------------- path-1 scan ----------------
__global__ void scan1_partial(const float* __restrict__ delta, const float* __restrict__ xc,
                              const float* __restrict__ dbl, const float* __restrict__ Alog) {
    int d = threadIdx.x;
    int chunk = blockIdx.x & (NCH - 1);
    int b = blockIdx.x >> 5;
    float A[NS], h[NS], P[NS];
    #pragma unroll
    for (int s = 0; s < NS; s++) { A[s] = -__expf(Alog[d * NS + s]); h[s] = 0.f; P[s] = 1.f; }
    int l0 = chunk * CLEN;
    for (int i = 0; i < CLEN; i++) {
        long t = (long)b * LL + l0 + i;
        float dl = delta[t * D1I + d];
        float xv = xc[t * D1I + d];
        const float* bl = dbl + t * DBL1 + DT1R;
        float dx = dl * xv;
        #pragma unroll
        for (int s = 0; s < NS; s++) {
            float dA = __expf(dl * A[s]);
            h[s] = dA * h[s] + dx * bl[s];
            P[s] *= dA;
        }
    }
    long o = (((long)b * D1I + d) * NCH + chunk) * NS;
    #pragma unroll
    for (int s = 0; s < NS; s++) { g_ckP[o + s] = P[s]; g_ckH[o + s] = h[s]; }
}

__global__ void scan1_carry() {
    int idx = blockIdx.x * 256 + threadIdx.x;
    if (idx >= BATCH * D1I) return;
    long base = (long)idx * NCH * NS;
    float h[NS];
    #pragma unroll
    for (int s = 0; s < NS; s++) h[s] = 0.f;
    for (int c = 0; c < NCH; c++) {
        long o = base + (long)c * NS;
        #pragma unroll
        for (int s = 0; s < NS; s++) {
            g_hin[o + s] = h[s];
            h[s] = g_ckP[o + s] * h[s] + g_ckH[o + s];
        }
    }
}

__global__ void scan1_final(const float* __restrict__ delta, const float* __restrict__ xc,
                            const float* __restrict__ dbl, const float* __restrict__ Alog,
                            const float* __restrict__ Dp, const float* __restrict__ xz,
                            float* __restrict__ y) {
    int d = threadIdx.x;
    int chunk = blockIdx.x & (NCH - 1);
    int b = blockIdx.x >> 5;
    float A[NS], h[NS];
    long hb = (((long)b * D1I + d) * NCH + chunk) * NS;
    #pragma unroll
    for (int s = 0; s < NS; s++) { A[s] = -__expf(Alog[d * NS + s]); h[s] = g_hin[hb + s]; }
    float Dv = Dp[d];
    int l0 = chunk * CLEN;
    for (int i = 0; i < CLEN; i++) {
        long t = (long)b * LL + l0 + i;
        float dl = delta[t * D1I + d];
        float xv = xc[t * D1I + d];
        const float* bl = dbl + t * DBL1 + DT1R;
        float dx = dl * xv;
        float acc = 0.f;
        #pragma unroll
        for (int s = 0; s < NS; s++) {
            float dA = __expf(dl * A[s]);
            h[s] = dA * h[s] + dx * bl[s];
            acc += h[s] * bl[NS + s];
        }
        float z = xz[t * (2 * D1I) + D1I + d];
        y[t * D1I + d] = rnd_tf32((acc + xv * Dv) * siluf(z));
    }
}

// ---------------- path-2 scan (xc fp16 in, y fp16 out) ----------------
__global__ void scan2_kernel(const float* __restrict__ delta, const __half* __restrict__ xc,
                             const float* __restrict__ dbl, const float* __restrict__ Alog,
                             const float* __restrict__ Dp, const float* __restrict__ xz,
                             __half* __restrict__ y) {
    int d = (blockIdx.x & 31) * 256 + threadIdx.x;
    int b = blockIdx.x >> 5;
    float A[NS], h[NS];
    #pragma unroll
    for (int s = 0; s < NS; s++) { A[s] = -__expf(Alog[d * NS + s]); h[s] = 0.f; }
    float Dv = Dp[d];
    for (int l = 0; l < CH; l++) {
        long t = (long)b * CH + l;
        float dl = delta[t * D2I + d];
        float xv = __half2float(xc[t * D2I + d]);
        const float* bl = dbl + t * DBL2 + DT2R;
        float dx = dl * xv;
        float acc = 0.f;
        #pragma unroll
        for (int s = 0; s < NS; s++) {
            float dA = __expf(dl * A[s]);
            h[s] = dA * h[s] + dx * bl[s];
            acc += h[s] * bl[NS + s];
        }
        float z = xz[t * (2 * D2I) + D2I + d];
        y[t * D2I + d] = __float2half_rn((acc + xv * Dv) * siluf(z));
    }
}

// ---------------- combine ----------------
__global__ void combine_kernel(const float* __restrict__ x, float* __restrict__ out) {
    long i = (long)blockIdx.x * 256 + threadIdx.x;
    if (i >= (long)BATCH * CH * LL) return;
    int l = (int)(i % LL);
    long t = i / LL;
    int c = (int)(t % CH);
    int b = (int)(t / CH);
    out[i] = x[i] + g_out2[i] + g_out1[((long)b * LL + l) * D1M + c];
}

// ---------------- launch ----------------
extern "C" void kernel_launch(void* const* d_in, const int* in_sizes, int n_in,
                              void* d_out, int out_size) {
    const float* x        = (const float*)d_in[0];
    const float* ln1_g    = (const float*)d_in[1];
    const float* ln1_b    = (const float*)d_in[2];
    const float* ln2_g    = (const float*)d_in[3];
    const float* ln2_b    = (const float*)d_in[4];
    const float* m1_in_w  = (const float*)d_in[5];
    const float* m1_cw    = (const float*)d_in[6];
    const float* m1_cb    = (const float*)d_in[7];
    const float* m1_xp_w  = (const float*)d_in[8];
    const float* m1_dt_w  = (const float*)d_in[9];
    const float* m1_dt_b  = (const float*)d_in[10];
    const float* m1_Alog  = (const float*)d_in[11];
    const float* m1_D     = (const float*)d_in[12];
    const float* m1_out_w = (const float*)d_in[13];
    const float* m2_in_w  = (const float*)d_in[14];
    const float* m2_cw    = (const float*)d_in[15];
    const float* m2_cb    = (const float*)d_in[16];
    const float* m2_xp_w  = (const float*)d_in[17];
    const float* m2_dt_w  = (const float*)d_in[18];
    const float* m2_dt_b  = (const float*)d_in[19];
    const float* m2_Alog  = (const float*)d_in[20];
    const float* m2_D     = (const float*)d_in[21];
    const float* m2_out_w = (const float*)d_in[22];
    float* out = (float*)d_out;

    float *pxn1, *pxz1, *pxc1, *pdbl1, *pdelta1, *py1, *pout1;
    float *pxz2, *pdbl2, *pdelta2, *pout2;
    __half *pxn2h, *pxc2h, *py2h, *pdbl2h;
    cudaGetSymbolAddress((void**)&pxn1, g_xn1);
    cudaGetSymbolAddress((void**)&pxz1, g_xz1);
    cudaGetSymbolAddress((void**)&pxc1, g_xc1);
    cudaGetSymbolAddress((void**)&pdbl1, g_dbl1);
    cudaGetSymbolAddress((void**)&pdelta1, g_delta1);
    cudaGetSymbolAddress((void**)&py1, g_y1);
    cudaGetSymbolAddress((void**)&pout1, g_out1);
    cudaGetSymbolAddress((void**)&pxz2, g_xz2);
    cudaGetSymbolAddress((void**)&pdbl2, g_dbl2);
    cudaGetSymbolAddress((void**)&pdelta2, g_delta2);
    cudaGetSymbolAddress((void**)&pout2, g_out2);
    cudaGetSymbolAddress((void**)&pxn2h, g_xn2h);
    cudaGetSymbolAddress((void**)&pxc2h, g_xc2h);
    cudaGetSymbolAddress((void**)&py2h, g_y2h);
    cudaGetSymbolAddress((void**)&pdbl2h, g_dbl2h);

    cudaFuncSetAttribute(tf32_gemm<0>, cudaFuncAttributeMaxDynamicSharedMemorySize, GSMEM_BYTES);
    cudaFuncSetAttribute(tf32_gemm<1>, cudaFuncAttributeMaxDynamicSharedMemorySize, GSMEM_BYTES);
    cudaFuncSetAttribute(fp16w_gemm<0>, cudaFuncAttributeMaxDynamicSharedMemorySize, HSMEM_BYTES);
    cudaFuncSetAttribute(fp16w_gemm<1>, cudaFuncAttributeMaxDynamicSharedMemorySize, HSMEM_BYTES);
    cudaFuncSetAttribute(fp16w_gemm<2>, cudaFuncAttributeMaxDynamicSharedMemorySize, HSMEM_BYTES);

    static cudaStream_t s2 = nullptr, s3 = nullptr;
    static cudaEvent_t evFork = nullptr, evFork3 = nullptr, evJoin = nullptr,
                       evJoinB = nullptr, evLn2 = nullptr;
    if (!s2) {
        cudaStreamCreateWithFlags(&s2, cudaStreamNonBlocking);
        cudaStreamCreateWithFlags(&s3, cudaStreamNonBlocking);
        cudaEventCreateWithFlags(&evFork, cudaEventDisableTiming);
        cudaEventCreateWithFlags(&evFork3, cudaEventDisableTiming);
        cudaEventCreateWithFlags(&evJoin, cudaEventDisableTiming);
        cudaEventCreateWithFlags(&evJoinB, cudaEventDisableTiming);
        cudaEventCreateWithFlags(&evLn2, cudaEventDisableTiming);
    }

    const int T = 256;
    const long IN_HALF = (long)D2I * D2M;   // fp32 elements per in_w half
    // fork at t=0
    cudaEventRecord(evFork, 0);
    cudaStreamWaitEvent(s2, evFork, 0);
    cudaEventRecord(evFork3, 0);
    cudaStreamWaitEvent(s3, evFork3, 0);

    // ---- main: ln2, then in2a (fp16 MMA, fp32 weights converted in-kernel) ----
    cudaMemsetAsync(pdbl2, 0, sizeof(float) * BATCH * CH * DBL2);
    cudaMemsetAsync(pout2, 0, sizeof(float) * BATCH * CH * D2M);
    ln2_kernel<<<BATCH * CH, T>>>(x, ln2_g, ln2_b, pxn2h);
    cudaEventRecord(evLn2, 0);
    fp16w_gemm<0><<<dim3(128, 1, 1), 256, HSMEM_BYTES>>>(
        pxn2h, m2_in_w, nullptr, pxz2, BATCH * CH, D2I, D2M, D2M, D2M, 2 * D2I);

    // ---- s3: in2b (z half) ----
    cudaStreamWaitEvent(s3, evLn2, 0);
    fp16w_gemm<0><<<dim3(128, 1, 1), 256, HSMEM_BYTES, s3>>>(
        pxn2h, m2_in_w + IN_HALF, nullptr, pxz2 + D2I,
        BATCH * CH, D2I, D2M, D2M, D2M, 2 * D2I);
    cudaEventRecord(evJoinB, s3);

    // ---- s2: full path 1 ----
    cudaMemsetAsync(pout1, 0, sizeof(float) * BATCH * LL * D1M, s2);
    ln1_kernel<<<BATCH * (LL / 32), T, 0, s2>>>(x, ln1_g, ln1_b, pxn1);
    tf32_gemm<0><<<dim3(4, 64, 1), 256, GSMEM_BYTES, s2>>>(
        pxn1, m1_in_w, nullptr, pxz1, BATCH * LL, 2 * D1I, D1M, D1M, D1M, 2 * D1I);
    conv_silu_kernel<0><<<(BATCH * LL * D1I / 4 + T - 1) / T, T, 0, s2>>>(
        pxz1, m1_cw, m1_cb, pxc1, LL, D1I);
    tf32_gemm<0><<<dim3(1, 64, 1), 256, GSMEM_BYTES, s2>>>(
        pxc1, m1_xp_w, nullptr, pdbl1, BATCH * LL, DBL1, D1I, D1I, D1I, DBL1);
    sgemm_kernel<1, true><<<dim3((D1I + 63) / 64, (BATCH * LL) / 64), T, 0, s2>>>(
        pdbl1, m1_dt_w, m1_dt_b, pdelta1, BATCH * LL, D1I, DT1R, DBL1, D1I);
    scan1_partial<<<BATCH * NCH, D1I, 0, s2>>>(pdelta1, pxc1, pdbl1, m1_Alog);
    scan1_carry<<<(BATCH * D1I + T - 1) / T, T, 0, s2>>>();
    scan1_final<<<BATCH * NCH, D1I, 0, s2>>>(pdelta1, pxc1, pdbl1, m1_Alog, m1_D, pxz1, py1);
    tf32_gemm<1><<<dim3(1, 64, 2), 256, GSMEM_BYTES, s2>>>(
        py1, m1_out_w, nullptr, pout1, BATCH * LL, D1M, D1I / 2, D1I, D1I, D1M);
    cudaEventRecord(evJoin, s2);

    // ---- main: dependent chain on xi half ----
    conv_silu_kernel<1><<<(BATCH * CH * D2I / 4 + T - 1) / T, T>>>(
        pxz2, m2_cw, m2_cb, pxc2h, CH, D2I);
    // xp2: dbl2[256, 272] split-K=32 atomic (160 CTAs)
    fp16w_gemm<1><<<dim3(5, 1, 32), 256, HSMEM_BYTES>>>(
        pxc2h, m2_xp_w, nullptr, pdbl2, BATCH * CH, DBL2, D2I / 32, D2I, D2I, DBL2);
    cvt_f2h<<<(int)(((long)BATCH * CH * DBL2) / 2048), T>>>(pdbl2, pdbl2h, (long)BATCH * CH * DBL2);
    // dt2: delta2 = softplus(dbl2h[:, :256] @ dt_w^T + b) (128 CTAs)
    fp16w_gemm<2><<<dim3(128, 1, 1), 256, HSMEM_BYTES>>>(
        pdbl2h, m2_dt_w, m2_dt_b, pdelta2, BATCH * CH, D2I, DT2R, DBL2, DT2R, D2I);
    cudaStreamWaitEvent(0, evJoinB, 0);
    scan2_kernel<<<BATCH * (D2I / 256), T>>>(pdelta2, pxc2h, pdbl2, m2_Alog, m2_D, pxz2, py2h);
    // out2: split-K=4 atomic (256 CTAs)
    fp16w_gemm<1><<<dim3(64, 1, 4), 256, HSMEM_BYTES>>>(
        py2h, m2_out_w, nullptr, pout2, BATCH * CH, D2M, D2I / 4, D2I, D2I, D2M);

    cudaStreamWaitEvent(0, evJoin, 0);
    combine_kernel<<<(BATCH * CH * LL + T - 1) / T, T>>>(x, out);
}

// round 15
// speedup vs baseline: 1.8644x; 1.0302x over previous
#include <cuda_runtime.h>
#include <cuda_fp16.h>
#include <cstdint>
#include <math.h>

// ---------------- problem constants ----------------
#define BATCH 2
#define CH    128
#define LL    4096
#define NS    8

#define D1M  128
#define D1I  256
#define DT1R 8
#define DBL1 24
#define D2M  4096
#define D2I  8192
#define DT2R 256
#define DBL2 272      // dt_rank(256) + 2*8

#define NCH  32
#define CLEN 128

// ---------------- scratch ----------------
__device__ __align__(16) float g_xn1[BATCH*LL*D1M];
__device__ __align__(16) float g_xz1[BATCH*LL*2*D1I];
__device__ __align__(16) float g_xc1[BATCH*LL*D1I];
__device__ __align__(16) float g_dbl1[BATCH*LL*DBL1];
__device__ __align__(16) float g_delta1[BATCH*LL*D1I];
__device__ __align__(16) float g_y1[BATCH*LL*D1I];
__device__ __align__(16) float g_out1[BATCH*LL*D1M];
__device__ __align__(16) float g_ckP[BATCH*D1I*NCH*NS];
__device__ __align__(16) float g_ckH[BATCH*D1I*NCH*NS];
__device__ __align__(16) float g_hin[BATCH*D1I*NCH*NS];

__device__ __align__(16) float g_xz2[BATCH*CH*2*D2I];   // only z half written now
__device__ __align__(16) float g_dbl2[BATCH*CH*DBL2];
__device__ __align__(16) float g_delta2[BATCH*CH*D2I];
__device__ __align__(16) float g_out2[BATCH*CH*D2M];

// fp16 scratch (activations only — weights stay fp32 in gmem)
__device__ __align__(16) __half g_xn2h[BATCH*CH*D2M];
__device__ __align__(16) __half g_xc2h[BATCH*CH*D2I];
__device__ __align__(16) __half g_y2h[BATCH*CH*D2I];
__device__ __align__(16) __half g_dbl2h[BATCH*CH*DBL2];

// ---------------- helpers ----------------
__device__ __forceinline__ uint32_t smem_u32(const void* p) {
    uint32_t a;
    asm("{ .reg .u64 t; cvta.to.shared.u64 t, %1; cvt.u32.u64 %0, t; }" : "=r"(a) : "l"(p));
    return a;
}
__device__ __forceinline__ void cp_async16(uint32_t dst, const void* src, int sz) {
    asm volatile("cp.async.cg.shared.global [%0], [%1], 16, %2;"
                 :: "r"(dst), "l"(src), "r"(sz) : "memory");
}
#define CP_COMMIT() asm volatile("cp.async.commit_group;" ::: "memory")
#define CP_WAIT1()  asm volatile("cp.async.wait_group 1;" ::: "memory")
#define CP_WAIT0()  asm volatile("cp.async.wait_group 0;" ::: "memory")

__device__ __forceinline__ uint32_t f2tf32(float f) {
    uint32_t r;
    asm("cvt.rna.tf32.f32 %0, %1;" : "=r"(r) : "f"(f));
    return r;
}
__device__ __forceinline__ float rnd_tf32(float v) { return __uint_as_float(f2tf32(v)); }

__device__ __forceinline__ void mma_tf32(float* d, const uint32_t* a, const uint32_t* b) {
    asm volatile(
        "mma.sync.aligned.m16n8k8.row.col.f32.tf32.tf32.f32 "
        "{%0,%1,%2,%3}, {%4,%5,%6,%7}, {%8,%9}, {%0,%1,%2,%3};"
        : "+f"(d[0]), "+f"(d[1]), "+f"(d[2]), "+f"(d[3])
        : "r"(a[0]), "r"(a[1]), "r"(a[2]), "r"(a[3]), "r"(b[0]), "r"(b[1]));
}
__device__ __forceinline__ void mma_f16(float* d, const uint32_t* a, const uint32_t* b) {
    asm volatile(
        "mma.sync.aligned.m16n8k16.row.col.f32.f16.f16.f32 "
        "{%0,%1,%2,%3}, {%4,%5,%6,%7}, {%8,%9}, {%0,%1,%2,%3};"
        : "+f"(d[0]), "+f"(d[1]), "+f"(d[2]), "+f"(d[3])
        : "r"(a[0]), "r"(a[1]), "r"(a[2]), "r"(a[3]), "r"(b[0]), "r"(b[1]));
}
__device__ __forceinline__ void ldsm_x4(uint32_t& r0, uint32_t& r1, uint32_t& r2, uint32_t& r3,
                                        uint32_t addr) {
    asm volatile("ldmatrix.sync.aligned.m8n8.x4.shared.b16 {%0,%1,%2,%3}, [%4];"
                 : "=r"(r0), "=r"(r1), "=r"(r2), "=r"(r3) : "r"(addr));
}

__device__ __forceinline__ float siluf(float v) { return v / (1.f + __expf(-v)); }
__device__ __forceinline__ float softplusf(float v) { return (v > 20.f) ? v : log1pf(__expf(v)); }

// ======================================================================
// tf32 mma.sync GEMM — path-1 GEMMs (unchanged)
// ======================================================================
#define SROW 36
#define GROWS 256
#define GSTG (GROWS * SROW)
#define GSMEM_BYTES (3 * GSTG * 4)      // 108 KB -> 2 CTAs/SM

template<int EPI>
__global__ void __launch_bounds__(256, 2)
tf32_gemm(const float* __restrict__ X, const float* __restrict__ W,
          const float* __restrict__ bias, float* __restrict__ C,
          int M, int N, int kLen, int ldx, int ldw, int ldc) {
    extern __shared__ float sm[];
    const int tid = threadIdx.x;
    const int wid = tid >> 5, lane = tid & 31;
    const int gid = lane >> 2, tig = lane & 3;
    const int wm = wid >> 2, wn = wid & 3;
    const int m0 = blockIdx.y * 128, n0 = blockIdx.x * 128;
    const long k0 = (long)blockIdx.z * kLen;
    const int nIter = kLen / 32;
    const uint32_t sS = smem_u32(sm);

    float acc[4][4][4];
    #pragma unroll
    for (int i = 0; i < 4; i++)
        #pragma unroll
        for (int j = 0; j < 4; j++)
            #pragma unroll
            for (int r = 0; r < 4; r++) acc[i][j][r] = 0.f;

    auto load_stage = [&](int buf, long kk) {
        #pragma unroll
        for (int i = 0; i < 8; i++) {
            int idx = tid + i * 256;
            int row = idx >> 3, ch = idx & 7;
            uint32_t off = (uint32_t)((buf * GROWS + row) * SROW + ch * 4) * 4u;
            if (row < 128) {
                cp_async16(sS + off, X + (long)(m0 + row) * ldx + kk + ch * 4, 16);
            } else {
                int nr = n0 + row - 128;
                const float* gb = W + (long)(nr < N ? nr : 0) * ldw + kk + ch * 4;
                cp_async16(sS + off, gb, nr < N ? 16 : 0);
            }
        }
    };

    const uint32_t aBase = sS +
        (uint32_t)(((wm * 64 + ((lane >> 3) & 1) * 8 + (lane & 7)) * SROW
                    + ((lane >> 4) & 1) * 4) * 4);
    const uint32_t bBase = sS +
        (uint32_t)(((128 + wn * 32 + ((lane >> 4) & 1) * 8 + (lane & 7)) * SROW
                    + ((lane >> 3) & 1) * 4) * 4);

    load_stage(0, k0); CP_COMMIT();
    load_stage(1, k0 + 32); CP_COMMIT();

    for (int it = 0; it < nIter; it++) {
        if (it + 1 < nIter) { CP_WAIT1(); } else { CP_WAIT0(); }
        __syncthreads();
        const uint32_t stgOff = (uint32_t)((it % 3) * GSTG * 4);
        const uint32_t aS = aBase + stgOff;
        const uint32_t bS = bBase + stgOff;
        #pragma unroll
        for (int ks = 0; ks < 4; ks++) {
            uint32_t a[4][4], b[4][2];
            #pragma unroll
            for (int mi = 0; mi < 4; mi++)
                ldsm_x4(a[mi][0], a[mi][1], a[mi][2], a[mi][3],
                        aS + (uint32_t)(mi * 16 * SROW * 4 + ks * 32));
            #pragma unroll
            for (int p = 0; p < 2; p++) {
                uint32_t r0, r1, r2, r3;
                ldsm_x4(r0, r1, r2, r3, bS + (uint32_t)(p * 16 * SROW * 4 + ks * 32));
                b[2 * p][0]     = f2tf32(__uint_as_float(r0));
                b[2 * p][1]     = f2tf32(__uint_as_float(r1));
                b[2 * p + 1][0] = f2tf32(__uint_as_float(r2));
                b[2 * p + 1][1] = f2tf32(__uint_as_float(r3));
            }
            #pragma unroll
            for (int mi = 0; mi < 4; mi++)
                #pragma unroll
                for (int ni = 0; ni < 4; ni++)
                    mma_tf32(acc[mi][ni], a[mi], b[ni]);
        }
        if (it + 2 < nIter) { load_stage((it + 2) % 3, k0 + (long)(it + 2) * 32); CP_COMMIT(); }
    }

    #pragma unroll
    for (int mi = 0; mi < 4; mi++) {
        int m = m0 + wm * 64 + mi * 16 + gid;
        #pragma unroll
        for (int ni = 0; ni < 4; ni++) {
            int n = n0 + wn * 32 + ni * 8 + tig * 2;
            if (n >= N) continue;
            float* p0 = C + (long)m * ldc + n;
            float* p1 = C + (long)(m + 8) * ldc + n;
            float c0 = acc[mi][ni][0], c1 = acc[mi][ni][1];
            float c2 = acc[mi][ni][2], c3 = acc[mi][ni][3];
            if (EPI == 1) {
                atomicAdd(p0, c0); atomicAdd(p0 + 1, c1);
                atomicAdd(p1, c2); atomicAdd(p1 + 1, c3);
            } else if (EPI == 2) {
                float b0v = bias[n], b1v = bias[n + 1];
                *reinterpret_cast<float2*>(p0) =
                    make_float2(softplusf(c0 + b0v), softplusf(c1 + b1v));
                *reinterpret_cast<float2*>(p1) =
                    make_float2(softplusf(c2 + b0v), softplusf(c3 + b1v));
            } else {
                *reinterpret_cast<float2*>(p0) = make_float2(c0, c1);
                *reinterpret_cast<float2*>(p1) = make_float2(c2, c3);
            }
        }
    }
}

// ======================================================================
// fp16 mma.sync GEMM, fp32 WEIGHTS CONVERTED IN-KERNEL.
// BM=256 (weights read once), BN=64; warps 4(m) x 2(n), warp tile 64x32.
// EPI: 0 = store, 1 = atomicAdd, 2 = softplus(v+bias[n]) store,
//      3 = fused causal conv(K=4)+SiLU -> fp16 hout  (in2a; grid.z==1)
// ======================================================================
#define SROWH 40
#define SROWB 36
#define HA_BYTES (256 * SROWH * 2)              // 20480
#define HB_BYTES (64 * SROWH * 2)               // 5120
#define HBF_OFF  (HA_BYTES + HB_BYTES)          // 25600
#define HSTAGE_BYTES (HBF_OFF + 64 * SROWB * 4) // 34816
#define HSMEM_BYTES (3 * HSTAGE_BYTES)          // 104448 -> 2 CTAs/SM

template<int EPI>
__global__ void __launch_bounds__(256, 2)
fp16w_gemm(const __half* __restrict__ X, const float* __restrict__ W,
           const float* __restrict__ bias, float* __restrict__ C,
           int M, int N, int kLen, int ldx, int ldw, int ldc,
           const float* __restrict__ cw, const float* __restrict__ cb,
           __half* __restrict__ hout) {
    extern __shared__ char smc[];
    const int tid = threadIdx.x;
    const int wid = tid >> 5, lane = tid & 31;
    const int gid = lane >> 2, tig = lane & 3;
    const int wm = wid >> 1, wn = wid & 1;       // 4 x 2 warp grid
    const int n0 = blockIdx.x * 64;
    const long k0 = (long)blockIdx.z * kLen;
    const int nIter = kLen / 32;
    const uint32_t sS = smem_u32(smc);

    float acc[4][4][4];
    #pragma unroll
    for (int i = 0; i < 4; i++)
        #pragma unroll
        for (int j = 0; j < 4; j++)
            #pragma unroll
            for (int r = 0; r < 4; r++) acc[i][j][r] = 0.f;

    auto load_stage = [&](int buf, long kk) {
        #pragma unroll
        for (int i = 0; i < 4; i++) {
            int idx = tid + i * 256;
            int row = idx >> 2, ch = idx & 3;
            uint32_t off = (uint32_t)(buf * HSTAGE_BYTES + row * (SROWH * 2) + ch * 16);
            cp_async16(sS + off, X + (long)row * ldx + kk + ch * 8, 16);
        }
        #pragma unroll
        for (int i = 0; i < 2; i++) {
            int idx = tid + i * 256;
            int row = idx >> 3, ch = idx & 7;
            int nr = n0 + row;
            const float* gb = W + (long)(nr < N ? nr : 0) * ldw + kk + ch * 4;
            uint32_t off = (uint32_t)(buf * HSTAGE_BYTES + HBF_OFF + row * (SROWB * 4) + ch * 16);
            cp_async16(sS + off, gb, nr < N ? 16 : 0);
        }
    };

    const uint32_t aBase = sS +
        (uint32_t)(((wm * 64 + ((lane >> 3) & 1) * 8 + (lane & 7)) * SROWH
                    + ((lane >> 4) & 1) * 8) * 2);
    const uint32_t bBase = sS + HA_BYTES +
        (uint32_t)(((wn * 32 + ((lane >> 4) & 1) * 8 + (lane & 7)) * SROWH
                    + ((lane >> 3) & 1) * 8) * 2);

    load_stage(0, k0); CP_COMMIT();
    load_stage(1, k0 + 32); CP_COMMIT();

    for (int it = 0; it < nIter; it++) {
        if (it + 1 < nIter) { CP_WAIT1(); } else { CP_WAIT0(); }
        __syncthreads();
        const uint32_t stgOff = (uint32_t)((it % 3) * HSTAGE_BYTES);
        if (it + 2 < nIter) { load_stage((it + 2) % 3, k0 + (long)(it + 2) * 32); CP_COMMIT(); }

        // convert this stage's B: 64 rows x 32 fp32 -> fp16 layout (8 elts/thread)
        {
            int row = tid >> 2, seg = tid & 3;
            const float* src = reinterpret_cast<const float*>(
                smc + stgOff + HBF_OFF) + row * SROWB + seg * 8;
            float4 v0 = *reinterpret_cast<const float4*>(src);
            float4 v1 = *reinterpret_cast<const float4*>(src + 4);
            __half2 h[4];
            h[0] = __floats2half2_rn(v0.x, v0.y);
            h[1] = __floats2half2_rn(v0.z, v0.w);
            h[2] = __floats2half2_rn(v1.x, v1.y);
            h[3] = __floats2half2_rn(v1.z, v1.w);
            __half* dst = reinterpret_cast<__half*>(smc + stgOff + HA_BYTES)
                          + row * SROWH + seg * 8;
            *reinterpret_cast<uint4*>(dst) = *reinterpret_cast<uint4*>(h);
        }
        __syncthreads();

        const uint32_t aS = aBase + stgOff;
        const uint32_t bS = bBase + stgOff;
        #pragma unroll
        for (int ks = 0; ks < 2; ks++) {
            uint32_t a[4][4], b[4][2];
            #pragma unroll
            for (int mi = 0; mi < 4; mi++)
                ldsm_x4(a[mi][0], a[mi][1], a[mi][2], a[mi][3],
                        aS + (uint32_t)(mi * 16 * SROWH * 2 + ks * 32));
            #pragma unroll
            for (int p = 0; p < 2; p++) {
                uint32_t r0, r1, r2, r3;
                ldsm_x4(r0, r1, r2, r3, bS + (uint32_t)(p * 16 * SROWH * 2 + ks * 32));
                b[2 * p][0] = r0;     b[2 * p][1] = r1;
                b[2 * p + 1][0] = r2; b[2 * p + 1][1] = r3;
            }
            #pragma unroll
            for (int mi = 0; mi < 4; mi++)
                #pragma unroll
                for (int ni = 0; ni < 4; ni++)
                    mma_f16(acc[mi][ni], a[mi], b[ni]);
        }
    }

    if (EPI == 3) {
        // fused causal depthwise conv (K=4) + SiLU over the CTA-local tile.
        // Ct[256][65] fp32 (pad 65 -> conflict-free token-strided reads)
        __syncthreads();                      // stage smem no longer needed
        float* Ct = reinterpret_cast<float*>(smc);
        #pragma unroll
        for (int mi = 0; mi < 4; mi++) {
            int m = wm * 64 + mi * 16 + gid;
            #pragma unroll
            for (int ni = 0; ni < 4; ni++) {
                int nc = wn * 32 + ni * 8 + tig * 2;
                Ct[m * 65 + nc]           = acc[mi][ni][0];
                Ct[m * 65 + nc + 1]       = acc[mi][ni][1];
                Ct[(m + 8) * 65 + nc]     = acc[mi][ni][2];
                Ct[(m + 8) * 65 + nc + 1] = acc[mi][ni][3];
            }
        }
        __syncthreads();
        const int dc = lane * 2, dg = n0 + dc;
        const float w00 = cw[dg * 4 + 0], w01 = cw[dg * 4 + 1],
                    w02 = cw[dg * 4 + 2], w03 = cw[dg * 4 + 3];
        const float w10 = cw[dg * 4 + 4], w11 = cw[dg * 4 + 5],
                    w12 = cw[dg * 4 + 6], w13 = cw[dg * 4 + 7];
        const float b0 = cb[dg], b1 = cb[dg + 1];
        for (int tok = wid; tok < 256; tok += 8) {
            int l = tok & 127;
            float a0 = b0, a1 = b1;
            if (l >= 3) { a0 += Ct[(tok - 3) * 65 + dc] * w00;
                          a1 += Ct[(tok - 3) * 65 + dc + 1] * w10; }
            if (l >= 2) { a0 += Ct[(tok - 2) * 65 + dc] * w01;
                          a1 += Ct[(tok - 2) * 65 + dc + 1] * w11; }
            if (l >= 1) { a0 += Ct[(tok - 1) * 65 + dc] * w02;
                          a1 += Ct[(tok - 1) * 65 + dc + 1] * w12; }
            a0 += Ct[tok * 65 + dc] * w03;
            a1 += Ct[tok * 65 + dc + 1] * w13;
            __half2 h = __floats2half2_rn(siluf(a0), siluf(a1));
            *reinterpret_cast<__half2*>(hout + (long)tok * D2I + dg) = h;
        }
        return;
    }

    #pragma unroll
    for (int mi = 0; mi < 4; mi++) {
        int m = wm * 64 + mi * 16 + gid;
        #pragma unroll
        for (int ni = 0; ni < 4; ni++) {
            int n = n0 + wn * 32 + ni * 8 + tig * 2;
            if (n >= N) continue;
            float* p0 = C + (long)m * ldc + n;
            float* p1 = C + (long)(m + 8) * ldc + n;
            float c0 = acc[mi][ni][0], c1 = acc[mi][ni][1];
            float c2 = acc[mi][ni][2], c3 = acc[mi][ni][3];
            if (EPI == 1) {
                atomicAdd(p0, c0); atomicAdd(p0 + 1, c1);
                atomicAdd(p1, c2); atomicAdd(p1 + 1, c3);
            } else if (EPI == 2) {
                float b0v = bias[n], b1v = bias[n + 1];
                *reinterpret_cast<float2*>(p0) =
                    make_float2(softplusf(c0 + b0v), softplusf(c1 + b1v));
                *reinterpret_cast<float2*>(p1) =
                    make_float2(softplusf(c2 + b0v), softplusf(c3 + b1v));
            } else {
                *reinterpret_cast<float2*>(p0) = make_float2(c0, c1);
                *reinterpret_cast<float2*>(p1) = make_float2(c2, c3);
            }
        }
    }
}

// ---------------- fp32 -> fp16 conversion (8 elts/thread) ----------------
__global__ void cvt_f2h(const float* __restrict__ src, __half* __restrict__ dst, long n) {
    long i = ((long)blockIdx.x * 256 + threadIdx.x) * 8;
    if (i >= n) return;
    float4 v0 = *reinterpret_cast<const float4*>(src + i);
    float4 v1 = *reinterpret_cast<const float4*>(src + i + 4);
    __half2 h[4];
    h[0] = __floats2half2_rn(v0.x, v0.y);
    h[1] = __floats2half2_rn(v0.z, v0.w);
    h[2] = __floats2half2_rn(v1.x, v1.y);
    h[3] = __floats2half2_rn(v1.z, v1.w);
    *reinterpret_cast<uint4*>(dst + i) = *reinterpret_cast<uint4*>(h);
}

// ---------------- LayerNorm 1 (tf32-rounded) ----------------
__global__ void ln1_kernel(const float* __restrict__ x, const float* __restrict__ g,
                           const float* __restrict__ bta, float* __restrict__ out) {
    int b  = blockIdx.x >> 7;
    int l0 = (blockIdx.x & 127) * 32;
    __shared__ float sm[128 * 33];
    int tid = threadIdx.x;
    #pragma unroll
    for (int i = 0; i < 16; i++) {
        int idx = tid + i * 256;
        int c = idx >> 5, l = idx & 31;
        sm[c * 33 + l] = x[((long)b * CH + c) * LL + l0 + l];
    }
    __syncthreads();
    int warp = tid >> 5, lane = tid & 31;
    for (int t = warp; t < 32; t += 8) {
        float v[4]; float s = 0.f, sq = 0.f;
        #pragma unroll
        for (int j = 0; j < 4; j++) {
            v[j] = sm[(lane + 32 * j) * 33 + t];
            s += v[j]; sq += v[j] * v[j];
        }
        #pragma unroll
        for (int o = 16; o; o >>= 1) {
            s  += __shfl_xor_sync(0xffffffffu, s,  o);
            sq += __shfl_xor_sync(0xffffffffu, sq, o);
        }
        float mu  = s * (1.f / 128.f);
        float var = sq * (1.f / 128.f) - mu * mu;
        float rs  = rsqrtf(var + 1e-5f);
        #pragma unroll
        for (int j = 0; j < 4; j++) {
            int c = lane + 32 * j;
            out[((long)b * LL + l0 + t) * D1M + c] = rnd_tf32((v[j] - mu) * rs * g[c] + bta[c]);
        }
    }
}

// ---------------- LayerNorm 2 (fp16 output) ----------------
__global__ void ln2_kernel(const float* __restrict__ x, const float* __restrict__ g,
                           const float* __restrict__ bta, __half* __restrict__ out) {
    long row = blockIdx.x;
    const float* xr = x + row * D2M;
    __half* orow = out + row * D2M;
    int tid = threadIdx.x;
    float v[16]; float s = 0.f, sq = 0.f;
    #pragma unroll
    for (int i = 0; i < 16; i++) {
        v[i] = xr[i * 256 + tid];
        s += v[i]; sq += v[i] * v[i];
    }
    #pragma unroll
    for (int o = 16; o; o >>= 1) {
        s  += __shfl_xor_sync(0xffffffffu, s,  o);
        sq += __shfl_xor_sync(0xffffffffu, sq, o);
    }
    __shared__ float ss[8], sqq[8];
    int lane = tid & 31, warp = tid >> 5;
    if (!lane) { ss[warp] = s; sqq[warp] = sq; }
    __syncthreads();
    s = 0.f; sq = 0.f;
    #pragma unroll
    for (int w = 0; w < 8; w++) { s += ss[w]; sq += sqq[w]; }
    float mu  = s * (1.f / 4096.f);
    float var = sq * (1.f / 4096.f) - mu * mu;
    float rs  = rsqrtf(var + 1e-5f);
    #pragma unroll
    for (int i = 0; i < 16; i++) {
        int col = i * 256 + tid;
        orow[col] = __float2half_rn((v[i] - mu) * rs * g[col] + bta[col]);
    }
}

// ---------------- fallback SGEMM (dt1: K=8) ----------------
template<int ACT, bool HASBIAS>
__global__ void sgemm_kernel(const float* __restrict__ X, const float* __restrict__ W,
                             const float* __restrict__ bias, float* __restrict__ out,
                             int M, int N, int K, int lda, int ldc) {
    constexpr int BM = 64, BN = 64, BK = 32, PAD = 4;
    __shared__ float As[BK][BM + PAD];
    __shared__ float Bs[BK][BN + PAD];
    int bm = blockIdx.y * BM, bn = blockIdx.x * BN;
    int tid = threadIdx.x;
    int tx = tid & 15, ty = tid >> 4;
    float acc[4][4] = {};
    for (int k0 = 0; k0 < K; k0 += BK) {
        #pragma unroll
        for (int i = 0; i < 2; i++) {
            int idx = tid + i * 256;
            int row = idx >> 3;
            int kc  = (idx & 7) << 2;
            int k   = k0 + kc;
            float4 va = make_float4(0.f, 0.f, 0.f, 0.f);
            float4 vb = make_float4(0.f, 0.f, 0.f, 0.f);
            if (k < K) {
                int m = bm + row;
                if (m < M) va = *reinterpret_cast<const float4*>(X + (long)m * lda + k);
                int n = bn + row;
                if (n < N) vb = *reinterpret_cast<const float4*>(W + (long)n * K + k);
            }
            As[kc][row] = va.x; As[kc + 1][row] = va.y; As[kc + 2][row] = va.z; As[kc + 3][row] = va.w;
            Bs[kc][row] = vb.x; Bs[kc + 1][row] = vb.y; Bs[kc + 2][row] = vb.z; Bs[kc + 3][row] = vb.w;
        }
        __syncthreads();
        #pragma unroll
        for (int kk = 0; kk < BK; kk++) {
            float4 a = *reinterpret_cast<const float4*>(&As[kk][ty << 2]);
            float4 b = *reinterpret_cast<const float4*>(&Bs[kk][tx << 2]);
            float av[4] = {a.x, a.y, a.z, a.w};
            float bv[4] = {b.x, b.y, b.z, b.w};
            #pragma unroll
            for (int i = 0; i < 4; i++)
                #pragma unroll
                for (int j = 0; j < 4; j++)
                    acc[i][j] += av[i] * bv[j];
        }
        __syncthreads();
    }
    #pragma unroll
    for (int i = 0; i < 4; i++) {
        int m = bm + (ty << 2) + i;
        if (m >= M) continue;
        #pragma unroll
        for (int j = 0; j < 4; j++) {
            int n = bn + (tx << 2) + j;
            if (n >= N) continue;
            float v = acc[i][j];
            if (HASBIAS) v += bias[n];
            if (ACT == 1) v = softplusf(v);
            out[(long)m * ldc + n] = v;
        }
    }
}

// ---------------- causal depthwise conv (K=4) + SiLU (path-1, fp32/tf32) ----------------
__global__ void conv_silu_kernel(const float* __restrict__ xz, const float* __restrict__ w,
                                 const float* __restrict__ bias, float* __restrict__ out,
                                 int Ltok, int dinner) {
    long tid = (long)blockIdx.x * 256 + threadIdx.x;
    long total = (long)BATCH * Ltok * (dinner / 4);
    if (tid >= total) return;
    int d4 = (int)(tid % (dinner / 4)) * 4;
    long t = tid / (dinner / 4);
    int l = (int)(t % Ltok);
    int b = (int)(t / Ltok);
    int rowstride = 2 * dinner;
    const float* base = xz + ((long)b * Ltok + l) * rowstride + d4;
    float4 bv = *reinterpret_cast<const float4*>(bias + d4);
    float acc0 = bv.x, acc1 = bv.y, acc2 = bv.z, acc3 = bv.w;
    #pragma unroll
    for (int k = 0; k < 4; k++) {
        int ll = l - 3 + k;
        if (ll >= 0) {
            float4 xv = *reinterpret_cast<const float4*>(base + (long)(ll - l) * rowstride);
            acc0 += xv.x * w[(d4 + 0) * 4 + k];
            acc1 += xv.y * w[(d4 + 1) * 4 + k];
            acc2 += xv.z * w[(d4 + 2) * 4 + k];
            acc3 += xv.w * w[(d4 + 3) * 4 + k];
        }
    }
    float4 ov;
    ov.x = rnd_tf32(siluf(acc0)); ov.y = rnd_tf32(siluf(acc1));
    ov.z = rnd_tf32(siluf(acc2)); ov.w = rnd_tf32(siluf(acc3));
    *reinterpret_cast<float4*>(out + ((long)b * Ltok + l) * dinner + d4) = ov;
}

// ---------------- path-1 scan ----------------
__global__ void scan1_partial(const float* __restrict__ delta, const float* __restrict__ xc,
                              const float* __restrict__ dbl, const float* __restrict__ Alog) {
    int d = threadIdx.x;
    int chunk = blockIdx.x & (NCH - 1);
    int b = blockIdx.x >> 5;
    float A[NS], h[NS], P[NS];
    #pragma unroll
    for (int s = 0; s < NS; s++) { A[s] = -__expf(Alog[d * NS + s]); h[s] = 0.f; P[s] = 1.f; }
    int l0 = chunk * CLEN;
    for (int i = 0; i < CLEN; i++) {
        long t = (long)b * LL + l0 + i;
        float dl = delta[t * D1I + d];
        float xv = xc[t * D1I + d];
        const float* bl = dbl + t * DBL1 + DT1R;
        float dx = dl * xv;
        #pragma unroll
        for (int s = 0; s < NS; s++) {
            float dA = __expf(dl * A[s]);
            h[s] = dA * h[s] + dx * bl[s];
            P[s] *= dA;
        }
    }
    long o = (((long)b * D1I + d) * NCH + chunk) * NS;
    #pragma unroll
    for (int s = 0; s < NS; s++) { g_ckP[o + s] = P[s]; g_ckH[o + s] = h[s]; }
}

__global__ void scan1_carry() {
    int idx = blockIdx.x * 256 + threadIdx.x;
    if (idx >= BATCH * D1I) return;
    long base = (long)idx * NCH * NS;
    float h[NS];
    #pragma unroll
    for (int s = 0; s < NS; s++) h[s] = 0.f;
    for (int c = 0; c < NCH; c++) {
        long o = base + (long)c * NS;
        #pragma unroll
        for (int s = 0; s < NS; s++) {
            g_hin[o + s] = h[s];
            h[s] = g_ckP[o + s] * h[s] + g_ckH[o + s];
        }
    }
}

__global__ void scan1_final(const float* __restrict__ delta, const float* __restrict__ xc,
                            const float* __restrict__ dbl, const float* __restrict__ Alog,
                            const float* __restrict__ Dp, const float* __restrict__ xz,
                            float* __restrict__ y) {
    int d = threadIdx.x;
    int chunk = blockIdx.x & (NCH - 1);
    int b = blockIdx.x >> 5;
    float A[NS], h[NS];
    long hb = (((long)b * D1I + d) * NCH + chunk) * NS;
    #pragma unroll
    for (int s = 0; s < NS; s++) { A[s] = -__expf(Alog[d * NS + s]); h[s] = g_hin[hb + s]; }
    float Dv = Dp[d];
    int l0 = chunk * CLEN;
    for (int i = 0; i < CLEN; i++) {
        long t = (long)b * LL + l0 + i;
        float dl = delta[t * D1I + d];
        float xv = xc[t * D1I + d];
        const float* bl = dbl + t * DBL1 + DT1R;
        float dx = dl * xv;
        float acc = 0.f;
        #pragma unroll
        for (int s = 0; s < NS; s++) {
            float dA = __expf(dl * A[s]);
            h[s] = dA * h[s] + dx * bl[s];
            acc += h[s] * bl[NS + s];
        }
        float z = xz[t * (2 * D1I) + D1I + d];
        y[t * D1I + d] = rnd_tf32((acc + xv * Dv) * siluf(z));
    }
}

// ---------------- path-2 scan (xc fp16 in, y fp16 out) ----------------
__global__ void scan2_kernel(const float* __restrict__ delta, const __half* __restrict__ xc,
                             const float* __restrict__ dbl, const float* __restrict__ Alog,
                             const float* __restrict__ Dp, const float* __restrict__ xz,
                             __half* __restrict__ y) {
    int d = (blockIdx.x & 31) * 256 + threadIdx.x;
    int b = blockIdx.x >> 5;
    float A[NS], h[NS];
    #pragma unroll
    for (int s = 0; s < NS; s++) { A[s] = -__expf(Alog[d * NS + s]); h[s] = 0.f; }
    float Dv = Dp[d];
    for (int l = 0; l < CH; l++) {
        long t = (long)b * CH + l;
        float dl = delta[t * D2I + d];
        float xv = __half2float(xc[t * D2I + d]);
        const float* bl = dbl + t * DBL2 + DT2R;
        float dx = dl * xv;
        float acc = 0.f;
        #pragma unroll
        for (int s = 0; s < NS; s++) {
            float dA = __expf(dl * A[s]);
            h[s] = dA * h[s] + dx * bl[s];
            acc += h[s] * bl[NS + s];
        }
        float z = xz[t * (2 * D2I) + D2I + d];
        y[t * D2I + d] = __float2half_rn((acc + xv * Dv) * siluf(z));
    }
}

// ---------------- combine ----------------
__global__ void combine_kernel(const float* __restrict__ x, float* __restrict__ out) {
    long i = (long)blockIdx.x * 256 + threadIdx.x;
    if (i >= (long)BATCH * CH * LL) return;
    int l = (int)(i % LL);
    long t = i / LL;
    int c = (int)(t % CH);
    int b = (int)(t / CH);
    out[i] = x[i] + g_out2[i] + g_out1[((long)b * LL + l) * D1M + c];
}

// ---------------- launch ----------------
extern "C" void kernel_launch(void* const* d_in, const int* in_sizes, int n_in,
                              void* d_out, int out_size) {
    const float* x        = (const float*)d_in[0];
    const float* ln1_g    = (const float*)d_in[1];
    const float* ln1_b    = (const float*)d_in[2];
    const float* ln2_g    = (const float*)d_in[3];
    const float* ln2_b    = (const float*)d_in[4];
    const float* m1_in_w  = (const float*)d_in[5];
    const float* m1_cw    = (const float*)d_in[6];
    const float* m1_cb    = (const float*)d_in[7];
    const float* m1_xp_w  = (const float*)d_in[8];
    const float* m1_dt_w  = (const float*)d_in[9];
    const float* m1_dt_b  = (const float*)d_in[10];
    const float* m1_Alog  = (const float*)d_in[11];
    const float* m1_D     = (const float*)d_in[12];
    const float* m1_out_w = (const float*)d_in[13];
    const float* m2_in_w  = (const float*)d_in[14];
    const float* m2_cw    = (const float*)d_in[15];
    const float* m2_cb    = (const float*)d_in[16];
    const float* m2_xp_w  = (const float*)d_in[17];
    const float* m2_dt_w  = (const float*)d_in[18];
    const float* m2_dt_b  = (const float*)d_in[19];
    const float* m2_Alog  = (const float*)d_in[20];
    const float* m2_D     = (const float*)d_in[21];
    const float* m2_out_w = (const float*)d_in[22];
    float* out = (float*)d_out;

    float *pxn1, *pxz1, *pxc1, *pdbl1, *pdelta1, *py1, *pout1;
    float *pxz2, *pdbl2, *pdelta2, *pout2;
    __half *pxn2h, *pxc2h, *py2h, *pdbl2h;
    cudaGetSymbolAddress((void**)&pxn1, g_xn1);
    cudaGetSymbolAddress((void**)&pxz1, g_xz1);
    cudaGetSymbolAddress((void**)&pxc1, g_xc1);
    cudaGetSymbolAddress((void**)&pdbl1, g_dbl1);
    cudaGetSymbolAddress((void**)&pdelta1, g_delta1);
    cudaGetSymbolAddress((void**)&py1, g_y1);
    cudaGetSymbolAddress((void**)&pout1, g_out1);
    cudaGetSymbolAddress((void**)&pxz2, g_xz2);
    cudaGetSymbolAddress((void**)&pdbl2, g_dbl2);
    cudaGetSymbolAddress((void**)&pdelta2, g_delta2);
    cudaGetSymbolAddress((void**)&pout2, g_out2);
    cudaGetSymbolAddress((void**)&pxn2h, g_xn2h);
    cudaGetSymbolAddress((void**)&pxc2h, g_xc2h);
    cudaGetSymbolAddress((void**)&py2h, g_y2h);
    cudaGetSymbolAddress((void**)&pdbl2h, g_dbl2h);

    cudaFuncSetAttribute(tf32_gemm<0>, cudaFuncAttributeMaxDynamicSharedMemorySize, GSMEM_BYTES);
    cudaFuncSetAttribute(tf32_gemm<1>, cudaFuncAttributeMaxDynamicSharedMemorySize, GSMEM_BYTES);
    cudaFuncSetAttribute(fp16w_gemm<0>, cudaFuncAttributeMaxDynamicSharedMemorySize, HSMEM_BYTES);
    cudaFuncSetAttribute(fp16w_gemm<1>, cudaFuncAttributeMaxDynamicSharedMemorySize, HSMEM_BYTES);
    cudaFuncSetAttribute(fp16w_gemm<2>, cudaFuncAttributeMaxDynamicSharedMemorySize, HSMEM_BYTES);
    cudaFuncSetAttribute(fp16w_gemm<3>, cudaFuncAttributeMaxDynamicSharedMemorySize, HSMEM_BYTES);

    static cudaStream_t s2 = nullptr, s3 = nullptr;
    static cudaEvent_t evFork = nullptr, evFork3 = nullptr, evJoin = nullptr,
                       evJoinB = nullptr, evLn2 = nullptr;
    if (!s2) {
        cudaStreamCreateWithFlags(&s2, cudaStreamNonBlocking);
        cudaStreamCreateWithFlags(&s3, cudaStreamNonBlocking);
        cudaEventCreateWithFlags(&evFork, cudaEventDisableTiming);
        cudaEventCreateWithFlags(&evFork3, cudaEventDisableTiming);
        cudaEventCreateWithFlags(&evJoin, cudaEventDisableTiming);
        cudaEventCreateWithFlags(&evJoinB, cudaEventDisableTiming);
        cudaEventCreateWithFlags(&evLn2, cudaEventDisableTiming);
    }

    const int T = 256;
    const long IN_HALF = (long)D2I * D2M;
    // fork at t=0
    cudaEventRecord(evFork, 0);
    cudaStreamWaitEvent(s2, evFork, 0);
    cudaEventRecord(evFork3, 0);
    cudaStreamWaitEvent(s3, evFork3, 0);

    // ---- main: ln2, then in2a with FUSED conv+SiLU -> xc2h ----
    cudaMemsetAsync(pdbl2, 0, sizeof(float) * BATCH * CH * DBL2);
    cudaMemsetAsync(pout2, 0, sizeof(float) * BATCH * CH * D2M);
    ln2_kernel<<<BATCH * CH, T>>>(x, ln2_g, ln2_b, pxn2h);
    cudaEventRecord(evLn2, 0);
    fp16w_gemm<3><<<dim3(128, 1, 1), 256, HSMEM_BYTES>>>(
        pxn2h, m2_in_w, nullptr, pxz2, BATCH * CH, D2I, D2M, D2M, D2M, 2 * D2I,
        m2_cw, m2_cb, pxc2h);

    // ---- s3: in2b (z half) ----
    cudaStreamWaitEvent(s3, evLn2, 0);
    fp16w_gemm<0><<<dim3(128, 1, 1), 256, HSMEM_BYTES, s3>>>(
        pxn2h, m2_in_w + IN_HALF, nullptr, pxz2 + D2I,
        BATCH * CH, D2I, D2M, D2M, D2M, 2 * D2I, nullptr, nullptr, nullptr);
    cudaEventRecord(evJoinB, s3);

    // ---- s2: full path 1 ----
    cudaMemsetAsync(pout1, 0, sizeof(float) * BATCH * LL * D1M, s2);
    ln1_kernel<<<BATCH * (LL / 32), T, 0, s2>>>(x, ln1_g, ln1_b, pxn1);
    tf32_gemm<0><<<dim3(4, 64, 1), 256, GSMEM_BYTES, s2>>>(
        pxn1, m1_in_w, nullptr, pxz1, BATCH * LL, 2 * D1I, D1M, D1M, D1M, 2 * D1I);
    conv_silu_kernel<<<(BATCH * LL * D1I / 4 + T - 1) / T, T, 0, s2>>>(
        pxz1, m1_cw, m1_cb, pxc1, LL, D1I);
    tf32_gemm<0><<<dim3(1, 64, 1), 256, GSMEM_BYTES, s2>>>(
        pxc1, m1_xp_w, nullptr, pdbl1, BATCH * LL, DBL1, D1I, D1I, D1I, DBL1);
    sgemm_kernel<1, true><<<dim3((D1I + 63) / 64, (BATCH * LL) / 64), T, 0, s2>>>(
        pdbl1, m1_dt_w, m1_dt_b, pdelta1, BATCH * LL, D1I, DT1R, DBL1, D1I);
    scan1_partial<<<BATCH * NCH, D1I, 0, s2>>>(pdelta1, pxc1, pdbl1, m1_Alog);
    scan1_carry<<<(BATCH * D1I + T - 1) / T, T, 0, s2>>>();
    scan1_final<<<BATCH * NCH, D1I, 0, s2>>>(pdelta1, pxc1, pdbl1, m1_Alog, m1_D, pxz1, py1);
    tf32_gemm<1><<<dim3(1, 64, 2), 256, GSMEM_BYTES, s2>>>(
        py1, m1_out_w, nullptr, pout1, BATCH * LL, D1M, D1I / 2, D1I, D1I, D1M);
    cudaEventRecord(evJoin, s2);

    // ---- main: dependent chain (conv already fused) ----
    // xp2: dbl2[256, 272] split-K=32 atomic (160 CTAs)
    fp16w_gemm<1><<<dim3(5, 1, 32), 256, HSMEM_BYTES>>>(
        pxc2h, m2_xp_w, nullptr, pdbl2, BATCH * CH, DBL2, D2I / 32, D2I, D2I, DBL2,
        nullptr, nullptr, nullptr);
    cvt_f2h<<<(int)(((long)BATCH * CH * DBL2) / 2048), T>>>(pdbl2, pdbl2h, (long)BATCH * CH * DBL2);
    // dt2: delta2 = softplus(dbl2h[:, :256] @ dt_w^T + b) (128 CTAs)
    fp16w_gemm<2><<<dim3(128, 1, 1), 256, HSMEM_BYTES>>>(
        pdbl2h, m2_dt_w, m2_dt_b, pdelta2, BATCH * CH, D2I, DT2R, DBL2, DT2R, D2I,
        nullptr, nullptr, nullptr);
    cudaStreamWaitEvent(0, evJoinB, 0);
    scan2_kernel<<<BATCH * (D2I / 256), T>>>(pdelta2, pxc2h, pdbl2, m2_Alog, m2_D, pxz2, py2h);
    // out2: split-K=4 atomic (256 CTAs)
    fp16w_gemm<1><<<dim3(64, 1, 4), 256, HSMEM_BYTES>>>(
        py2h, m2_out_w, nullptr, pout2, BATCH * CH, D2M, D2I / 4, D2I, D2I, D2M,
        nullptr, nullptr, nullptr);

    cudaStreamWaitEvent(0, evJoin, 0);
    combine_kernel<<<(BATCH * CH * LL + T - 1) / T, T>>>(x, out);
}

// round 16
// speedup vs baseline: 1.9507x; 1.0463x over previous
#include <cuda_runtime.h>
#include <cuda_fp16.h>
#include <cstdint>
#include <math.h>

// ---------------- problem constants ----------------
#define BATCH 2
#define CH    128
#define LL    4096
#define NS    8

#define D1M  128
#define D1I  256
#define DT1R 8
#define DBL1 24
#define D2M  4096
#define D2I  8192
#define DT2R 256
#define DBL2 272      // dt_rank(256) + 2*8

#define NCH  32
#define CLEN 128

// ---------------- scratch ----------------
__device__ __align__(16) float g_xn1[BATCH*LL*D1M];
__device__ __align__(16) float g_xz1[BATCH*LL*2*D1I];
__device__ __align__(16) float g_xc1[BATCH*LL*D1I];
__device__ __align__(16) float g_dbl1[BATCH*LL*DBL1];
__device__ __align__(16) float g_delta1[BATCH*LL*D1I];
__device__ __align__(16) float g_y1[BATCH*LL*D1I];
__device__ __align__(16) float g_out1[BATCH*LL*D1M];
__device__ __align__(16) float g_ckP[BATCH*D1I*NCH*NS];
__device__ __align__(16) float g_ckH[BATCH*D1I*NCH*NS];
__device__ __align__(16) float g_hin[BATCH*D1I*NCH*NS];

__device__ __align__(16) float g_xz2[BATCH*CH*2*D2I];   // only z half written now
__device__ __align__(16) float g_dbl2[BATCH*CH*DBL2];
__device__ __align__(16) float g_delta2[BATCH*CH*D2I];
__device__ __align__(16) float g_out2[BATCH*CH*D2M];

// fp16 scratch (activations only — weights stay fp32 in gmem)
__device__ __align__(16) __half g_xn2h[BATCH*CH*D2M];
__device__ __align__(16) __half g_xc2h[BATCH*CH*D2I];
__device__ __align__(16) __half g_y2h[BATCH*CH*D2I];
__device__ __align__(16) __half g_dbl2h[BATCH*CH*DBL2];

// ---------------- helpers ----------------
__device__ __forceinline__ uint32_t smem_u32(const void* p) {
    uint32_t a;
    asm("{ .reg .u64 t; cvta.to.shared.u64 t, %1; cvt.u32.u64 %0, t; }" : "=r"(a) : "l"(p));
    return a;
}
__device__ __forceinline__ void cp_async16(uint32_t dst, const void* src, int sz) {
    asm volatile("cp.async.cg.shared.global [%0], [%1], 16, %2;"
                 :: "r"(dst), "l"(src), "r"(sz) : "memory");
}
#define CP_COMMIT() asm volatile("cp.async.commit_group;" ::: "memory")
#define CP_WAIT1()  asm volatile("cp.async.wait_group 1;" ::: "memory")
#define CP_WAIT0()  asm volatile("cp.async.wait_group 0;" ::: "memory")

__device__ __forceinline__ uint32_t f2tf32(float f) {
    uint32_t r;
    asm("cvt.rna.tf32.f32 %0, %1;" : "=r"(r) : "f"(f));
    return r;
}
__device__ __forceinline__ float rnd_tf32(float v) { return __uint_as_float(f2tf32(v)); }

__device__ __forceinline__ void mma_tf32(float* d, const uint32_t* a, const uint32_t* b) {
    asm volatile(
        "mma.sync.aligned.m16n8k8.row.col.f32.tf32.tf32.f32 "
        "{%0,%1,%2,%3}, {%4,%5,%6,%7}, {%8,%9}, {%0,%1,%2,%3};"
        : "+f"(d[0]), "+f"(d[1]), "+f"(d[2]), "+f"(d[3])
        : "r"(a[0]), "r"(a[1]), "r"(a[2]), "r"(a[3]), "r"(b[0]), "r"(b[1]));
}
__device__ __forceinline__ void mma_f16(float* d, const uint32_t* a, const uint32_t* b) {
    asm volatile(
        "mma.sync.aligned.m16n8k16.row.col.f32.f16.f16.f32 "
        "{%0,%1,%2,%3}, {%4,%5,%6,%7}, {%8,%9}, {%0,%1,%2,%3};"
        : "+f"(d[0]), "+f"(d[1]), "+f"(d[2]), "+f"(d[3])
        : "r"(a[0]), "r"(a[1]), "r"(a[2]), "r"(a[3]), "r"(b[0]), "r"(b[1]));
}
__device__ __forceinline__ void ldsm_x4(uint32_t& r0, uint32_t& r1, uint32_t& r2, uint32_t& r3,
                                        uint32_t addr) {
    asm volatile("ldmatrix.sync.aligned.m8n8.x4.shared.b16 {%0,%1,%2,%3}, [%4];"
                 : "=r"(r0), "=r"(r1), "=r"(r2), "=r"(r3) : "r"(addr));
}

__device__ __forceinline__ float siluf(float v) { return v / (1.f + __expf(-v)); }
__device__ __forceinline__ float softplusf(float v) { return (v > 20.f) ? v : log1pf(__expf(v)); }

// ======================================================================
// tf32 mma.sync GEMM — path-1 GEMMs (unchanged)
// ======================================================================
#define SROW 36
#define GROWS 256
#define GSTG (GROWS * SROW)
#define GSMEM_BYTES (3 * GSTG * 4)      // 108 KB -> 2 CTAs/SM

template<int EPI>
__global__ void __launch_bounds__(256, 2)
tf32_gemm(const float* __restrict__ X, const float* __restrict__ W,
          const float* __restrict__ bias, float* __restrict__ C,
          int M, int N, int kLen, int ldx, int ldw, int ldc) {
    extern __shared__ float sm[];
    const int tid = threadIdx.x;
    const int wid = tid >> 5, lane = tid & 31;
    const int gid = lane >> 2, tig = lane & 3;
    const int wm = wid >> 2, wn = wid & 3;
    const int m0 = blockIdx.y * 128, n0 = blockIdx.x * 128;
    const long k0 = (long)blockIdx.z * kLen;
    const int nIter = kLen / 32;
    const uint32_t sS = smem_u32(sm);

    float acc[4][4][4];
    #pragma unroll
    for (int i = 0; i < 4; i++)
        #pragma unroll
        for (int j = 0; j < 4; j++)
            #pragma unroll
            for (int r = 0; r < 4; r++) acc[i][j][r] = 0.f;

    auto load_stage = [&](int buf, long kk) {
        #pragma unroll
        for (int i = 0; i < 8; i++) {
            int idx = tid + i * 256;
            int row = idx >> 3, ch = idx & 7;
            uint32_t off = (uint32_t)((buf * GROWS + row) * SROW + ch * 4) * 4u;
            if (row < 128) {
                cp_async16(sS + off, X + (long)(m0 + row) * ldx + kk + ch * 4, 16);
            } else {
                int nr = n0 + row - 128;
                const float* gb = W + (long)(nr < N ? nr : 0) * ldw + kk + ch * 4;
                cp_async16(sS + off, gb, nr < N ? 16 : 0);
            }
        }
    };

    const uint32_t aBase = sS +
        (uint32_t)(((wm * 64 + ((lane >> 3) & 1) * 8 + (lane & 7)) * SROW
                    + ((lane >> 4) & 1) * 4) * 4);
    const uint32_t bBase = sS +
        (uint32_t)(((128 + wn * 32 + ((lane >> 4) & 1) * 8 + (lane & 7)) * SROW
                    + ((lane >> 3) & 1) * 4) * 4);

    load_stage(0, k0); CP_COMMIT();
    load_stage(1, k0 + 32); CP_COMMIT();

    for (int it = 0; it < nIter; it++) {
        if (it + 1 < nIter) { CP_WAIT1(); } else { CP_WAIT0(); }
        __syncthreads();
        const uint32_t stgOff = (uint32_t)((it % 3) * GSTG * 4);
        const uint32_t aS = aBase + stgOff;
        const uint32_t bS = bBase + stgOff;
        #pragma unroll
        for (int ks = 0; ks < 4; ks++) {
            uint32_t a[4][4], b[4][2];
            #pragma unroll
            for (int mi = 0; mi < 4; mi++)
                ldsm_x4(a[mi][0], a[mi][1], a[mi][2], a[mi][3],
                        aS + (uint32_t)(mi * 16 * SROW * 4 + ks * 32));
            #pragma unroll
            for (int p = 0; p < 2; p++) {
                uint32_t r0, r1, r2, r3;
                ldsm_x4(r0, r1, r2, r3, bS + (uint32_t)(p * 16 * SROW * 4 + ks * 32));
                b[2 * p][0]     = f2tf32(__uint_as_float(r0));
                b[2 * p][1]     = f2tf32(__uint_as_float(r1));
                b[2 * p + 1][0] = f2tf32(__uint_as_float(r2));
                b[2 * p + 1][1] = f2tf32(__uint_as_float(r3));
            }
            #pragma unroll
            for (int mi = 0; mi < 4; mi++)
                #pragma unroll
                for (int ni = 0; ni < 4; ni++)
                    mma_tf32(acc[mi][ni], a[mi], b[ni]);
        }
        if (it + 2 < nIter) { load_stage((it + 2) % 3, k0 + (long)(it + 2) * 32); CP_COMMIT(); }
    }

    #pragma unroll
    for (int mi = 0; mi < 4; mi++) {
        int m = m0 + wm * 64 + mi * 16 + gid;
        #pragma unroll
        for (int ni = 0; ni < 4; ni++) {
            int n = n0 + wn * 32 + ni * 8 + tig * 2;
            if (n >= N) continue;
            float* p0 = C + (long)m * ldc + n;
            float* p1 = C + (long)(m + 8) * ldc + n;
            float c0 = acc[mi][ni][0], c1 = acc[mi][ni][1];
            float c2 = acc[mi][ni][2], c3 = acc[mi][ni][3];
            if (EPI == 1) {
                atomicAdd(p0, c0); atomicAdd(p0 + 1, c1);
                atomicAdd(p1, c2); atomicAdd(p1 + 1, c3);
            } else if (EPI == 2) {
                float b0v = bias[n], b1v = bias[n + 1];
                *reinterpret_cast<float2*>(p0) =
                    make_float2(softplusf(c0 + b0v), softplusf(c1 + b1v));
                *reinterpret_cast<float2*>(p1) =
                    make_float2(softplusf(c2 + b0v), softplusf(c3 + b1v));
            } else {
                *reinterpret_cast<float2*>(p0) = make_float2(c0, c1);
                *reinterpret_cast<float2*>(p1) = make_float2(c2, c3);
            }
        }
    }
}

// ======================================================================
// fp16 mma.sync GEMM, fp32 WEIGHTS via REGISTERS (LDG -> cvt -> STS fp16).
// BM=256 (weights read once), BN=64; warps 4(m) x 2(n), warp tile 64x32.
// ONE __syncthreads per K-iter. A: cp.async fp16 3-stage.
// EPI: 0 = store, 1 = atomicAdd, 2 = softplus(v+bias[n]) store,
//      3 = fused causal conv(K=4)+SiLU -> fp16 hout  (in2a; grid.z==1)
// ======================================================================
#define SROWH 40
#define HA_BYTES (256 * SROWH * 2)              // 20480
#define HSTAGE_BYTES (HA_BYTES + 64 * SROWH * 2)// 25600
#define HSMEM_BYTES (3 * HSTAGE_BYTES)          // 76800 -> 2 CTAs/SM

template<int EPI>
__global__ void __launch_bounds__(256, 2)
fp16w_gemm(const __half* __restrict__ X, const float* __restrict__ W,
           const float* __restrict__ bias, float* __restrict__ C,
           int M, int N, int kLen, int ldx, int ldw, int ldc,
           const float* __restrict__ cw, const float* __restrict__ cb,
           __half* __restrict__ hout) {
    extern __shared__ char smc[];
    const int tid = threadIdx.x;
    const int wid = tid >> 5, lane = tid & 31;
    const int gid = lane >> 2, tig = lane & 3;
    const int wm = wid >> 1, wn = wid & 1;       // 4 x 2 warp grid
    const int n0 = blockIdx.x * 64;
    const long k0 = (long)blockIdx.z * kLen;
    const int nIter = kLen / 32;
    const uint32_t sS = smem_u32(smc);

    float acc[4][4][4];
    #pragma unroll
    for (int i = 0; i < 4; i++)
        #pragma unroll
        for (int j = 0; j < 4; j++)
            #pragma unroll
            for (int r = 0; r < 4; r++) acc[i][j][r] = 0.f;

    // B weights: one thread handles 8 consecutive fp32 of one row per stage
    const int brow = tid >> 2, bseg = tid & 3;
    const int bnr = n0 + brow;
    const float* bsrc = W + (long)(bnr < N ? bnr : 0) * ldw + bseg * 8;
    __half* bdstBase = reinterpret_cast<__half*>(smc) + brow * SROWH + bseg * 8;

    auto ldgB = [&](long kk, float4& v0, float4& v1) {
        v0 = *reinterpret_cast<const float4*>(bsrc + kk);
        v1 = *reinterpret_cast<const float4*>(bsrc + kk + 4);
    };
    auto stsB = [&](int buf, const float4& v0, const float4& v1) {
        __half2 h[4];
        h[0] = __floats2half2_rn(v0.x, v0.y);
        h[1] = __floats2half2_rn(v0.z, v0.w);
        h[2] = __floats2half2_rn(v1.x, v1.y);
        h[3] = __floats2half2_rn(v1.z, v1.w);
        *reinterpret_cast<uint4*>(
            reinterpret_cast<char*>(bdstBase) + buf * HSTAGE_BYTES + HA_BYTES)
            = *reinterpret_cast<uint4*>(h);
    };
    auto loadA = [&](int buf, long kk) {
        #pragma unroll
        for (int i = 0; i < 4; i++) {
            int idx = tid + i * 256;
            int row = idx >> 2, ch = idx & 3;
            uint32_t off = (uint32_t)(buf * HSTAGE_BYTES + row * (SROWH * 2) + ch * 16);
            cp_async16(sS + off, X + (long)row * ldx + kk + ch * 8, 16);
        }
    };

    const uint32_t aBase = sS +
        (uint32_t)(((wm * 64 + ((lane >> 3) & 1) * 8 + (lane & 7)) * SROWH
                    + ((lane >> 4) & 1) * 8) * 2);
    const uint32_t bBase = sS + HA_BYTES +
        (uint32_t)(((wn * 32 + ((lane >> 4) & 1) * 8 + (lane & 7)) * SROWH
                    + ((lane >> 3) & 1) * 8) * 2);

    // prologue: B0, B1 straight to smem; B2 held in registers
    float4 b0r, b1r;
    ldgB(k0, b0r, b1r); stsB(0, b0r, b1r);
    ldgB(k0 + 32, b0r, b1r); stsB(1, b0r, b1r);
    if (nIter > 2) ldgB(k0 + 64, b0r, b1r);
    loadA(0, k0); CP_COMMIT();
    loadA(1, k0 + 32); CP_COMMIT();

    for (int it = 0; it < nIter; it++) {
        if (it + 1 < nIter) { CP_WAIT1(); } else { CP_WAIT0(); }
        __syncthreads();
        if (it + 2 < nIter) {
            loadA((it + 2) % 3, k0 + (long)(it + 2) * 32); CP_COMMIT();
            stsB((it + 2) % 3, b0r, b1r);
        }
        if (it + 3 < nIter) ldgB(k0 + (long)(it + 3) * 32, b0r, b1r);

        const uint32_t stgOff = (uint32_t)((it % 3) * HSTAGE_BYTES);
        const uint32_t aS = aBase + stgOff;
        const uint32_t bS = bBase + stgOff;
        #pragma unroll
        for (int ks = 0; ks < 2; ks++) {
            uint32_t a[4][4], b[4][2];
            #pragma unroll
            for (int mi = 0; mi < 4; mi++)
                ldsm_x4(a[mi][0], a[mi][1], a[mi][2], a[mi][3],
                        aS + (uint32_t)(mi * 16 * SROWH * 2 + ks * 32));
            #pragma unroll
            for (int p = 0; p < 2; p++) {
                uint32_t r0, r1, r2, r3;
                ldsm_x4(r0, r1, r2, r3, bS + (uint32_t)(p * 16 * SROWH * 2 + ks * 32));
                b[2 * p][0] = r0;     b[2 * p][1] = r1;
                b[2 * p + 1][0] = r2; b[2 * p + 1][1] = r3;
            }
            #pragma unroll
            for (int mi = 0; mi < 4; mi++)
                #pragma unroll
                for (int ni = 0; ni < 4; ni++)
                    mma_f16(acc[mi][ni], a[mi], b[ni]);
        }
    }

    if (EPI == 3) {
        // fused causal depthwise conv (K=4) + SiLU over the CTA-local tile.
        __syncthreads();                      // stage smem no longer needed
        float* Ct = reinterpret_cast<float*>(smc);   // [256][65] = 66560B <= 76800
        #pragma unroll
        for (int mi = 0; mi < 4; mi++) {
            int m = wm * 64 + mi * 16 + gid;
            #pragma unroll
            for (int ni = 0; ni < 4; ni++) {
                int nc = wn * 32 + ni * 8 + tig * 2;
                Ct[m * 65 + nc]           = acc[mi][ni][0];
                Ct[m * 65 + nc + 1]       = acc[mi][ni][1];
                Ct[(m + 8) * 65 + nc]     = acc[mi][ni][2];
                Ct[(m + 8) * 65 + nc + 1] = acc[mi][ni][3];
            }
        }
        __syncthreads();
        const int dc = lane * 2, dg = n0 + dc;
        const float w00 = cw[dg * 4 + 0], w01 = cw[dg * 4 + 1],
                    w02 = cw[dg * 4 + 2], w03 = cw[dg * 4 + 3];
        const float w10 = cw[dg * 4 + 4], w11 = cw[dg * 4 + 5],
                    w12 = cw[dg * 4 + 6], w13 = cw[dg * 4 + 7];
        const float b0 = cb[dg], b1 = cb[dg + 1];
        for (int tok = wid; tok < 256; tok += 8) {
            int l = tok & 127;
            float a0 = b0, a1 = b1;
            if (l >= 3) { a0 += Ct[(tok - 3) * 65 + dc] * w00;
                          a1 += Ct[(tok - 3) * 65 + dc + 1] * w10; }
            if (l >= 2) { a0 += Ct[(tok - 2) * 65 + dc] * w01;
                          a1 += Ct[(tok - 2) * 65 + dc + 1] * w11; }
            if (l >= 1) { a0 += Ct[(tok - 1) * 65 + dc] * w02;
                          a1 += Ct[(tok - 1) * 65 + dc + 1] * w12; }
            a0 += Ct[tok * 65 + dc] * w03;
            a1 += Ct[tok * 65 + dc + 1] * w13;
            __half2 h = __floats2half2_rn(siluf(a0), siluf(a1));
            *reinterpret_cast<__half2*>(hout + (long)tok * D2I + dg) = h;
        }
        return;
    }

    #pragma unroll
    for (int mi = 0; mi < 4; mi++) {
        int m = wm * 64 + mi * 16 + gid;
        #pragma unroll
        for (int ni = 0; ni < 4; ni++) {
            int n = n0 + wn * 32 + ni * 8 + tig * 2;
            if (n >= N) continue;
            float* p0 = C + (long)m * ldc + n;
            float* p1 = C + (long)(m + 8) * ldc + n;
            float c0 = acc[mi][ni][0], c1 = acc[mi][ni][1];
            float c2 = acc[mi][ni][2], c3 = acc[mi][ni][3];
            if (EPI == 1) {
                atomicAdd(p0, c0); atomicAdd(p0 + 1, c1);
                atomicAdd(p1, c2); atomicAdd(p1 + 1, c3);
            } else if (EPI == 2) {
                float b0v = bias[n], b1v = bias[n + 1];
                *reinterpret_cast<float2*>(p0) =
                    make_float2(softplusf(c0 + b0v), softplusf(c1 + b1v));
                *reinterpret_cast<float2*>(p1) =
                    make_float2(softplusf(c2 + b0v), softplusf(c3 + b1v));
            } else {
                *reinterpret_cast<float2*>(p0) = make_float2(c0, c1);
                *reinterpret_cast<float2*>(p1) = make_float2(c2, c3);
            }
        }
    }
}

// ---------------- fp32 -> fp16 conversion (8 elts/thread) ----------------
__global__ void cvt_f2h(const float* __restrict__ src, __half* __restrict__ dst, long n) {
    long i = ((long)blockIdx.x * 256 + threadIdx.x) * 8;
    if (i >= n) return;
    float4 v0 = *reinterpret_cast<const float4*>(src + i);
    float4 v1 = *reinterpret_cast<const float4*>(src + i + 4);
    __half2 h[4];
    h[0] = __floats2half2_rn(v0.x, v0.y);
    h[1] = __floats2half2_rn(v0.z, v0.w);
    h[2] = __floats2half2_rn(v1.x, v1.y);
    h[3] = __floats2half2_rn(v1.z, v1.w);
    *reinterpret_cast<uint4*>(dst + i) = *reinterpret_cast<uint4*>(h);
}

// ---------------- LayerNorm 1 (tf32-rounded) ----------------
__global__ void ln1_kernel(const float* __restrict__ x, const float* __restrict__ g,
                           const float* __restrict__ bta, float* __restrict__ out) {
    int b  = blockIdx.x >> 7;
    int l0 = (blockIdx.x & 127) * 32;
    __shared__ float sm[128 * 33];
    int tid = threadIdx.x;
    #pragma unroll
    for (int i = 0; i < 16; i++) {
        int idx = tid + i * 256;
        int c = idx >> 5, l = idx & 31;
        sm[c * 33 + l] = x[((long)b * CH + c) * LL + l0 + l];
    }
    __syncthreads();
    int warp = tid >> 5, lane = tid & 31;
    for (int t = warp; t < 32; t += 8) {
        float v[4]; float s = 0.f, sq = 0.f;
        #pragma unroll
        for (int j = 0; j < 4; j++) {
            v[j] = sm[(lane + 32 * j) * 33 + t];
            s += v[j]; sq += v[j] * v[j];
        }
        #pragma unroll
        for (int o = 16; o; o >>= 1) {
            s  += __shfl_xor_sync(0xffffffffu, s,  o);
            sq += __shfl_xor_sync(0xffffffffu, sq, o);
        }
        float mu  = s * (1.f / 128.f);
        float var = sq * (1.f / 128.f) - mu * mu;
        float rs  = rsqrtf(var + 1e-5f);
        #pragma unroll
        for (int j = 0; j < 4; j++) {
            int c = lane + 32 * j;
            out[((long)b * LL + l0 + t) * D1M + c] = rnd_tf32((v[j] - mu) * rs * g[c] + bta[c]);
        }
    }
}

// ---------------- LayerNorm 2 (fp16 output) ----------------
__global__ void ln2_kernel(const float* __restrict__ x, const float* __restrict__ g,
                           const float* __restrict__ bta, __half* __restrict__ out) {
    long row = blockIdx.x;
    const float* xr = x + row * D2M;
    __half* orow = out + row * D2M;
    int tid = threadIdx.x;
    float v[16]; float s = 0.f, sq = 0.f;
    #pragma unroll
    for (int i = 0; i < 16; i++) {
        v[i] = xr[i * 256 + tid];
        s += v[i]; sq += v[i] * v[i];
    }
    #pragma unroll
    for (int o = 16; o; o >>= 1) {
        s  += __shfl_xor_sync(0xffffffffu, s,  o);
        sq += __shfl_xor_sync(0xffffffffu, sq, o);
    }
    __shared__ float ss[8], sqq[8];
    int lane = tid & 31, warp = tid >> 5;
    if (!lane) { ss[warp] = s; sqq[warp] = sq; }
    __syncthreads();
    s = 0.f; sq = 0.f;
    #pragma unroll
    for (int w = 0; w < 8; w++) { s += ss[w]; sq += sqq[w]; }
    float mu  = s * (1.f / 4096.f);
    float var = sq * (1.f / 4096.f) - mu * mu;
    float rs  = rsqrtf(var + 1e-5f);
    #pragma unroll
    for (int i = 0; i < 16; i++) {
        int col = i * 256 + tid;
        orow[col] = __float2half_rn((v[i] - mu) * rs * g[col] + bta[col]);
    }
}

// ---------------- fallback SGEMM (dt1: K=8) ----------------
template<int ACT, bool HASBIAS>
__global__ void sgemm_kernel(const float* __restrict__ X, const float* __restrict__ W,
                             const float* __restrict__ bias, float* __restrict__ out,
                             int M, int N, int K, int lda, int ldc) {
    constexpr int BM = 64, BN = 64, BK = 32, PAD = 4;
    __shared__ float As[BK][BM + PAD];
    __shared__ float Bs[BK][BN + PAD];
    int bm = blockIdx.y * BM, bn = blockIdx.x * BN;
    int tid = threadIdx.x;
    int tx = tid & 15, ty = tid >> 4;
    float acc[4][4] = {};
    for (int k0 = 0; k0 < K; k0 += BK) {
        #pragma unroll
        for (int i = 0; i < 2; i++) {
            int idx = tid + i * 256;
            int row = idx >> 3;
            int kc  = (idx & 7) << 2;
            int k   = k0 + kc;
            float4 va = make_float4(0.f, 0.f, 0.f, 0.f);
            float4 vb = make_float4(0.f, 0.f, 0.f, 0.f);
            if (k < K) {
                int m = bm + row;
                if (m < M) va = *reinterpret_cast<const float4*>(X + (long)m * lda + k);
                int n = bn + row;
                if (n < N) vb = *reinterpret_cast<const float4*>(W + (long)n * K + k);
            }
            As[kc][row] = va.x; As[kc + 1][row] = va.y; As[kc + 2][row] = va.z; As[kc + 3][row] = va.w;
            Bs[kc][row] = vb.x; Bs[kc + 1][row] = vb.y; Bs[kc + 2][row] = vb.z; Bs[kc + 3][row] = vb.w;
        }
        __syncthreads();
        #pragma unroll
        for (int kk = 0; kk < BK; kk++) {
            float4 a = *reinterpret_cast<const float4*>(&As[kk][ty << 2]);
            float4 b = *reinterpret_cast<const float4*>(&Bs[kk][tx << 2]);
            float av[4] = {a.x, a.y, a.z, a.w};
            float bv[4] = {b.x, b.y, b.z, b.w};
            #pragma unroll
            for (int i = 0; i < 4; i++)
                #pragma unroll
                for (int j = 0; j < 4; j++)
                    acc[i][j] += av[i] * bv[j];
        }
        __syncthreads();
    }
    #pragma unroll
    for (int i = 0; i < 4; i++) {
        int m = bm + (ty << 2) + i;
        if (m >= M) continue;
        #pragma unroll
        for (int j = 0; j < 4; j++) {
            int n = bn + (tx << 2) + j;
            if (n >= N) continue;
            float v = acc[i][j];
            if (HASBIAS) v += bias[n];
            if (ACT == 1) v = softplusf(v);
            out[(long)m * ldc + n] = v;
        }
    }
}

// ---------------- causal depthwise conv (K=4) + SiLU (path-1, fp32/tf32) ----------------
__global__ void conv_silu_kernel(const float* __restrict__ xz, const float* __restrict__ w,
                                 const float* __restrict__ bias, float* __restrict__ out,
                                 int Ltok, int dinner) {
    long tid = (long)blockIdx.x * 256 + threadIdx.x;
    long total = (long)BATCH * Ltok * (dinner / 4);
    if (tid >= total) return;
    int d4 = (int)(tid % (dinner / 4)) * 4;
    long t = tid / (dinner / 4);
    int l = (int)(t % Ltok);
    int b = (int)(t / Ltok);
    int rowstride = 2 * dinner;
    const float* base = xz + ((long)b * Ltok + l) * rowstride + d4;
    float4 bv = *reinterpret_cast<const float4*>(bias + d4);
    float acc0 = bv.x, acc1 = bv.y, acc2 = bv.z, acc3 = bv.w;
    #pragma unroll
    for (int k = 0; k < 4; k++) {
        int ll = l - 3 + k;
        if (ll >= 0) {
            float4 xv = *reinterpret_cast<const float4*>(base + (long)(ll - l) * rowstride);
            acc0 += xv.x * w[(d4 + 0) * 4 + k];
            acc1 += xv.y * w[(d4 + 1) * 4 + k];
            acc2 += xv.z * w[(d4 + 2) * 4 + k];
            acc3 += xv.w * w[(d4 + 3) * 4 + k];
        }
    }
    float4 ov;
    ov.x = rnd_tf32(siluf(acc0)); ov.y = rnd_tf32(siluf(acc1));
    ov.z = rnd_tf32(siluf(acc2)); ov.w = rnd_tf32(siluf(acc3));
    *reinterpret_cast<float4*>(out + ((long)b * Ltok + l) * dinner + d4) = ov;
}

// ---------------- path-1 scan ----------------
__global__ void scan1_partial(const float* __restrict__ delta, const float* __restrict__ xc,
                              const float* __restrict__ dbl, const float* __restrict__ Alog) {
    int d = threadIdx.x;
    int chunk = blockIdx.x & (NCH - 1);
    int b = blockIdx.x >> 5;
    float A[NS], h[NS], P[NS];
    #pragma unroll
    for (int s = 0; s < NS; s++) { A[s] = -__expf(Alog[d * NS + s]); h[s] = 0.f; P[s] = 1.f; }
    int l0 = chunk * CLEN;
    for (int i = 0; i < CLEN; i++) {
        long t = (long)b * LL + l0 + i;
        float dl = delta[t * D1I + d];
        float xv = xc[t * D1I + d];
        const float* bl = dbl + t * DBL1 + DT1R;
        float dx = dl * xv;
        #pragma unroll
        for (int s = 0; s < NS; s++) {
            float dA = __expf(dl * A[s]);
            h[s] = dA * h[s] + dx * bl[s];
            P[s] *= dA;
        }
    }
    long o = (((long)b * D1I + d) * NCH + chunk) * NS;
    #pragma unroll
    for (int s = 0; s < NS; s++) { g_ckP[o + s] = P[s]; g_ckH[o + s] = h[s]; }
}

__global__ void scan1_carry() {
    int idx = blockIdx.x * 256 + threadIdx.x;
    if (idx >= BATCH * D1I) return;
    long base = (long)idx * NCH * NS;
    float h[NS];
    #pragma unroll
    for (int s = 0; s < NS; s++) h[s] = 0.f;
    for (int c = 0; c < NCH; c++) {
        long o = base + (long)c * NS;
        #pragma unroll
        for (int s = 0; s < NS; s++) {
            g_hin[o + s] = h[s];
            h[s] = g_ckP[o + s] * h[s] + g_ckH[o + s];
        }
    }
}

__global__ void scan1_final(const float* __restrict__ delta, const float* __restrict__ xc,
                            const float* __restrict__ dbl, const float* __restrict__ Alog,
                            const float* __restrict__ Dp, const float* __restrict__ xz,
                            float* __restrict__ y) {
    int d = threadIdx.x;
    int chunk = blockIdx.x & (NCH - 1);
    int b = blockIdx.x >> 5;
    float A[NS], h[NS];
    long hb = (((long)b * D1I + d) * NCH + chunk) * NS;
    #pragma unroll
    for (int s = 0; s < NS; s++) { A[s] = -__expf(Alog[d * NS + s]); h[s] = g_hin[hb + s]; }
    float Dv = Dp[d];
    int l0 = chunk * CLEN;
    for (int i = 0; i < CLEN; i++) {
        long t = (long)b * LL + l0 + i;
        float dl = delta[t * D1I + d];
        float xv = xc[t * D1I + d];
        const float* bl = dbl + t * DBL1 + DT1R;
        float dx = dl * xv;
        float acc = 0.f;
        #pragma unroll
        for (int s = 0; s < NS; s++) {
            float dA = __expf(dl * A[s]);
            h[s] = dA * h[s] + dx * bl[s];
            acc += h[s] * bl[NS + s];
        }
        float z = xz[t * (2 * D1I) + D1I + d];
        y[t * D1I + d] = rnd_tf32((acc + xv * Dv) * siluf(z));
    }
}

// ---------------- path-2 scan (xc fp16 in, y fp16 out) ----------------
__global__ void scan2_kernel(const float* __restrict__ delta, const __half* __restrict__ xc,
                             const float* __restrict__ dbl, const float* __restrict__ Alog,
                             const float* __restrict__ Dp, const float* __restrict__ xz,
                             __half* __restrict__ y) {
    int d = (blockIdx.x & 31) * 256 + threadIdx.x;
    int b = blockIdx.x >> 5;
    float A[NS], h[NS];
    #pragma unroll
    for (int s = 0; s < NS; s++) { A[s] = -__expf(Alog[d * NS + s]); h[s] = 0.f; }
    float Dv = Dp[d];
    for (int l = 0; l < CH; l++) {
        long t = (long)b * CH + l;
        float dl = delta[t * D2I + d];
        float xv = __half2float(xc[t * D2I + d]);
        const float* bl = dbl + t * DBL2 + DT2R;
        float dx = dl * xv;
        float acc = 0.f;
        #pragma unroll
        for (int s = 0; s < NS; s++) {
            float dA = __expf(dl * A[s]);
            h[s] = dA * h[s] + dx * bl[s];
            acc += h[s] * bl[NS + s];
        }
        float z = xz[t * (2 * D2I) + D2I + d];
        y[t * D2I + d] = __float2half_rn((acc + xv * Dv) * siluf(z));
    }
}

// ---------------- combine ----------------
__global__ void combine_kernel(const float* __restrict__ x, float* __restrict__ out) {
    long i = (long)blockIdx.x * 256 + threadIdx.x;
    if (i >= (long)BATCH * CH * LL) return;
    int l = (int)(i % LL);
    long t = i / LL;
    int c = (int)(t % CH);
    int b = (int)(t / CH);
    out[i] = x[i] + g_out2[i] + g_out1[((long)b * LL + l) * D1M + c];
}

// ---------------- launch ----------------
extern "C" void kernel_launch(void* const* d_in, const int* in_sizes, int n_in,
                              void* d_out, int out_size) {
    const float* x        = (const float*)d_in[0];
    const float* ln1_g    = (const float*)d_in[1];
    const float* ln1_b    = (const float*)d_in[2];
    const float* ln2_g    = (const float*)d_in[3];
    const float* ln2_b    = (const float*)d_in[4];
    const float* m1_in_w  = (const float*)d_in[5];
    const float* m1_cw    = (const float*)d_in[6];
    const float* m1_cb    = (const float*)d_in[7];
    const float* m1_xp_w  = (const float*)d_in[8];
    const float* m1_dt_w  = (const float*)d_in[9];
    const float* m1_dt_b  = (const float*)d_in[10];
    const float* m1_Alog  = (const float*)d_in[11];
    const float* m1_D     = (const float*)d_in[12];
    const float* m1_out_w = (const float*)d_in[13];
    const float* m2_in_w  = (const float*)d_in[14];
    const float* m2_cw    = (const float*)d_in[15];
    const float* m2_cb    = (const float*)d_in[16];
    const float* m2_xp_w  = (const float*)d_in[17];
    const float* m2_dt_w  = (const float*)d_in[18];
    const float* m2_dt_b  = (const float*)d_in[19];
    const float* m2_Alog  = (const float*)d_in[20];
    const float* m2_D     = (const float*)d_in[21];
    const float* m2_out_w = (const float*)d_in[22];
    float* out = (float*)d_out;

    float *pxn1, *pxz1, *pxc1, *pdbl1, *pdelta1, *py1, *pout1;
    float *pxz2, *pdbl2, *pdelta2, *pout2;
    __half *pxn2h, *pxc2h, *py2h, *pdbl2h;
    cudaGetSymbolAddress((void**)&pxn1, g_xn1);
    cudaGetSymbolAddress((void**)&pxz1, g_xz1);
    cudaGetSymbolAddress((void**)&pxc1, g_xc1);
    cudaGetSymbolAddress((void**)&pdbl1, g_dbl1);
    cudaGetSymbolAddress((void**)&pdelta1, g_delta1);
    cudaGetSymbolAddress((void**)&py1, g_y1);
    cudaGetSymbolAddress((void**)&pout1, g_out1);
    cudaGetSymbolAddress((void**)&pxz2, g_xz2);
    cudaGetSymbolAddress((void**)&pdbl2, g_dbl2);
    cudaGetSymbolAddress((void**)&pdelta2, g_delta2);
    cudaGetSymbolAddress((void**)&pout2, g_out2);
    cudaGetSymbolAddress((void**)&pxn2h, g_xn2h);
    cudaGetSymbolAddress((void**)&pxc2h, g_xc2h);
    cudaGetSymbolAddress((void**)&py2h, g_y2h);
    cudaGetSymbolAddress((void**)&pdbl2h, g_dbl2h);

    cudaFuncSetAttribute(tf32_gemm<0>, cudaFuncAttributeMaxDynamicSharedMemorySize, GSMEM_BYTES);
    cudaFuncSetAttribute(tf32_gemm<1>, cudaFuncAttributeMaxDynamicSharedMemorySize, GSMEM_BYTES);
    cudaFuncSetAttribute(fp16w_gemm<0>, cudaFuncAttributeMaxDynamicSharedMemorySize, HSMEM_BYTES);
    cudaFuncSetAttribute(fp16w_gemm<1>, cudaFuncAttributeMaxDynamicSharedMemorySize, HSMEM_BYTES);
    cudaFuncSetAttribute(fp16w_gemm<2>, cudaFuncAttributeMaxDynamicSharedMemorySize, HSMEM_BYTES);
    cudaFuncSetAttribute(fp16w_gemm<3>, cudaFuncAttributeMaxDynamicSharedMemorySize, HSMEM_BYTES);

    static cudaStream_t s2 = nullptr, s3 = nullptr;
    static cudaEvent_t evFork = nullptr, evFork3 = nullptr, evJoin = nullptr,
                       evJoinB = nullptr, evLn2 = nullptr;
    if (!s2) {
        cudaStreamCreateWithFlags(&s2, cudaStreamNonBlocking);
        cudaStreamCreateWithFlags(&s3, cudaStreamNonBlocking);
        cudaEventCreateWithFlags(&evFork, cudaEventDisableTiming);
        cudaEventCreateWithFlags(&evFork3, cudaEventDisableTiming);
        cudaEventCreateWithFlags(&evJoin, cudaEventDisableTiming);
        cudaEventCreateWithFlags(&evJoinB, cudaEventDisableTiming);
        cudaEventCreateWithFlags(&evLn2, cudaEventDisableTiming);
    }

    const int T = 256;
    const long IN_HALF = (long)D2I * D2M;
    // fork at t=0
    cudaEventRecord(evFork, 0);
    cudaStreamWaitEvent(s2, evFork, 0);
    cudaEventRecord(evFork3, 0);
    cudaStreamWaitEvent(s3, evFork3, 0);

    // ---- main: ln2, then in2a with FUSED conv+SiLU -> xc2h ----
    cudaMemsetAsync(pdbl2, 0, sizeof(float) * BATCH * CH * DBL2);
    cudaMemsetAsync(pout2, 0, sizeof(float) * BATCH * CH * D2M);
    ln2_kernel<<<BATCH * CH, T>>>(x, ln2_g, ln2_b, pxn2h);
    cudaEventRecord(evLn2, 0);
    fp16w_gemm<3><<<dim3(128, 1, 1), 256, HSMEM_BYTES>>>(
        pxn2h, m2_in_w, nullptr, pxz2, BATCH * CH, D2I, D2M, D2M, D2M, 2 * D2I,
        m2_cw, m2_cb, pxc2h);

    // ---- s3: in2b (z half) ----
    cudaStreamWaitEvent(s3, evLn2, 0);
    fp16w_gemm<0><<<dim3(128, 1, 1), 256, HSMEM_BYTES, s3>>>(
        pxn2h, m2_in_w + IN_HALF, nullptr, pxz2 + D2I,
        BATCH * CH, D2I, D2M, D2M, D2M, 2 * D2I, nullptr, nullptr, nullptr);
    cudaEventRecord(evJoinB, s3);

    // ---- s2: full path 1 ----
    cudaMemsetAsync(pout1, 0, sizeof(float) * BATCH * LL * D1M, s2);
    ln1_kernel<<<BATCH * (LL / 32), T, 0, s2>>>(x, ln1_g, ln1_b, pxn1);
    tf32_gemm<0><<<dim3(4, 64, 1), 256, GSMEM_BYTES, s2>>>(
        pxn1, m1_in_w, nullptr, pxz1, BATCH * LL, 2 * D1I, D1M, D1M, D1M, 2 * D1I);
    conv_silu_kernel<<<(BATCH * LL * D1I / 4 + T - 1) / T, T, 0, s2>>>(
        pxz1, m1_cw, m1_cb, pxc1, LL, D1I);
    tf32_gemm<0><<<dim3(1, 64, 1), 256, GSMEM_BYTES, s2>>>(
        pxc1, m1_xp_w, nullptr, pdbl1, BATCH * LL, DBL1, D1I, D1I, D1I, DBL1);
    sgemm_kernel<1, true><<<dim3((D1I + 63) / 64, (BATCH * LL) / 64), T, 0, s2>>>(
        pdbl1, m1_dt_w, m1_dt_b, pdelta1, BATCH * LL, D1I, DT1R, DBL1, D1I);
    scan1_partial<<<BATCH * NCH, D1I, 0, s2>>>(pdelta1, pxc1, pdbl1, m1_Alog);
    scan1_carry<<<(BATCH * D1I + T - 1) / T, T, 0, s2>>>();
    scan1_final<<<BATCH * NCH, D1I, 0, s2>>>(pdelta1, pxc1, pdbl1, m1_Alog, m1_D, pxz1, py1);
    tf32_gemm<1><<<dim3(1, 64, 2), 256, GSMEM_BYTES, s2>>>(
        py1, m1_out_w, nullptr, pout1, BATCH * LL, D1M, D1I / 2, D1I, D1I, D1M);
    cudaEventRecord(evJoin, s2);

    // ---- main: dependent chain (conv already fused) ----
    // xp2: dbl2[256, 272] split-K=32 atomic (160 CTAs)
    fp16w_gemm<1><<<dim3(5, 1, 32), 256, HSMEM_BYTES>>>(
        pxc2h, m2_xp_w, nullptr, pdbl2, BATCH * CH, DBL2, D2I / 32, D2I, D2I, DBL2,
        nullptr, nullptr, nullptr);
    cvt_f2h<<<(int)(((long)BATCH * CH * DBL2) / 2048), T>>>(pdbl2, pdbl2h, (long)BATCH * CH * DBL2);
    // dt2: delta2 = softplus(dbl2h[:, :256] @ dt_w^T + b) (128 CTAs)
    fp16w_gemm<2><<<dim3(128, 1, 1), 256, HSMEM_BYTES>>>(
        pdbl2h, m2_dt_w, m2_dt_b, pdelta2, BATCH * CH, D2I, DT2R, DBL2, DT2R, D2I,
        nullptr, nullptr, nullptr);
    cudaStreamWaitEvent(0, evJoinB, 0);
    scan2_kernel<<<BATCH * (D2I / 256), T>>>(pdelta2, pxc2h, pdbl2, m2_Alog, m2_D, pxz2, py2h);
    // out2: split-K=4 atomic (256 CTAs)
    fp16w_gemm<1><<<dim3(64, 1, 4), 256, HSMEM_BYTES>>>(
        py2h, m2_out_w, nullptr, pout2, BATCH * CH, D2M, D2I / 4, D2I, D2I, D2M,
        nullptr, nullptr, nullptr);

    cudaStreamWaitEvent(0, evJoin, 0);
    combine_kernel<<<(BATCH * CH * LL + T - 1) / T, T>>>(x, out);
}

// round 17
// speedup vs baseline: 1.9670x; 1.0083x over previous
#include <cuda_runtime.h>
#include <cuda_fp16.h>
#include <cstdint>
#include <math.h>

// ---------------- problem constants ----------------
#define BATCH 2
#define CH    128
#define LL    4096
#define NS    8

#define D1M  128
#define D1I  256
#define DT1R 8
#define DBL1 24
#define D2M  4096
#define D2I  8192
#define DT2R 256
#define DBL2 272      // dt_rank(256) + 2*8

#define NCH  32
#define CLEN 128

// ---------------- scratch ----------------
__device__ __align__(16) float g_xn1[BATCH*LL*D1M];
__device__ __align__(16) float g_xz1[BATCH*LL*2*D1I];
__device__ __align__(16) float g_xc1[BATCH*LL*D1I];
__device__ __align__(16) float g_dbl1[BATCH*LL*DBL1];
__device__ __align__(16) float g_delta1[BATCH*LL*D1I];
__device__ __align__(16) float g_y1[BATCH*LL*D1I];
__device__ __align__(16) float g_out1[BATCH*LL*D1M];
__device__ __align__(16) float g_ckP[BATCH*D1I*NCH*NS];
__device__ __align__(16) float g_ckH[BATCH*D1I*NCH*NS];
__device__ __align__(16) float g_hin[BATCH*D1I*NCH*NS];

__device__ __align__(16) float g_dbl2[BATCH*CH*DBL2];
__device__ __align__(16) float g_out2[BATCH*CH*D2M];

// fp16 scratch (activations only — weights stay fp32 in gmem)
__device__ __align__(16) __half g_xn2h[BATCH*CH*D2M];
__device__ __align__(16) __half g_xc2h[BATCH*CH*D2I];
__device__ __align__(16) __half g_z2h[BATCH*CH*D2I];
__device__ __align__(16) __half g_delta2h[BATCH*CH*D2I];
__device__ __align__(16) __half g_y2h[BATCH*CH*D2I];
__device__ __align__(16) __half g_dbl2h[BATCH*CH*DBL2];

// ---------------- helpers ----------------
__device__ __forceinline__ uint32_t smem_u32(const void* p) {
    uint32_t a;
    asm("{ .reg .u64 t; cvta.to.shared.u64 t, %1; cvt.u32.u64 %0, t; }" : "=r"(a) : "l"(p));
    return a;
}
__device__ __forceinline__ void cp_async16(uint32_t dst, const void* src, int sz) {
    asm volatile("cp.async.cg.shared.global [%0], [%1], 16, %2;"
                 :: "r"(dst), "l"(src), "r"(sz) : "memory");
}
#define CP_COMMIT() asm volatile("cp.async.commit_group;" ::: "memory")
#define CP_WAIT1()  asm volatile("cp.async.wait_group 1;" ::: "memory")
#define CP_WAIT0()  asm volatile("cp.async.wait_group 0;" ::: "memory")

__device__ __forceinline__ uint32_t f2tf32(float f) {
    uint32_t r;
    asm("cvt.rna.tf32.f32 %0, %1;" : "=r"(r) : "f"(f));
    return r;
}
__device__ __forceinline__ float rnd_tf32(float v) { return __uint_as_float(f2tf32(v)); }

__device__ __forceinline__ void mma_tf32(float* d, const uint32_t* a, const uint32_t* b) {
    asm volatile(
        "mma.sync.aligned.m16n8k8.row.col.f32.tf32.tf32.f32 "
        "{%0,%1,%2,%3}, {%4,%5,%6,%7}, {%8,%9}, {%0,%1,%2,%3};"
        : "+f"(d[0]), "+f"(d[1]), "+f"(d[2]), "+f"(d[3])
        : "r"(a[0]), "r"(a[1]), "r"(a[2]), "r"(a[3]), "r"(b[0]), "r"(b[1]));
}
__device__ __forceinline__ void mma_f16(float* d, const uint32_t* a, const uint32_t* b) {
    asm volatile(
        "mma.sync.aligned.m16n8k16.row.col.f32.f16.f16.f32 "
        "{%0,%1,%2,%3}, {%4,%5,%6,%7}, {%8,%9}, {%0,%1,%2,%3};"
        : "+f"(d[0]), "+f"(d[1]), "+f"(d[2]), "+f"(d[3])
        : "r"(a[0]), "r"(a[1]), "r"(a[2]), "r"(a[3]), "r"(b[0]), "r"(b[1]));
}
__device__ __forceinline__ void ldsm_x4(uint32_t& r0, uint32_t& r1, uint32_t& r2, uint32_t& r3,
                                        uint32_t addr) {
    asm volatile("ldmatrix.sync.aligned.m8n8.x4.shared.b16 {%0,%1,%2,%3}, [%4];"
                 : "=r"(r0), "=r"(r1), "=r"(r2), "=r"(r3) : "r"(addr));
}

__device__ __forceinline__ float siluf(float v) { return v / (1.f + __expf(-v)); }
__device__ __forceinline__ float softplusf(float v) { return (v > 20.f) ? v : log1pf(__expf(v)); }

// ======================================================================
// tf32 mma.sync GEMM — path-1 GEMMs (unchanged)
// ======================================================================
#define SROW 36
#define GROWS 256
#define GSTG (GROWS * SROW)
#define GSMEM_BYTES (3 * GSTG * 4)      // 108 KB -> 2 CTAs/SM

template<int EPI>
__global__ void __launch_bounds__(256, 2)
tf32_gemm(const float* __restrict__ X, const float* __restrict__ W,
          const float* __restrict__ bias, float* __restrict__ C,
          int M, int N, int kLen, int ldx, int ldw, int ldc) {
    extern __shared__ float sm[];
    const int tid = threadIdx.x;
    const int wid = tid >> 5, lane = tid & 31;
    const int gid = lane >> 2, tig = lane & 3;
    const int wm = wid >> 2, wn = wid & 3;
    const int m0 = blockIdx.y * 128, n0 = blockIdx.x * 128;
    const long k0 = (long)blockIdx.z * kLen;
    const int nIter = kLen / 32;
    const uint32_t sS = smem_u32(sm);

    float acc[4][4][4];
    #pragma unroll
    for (int i = 0; i < 4; i++)
        #pragma unroll
        for (int j = 0; j < 4; j++)
            #pragma unroll
            for (int r = 0; r < 4; r++) acc[i][j][r] = 0.f;

    auto load_stage = [&](int buf, long kk) {
        #pragma unroll
        for (int i = 0; i < 8; i++) {
            int idx = tid + i * 256;
            int row = idx >> 3, ch = idx & 7;
            uint32_t off = (uint32_t)((buf * GROWS + row) * SROW + ch * 4) * 4u;
            if (row < 128) {
                cp_async16(sS + off, X + (long)(m0 + row) * ldx + kk + ch * 4, 16);
            } else {
                int nr = n0 + row - 128;
                const float* gb = W + (long)(nr < N ? nr : 0) * ldw + kk + ch * 4;
                cp_async16(sS + off, gb, nr < N ? 16 : 0);
            }
        }
    };

    const uint32_t aBase = sS +
        (uint32_t)(((wm * 64 + ((lane >> 3) & 1) * 8 + (lane & 7)) * SROW
                    + ((lane >> 4) & 1) * 4) * 4);
    const uint32_t bBase = sS +
        (uint32_t)(((128 + wn * 32 + ((lane >> 4) & 1) * 8 + (lane & 7)) * SROW
                    + ((lane >> 3) & 1) * 4) * 4);

    load_stage(0, k0); CP_COMMIT();
    load_stage(1, k0 + 32); CP_COMMIT();

    for (int it = 0; it < nIter; it++) {
        if (it + 1 < nIter) { CP_WAIT1(); } else { CP_WAIT0(); }
        __syncthreads();
        const uint32_t stgOff = (uint32_t)((it % 3) * GSTG * 4);
        const uint32_t aS = aBase + stgOff;
        const uint32_t bS = bBase + stgOff;
        #pragma unroll
        for (int ks = 0; ks < 4; ks++) {
            uint32_t a[4][4], b[4][2];
            #pragma unroll
            for (int mi = 0; mi < 4; mi++)
                ldsm_x4(a[mi][0], a[mi][1], a[mi][2], a[mi][3],
                        aS + (uint32_t)(mi * 16 * SROW * 4 + ks * 32));
            #pragma unroll
            for (int p = 0; p < 2; p++) {
                uint32_t r0, r1, r2, r3;
                ldsm_x4(r0, r1, r2, r3, bS + (uint32_t)(p * 16 * SROW * 4 + ks * 32));
                b[2 * p][0]     = f2tf32(__uint_as_float(r0));
                b[2 * p][1]     = f2tf32(__uint_as_float(r1));
                b[2 * p + 1][0] = f2tf32(__uint_as_float(r2));
                b[2 * p + 1][1] = f2tf32(__uint_as_float(r3));
            }
            #pragma unroll
            for (int mi = 0; mi < 4; mi++)
                #pragma unroll
                for (int ni = 0; ni < 4; ni++)
                    mma_tf32(acc[mi][ni], a[mi], b[ni]);
        }
        if (it + 2 < nIter) { load_stage((it + 2) % 3, k0 + (long)(it + 2) * 32); CP_COMMIT(); }
    }

    #pragma unroll
    for (int mi = 0; mi < 4; mi++) {
        int m = m0 + wm * 64 + mi * 16 + gid;
        #pragma unroll
        for (int ni = 0; ni < 4; ni++) {
            int n = n0 + wn * 32 + ni * 8 + tig * 2;
            if (n >= N) continue;
            float* p0 = C + (long)m * ldc + n;
            float* p1 = C + (long)(m + 8) * ldc + n;
            float c0 = acc[mi][ni][0], c1 = acc[mi][ni][1];
            float c2 = acc[mi][ni][2], c3 = acc[mi][ni][3];
            if (EPI == 1) {
                atomicAdd(p0, c0); atomicAdd(p0 + 1, c1);
                atomicAdd(p1, c2); atomicAdd(p1 + 1, c3);
            } else if (EPI == 2) {
                float b0v = bias[n], b1v = bias[n + 1];
                *reinterpret_cast<float2*>(p0) =
                    make_float2(softplusf(c0 + b0v), softplusf(c1 + b1v));
                *reinterpret_cast<float2*>(p1) =
                    make_float2(softplusf(c2 + b0v), softplusf(c3 + b1v));
            } else {
                *reinterpret_cast<float2*>(p0) = make_float2(c0, c1);
                *reinterpret_cast<float2*>(p1) = make_float2(c2, c3);
            }
        }
    }
}

// ======================================================================
// fp16 mma.sync GEMM, fp32 WEIGHTS via REGISTERS (LDG -> cvt -> STS fp16).
// BM=256 (weights read once), BN=64; warps 4(m) x 2(n), warp tile 64x32.
// ONE __syncthreads per K-iter. A: cp.async fp16 3-stage.
// EPI: 0 = store fp32, 1 = atomicAdd, 2 = softplus(v+bias[n]) fp32 store,
//      3 = merged in2: n0<nHalf -> fused conv+SiLU -> hout (xc2h);
//                      n0>=nHalf -> fp16 store -> zout (z2h)
//      5 = softplus(v+bias[n]) -> fp16 store to hout (ldc stride)
// ======================================================================
#define SROWH 40
#define HA_BYTES (256 * SROWH * 2)              // 20480
#define HSTAGE_BYTES (HA_BYTES + 64 * SROWH * 2)// 25600
#define HSMEM_BYTES (3 * HSTAGE_BYTES)          // 76800 -> 2 CTAs/SM

template<int EPI>
__global__ void __launch_bounds__(256, 2)
fp16w_gemm(const __half* __restrict__ X, const float* __restrict__ W,
           const float* __restrict__ bias, float* __restrict__ C,
           int M, int N, int kLen, int ldx, int ldw, int ldc,
           const float* __restrict__ cw, const float* __restrict__ cb,
           __half* __restrict__ hout, __half* __restrict__ zout, int nHalf) {
    extern __shared__ char smc[];
    const int tid = threadIdx.x;
    const int wid = tid >> 5, lane = tid & 31;
    const int gid = lane >> 2, tig = lane & 3;
    const int wm = wid >> 1, wn = wid & 1;       // 4 x 2 warp grid
    const int n0 = blockIdx.x * 64;
    const long k0 = (long)blockIdx.z * kLen;
    const int nIter = kLen / 32;
    const uint32_t sS = smem_u32(smc);

    float acc[4][4][4];
    #pragma unroll
    for (int i = 0; i < 4; i++)
        #pragma unroll
        for (int j = 0; j < 4; j++)
            #pragma unroll
            for (int r = 0; r < 4; r++) acc[i][j][r] = 0.f;

    // B weights: one thread handles 8 consecutive fp32 of one row per stage
    const int brow = tid >> 2, bseg = tid & 3;
    const int bnr = n0 + brow;
    const float* bsrc = W + (long)(bnr < N ? bnr : 0) * ldw + bseg * 8;
    __half* bdstBase = reinterpret_cast<__half*>(smc) + brow * SROWH + bseg * 8;

    auto ldgB = [&](long kk, float4& v0, float4& v1) {
        v0 = *reinterpret_cast<const float4*>(bsrc + kk);
        v1 = *reinterpret_cast<const float4*>(bsrc + kk + 4);
    };
    auto stsB = [&](int buf, const float4& v0, const float4& v1) {
        __half2 h[4];
        h[0] = __floats2half2_rn(v0.x, v0.y);
        h[1] = __floats2half2_rn(v0.z, v0.w);
        h[2] = __floats2half2_rn(v1.x, v1.y);
        h[3] = __floats2half2_rn(v1.z, v1.w);
        *reinterpret_cast<uint4*>(
            reinterpret_cast<char*>(bdstBase) + buf * HSTAGE_BYTES + HA_BYTES)
            = *reinterpret_cast<uint4*>(h);
    };
    auto loadA = [&](int buf, long kk) {
        #pragma unroll
        for (int i = 0; i < 4; i++) {
            int idx = tid + i * 256;
            int row = idx >> 2, ch = idx & 3;
            uint32_t off = (uint32_t)(buf * HSTAGE_BYTES + row * (SROWH * 2) + ch * 16);
            cp_async16(sS + off, X + (long)row * ldx + kk + ch * 8, 16);
        }
    };

    const uint32_t aBase = sS +
        (uint32_t)(((wm * 64 + ((lane >> 3) & 1) * 8 + (lane & 7)) * SROWH
                    + ((lane >> 4) & 1) * 8) * 2);
    const uint32_t bBase = sS + HA_BYTES +
        (uint32_t)(((wn * 32 + ((lane >> 4) & 1) * 8 + (lane & 7)) * SROWH
                    + ((lane >> 3) & 1) * 8) * 2);

    // prologue: B0, B1 straight to smem; B2 held in registers
    float4 b0r, b1r;
    ldgB(k0, b0r, b1r); stsB(0, b0r, b1r);
    ldgB(k0 + 32, b0r, b1r); stsB(1, b0r, b1r);
    if (nIter > 2) ldgB(k0 + 64, b0r, b1r);
    loadA(0, k0); CP_COMMIT();
    loadA(1, k0 + 32); CP_COMMIT();

    for (int it = 0; it < nIter; it++) {
        if (it + 1 < nIter) { CP_WAIT1(); } else { CP_WAIT0(); }
        __syncthreads();
        if (it + 2 < nIter) {
            loadA((it + 2) % 3, k0 + (long)(it + 2) * 32); CP_COMMIT();
            stsB((it + 2) % 3, b0r, b1r);
        }
        if (it + 3 < nIter) ldgB(k0 + (long)(it + 3) * 32, b0r, b1r);

        const uint32_t stgOff = (uint32_t)((it % 3) * HSTAGE_BYTES);
        const uint32_t aS = aBase + stgOff;
        const uint32_t bS = bBase + stgOff;
        #pragma unroll
        for (int ks = 0; ks < 2; ks++) {
            uint32_t a[4][4], b[4][2];
            #pragma unroll
            for (int mi = 0; mi < 4; mi++)
                ldsm_x4(a[mi][0], a[mi][1], a[mi][2], a[mi][3],
                        aS + (uint32_t)(mi * 16 * SROWH * 2 + ks * 32));
            #pragma unroll
            for (int p = 0; p < 2; p++) {
                uint32_t r0, r1, r2, r3;
                ldsm_x4(r0, r1, r2, r3, bS + (uint32_t)(p * 16 * SROWH * 2 + ks * 32));
                b[2 * p][0] = r0;     b[2 * p][1] = r1;
                b[2 * p + 1][0] = r2; b[2 * p + 1][1] = r3;
            }
            #pragma unroll
            for (int mi = 0; mi < 4; mi++)
                #pragma unroll
                for (int ni = 0; ni < 4; ni++)
                    mma_f16(acc[mi][ni], a[mi], b[ni]);
        }
    }

    if (EPI == 3) {
        if (n0 >= nHalf) {
            // z half: fp16 store to zout (channel stride D2I)
            #pragma unroll
            for (int mi = 0; mi < 4; mi++) {
                int m = wm * 64 + mi * 16 + gid;
                #pragma unroll
                for (int ni = 0; ni < 4; ni++) {
                    int cg = n0 - nHalf + wn * 32 + ni * 8 + tig * 2;
                    __half2 h0 = __floats2half2_rn(acc[mi][ni][0], acc[mi][ni][1]);
                    __half2 h1 = __floats2half2_rn(acc[mi][ni][2], acc[mi][ni][3]);
                    *reinterpret_cast<__half2*>(zout + (long)m * D2I + cg) = h0;
                    *reinterpret_cast<__half2*>(zout + (long)(m + 8) * D2I + cg) = h1;
                }
            }
            return;
        }
        // xi half: fused causal depthwise conv (K=4) + SiLU over CTA-local tile.
        __syncthreads();                      // stage smem no longer needed
        float* Ct = reinterpret_cast<float*>(smc);   // [256][65] = 66560B <= 76800
        #pragma unroll
        for (int mi = 0; mi < 4; mi++) {
            int m = wm * 64 + mi * 16 + gid;
            #pragma unroll
            for (int ni = 0; ni < 4; ni++) {
                int nc = wn * 32 + ni * 8 + tig * 2;
                Ct[m * 65 + nc]           = acc[mi][ni][0];
                Ct[m * 65 + nc + 1]       = acc[mi][ni][1];
                Ct[(m + 8) * 65 + nc]     = acc[mi][ni][2];
                Ct[(m + 8) * 65 + nc + 1] = acc[mi][ni][3];
            }
        }
        __syncthreads();
        const int dc = lane * 2, dg = n0 + dc;
        const float w00 = cw[dg * 4 + 0], w01 = cw[dg * 4 + 1],
                    w02 = cw[dg * 4 + 2], w03 = cw[dg * 4 + 3];
        const float w10 = cw[dg * 4 + 4], w11 = cw[dg * 4 + 5],
                    w12 = cw[dg * 4 + 6], w13 = cw[dg * 4 + 7];
        const float b0 = cb[dg], b1 = cb[dg + 1];
        for (int tok = wid; tok < 256; tok += 8) {
            int l = tok & 127;
            float a0 = b0, a1 = b1;
            if (l >= 3) { a0 += Ct[(tok - 3) * 65 + dc] * w00;
                          a1 += Ct[(tok - 3) * 65 + dc + 1] * w10; }
            if (l >= 2) { a0 += Ct[(tok - 2) * 65 + dc] * w01;
                          a1 += Ct[(tok - 2) * 65 + dc + 1] * w11; }
            if (l >= 1) { a0 += Ct[(tok - 1) * 65 + dc] * w02;
                          a1 += Ct[(tok - 1) * 65 + dc + 1] * w12; }
            a0 += Ct[tok * 65 + dc] * w03;
            a1 += Ct[tok * 65 + dc + 1] * w13;
            __half2 h = __floats2half2_rn(siluf(a0), siluf(a1));
            *reinterpret_cast<__half2*>(hout + (long)tok * D2I + dg) = h;
        }
        return;
    }

    #pragma unroll
    for (int mi = 0; mi < 4; mi++) {
        int m = wm * 64 + mi * 16 + gid;
        #pragma unroll
        for (int ni = 0; ni < 4; ni++) {
            int n = n0 + wn * 32 + ni * 8 + tig * 2;
            if (n >= N) continue;
            float c0 = acc[mi][ni][0], c1 = acc[mi][ni][1];
            float c2 = acc[mi][ni][2], c3 = acc[mi][ni][3];
            if (EPI == 5) {
                float b0v = bias[n], b1v = bias[n + 1];
                __half2 h0 = __floats2half2_rn(softplusf(c0 + b0v), softplusf(c1 + b1v));
                __half2 h1 = __floats2half2_rn(softplusf(c2 + b0v), softplusf(c3 + b1v));
                *reinterpret_cast<__half2*>(hout + (long)m * ldc + n) = h0;
                *reinterpret_cast<__half2*>(hout + (long)(m + 8) * ldc + n) = h1;
            } else {
                float* p0 = C + (long)m * ldc + n;
                float* p1 = C + (long)(m + 8) * ldc + n;
                if (EPI == 1) {
                    atomicAdd(p0, c0); atomicAdd(p0 + 1, c1);
                    atomicAdd(p1, c2); atomicAdd(p1 + 1, c3);
                } else if (EPI == 2) {
                    float b0v = bias[n], b1v = bias[n + 1];
                    *reinterpret_cast<float2*>(p0) =
                        make_float2(softplusf(c0 + b0v), softplusf(c1 + b1v));
                    *reinterpret_cast<float2*>(p1) =
                        make_float2(softplusf(c2 + b0v), softplusf(c3 + b1v));
                } else {
                    *reinterpret_cast<float2*>(p0) = make_float2(c0, c1);
                    *reinterpret_cast<float2*>(p1) = make_float2(c2, c3);
                }
            }
        }
    }
}

// ---------------- fp32 -> fp16 conversion (8 elts/thread) ----------------
__global__ void cvt_f2h(const float* __restrict__ src, __half* __restrict__ dst, long n) {
    long i = ((long)blockIdx.x * 256 + threadIdx.x) * 8;
    if (i >= n) return;
    float4 v0 = *reinterpret_cast<const float4*>(src + i);
    float4 v1 = *reinterpret_cast<const float4*>(src + i + 4);
    __half2 h[4];
    h[0] = __floats2half2_rn(v0.x, v0.y);
    h[1] = __floats2half2_rn(v0.z, v0.w);
    h[2] = __floats2half2_rn(v1.x, v1.y);
    h[3] = __floats2half2_rn(v1.z, v1.w);
    *reinterpret_cast<uint4*>(dst + i) = *reinterpret_cast<uint4*>(h);
}

// ---------------- LayerNorm 1 (tf32-rounded) ----------------
__global__ void ln1_kernel(const float* __restrict__ x, const float* __restrict__ g,
                           const float* __restrict__ bta, float* __restrict__ out) {
    int b  = blockIdx.x >> 7;
    int l0 = (blockIdx.x & 127) * 32;
    __shared__ float sm[128 * 33];
    int tid = threadIdx.x;
    #pragma unroll
    for (int i = 0; i < 16; i++) {
        int idx = tid + i * 256;
        int c = idx >> 5, l = idx & 31;
        sm[c * 33 + l] = x[((long)b * CH + c) * LL + l0 + l];
    }
    __syncthreads();
    int warp = tid >> 5, lane = tid & 31;
    for (int t = warp; t < 32; t += 8) {
        float v[4]; float s = 0.f, sq = 0.f;
        #pragma unroll
        for (int j = 0; j < 4; j++) {
            v[j] = sm[(lane + 32 * j) * 33 + t];
            s += v[j]; sq += v[j] * v[j];
        }
        #pragma unroll
        for (int o = 16; o; o >>= 1) {
            s  += __shfl_xor_sync(0xffffffffu, s,  o);
            sq += __shfl_xor_sync(0xffffffffu, sq, o);
        }
        float mu  = s * (1.f / 128.f);
        float var = sq * (1.f / 128.f) - mu * mu;
        float rs  = rsqrtf(var + 1e-5f);
        #pragma unroll
        for (int j = 0; j < 4; j++) {
            int c = lane + 32 * j;
            out[((long)b * LL + l0 + t) * D1M + c] = rnd_tf32((v[j] - mu) * rs * g[c] + bta[c]);
        }
    }
}

// ---------------- LayerNorm 2 (fp16 output) ----------------
__global__ void ln2_kernel(const float* __restrict__ x, const float* __restrict__ g,
                           const float* __restrict__ bta, __half* __restrict__ out) {
    long row = blockIdx.x;
    const float* xr = x + row * D2M;
    __half* orow = out + row * D2M;
    int tid = threadIdx.x;
    float v[16]; float s = 0.f, sq = 0.f;
    #pragma unroll
    for (int i = 0; i < 16; i++) {
        v[i] = xr[i * 256 + tid];
        s += v[i]; sq += v[i] * v[i];
    }
    #pragma unroll
    for (int o = 16; o; o >>= 1) {
        s  += __shfl_xor_sync(0xffffffffu, s,  o);
        sq += __shfl_xor_sync(0xffffffffu, sq, o);
    }
    __shared__ float ss[8], sqq[8];
    int lane = tid & 31, warp = tid >> 5;
    if (!lane) { ss[warp] = s; sqq[warp] = sq; }
    __syncthreads();
    s = 0.f; sq = 0.f;
    #pragma unroll
    for (int w = 0; w < 8; w++) { s += ss[w]; sq += sqq[w]; }
    float mu  = s * (1.f / 4096.f);
    float var = sq * (1.f / 4096.f) - mu * mu;
    float rs  = rsqrtf(var + 1e-5f);
    #pragma unroll
    for (int i = 0; i < 16; i++) {
        int col = i * 256 + tid;
        orow[col] = __float2half_rn((v[i] - mu) * rs * g[col] + bta[col]);
    }
}

// ---------------- fallback SGEMM (dt1: K=8) ----------------
template<int ACT, bool HASBIAS>
__global__ void sgemm_kernel(const float* __restrict__ X, const float* __restrict__ W,
                             const float* __restrict__ bias, float* __restrict__ out,
                             int M, int N, int K, int lda, int ldc) {
    constexpr int BM = 64, BN = 64, BK = 32, PAD = 4;
    __shared__ float As[BK][BM + PAD];
    __shared__ float Bs[BK][BN + PAD];
    int bm = blockIdx.y * BM, bn = blockIdx.x * BN;
    int tid = threadIdx.x;
    int tx = tid & 15, ty = tid >> 4;
    float acc[4][4] = {};
    for (int k0 = 0; k0 < K; k0 += BK) {
        #pragma unroll
        for (int i = 0; i < 2; i++) {
            int idx = tid + i * 256;
            int row = idx >> 3;
            int kc  = (idx & 7) << 2;
            int k   = k0 + kc;
            float4 va = make_float4(0.f, 0.f, 0.f, 0.f);
            float4 vb = make_float4(0.f, 0.f, 0.f, 0.f);
            if (k < K) {
                int m = bm + row;
                if (m < M) va = *reinterpret_cast<const float4*>(X + (long)m * lda + k);
                int n = bn + row;
                if (n < N) vb = *reinterpret_cast<const float4*>(W + (long)n * K + k);
            }
            As[kc][row] = va.x; As[kc + 1][row] = va.y; As[kc + 2][row] = va.z; As[kc + 3][row] = va.w;
            Bs[kc][row] = vb.x; Bs[kc + 1][row] = vb.y; Bs[kc + 2][row] = vb.z; Bs[kc + 3][row] = vb.w;
        }
        __syncthreads();
        #pragma unroll
        for (int kk = 0; kk < BK; kk++) {
            float4 a = *reinterpret_cast<const float4*>(&As[kk][ty << 2]);
            float4 b = *reinterpret_cast<const float4*>(&Bs[kk][tx << 2]);
            float av[4] = {a.x, a.y, a.z, a.w};
            float bv[4] = {b.x, b.y, b.z, b.w};
            #pragma unroll
            for (int i = 0; i < 4; i++)
                #pragma unroll
                for (int j = 0; j < 4; j++)
                    acc[i][j] += av[i] * bv[j];
        }
        __syncthreads();
    }
    #pragma unroll
    for (int i = 0; i < 4; i++) {
        int m = bm + (ty << 2) + i;
        if (m >= M) continue;
        #pragma unroll
        for (int j = 0; j < 4; j++) {
            int n = bn + (tx << 2) + j;
            if (n >= N) continue;
            float v = acc[i][j];
            if (HASBIAS) v += bias[n];
            if (ACT == 1) v = softplusf(v);
            out[(long)m * ldc + n] = v;
        }
    }
}

// ---------------- causal depthwise conv (K=4) + SiLU (path-1, fp32/tf32) ----------------
__global__ void conv_silu_kernel(const float* __restrict__ xz, const float* __restrict__ w,
                                 const float* __restrict__ bias, float* __restrict__ out,
                                 int Ltok, int dinner) {
    long tid = (long)blockIdx.x * 256 + threadIdx.x;
    long total = (long)BATCH * Ltok * (dinner / 4);
    if (tid >= total) return;
    int d4 = (int)(tid % (dinner / 4)) * 4;
    long t = tid / (dinner / 4);
    int l = (int)(t % Ltok);
    int b = (int)(t / Ltok);
    int rowstride = 2 * dinner;
    const float* base = xz + ((long)b * Ltok + l) * rowstride + d4;
    float4 bv = *reinterpret_cast<const float4*>(bias + d4);
    float acc0 = bv.x, acc1 = bv.y, acc2 = bv.z, acc3 = bv.w;
    #pragma unroll
    for (int k = 0; k < 4; k++) {
        int ll = l - 3 + k;
        if (ll >= 0) {
            float4 xv = *reinterpret_cast<const float4*>(base + (long)(ll - l) * rowstride);
            acc0 += xv.x * w[(d4 + 0) * 4 + k];
            acc1 += xv.y * w[(d4 + 1) * 4 + k];
            acc2 += xv.z * w[(d4 + 2) * 4 + k];
            acc3 += xv.w * w[(d4 + 3) * 4 + k];
        }
    }
    float4 ov;
    ov.x = rnd_tf32(siluf(acc0)); ov.y = rnd_tf32(siluf(acc1));
    ov.z = rnd_tf32(siluf(acc2)); ov.w = rnd_tf32(siluf(acc3));
    *reinterpret_cast<float4*>(out + ((long)b * Ltok + l) * dinner + d4) = ov;
}

// ---------------- path-1 scan ----------------
__global__ void scan1_partial(const float* __restrict__ delta, const float* __restrict__ xc,
                              const float* __restrict__ dbl, const float* __restrict__ Alog) {
    int d = threadIdx.x;
    int chunk = blockIdx.x & (NCH - 1);
    int b = blockIdx.x >> 5;
    float A[NS], h[NS], P[NS];
    #pragma unroll
    for (int s = 0; s < NS; s++) { A[s] = -__expf(Alog[d * NS + s]); h[s] = 0.f; P[s] = 1.f; }
    int l0 = chunk * CLEN;
    for (int i = 0; i < CLEN; i++) {
        long t = (long)b * LL + l0 + i;
        float dl = delta[t * D1I + d];
        float xv = xc[t * D1I + d];
        const float* bl = dbl + t * DBL1 + DT1R;
        float dx = dl * xv;
        #pragma unroll
        for (int s = 0; s < NS; s++) {
            float dA = __expf(dl * A[s]);
            h[s] = dA * h[s] + dx * bl[s];
            P[s] *= dA;
        }
    }
    long o = (((long)b * D1I + d) * NCH + chunk) * NS;
    #pragma unroll
    for (int s = 0; s < NS; s++) { g_ckP[o + s] = P[s]; g_ckH[o + s] = h[s]; }
}

__global__ void scan1_carry() {
    int idx = blockIdx.x * 256 + threadIdx.x;
    if (idx >= BATCH * D1I) return;
    long base = (long)idx * NCH * NS;
    float h[NS];
    #pragma unroll
    for (int s = 0; s < NS; s++) h[s] = 0.f;
    for (int c = 0; c < NCH; c++) {
        long o = base + (long)c * NS;
        #pragma unroll
        for (int s = 0; s < NS; s++) {
            g_hin[o + s] = h[s];
            h[s] = g_ckP[o + s] * h[s] + g_ckH[o + s];
        }
    }
}

__global__ void scan1_final(const float* __restrict__ delta, const float* __restrict__ xc,
                            const float* __restrict__ dbl, const float* __restrict__ Alog,
                            const float* __restrict__ Dp, const float* __restrict__ xz,
                            float* __restrict__ y) {
    int d = threadIdx.x;
    int chunk = blockIdx.x & (NCH - 1);
    int b = blockIdx.x >> 5;
    float A[NS], h[NS];
    long hb = (((long)b * D1I + d) * NCH + chunk) * NS;
    #pragma unroll
    for (int s = 0; s < NS; s++) { A[s] = -__expf(Alog[d * NS + s]); h[s] = g_hin[hb + s]; }
    float Dv = Dp[d];
    int l0 = chunk * CLEN;
    for (int i = 0; i < CLEN; i++) {
        long t = (long)b * LL + l0 + i;
        float dl = delta[t * D1I + d];
        float xv = xc[t * D1I + d];
        const float* bl = dbl + t * DBL1 + DT1R;
        float dx = dl * xv;
        float acc = 0.f;
        #pragma unroll
        for (int s = 0; s < NS; s++) {
            float dA = __expf(dl * A[s]);
            h[s] = dA * h[s] + dx * bl[s];
            acc += h[s] * bl[NS + s];
        }
        float z = xz[t * (2 * D1I) + D1I + d];
        y[t * D1I + d] = rnd_tf32((acc + xv * Dv) * siluf(z));
    }
}

// ---------------- path-2 scan (all-fp16 activations) ----------------
__global__ void scan2_kernel(const __half* __restrict__ delta, const __half* __restrict__ xc,
                             const float* __restrict__ dbl, const float* __restrict__ Alog,
                             const float* __restrict__ Dp, const __half* __restrict__ zh,
                             __half* __restrict__ y) {
    int d = (blockIdx.x & 31) * 256 + threadIdx.x;
    int b = blockIdx.x >> 5;
    float A[NS], h[NS];
    #pragma unroll
    for (int s = 0; s < NS; s++) { A[s] = -__expf(Alog[d * NS + s]); h[s] = 0.f; }
    float Dv = Dp[d];
    for (int l = 0; l < CH; l++) {
        long t = (long)b * CH + l;
        float dl = __half2float(delta[t * D2I + d]);
        float xv = __half2float(xc[t * D2I + d]);
        const float* bl = dbl + t * DBL2 + DT2R;
        float dx = dl * xv;
        float acc = 0.f;
        #pragma unroll
        for (int s = 0; s < NS; s++) {
            float dA = __expf(dl * A[s]);
            h[s] = dA * h[s] + dx * bl[s];
            acc += h[s] * bl[NS + s];
        }
        float z = __half2float(zh[t * D2I + d]);
        y[t * D2I + d] = __float2half_rn((acc + xv * Dv) * siluf(z));
    }
}

// ---------------- combine ----------------
__global__ void combine_kernel(const float* __restrict__ x, float* __restrict__ out) {
    long i = (long)blockIdx.x * 256 + threadIdx.x;
    if (i >= (long)BATCH * CH * LL) return;
    int l = (int)(i % LL);
    long t = i / LL;
    int c = (int)(t % CH);
    int b = (int)(t / CH);
    out[i] = x[i] + g_out2[i] + g_out1[((long)b * LL + l) * D1M + c];
}

// ---------------- launch ----------------
extern "C" void kernel_launch(void* const* d_in, const int* in_sizes, int n_in,
                              void* d_out, int out_size) {
    const float* x        = (const float*)d_in[0];
    const float* ln1_g    = (const float*)d_in[1];
    const float* ln1_b    = (const float*)d_in[2];
    const float* ln2_g    = (const float*)d_in[3];
    const float* ln2_b    = (const float*)d_in[4];
    const float* m1_in_w  = (const float*)d_in[5];
    const float* m1_cw    = (const float*)d_in[6];
    const float* m1_cb    = (const float*)d_in[7];
    const float* m1_xp_w  = (const float*)d_in[8];
    const float* m1_dt_w  = (const float*)d_in[9];
    const float* m1_dt_b  = (const float*)d_in[10];
    const float* m1_Alog  = (const float*)d_in[11];
    const float* m1_D     = (const float*)d_in[12];
    const float* m1_out_w = (const float*)d_in[13];
    const float* m2_in_w  = (const float*)d_in[14];
    const float* m2_cw    = (const float*)d_in[15];
    const float* m2_cb    = (const float*)d_in[16];
    const float* m2_xp_w  = (const float*)d_in[17];
    const float* m2_dt_w  = (const float*)d_in[18];
    const float* m2_dt_b  = (const float*)d_in[19];
    const float* m2_Alog  = (const float*)d_in[20];
    const float* m2_D     = (const float*)d_in[21];
    const float* m2_out_w = (const float*)d_in[22];
    float* out = (float*)d_out;

    float *pxn1, *pxz1, *pxc1, *pdbl1, *pdelta1, *py1, *pout1;
    float *pdbl2, *pout2;
    __half *pxn2h, *pxc2h, *pz2h, *pdelta2h, *py2h, *pdbl2h;
    cudaGetSymbolAddress((void**)&pxn1, g_xn1);
    cudaGetSymbolAddress((void**)&pxz1, g_xz1);
    cudaGetSymbolAddress((void**)&pxc1, g_xc1);
    cudaGetSymbolAddress((void**)&pdbl1, g_dbl1);
    cudaGetSymbolAddress((void**)&pdelta1, g_delta1);
    cudaGetSymbolAddress((void**)&py1, g_y1);
    cudaGetSymbolAddress((void**)&pout1, g_out1);
    cudaGetSymbolAddress((void**)&pdbl2, g_dbl2);
    cudaGetSymbolAddress((void**)&pout2, g_out2);
    cudaGetSymbolAddress((void**)&pxn2h, g_xn2h);
    cudaGetSymbolAddress((void**)&pxc2h, g_xc2h);
    cudaGetSymbolAddress((void**)&pz2h, g_z2h);
    cudaGetSymbolAddress((void**)&pdelta2h, g_delta2h);
    cudaGetSymbolAddress((void**)&py2h, g_y2h);
    cudaGetSymbolAddress((void**)&pdbl2h, g_dbl2h);

    cudaFuncSetAttribute(tf32_gemm<0>, cudaFuncAttributeMaxDynamicSharedMemorySize, GSMEM_BYTES);
    cudaFuncSetAttribute(tf32_gemm<1>, cudaFuncAttributeMaxDynamicSharedMemorySize, GSMEM_BYTES);
    cudaFuncSetAttribute(fp16w_gemm<1>, cudaFuncAttributeMaxDynamicSharedMemorySize, HSMEM_BYTES);
    cudaFuncSetAttribute(fp16w_gemm<3>, cudaFuncAttributeMaxDynamicSharedMemorySize, HSMEM_BYTES);
    cudaFuncSetAttribute(fp16w_gemm<5>, cudaFuncAttributeMaxDynamicSharedMemorySize, HSMEM_BYTES);

    static cudaStream_t s2 = nullptr;
    static cudaEvent_t evFork = nullptr, evJoin = nullptr;
    if (!s2) {
        cudaStreamCreateWithFlags(&s2, cudaStreamNonBlocking);
        cudaEventCreateWithFlags(&evFork, cudaEventDisableTiming);
        cudaEventCreateWithFlags(&evJoin, cudaEventDisableTiming);
    }

    const int T = 256;
    // fork at t=0
    cudaEventRecord(evFork, 0);
    cudaStreamWaitEvent(s2, evFork, 0);

    // ---- main: ln2, then MERGED in2 (xi: fused conv+SiLU->xc2h; z: fp16->z2h) ----
    cudaMemsetAsync(pdbl2, 0, sizeof(float) * BATCH * CH * DBL2);
    cudaMemsetAsync(pout2, 0, sizeof(float) * BATCH * CH * D2M);
    ln2_kernel<<<BATCH * CH, T>>>(x, ln2_g, ln2_b, pxn2h);
    fp16w_gemm<3><<<dim3(256, 1, 1), 256, HSMEM_BYTES>>>(
        pxn2h, m2_in_w, nullptr, nullptr, BATCH * CH, 2 * D2I, D2M, D2M, D2M, 2 * D2I,
        m2_cw, m2_cb, pxc2h, pz2h, D2I);

    // ---- s2: full path 1 ----
    cudaMemsetAsync(pout1, 0, sizeof(float) * BATCH * LL * D1M, s2);
    ln1_kernel<<<BATCH * (LL / 32), T, 0, s2>>>(x, ln1_g, ln1_b, pxn1);
    tf32_gemm<0><<<dim3(4, 64, 1), 256, GSMEM_BYTES, s2>>>(
        pxn1, m1_in_w, nullptr, pxz1, BATCH * LL, 2 * D1I, D1M, D1M, D1M, 2 * D1I);
    conv_silu_kernel<<<(BATCH * LL * D1I / 4 + T - 1) / T, T, 0, s2>>>(
        pxz1, m1_cw, m1_cb, pxc1, LL, D1I);
    tf32_gemm<0><<<dim3(1, 64, 1), 256, GSMEM_BYTES, s2>>>(
        pxc1, m1_xp_w, nullptr, pdbl1, BATCH * LL, DBL1, D1I, D1I, D1I, DBL1);
    sgemm_kernel<1, true><<<dim3((D1I + 63) / 64, (BATCH * LL) / 64), T, 0, s2>>>(
        pdbl1, m1_dt_w, m1_dt_b, pdelta1, BATCH * LL, D1I, DT1R, DBL1, D1I);
    scan1_partial<<<BATCH * NCH, D1I, 0, s2>>>(pdelta1, pxc1, pdbl1, m1_Alog);
    scan1_carry<<<(BATCH * D1I + T - 1) / T, T, 0, s2>>>();
    scan1_final<<<BATCH * NCH, D1I, 0, s2>>>(pdelta1, pxc1, pdbl1, m1_Alog, m1_D, pxz1, py1);
    tf32_gemm<1><<<dim3(1, 64, 2), 256, GSMEM_BYTES, s2>>>(
        py1, m1_out_w, nullptr, pout1, BATCH * LL, D1M, D1I / 2, D1I, D1I, D1M);
    cudaEventRecord(evJoin, s2);

    // ---- main: dependent chain ----
    // xp2: dbl2[256, 272] split-K=32 atomic (160 CTAs)
    fp16w_gemm<1><<<dim3(5, 1, 32), 256, HSMEM_BYTES>>>(
        pxc2h, m2_xp_w, nullptr, pdbl2, BATCH * CH, DBL2, D2I / 32, D2I, D2I, DBL2,
        nullptr, nullptr, nullptr, nullptr, 0);
    cvt_f2h<<<(int)(((long)BATCH * CH * DBL2) / 2048), T>>>(pdbl2, pdbl2h, (long)BATCH * CH * DBL2);
    // dt2: delta2h = softplus(dbl2h[:, :256] @ dt_w^T + b) -> fp16 (128 CTAs)
    fp16w_gemm<5><<<dim3(128, 1, 1), 256, HSMEM_BYTES>>>(
        pdbl2h, m2_dt_w, m2_dt_b, nullptr, BATCH * CH, D2I, DT2R, DBL2, DT2R, D2I,
        nullptr, nullptr, pdelta2h, nullptr, 0);
    scan2_kernel<<<BATCH * (D2I / 256), T>>>(pdelta2h, pxc2h, pdbl2, m2_Alog, m2_D, pz2h, py2h);
    // out2: split-K=4 atomic (256 CTAs)
    fp16w_gemm<1><<<dim3(64, 1, 4), 256, HSMEM_BYTES>>>(
        py2h, m2_out_w, nullptr, pout2, BATCH * CH, D2M, D2I / 4, D2I, D2I, D2M,
        nullptr, nullptr, nullptr, nullptr, 0);

    cudaStreamWaitEvent(0, evJoin, 0);
    combine_kernel<<<(BATCH * CH * LL + T - 1) / T, T>>>(x, out);
}